// round 2
// baseline (speedup 1.0000x reference)
#include <cuda_runtime.h>
#include <cuda_bf16.h>
#include <math_constants.h>

// Problem constants
#define NB   2      // batch
#define C    256
#define A    3
#define KTOP 20
#define D    256
#define BOXC 12     // A*BOX
#define MAXHW 10240

// ---------------- scratch (device globals; no allocation allowed) ----------
__device__ float g_t1[NB * C * MAXHW];
__device__ float g_t2[NB * C * MAXHW];
__device__ float g_o1[NB * MAXHW * D];   // o_proj, then h2
__device__ float g_o2[NB * MAXHW * D];   // k-summed h
__device__ float g_cell[NB * MAXHW];
__device__ float g_cand_hid[NB * C * 80];
__device__ float g_cand_sc[NB * 80];
__device__ int   g_keep[NB * KTOP];
__device__ float g_pproj[NB * KTOP * D];

// ---------------- conv3x3 (C=256 -> C=256), SAME, +bias, optional relu -----
#define CONV_TC 32
#define CONV_TH 4
#define CONV_TW 16
#define CONV_CI 16

__global__ __launch_bounds__(256)
void conv3x3_relu_kernel(const float* __restrict__ src,
                         const float* __restrict__ w,     // [C][C][3][3]
                         const float* __restrict__ bias,  // [C]
                         float* __restrict__ dst,
                         int H, int W, int relu_flag)
{
    const int tilesX = (W + CONV_TW - 1) / CONV_TW;
    const int tX = blockIdx.x % tilesX;
    const int tY = blockIdx.x / tilesX;
    const int ocBase = blockIdx.y * CONV_TC;
    const int n = blockIdx.z;
    const int h0 = tY * CONV_TH;
    const int w0 = tX * CONV_TW;
    const int HWs = H * W;
    const float* srcn = src + (size_t)n * C * HWs;

    __shared__ float s_in[CONV_CI][CONV_TH + 2][CONV_TW + 2];
    __shared__ float s_w[CONV_CI * 9][CONV_TC];

    const int tid = threadIdx.x;
    const int pxpair = tid & 31;            // 0..31 (2 adjacent px each)
    const int ocg = tid >> 5;               // 0..7  (4 oc each)
    const int row = (2 * pxpair) >> 4;      // 0..3
    const int c0  = (2 * pxpair) & 15;      // even column in tile

    float acc[4][2];
#pragma unroll
    for (int i = 0; i < 4; i++) { acc[i][0] = 0.f; acc[i][1] = 0.f; }

    for (int cb = 0; cb < C; cb += CONV_CI) {
        __syncthreads();
        // input tile with halo: 16 x 6 x 18
        for (int idx = tid; idx < CONV_CI * (CONV_TH + 2) * (CONV_TW + 2); idx += 256) {
            int ci  = idx / ((CONV_TH + 2) * (CONV_TW + 2));
            int rem = idx % ((CONV_TH + 2) * (CONV_TW + 2));
            int r  = rem / (CONV_TW + 2);
            int cc = rem % (CONV_TW + 2);
            int gh = h0 + r - 1;
            int gw = w0 + cc - 1;
            float v = 0.f;
            if (gh >= 0 && gh < H && gw >= 0 && gw < W)
                v = srcn[(size_t)(cb + ci) * HWs + gh * W + gw];
            s_in[ci][r][cc] = v;
        }
        // weights: 32 oc x 16 ci x 9 taps, stored [ci*9+tap][oc]
        for (int idx = tid; idx < CONV_TC * CONV_CI * 9; idx += 256) {
            int oc  = idx / (CONV_CI * 9);
            int rem = idx % (CONV_CI * 9);
            s_w[rem][oc] = w[((size_t)(ocBase + oc) * C + cb) * 9 + rem];
        }
        __syncthreads();

#pragma unroll
        for (int ci = 0; ci < CONV_CI; ci++) {
            float iv[3][4];
#pragma unroll
            for (int r = 0; r < 3; r++) {
                float2 a = *(const float2*)&s_in[ci][row + r][c0];
                float2 b = *(const float2*)&s_in[ci][row + r][c0 + 2];
                iv[r][0] = a.x; iv[r][1] = a.y; iv[r][2] = b.x; iv[r][3] = b.y;
            }
#pragma unroll
            for (int kh = 0; kh < 3; kh++)
#pragma unroll
            for (int kw = 0; kw < 3; kw++) {
                float4 wv = *(const float4*)&s_w[ci * 9 + kh * 3 + kw][ocg * 4];
                float v0 = iv[kh][kw], v1 = iv[kh][kw + 1];
                acc[0][0] += wv.x * v0; acc[0][1] += wv.x * v1;
                acc[1][0] += wv.y * v0; acc[1][1] += wv.y * v1;
                acc[2][0] += wv.z * v0; acc[2][1] += wv.z * v1;
                acc[3][0] += wv.w * v0; acc[3][1] += wv.w * v1;
            }
        }
    }

    const int gh = h0 + row;
    if (gh < H) {
#pragma unroll
        for (int j = 0; j < 4; j++) {
            int oc = ocBase + ocg * 4 + j;
            float b = bias[oc];
#pragma unroll
            for (int p = 0; p < 2; p++) {
                int gw = w0 + c0 + p;
                if (gw < W) {
                    float v = acc[j][p] + b;
                    if (relu_flag) v = fmaxf(v, 0.f);
                    dst[((size_t)n * C + oc) * HWs + gh * W + gw] = v;
                }
            }
        }
    }
}

// ---------------- person heads: 1x1 logits(A) + deltas(12) + cell score ----
__global__ __launch_bounds__(256)
void heads_p_kernel(const float* __restrict__ hid,
                    const float* __restrict__ pl_w, const float* __restrict__ pl_b,
                    const float* __restrict__ pd_w, const float* __restrict__ pd_b,
                    float* __restrict__ plog_out,   // [N][A][HW]
                    float* __restrict__ pdel_out,   // [N][12][HW]
                    float* __restrict__ cell,       // [N][HW]
                    int HW)
{
    __shared__ float swl[A * C];
    __shared__ float swd[BOXC * C];
    const int tid = threadIdx.x;
    for (int i = tid; i < A * C; i += 256) swl[i] = pl_w[i];
    for (int i = tid; i < BOXC * C; i += 256) swd[i] = pd_w[i];
    __syncthreads();

    const int p = blockIdx.x * 256 + tid;
    const int n = blockIdx.y;
    if (p >= HW) return;
    const float* h = hid + (size_t)n * C * HW + p;

    float accl[A], accd[BOXC];
#pragma unroll
    for (int a = 0; a < A; a++) accl[a] = pl_b[a];
#pragma unroll
    for (int j = 0; j < BOXC; j++) accd[j] = pd_b[j];

    for (int c = 0; c < C; c++) {
        float v = h[(size_t)c * HW];
#pragma unroll
        for (int a = 0; a < A; a++) accl[a] += swl[a * C + c] * v;
#pragma unroll
        for (int j = 0; j < BOXC; j++) accd[j] += swd[j * C + c] * v;
    }
    float m = accl[0];
#pragma unroll
    for (int a = 0; a < A; a++) {
        plog_out[((size_t)n * A + a) * HW + p] = accl[a];
        m = fmaxf(m, accl[a]);
    }
#pragma unroll
    for (int j = 0; j < BOXC; j++)
        pdel_out[((size_t)n * BOXC + j) * HW + p] = accd[j];
    cell[(size_t)n * HW + p] = m;
}

// ---------------- object delta head: 1x1 (12) ------------------------------
__global__ __launch_bounds__(256)
void heads_od_kernel(const float* __restrict__ hid,
                     const float* __restrict__ od_w, const float* __restrict__ od_b,
                     float* __restrict__ odel_out, int HW)
{
    __shared__ float sw[BOXC * C];
    const int tid = threadIdx.x;
    for (int i = tid; i < BOXC * C; i += 256) sw[i] = od_w[i];
    __syncthreads();

    const int p = blockIdx.x * 256 + tid;
    const int n = blockIdx.y;
    if (p >= HW) return;
    const float* h = hid + (size_t)n * C * HW + p;

    float acc[BOXC];
#pragma unroll
    for (int j = 0; j < BOXC; j++) acc[j] = od_b[j];
    for (int c = 0; c < C; c++) {
        float v = h[(size_t)c * HW];
#pragma unroll
        for (int j = 0; j < BOXC; j++) acc[j] += sw[j * C + c] * v;
    }
#pragma unroll
    for (int j = 0; j < BOXC; j++)
        odel_out[((size_t)n * BOXC + j) * HW + p] = acc[j];
}

// ---------------- per-scale top-K + hidden gather --------------------------
__global__ __launch_bounds__(256)
void topk_scale_kernel(const float* __restrict__ cell,
                       const float* __restrict__ hid,
                       float* __restrict__ cand_hid,  // [N][C][80]
                       float* __restrict__ cand_sc,   // [N][80]
                       int HW, int slot0)
{
    const int n = blockIdx.x;
    const int tid = threadIdx.x;
    __shared__ float s_val[256];
    __shared__ int   s_idx[256];
    __shared__ int   sel[KTOP];
    const float* cs = cell + (size_t)n * HW;

    for (int k = 0; k < KTOP; k++) {
        float best = -CUDART_INF_F;
        int bi = HW;  // sentinel (largest index)
        for (int i = tid; i < HW; i += 256) {
            bool ex = false;
            for (int j = 0; j < k; j++) if (sel[j] == i) ex = true;
            if (ex) continue;
            float v = cs[i];
            if (v > best || (v == best && i < bi)) { best = v; bi = i; }
        }
        s_val[tid] = best; s_idx[tid] = bi;
        __syncthreads();
        for (int off = 128; off > 0; off >>= 1) {
            if (tid < off) {
                float v2 = s_val[tid + off]; int i2 = s_idx[tid + off];
                if (v2 > s_val[tid] || (v2 == s_val[tid] && i2 < s_idx[tid])) {
                    s_val[tid] = v2; s_idx[tid] = i2;
                }
            }
            __syncthreads();
        }
        if (tid == 0) {
            sel[k] = s_idx[0];
            cand_sc[(size_t)n * 80 + slot0 + k] = s_val[0];
        }
        __syncthreads();
    }
    // gather hidden vectors at selected cells
    for (int idx = tid; idx < C * KTOP; idx += 256) {
        int c = idx / KTOP, k = idx % KTOP;
        cand_hid[((size_t)n * C + c) * 80 + slot0 + k] =
            hid[((size_t)n * C + c) * HW + sel[k]];
    }
}

// ---------------- global top-K over 80 candidates ---------------------------
__global__ void topk_global_kernel(const float* __restrict__ sc, int* __restrict__ keep)
{
    const int n = blockIdx.x;
    bool used[80];
    for (int i = 0; i < 80; i++) used[i] = false;
    const float* s = sc + (size_t)n * 80;
    for (int k = 0; k < KTOP; k++) {
        float best = -CUDART_INF_F; int bi = 0;
        for (int i = 0; i < 80; i++) {
            if (!used[i] && s[i] > best) { best = s[i]; bi = i; }
        }
        used[bi] = true;
        keep[n * KTOP + k] = bi;
    }
}

// ---------------- p_proj = pf @ Wp^T + b  (tiny GEMM) -----------------------
__global__ __launch_bounds__(256)
void pproj_kernel(const float* __restrict__ cand_hid, const int* __restrict__ keep,
                  const float* __restrict__ rn1_w, const float* __restrict__ rn1_b,
                  float* __restrict__ pproj)
{
    const int k = blockIdx.x, n = blockIdx.y, d = threadIdx.x;
    __shared__ float sh[C];
    const int col = keep[n * KTOP + k];
    sh[d] = cand_hid[((size_t)n * C + d) * 80 + col];
    __syncthreads();
    float acc = rn1_b[d];
    const float* wrow = rn1_w + (size_t)d * (2 * C) + C;  // Wp
    for (int c = 0; c < C; c++) acc += sh[c] * wrow[c];
    pproj[((size_t)n * KTOP + k) * D + d] = acc;
}

// ---------------- o_proj GEMM: out[n][s][d] = sum_c hid[n][c][s]*Wo[d][c] ---
__global__ __launch_bounds__(256)
void gemm_oproj_kernel(const float* __restrict__ hid, const float* __restrict__ rn1_w,
                       float* __restrict__ oproj, int HW)
{
    __shared__ float As[16][66];
    __shared__ float Bs[16][66];
    const int n = blockIdx.z;
    const int s0 = blockIdx.x * 64;
    const int d0 = blockIdx.y * 64;
    const int tid = threadIdx.x;
    const int td = tid % 16, ts = tid / 16;
    float acc[4][4];
#pragma unroll
    for (int i = 0; i < 4; i++)
#pragma unroll
        for (int j = 0; j < 4; j++) acc[i][j] = 0.f;
    const float* hb = hid + (size_t)n * C * HW;

    for (int cb = 0; cb < C; cb += 16) {
        for (int i = tid; i < 16 * 64; i += 256) {
            int c = i / 64, s = i % 64;
            int gs = s0 + s;
            As[c][s] = (gs < HW) ? hb[(size_t)(cb + c) * HW + gs] : 0.f;
        }
        for (int i = tid; i < 64 * 16; i += 256) {
            int d = i / 16, c = i % 16;
            Bs[c][d] = rn1_w[(size_t)(d0 + d) * (2 * C) + cb + c];  // Wo
        }
        __syncthreads();
#pragma unroll
        for (int c = 0; c < 16; c++) {
            float a[4], b[4];
#pragma unroll
            for (int i = 0; i < 4; i++) a[i] = As[c][ts * 4 + i];
#pragma unroll
            for (int i = 0; i < 4; i++) b[i] = Bs[c][td * 4 + i];
#pragma unroll
            for (int i = 0; i < 4; i++)
#pragma unroll
                for (int j = 0; j < 4; j++) acc[i][j] += a[i] * b[j];
        }
        __syncthreads();
    }
#pragma unroll
    for (int i = 0; i < 4; i++) {
        int gs = s0 + ts * 4 + i;
        if (gs < HW)
#pragma unroll
            for (int j = 0; j < 4; j++)
                oproj[((size_t)n * HW + gs) * D + d0 + td * 4 + j] = acc[i][j];
    }
}

// ---------------- h[n][s][d] = sum_k relu(o_proj + p_proj_k) ----------------
__global__ __launch_bounds__(256)
void hsum_kernel(const float* __restrict__ oproj, const float* __restrict__ pproj,
                 float* __restrict__ hout, int HW)
{
    const int s = blockIdx.x, n = blockIdx.y, d = threadIdx.x;
    const float o = oproj[((size_t)n * HW + s) * D + d];
    float acc = 0.f;
#pragma unroll 4
    for (int k = 0; k < KTOP; k++)
        acc += fmaxf(o + pproj[((size_t)n * KTOP + k) * D + d], 0.f);
    hout[((size_t)n * HW + s) * D + d] = acc;
}

// ---------------- rn2 GEMM: out = relu(h @ rn2^T + b) -----------------------
__global__ __launch_bounds__(256)
void gemm_rn2_kernel(const float* __restrict__ hin, const float* __restrict__ rn2_w,
                     const float* __restrict__ rn2_b,
                     float* __restrict__ hout, int HW)
{
    __shared__ float As[16][66];
    __shared__ float Bs[16][66];
    const int n = blockIdx.z;
    const int s0 = blockIdx.x * 64;
    const int e0 = blockIdx.y * 64;
    const int tid = threadIdx.x;
    const int td = tid % 16, ts = tid / 16;
    float acc[4][4];
#pragma unroll
    for (int i = 0; i < 4; i++)
#pragma unroll
        for (int j = 0; j < 4; j++) acc[i][j] = 0.f;

    for (int db = 0; db < D; db += 16) {
        for (int i = tid; i < 64 * 16; i += 256) {
            int s = i / 16, c = i % 16;
            int gs = s0 + s;
            As[c][s] = (gs < HW) ? hin[((size_t)n * HW + gs) * D + db + c] : 0.f;
        }
        for (int i = tid; i < 64 * 16; i += 256) {
            int e = i / 16, c = i % 16;
            Bs[c][e] = rn2_w[(size_t)(e0 + e) * D + db + c];
        }
        __syncthreads();
#pragma unroll
        for (int c = 0; c < 16; c++) {
            float a[4], b[4];
#pragma unroll
            for (int i = 0; i < 4; i++) a[i] = As[c][ts * 4 + i];
#pragma unroll
            for (int i = 0; i < 4; i++) b[i] = Bs[c][td * 4 + i];
#pragma unroll
            for (int i = 0; i < 4; i++)
#pragma unroll
                for (int j = 0; j < 4; j++) acc[i][j] += a[i] * b[j];
        }
        __syncthreads();
    }
#pragma unroll
    for (int i = 0; i < 4; i++) {
        int gs = s0 + ts * 4 + i;
        if (gs < HW)
#pragma unroll
            for (int j = 0; j < 4; j++) {
                int e = e0 + td * 4 + j;
                float v = acc[i][j] + rn2_b[e];
                hout[((size_t)n * HW + gs) * D + e] = fmaxf(v, 0.f);
            }
    }
}

// ---------------- ol head: o_log[n][a][s] = h2 . ol_w[a] + b ----------------
__global__ __launch_bounds__(256)
void ol_kernel(const float* __restrict__ h2, const float* __restrict__ ol_w,
               const float* __restrict__ ol_b, float* __restrict__ olog_out, int HW)
{
    const int tid = threadIdx.x;
    const int warp = tid >> 5, lane = tid & 31;
    const int n = blockIdx.y;
    const int s = blockIdx.x * 8 + warp;
    if (s >= HW) return;
    const float* h = h2 + ((size_t)n * HW + s) * D;
    float a0 = 0.f, a1 = 0.f, a2 = 0.f;
    for (int d = lane; d < D; d += 32) {
        float v = h[d];
        a0 += v * ol_w[d];
        a1 += v * ol_w[D + d];
        a2 += v * ol_w[2 * D + d];
    }
#pragma unroll
    for (int off = 16; off > 0; off >>= 1) {
        a0 += __shfl_down_sync(0xFFFFFFFFu, a0, off);
        a1 += __shfl_down_sync(0xFFFFFFFFu, a1, off);
        a2 += __shfl_down_sync(0xFFFFFFFFu, a2, off);
    }
    if (lane == 0) {
        olog_out[((size_t)n * A + 0) * HW + s] = a0 + ol_b[0];
        olog_out[((size_t)n * A + 1) * HW + s] = a1 + ol_b[1];
        olog_out[((size_t)n * A + 2) * HW + s] = a2 + ol_b[2];
    }
}

// ---------------------------- host orchestration ----------------------------
extern "C" void kernel_launch(void* const* d_in, const int* in_sizes, int n_in,
                              void* d_out, int out_size)
{
    const float* feats[4] = {(const float*)d_in[0], (const float*)d_in[1],
                             (const float*)d_in[2], (const float*)d_in[3]};
    const float* pc1_w = (const float*)d_in[4];
    const float* pc1_b = (const float*)d_in[5];
    const float* pc2_w = (const float*)d_in[6];
    const float* pc2_b = (const float*)d_in[7];
    const float* oc1_w = (const float*)d_in[8];
    const float* oc1_b = (const float*)d_in[9];
    const float* oc2_w = (const float*)d_in[10];
    const float* oc2_b = (const float*)d_in[11];
    const float* rn1_w = (const float*)d_in[12];
    const float* rn1_b = (const float*)d_in[13];
    const float* rn2_w = (const float*)d_in[14];
    const float* rn2_b = (const float*)d_in[15];
    const float* pl_w  = (const float*)d_in[16];
    const float* pl_b  = (const float*)d_in[17];
    const float* pd_w  = (const float*)d_in[18];
    const float* pd_b  = (const float*)d_in[19];
    const float* ol_w  = (const float*)d_in[20];
    const float* ol_b  = (const float*)d_in[21];
    const float* od_w  = (const float*)d_in[22];
    const float* od_b  = (const float*)d_in[23];
    float* out = (float*)d_out;

    float *t1, *t2, *o1, *o2, *cell, *cand_hid, *cand_sc, *pproj;
    int* keep;
    cudaGetSymbolAddress((void**)&t1, g_t1);
    cudaGetSymbolAddress((void**)&t2, g_t2);
    cudaGetSymbolAddress((void**)&o1, g_o1);
    cudaGetSymbolAddress((void**)&o2, g_o2);
    cudaGetSymbolAddress((void**)&cell, g_cell);
    cudaGetSymbolAddress((void**)&cand_hid, g_cand_hid);
    cudaGetSymbolAddress((void**)&cand_sc, g_cand_sc);
    cudaGetSymbolAddress((void**)&keep, g_keep);
    cudaGetSymbolAddress((void**)&pproj, g_pproj);

    static const int Hs[4]  = {80, 40, 20, 10};
    static const int Ws[4]  = {128, 64, 32, 16};
    static const int HWv[4] = {10240, 2560, 640, 160};
    static const int plog_off[4] = {0,      61440,  76800,  80640};
    static const int pdel_off[4] = {81600,  327360, 388800, 404160};
    static const int olog_off[4] = {408000, 469440, 484800, 488640};
    static const int odel_off[4] = {489600, 735360, 796800, 812160};

    // ---- person branch per scale + per-scale top-k ----
    for (int s = 0; s < 4; s++) {
        int H = Hs[s], W = Ws[s], HW = HWv[s];
        dim3 cg(((W + CONV_TW - 1) / CONV_TW) * ((H + CONV_TH - 1) / CONV_TH), C / CONV_TC, NB);
        conv3x3_relu_kernel<<<cg, 256>>>(feats[s], pc1_w, pc1_b, t1, H, W, 1);
        conv3x3_relu_kernel<<<cg, 256>>>(t1, pc2_w, pc2_b, t2, H, W, 1);
        dim3 hg((HW + 255) / 256, NB);
        heads_p_kernel<<<hg, 256>>>(t2, pl_w, pl_b, pd_w, pd_b,
                                    out + plog_off[s], out + pdel_off[s], cell, HW);
        topk_scale_kernel<<<NB, 256>>>(cell, t2, cand_hid, cand_sc, HW, s * KTOP);
    }

    // ---- global top-k + p_proj ----
    topk_global_kernel<<<NB, 1>>>(cand_sc, keep);
    pproj_kernel<<<dim3(KTOP, NB), 256>>>(cand_hid, keep, rn1_w, rn1_b, pproj);

    // ---- object branch per scale ----
    for (int s = 0; s < 4; s++) {
        int H = Hs[s], W = Ws[s], HW = HWv[s];
        dim3 cg(((W + CONV_TW - 1) / CONV_TW) * ((H + CONV_TH - 1) / CONV_TH), C / CONV_TC, NB);
        conv3x3_relu_kernel<<<cg, 256>>>(feats[s], oc1_w, oc1_b, t1, H, W, 1);
        conv3x3_relu_kernel<<<cg, 256>>>(t1, oc2_w, oc2_b, t2, H, W, 1);
        dim3 hg((HW + 255) / 256, NB);
        heads_od_kernel<<<hg, 256>>>(t2, od_w, od_b, out + odel_off[s], HW);
        dim3 gg((HW + 63) / 64, D / 64, NB);
        gemm_oproj_kernel<<<gg, 256>>>(t2, rn1_w, o1, HW);
        hsum_kernel<<<dim3(HW, NB), 256>>>(o1, pproj, o2, HW);
        gemm_rn2_kernel<<<gg, 256>>>(o2, rn2_w, rn2_b, o1, HW);
        ol_kernel<<<dim3((HW + 7) / 8, NB), 256>>>(o1, ol_w, ol_b, out + olog_off[s], HW);
    }
    (void)in_sizes; (void)n_in; (void)out_size;
}

// round 3
// speedup vs baseline: 2.3056x; 2.3056x over previous
#include <cuda_runtime.h>
#include <cuda_bf16.h>
#include <math_constants.h>

// Problem constants
#define NB   2
#define C    256
#define A    3
#define KTOP 20
#define D    256
#define BOXC 12
#define SUMHW 13600   // 10240 + 2560 + 640 + 160

// ---------------- scratch (device globals) ----------------------------------
__device__ float g_t1[NB * C * SUMHW];
__device__ float g_t2[NB * C * SUMHW];
__device__ float g_o1[NB * SUMHW * D];
__device__ float g_o2[NB * SUMHW * D];
__device__ float g_cell[NB * SUMHW];
__device__ float g_cand_hid[NB * C * 80];
__device__ float g_cand_sc[NB * 80];
__device__ int   g_keep[NB * KTOP];
__device__ float g_pproj[NB * KTOP * D];

// per-scale constants
__device__ __constant__ int cOFF[4]  = {0, 10240, 12800, 13440};
__device__ __constant__ int cHW[4]   = {10240, 2560, 640, 160};
__device__ __constant__ int cH[4]    = {80, 40, 20, 10};
__device__ __constant__ int cW[4]    = {128, 64, 32, 16};
__device__ __constant__ int cPLOG[4] = {0,      61440,  76800,  80640};
__device__ __constant__ int cPDEL[4] = {81600,  327360, 388800, 404160};
__device__ __constant__ int cOLOG[4] = {408000, 469440, 484800, 488640};
__device__ __constant__ int cODEL[4] = {489600, 735360, 796800, 812160};

__device__ __forceinline__ int scale_of(int p) {
    return (p < 10240) ? 0 : (p < 12800) ? 1 : (p < 13440) ? 2 : 3;
}

// ---------------- conv3x3 all scales, flat output layout --------------------
// block: 256 thr = 8 ocg x 32 pxg; each thread 8 oc x 4 px; block tile 64oc x (8x16)px
#define CTH 8
#define CTW 16
#define CCI 8

__global__ __launch_bounds__(256, 2)
void conv3x3_flat(const float* __restrict__ f0, const float* __restrict__ f1,
                  const float* __restrict__ f2, const float* __restrict__ f3,
                  const float* __restrict__ w,     // [C][C][3][3]
                  const float* __restrict__ bias,
                  float* __restrict__ dst,         // [n][C][SUMHW]
                  int layer1)
{
    __shared__ __align__(16) float s_in[CCI][10][20];
    __shared__ __align__(16) float s_w[CCI * 9][68];

    const int bx = blockIdx.x;
    int s, t;
    if (bx < 80)       { s = 0; t = bx; }
    else if (bx < 100) { s = 1; t = bx - 80; }
    else if (bx < 106) { s = 2; t = bx - 100; }
    else               { s = 3; t = bx - 106; }
    const int H = cH[s], W = cW[s];
    const int tilesX = (W + CTW - 1) / CTW;
    const int tY = t / tilesX, tX = t % tilesX;
    const int h0 = tY * CTH, w0 = tX * CTW;
    const int n = blockIdx.z;
    const int ocBase = blockIdx.y * 64;

    const float* srcs = (s == 0) ? f0 : (s == 1) ? f1 : (s == 2) ? f2 : f3;
    const int srcCS  = layer1 ? (H * W) : SUMHW;
    const int srcOff = layer1 ? 0 : cOFF[s];
    const float* src = srcs + (size_t)n * C * srcCS + srcOff;

    const int tid = threadIdx.x;
    const int ocg = tid >> 5;
    const int pxg = tid & 31;
    const int row = pxg >> 2;
    const int c4  = (pxg & 3) * 4;

    float acc[8][4];
#pragma unroll
    for (int j = 0; j < 8; j++)
#pragma unroll
        for (int p = 0; p < 4; p++) acc[j][p] = 0.f;

    for (int cb = 0; cb < C; cb += CCI) {
        __syncthreads();
        // input tile + halo: CCI x 10 x 18
        for (int idx = tid; idx < CCI * 10 * 18; idx += 256) {
            int ci = idx / 180;
            int rem = idx % 180;
            int r = rem / 18, cc = rem % 18;
            int gh = h0 + r - 1, gw = w0 + cc - 1;
            float v = 0.f;
            if (gh >= 0 && gh < H && gw >= 0 && gw < W)
                v = src[(size_t)(cb + ci) * srcCS + gh * W + gw];
            s_in[ci][r][cc] = v;
        }
        // weights: 64 oc x (8 ci x 9 taps), gmem-contiguous over (ci,tap)
        for (int idx = tid; idx < 64 * 72; idx += 256) {
            int oc = idx / 72, ct = idx % 72;
            s_w[ct][oc] = w[((size_t)(ocBase + oc) * C + cb) * 9 + ct];
        }
        __syncthreads();

#pragma unroll 2
        for (int ci = 0; ci < CCI; ci++) {
            float iv[3][6];
#pragma unroll
            for (int r = 0; r < 3; r++) {
                float4 a = *(const float4*)&s_in[ci][row + r][c4];
                float2 b = *(const float2*)&s_in[ci][row + r][c4 + 4];
                iv[r][0] = a.x; iv[r][1] = a.y; iv[r][2] = a.z;
                iv[r][3] = a.w; iv[r][4] = b.x; iv[r][5] = b.y;
            }
#pragma unroll
            for (int kh = 0; kh < 3; kh++)
#pragma unroll
            for (int kw = 0; kw < 3; kw++) {
                const float* wr = &s_w[ci * 9 + kh * 3 + kw][ocg * 8];
                float4 w0v = *(const float4*)wr;
                float4 w1v = *(const float4*)(wr + 4);
#pragma unroll
                for (int p = 0; p < 4; p++) {
                    float v = iv[kh][kw + p];
                    acc[0][p] += w0v.x * v; acc[1][p] += w0v.y * v;
                    acc[2][p] += w0v.z * v; acc[3][p] += w0v.w * v;
                    acc[4][p] += w1v.x * v; acc[5][p] += w1v.y * v;
                    acc[6][p] += w1v.z * v; acc[7][p] += w1v.w * v;
                }
            }
        }
    }

    const int gh = h0 + row;
    if (gh < H) {
        float* dn = dst + (size_t)n * C * SUMHW + cOFF[s] + gh * W + w0 + c4;
#pragma unroll
        for (int j = 0; j < 8; j++) {
            int oc = ocBase + ocg * 8 + j;
            float b = bias[oc];
            float* dp = dn + (size_t)oc * SUMHW;
#pragma unroll
            for (int p = 0; p < 4; p++) {
                int gw = w0 + c4 + p;
                if (gw < W) dp[p] = fmaxf(acc[j][p] + b, 0.f);
            }
        }
    }
}

// ---------------- person heads flat -----------------------------------------
__global__ __launch_bounds__(256)
void heads_p_flat(const float* __restrict__ hid,
                  const float* __restrict__ pl_w, const float* __restrict__ pl_b,
                  const float* __restrict__ pd_w, const float* __restrict__ pd_b,
                  float* __restrict__ out, float* __restrict__ cell)
{
    __shared__ float swl[A * C];
    __shared__ float swd[BOXC * C];
    const int tid = threadIdx.x;
    for (int i = tid; i < A * C; i += 256) swl[i] = pl_w[i];
    for (int i = tid; i < BOXC * C; i += 256) swd[i] = pd_w[i];
    __syncthreads();

    const int p = blockIdx.x * 256 + tid;
    const int n = blockIdx.y;
    if (p >= SUMHW) return;
    const int s = scale_of(p);
    const int ploc = p - cOFF[s];
    const int HW = cHW[s];
    const float* h = hid + (size_t)n * C * SUMHW + p;

    float accl[A], accd[BOXC];
#pragma unroll
    for (int a = 0; a < A; a++) accl[a] = pl_b[a];
#pragma unroll
    for (int j = 0; j < BOXC; j++) accd[j] = pd_b[j];

    for (int c = 0; c < C; c++) {
        float v = h[(size_t)c * SUMHW];
#pragma unroll
        for (int a = 0; a < A; a++) accl[a] += swl[a * C + c] * v;
#pragma unroll
        for (int j = 0; j < BOXC; j++) accd[j] += swd[j * C + c] * v;
    }
    float m = accl[0];
#pragma unroll
    for (int a = 0; a < A; a++) {
        out[cPLOG[s] + ((size_t)n * A + a) * HW + ploc] = accl[a];
        m = fmaxf(m, accl[a]);
    }
#pragma unroll
    for (int j = 0; j < BOXC; j++)
        out[cPDEL[s] + ((size_t)n * BOXC + j) * HW + ploc] = accd[j];
    cell[(size_t)n * SUMHW + p] = m;
}

// ---------------- object delta head flat ------------------------------------
__global__ __launch_bounds__(256)
void heads_od_flat(const float* __restrict__ hid,
                   const float* __restrict__ od_w, const float* __restrict__ od_b,
                   float* __restrict__ out)
{
    __shared__ float sw[BOXC * C];
    const int tid = threadIdx.x;
    for (int i = tid; i < BOXC * C; i += 256) sw[i] = od_w[i];
    __syncthreads();

    const int p = blockIdx.x * 256 + tid;
    const int n = blockIdx.y;
    if (p >= SUMHW) return;
    const int s = scale_of(p);
    const int ploc = p - cOFF[s];
    const int HW = cHW[s];
    const float* h = hid + (size_t)n * C * SUMHW + p;

    float acc[BOXC];
#pragma unroll
    for (int j = 0; j < BOXC; j++) acc[j] = od_b[j];
    for (int c = 0; c < C; c++) {
        float v = h[(size_t)c * SUMHW];
#pragma unroll
        for (int j = 0; j < BOXC; j++) acc[j] += sw[j * C + c] * v;
    }
#pragma unroll
    for (int j = 0; j < BOXC; j++)
        out[cODEL[s] + ((size_t)n * BOXC + j) * HW + ploc] = acc[j];
}

// ---------------- per-scale top-K (smem-cached) -----------------------------
__global__ __launch_bounds__(256)
void topk_flat(const float* __restrict__ cell, const float* __restrict__ hid,
               float* __restrict__ cand_hid, float* __restrict__ cand_sc)
{
    const int s = blockIdx.x;
    const int n = blockIdx.y;
    const int HW = cHW[s], off = cOFF[s];
    __shared__ float sc[10240];
    __shared__ float s_val[256];
    __shared__ int   s_idx[256];
    __shared__ int   sel[KTOP];
    const int tid = threadIdx.x;

    for (int i = tid; i < HW; i += 256)
        sc[i] = cell[(size_t)n * SUMHW + off + i];
    __syncthreads();

    for (int k = 0; k < KTOP; k++) {
        float best = -CUDART_INF_F;
        int bi = HW;
        for (int i = tid; i < HW; i += 256) {
            float v = sc[i];
            if (v > best) { best = v; bi = i; }   // strided ascending: strict > keeps smallest idx
        }
        s_val[tid] = best; s_idx[tid] = bi;
        __syncthreads();
        for (int offr = 128; offr > 0; offr >>= 1) {
            if (tid < offr) {
                float v2 = s_val[tid + offr]; int i2 = s_idx[tid + offr];
                if (v2 > s_val[tid] || (v2 == s_val[tid] && i2 < s_idx[tid])) {
                    s_val[tid] = v2; s_idx[tid] = i2;
                }
            }
            __syncthreads();
        }
        if (tid == 0) {
            sel[k] = s_idx[0];
            cand_sc[(size_t)n * 80 + s * KTOP + k] = s_val[0];
            sc[s_idx[0]] = -CUDART_INF_F;
        }
        __syncthreads();
    }
    for (int idx = tid; idx < C * KTOP; idx += 256) {
        int c = idx / KTOP, k = idx % KTOP;
        cand_hid[((size_t)n * C + c) * 80 + s * KTOP + k] =
            hid[((size_t)n * C + c) * SUMHW + off + sel[k]];
    }
}

// ---------------- global top-K over 80 --------------------------------------
__global__ void topk_global_kernel(const float* __restrict__ sc, int* __restrict__ keep)
{
    const int n = blockIdx.x;
    bool used[80];
    for (int i = 0; i < 80; i++) used[i] = false;
    const float* s = sc + (size_t)n * 80;
    for (int k = 0; k < KTOP; k++) {
        float best = -CUDART_INF_F; int bi = 0;
        for (int i = 0; i < 80; i++)
            if (!used[i] && s[i] > best) { best = s[i]; bi = i; }
        used[bi] = true;
        keep[n * KTOP + k] = bi;
    }
}

// ---------------- p_proj ----------------------------------------------------
__global__ __launch_bounds__(256)
void pproj_kernel(const float* __restrict__ cand_hid, const int* __restrict__ keep,
                  const float* __restrict__ rn1_w, const float* __restrict__ rn1_b,
                  float* __restrict__ pproj)
{
    const int k = blockIdx.x, n = blockIdx.y, d = threadIdx.x;
    __shared__ float sh[C];
    const int col = keep[n * KTOP + k];
    sh[d] = cand_hid[((size_t)n * C + d) * 80 + col];
    __syncthreads();
    float acc = rn1_b[d];
    const float* wrow = rn1_w + (size_t)d * (2 * C) + C;   // Wp
    for (int c = 0; c < C; c++) acc += sh[c] * wrow[c];
    pproj[((size_t)n * KTOP + k) * D + d] = acc;
}

// ---------------- o_proj GEMM flat ------------------------------------------
__global__ __launch_bounds__(256)
void gemm_oproj_flat(const float* __restrict__ hid, const float* __restrict__ rn1_w,
                     float* __restrict__ oproj)
{
    __shared__ __align__(16) float As[16][68];
    __shared__ __align__(16) float Bs[16][68];
    const int n = blockIdx.z;
    const int s0 = blockIdx.x * 64;
    const int d0 = blockIdx.y * 64;
    const int tid = threadIdx.x;
    const int td = tid % 16, ts = tid / 16;
    float acc[4][4];
#pragma unroll
    for (int i = 0; i < 4; i++)
#pragma unroll
        for (int j = 0; j < 4; j++) acc[i][j] = 0.f;
    const float* hb = hid + (size_t)n * C * SUMHW;

    for (int cb = 0; cb < C; cb += 16) {
        for (int i = tid; i < 16 * 64; i += 256) {
            int c = i >> 6, sx = i & 63;
            int gs = s0 + sx;
            As[c][sx] = (gs < SUMHW) ? hb[(size_t)(cb + c) * SUMHW + gs] : 0.f;
        }
        for (int i = tid; i < 64 * 16; i += 256) {
            int d = i >> 4, c = i & 15;
            Bs[c][d] = rn1_w[(size_t)(d0 + d) * (2 * C) + cb + c];   // Wo
        }
        __syncthreads();
#pragma unroll
        for (int c = 0; c < 16; c++) {
            float4 a4 = *(const float4*)&As[c][ts * 4];
            float4 b4 = *(const float4*)&Bs[c][td * 4];
            float a[4] = {a4.x, a4.y, a4.z, a4.w};
            float b[4] = {b4.x, b4.y, b4.z, b4.w};
#pragma unroll
            for (int i = 0; i < 4; i++)
#pragma unroll
                for (int j = 0; j < 4; j++) acc[i][j] += a[i] * b[j];
        }
        __syncthreads();
    }
#pragma unroll
    for (int i = 0; i < 4; i++) {
        int gs = s0 + ts * 4 + i;
        if (gs < SUMHW)
#pragma unroll
            for (int j = 0; j < 4; j++)
                oproj[((size_t)n * SUMHW + gs) * D + d0 + td * 4 + j] = acc[i][j];
    }
}

// ---------------- hsum: 8 pixels per block ----------------------------------
__global__ __launch_bounds__(256)
void hsum8(const float* __restrict__ oproj, const float* __restrict__ pproj,
           float* __restrict__ hout)
{
    const int n = blockIdx.y;
    const int s0 = blockIdx.x * 8;
    const int d = threadIdx.x;
    float pp[KTOP];
#pragma unroll
    for (int k = 0; k < KTOP; k++)
        pp[k] = pproj[((size_t)n * KTOP + k) * D + d];
#pragma unroll
    for (int i = 0; i < 8; i++) {
        int sflat = s0 + i;
        float o = oproj[((size_t)n * SUMHW + sflat) * D + d];
        float acc = 0.f;
#pragma unroll
        for (int k = 0; k < KTOP; k++) acc += fmaxf(o + pp[k], 0.f);
        hout[((size_t)n * SUMHW + sflat) * D + d] = acc;
    }
}

// ---------------- rn2 GEMM flat ---------------------------------------------
__global__ __launch_bounds__(256)
void gemm_rn2_flat(const float* __restrict__ hin, const float* __restrict__ rn2_w,
                   const float* __restrict__ rn2_b, float* __restrict__ hout)
{
    __shared__ __align__(16) float As[16][68];
    __shared__ __align__(16) float Bs[16][68];
    const int n = blockIdx.z;
    const int s0 = blockIdx.x * 64;
    const int e0 = blockIdx.y * 64;
    const int tid = threadIdx.x;
    const int td = tid % 16, ts = tid / 16;
    float acc[4][4];
#pragma unroll
    for (int i = 0; i < 4; i++)
#pragma unroll
        for (int j = 0; j < 4; j++) acc[i][j] = 0.f;

    for (int db = 0; db < D; db += 16) {
        for (int i = tid; i < 64 * 16; i += 256) {
            int sx = i >> 4, c = i & 15;
            int gs = s0 + sx;
            As[c][sx] = (gs < SUMHW) ? hin[((size_t)n * SUMHW + gs) * D + db + c] : 0.f;
        }
        for (int i = tid; i < 64 * 16; i += 256) {
            int e = i >> 4, c = i & 15;
            Bs[c][e] = rn2_w[(size_t)(e0 + e) * D + db + c];
        }
        __syncthreads();
#pragma unroll
        for (int c = 0; c < 16; c++) {
            float4 a4 = *(const float4*)&As[c][ts * 4];
            float4 b4 = *(const float4*)&Bs[c][td * 4];
            float a[4] = {a4.x, a4.y, a4.z, a4.w};
            float b[4] = {b4.x, b4.y, b4.z, b4.w};
#pragma unroll
            for (int i = 0; i < 4; i++)
#pragma unroll
                for (int j = 0; j < 4; j++) acc[i][j] += a[i] * b[j];
        }
        __syncthreads();
    }
#pragma unroll
    for (int i = 0; i < 4; i++) {
        int gs = s0 + ts * 4 + i;
        if (gs < SUMHW)
#pragma unroll
            for (int j = 0; j < 4; j++) {
                int e = e0 + td * 4 + j;
                hout[((size_t)n * SUMHW + gs) * D + e] = fmaxf(acc[i][j] + rn2_b[e], 0.f);
            }
    }
}

// ---------------- ol head flat ----------------------------------------------
__global__ __launch_bounds__(256)
void ol_flat(const float* __restrict__ h2, const float* __restrict__ ol_w,
             const float* __restrict__ ol_b, float* __restrict__ out)
{
    const int tid = threadIdx.x;
    const int warp = tid >> 5, lane = tid & 31;
    const int n = blockIdx.y;
    const int p = blockIdx.x * 8 + warp;
    if (p >= SUMHW) return;
    const int s = scale_of(p);
    const int ploc = p - cOFF[s];
    const int HW = cHW[s];
    const float* h = h2 + ((size_t)n * SUMHW + p) * D;
    float a0 = 0.f, a1 = 0.f, a2 = 0.f;
    for (int d = lane; d < D; d += 32) {
        float v = h[d];
        a0 += v * ol_w[d];
        a1 += v * ol_w[D + d];
        a2 += v * ol_w[2 * D + d];
    }
#pragma unroll
    for (int off = 16; off > 0; off >>= 1) {
        a0 += __shfl_down_sync(0xFFFFFFFFu, a0, off);
        a1 += __shfl_down_sync(0xFFFFFFFFu, a1, off);
        a2 += __shfl_down_sync(0xFFFFFFFFu, a2, off);
    }
    if (lane == 0) {
        out[cOLOG[s] + ((size_t)n * A + 0) * HW + ploc] = a0 + ol_b[0];
        out[cOLOG[s] + ((size_t)n * A + 1) * HW + ploc] = a1 + ol_b[1];
        out[cOLOG[s] + ((size_t)n * A + 2) * HW + ploc] = a2 + ol_b[2];
    }
}

// ---------------------------- host orchestration ----------------------------
extern "C" void kernel_launch(void* const* d_in, const int* in_sizes, int n_in,
                              void* d_out, int out_size)
{
    const float* f0 = (const float*)d_in[0];
    const float* f1 = (const float*)d_in[1];
    const float* f2 = (const float*)d_in[2];
    const float* f3 = (const float*)d_in[3];
    const float* pc1_w = (const float*)d_in[4];
    const float* pc1_b = (const float*)d_in[5];
    const float* pc2_w = (const float*)d_in[6];
    const float* pc2_b = (const float*)d_in[7];
    const float* oc1_w = (const float*)d_in[8];
    const float* oc1_b = (const float*)d_in[9];
    const float* oc2_w = (const float*)d_in[10];
    const float* oc2_b = (const float*)d_in[11];
    const float* rn1_w = (const float*)d_in[12];
    const float* rn1_b = (const float*)d_in[13];
    const float* rn2_w = (const float*)d_in[14];
    const float* rn2_b = (const float*)d_in[15];
    const float* pl_w  = (const float*)d_in[16];
    const float* pl_b  = (const float*)d_in[17];
    const float* pd_w  = (const float*)d_in[18];
    const float* pd_b  = (const float*)d_in[19];
    const float* ol_w  = (const float*)d_in[20];
    const float* ol_b  = (const float*)d_in[21];
    const float* od_w  = (const float*)d_in[22];
    const float* od_b  = (const float*)d_in[23];
    float* out = (float*)d_out;

    float *t1, *t2, *o1, *o2, *cell, *cand_hid, *cand_sc, *pproj;
    int* keep;
    cudaGetSymbolAddress((void**)&t1, g_t1);
    cudaGetSymbolAddress((void**)&t2, g_t2);
    cudaGetSymbolAddress((void**)&o1, g_o1);
    cudaGetSymbolAddress((void**)&o2, g_o2);
    cudaGetSymbolAddress((void**)&cell, g_cell);
    cudaGetSymbolAddress((void**)&cand_hid, g_cand_hid);
    cudaGetSymbolAddress((void**)&cand_sc, g_cand_sc);
    cudaGetSymbolAddress((void**)&keep, g_keep);
    cudaGetSymbolAddress((void**)&pproj, g_pproj);

    const dim3 convGrid(108, 4, NB);               // 108 tiles, 4 oc-groups, batch
    const dim3 headGrid((SUMHW + 255) / 256, NB);
    const dim3 gemmGrid((SUMHW + 63) / 64, D / 64, NB);

    // ---- person branch ----
    conv3x3_flat<<<convGrid, 256>>>(f0, f1, f2, f3, pc1_w, pc1_b, t1, 1);
    conv3x3_flat<<<convGrid, 256>>>(t1, t1, t1, t1, pc2_w, pc2_b, t2, 0);
    heads_p_flat<<<headGrid, 256>>>(t2, pl_w, pl_b, pd_w, pd_b, out, cell);
    topk_flat<<<dim3(4, NB), 256>>>(cell, t2, cand_hid, cand_sc);
    topk_global_kernel<<<NB, 1>>>(cand_sc, keep);
    pproj_kernel<<<dim3(KTOP, NB), 256>>>(cand_hid, keep, rn1_w, rn1_b, pproj);

    // ---- object branch ----
    conv3x3_flat<<<convGrid, 256>>>(f0, f1, f2, f3, oc1_w, oc1_b, t1, 1);
    conv3x3_flat<<<convGrid, 256>>>(t1, t1, t1, t1, oc2_w, oc2_b, t2, 0);
    heads_od_flat<<<headGrid, 256>>>(t2, od_w, od_b, out);
    gemm_oproj_flat<<<gemmGrid, 256>>>(t2, rn1_w, o1);
    hsum8<<<dim3(SUMHW / 8, NB), 256>>>(o1, pproj, o2);
    gemm_rn2_flat<<<gemmGrid, 256>>>(o2, rn2_w, rn2_b, o1);
    ol_flat<<<dim3((SUMHW + 7) / 8, NB), 256>>>(o1, ol_w, ol_b, out);

    (void)in_sizes; (void)n_in; (void)out_size;
}

// round 4
// speedup vs baseline: 2.8388x; 1.2312x over previous
#include <cuda_runtime.h>
#include <cuda_bf16.h>
#include <math_constants.h>
#include <stdint.h>

// Problem constants
#define NB   2
#define C    256
#define A    3
#define KTOP 20
#define D    256
#define BOXC 12
#define SUMHW 13600   // 10240 + 2560 + 640 + 160

// ---------------- scratch (device globals) ----------------------------------
__device__ float g_t1[NB * C * SUMHW];
__device__ float g_t2[NB * C * SUMHW];
__device__ float g_o1[NB * SUMHW * D];
__device__ float g_o2[NB * SUMHW * D];
__device__ float g_cell[NB * SUMHW];
__device__ float g_cand_hid[NB * C * 80];
__device__ float g_cand_sc[NB * 80];
__device__ int   g_keep[NB * KTOP];
__device__ float g_pproj[NB * KTOP * D];

// per-scale constants
__device__ __constant__ int cOFF[4]  = {0, 10240, 12800, 13440};
__device__ __constant__ int cHW[4]   = {10240, 2560, 640, 160};
__device__ __constant__ int cH[4]    = {80, 40, 20, 10};
__device__ __constant__ int cW[4]    = {128, 64, 32, 16};
__device__ __constant__ int cPLOG[4] = {0,      61440,  76800,  80640};
__device__ __constant__ int cPDEL[4] = {81600,  327360, 388800, 404160};
__device__ __constant__ int cOLOG[4] = {408000, 469440, 484800, 488640};
__device__ __constant__ int cODEL[4] = {489600, 735360, 796800, 812160};

__device__ __forceinline__ int scale_of(int p) {
    return (p < 10240) ? 0 : (p < 12800) ? 1 : (p < 13440) ? 2 : 3;
}

// ---------------- TF32 helpers ----------------------------------------------
__device__ __forceinline__ uint32_t f2tf(float v) {
    uint32_t r;
    asm("cvt.rna.tf32.f32 %0, %1;" : "=r"(r) : "f"(v));
    return r;
}
__device__ __forceinline__ void mma_tf32(float* c, const uint32_t* a,
                                         uint32_t b0, uint32_t b1) {
    asm volatile(
        "mma.sync.aligned.m16n8k8.row.col.f32.tf32.tf32.f32 "
        "{%0,%1,%2,%3}, {%4,%5,%6,%7}, {%8,%9}, {%0,%1,%2,%3};\n"
        : "+f"(c[0]), "+f"(c[1]), "+f"(c[2]), "+f"(c[3])
        : "r"(a[0]), "r"(a[1]), "r"(a[2]), "r"(a[3]), "r"(b0), "r"(b1));
}

// ---------------- conv3x3 via 3xTF32 mma (all scales) -----------------------
// Block: 256 thr = 8 warps. Block tile: 64 oc x (8 rows x 32 cols).
// Warp w = output row w; warp tile 64 oc x 32 px.
// K loop: 8 ci per chunk, 9 taps, mma m16n8k8 (16oc x 8px x 8ci).
// smem: s_in2[8ci][10r][38c] float2{hi,lo}; s_w2[72(ci*9+tap)][68oc] float2.
#define SIN_R 38
#define SIN_C (10 * SIN_R)          // 380 float2 per ci
#define SW_R  68

__global__ __launch_bounds__(256, 2)
void conv3x3_mma(const float* __restrict__ f0, const float* __restrict__ f1,
                 const float* __restrict__ f2, const float* __restrict__ f3,
                 const float* __restrict__ w,     // [C][C][3][3]
                 const float* __restrict__ bias,
                 float* __restrict__ dst,         // [n][C][SUMHW]
                 int layer1)
{
    extern __shared__ float2 smem[];
    float2* s_in2 = smem;                 // 8 * 380 = 3040
    float2* s_w2  = smem + 8 * SIN_C;     // 72 * 68  = 4896
    __shared__ float s_bias[64];

    const int bx = blockIdx.x;
    int s, t_;
    if (bx < 40)      { s = 0; t_ = bx; }
    else if (bx < 50) { s = 1; t_ = bx - 40; }
    else if (bx < 53) { s = 2; t_ = bx - 50; }
    else              { s = 3; t_ = bx - 53; }
    const int H = cH[s], W = cW[s];
    const int tilesX = (W >= 32) ? (W / 32) : 1;
    const int ty = t_ / tilesX, tx = t_ % tilesX;
    const int h0 = ty * 8, w0 = tx * 32;
    const int n = blockIdx.z;
    const int ocBase = blockIdx.y * 64;

    const float* srcs = (s == 0) ? f0 : (s == 1) ? f1 : (s == 2) ? f2 : f3;
    const int srcCS  = layer1 ? (H * W) : SUMHW;
    const int srcOff = layer1 ? 0 : cOFF[s];
    const float* src = srcs + (size_t)n * C * srcCS + srcOff;

    const int tid  = threadIdx.x;
    const int warp = tid >> 5;        // output row within tile
    const int lane = tid & 31;
    const int g = lane >> 2;          // groupID
    const int t = lane & 3;           // threadID_in_group

    if (tid < 64) s_bias[tid] = bias[ocBase + tid];

    float acc[4][4][4];
#pragma unroll
    for (int i = 0; i < 4; i++)
#pragma unroll
        for (int j = 0; j < 4; j++)
#pragma unroll
            for (int k = 0; k < 4; k++) acc[i][j][k] = 0.f;

    for (int cb = 0; cb < C; cb += 8) {
        __syncthreads();
        // input halo tile: 8 ci x 10 rows x 34 cols -> float2{hi,lo}
        for (int idx = tid; idx < 8 * 10 * 34; idx += 256) {
            int ci = idx / 340;
            int rem = idx % 340;
            int r = rem / 34, cc = rem % 34;
            int gh = h0 + r - 1, gw = w0 + cc - 1;
            float v = 0.f;
            if (gh >= 0 && gh < H && gw >= 0 && gw < W)
                v = src[(size_t)(cb + ci) * srcCS + gh * W + gw];
            uint32_t hi = f2tf(v);
            float hif = __uint_as_float(hi);
            uint32_t lo = f2tf(v - hif);
            s_in2[ci * SIN_C + r * SIN_R + cc] =
                make_float2(hif, __uint_as_float(lo));
        }
        // weights: 64 oc x 72 (ci*9+tap) -> s_w2[ct][oc]
        for (int idx = tid; idx < 64 * 72; idx += 256) {
            int oc = idx / 72, ct = idx % 72;
            float v = w[(size_t)(ocBase + oc) * 2304 + cb * 9 + ct];
            uint32_t hi = f2tf(v);
            float hif = __uint_as_float(hi);
            uint32_t lo = f2tf(v - hif);
            s_w2[ct * SW_R + oc] = make_float2(hif, __uint_as_float(lo));
        }
        __syncthreads();

#pragma unroll
        for (int kh = 0; kh < 3; kh++)
#pragma unroll
        for (int kw = 0; kw < 3; kw++) {
            const int tap = kh * 3 + kw;
            uint32_t ah[4][4], al[4][4];
            const int r1 = (t * 9 + tap) * SW_R;
            const int r2 = ((t + 4) * 9 + tap) * SW_R;
#pragma unroll
            for (int o4 = 0; o4 < 4; o4++) {
                int oc = o4 * 16 + g;
                float2 x0 = s_w2[r1 + oc];
                float2 x1 = s_w2[r1 + oc + 8];
                float2 x2 = s_w2[r2 + oc];
                float2 x3 = s_w2[r2 + oc + 8];
                ah[o4][0] = __float_as_uint(x0.x); al[o4][0] = __float_as_uint(x0.y);
                ah[o4][1] = __float_as_uint(x1.x); al[o4][1] = __float_as_uint(x1.y);
                ah[o4][2] = __float_as_uint(x2.x); al[o4][2] = __float_as_uint(x2.y);
                ah[o4][3] = __float_as_uint(x3.x); al[o4][3] = __float_as_uint(x3.y);
            }
            const int ib = (warp + kh) * SIN_R + kw + g;
#pragma unroll
            for (int p4 = 0; p4 < 4; p4++) {
                float2 e0 = s_in2[t * SIN_C + ib + p4 * 8];
                float2 e1 = s_in2[(t + 4) * SIN_C + ib + p4 * 8];
                uint32_t bh0 = __float_as_uint(e0.x), bl0 = __float_as_uint(e0.y);
                uint32_t bh1 = __float_as_uint(e1.x), bl1 = __float_as_uint(e1.y);
#pragma unroll
                for (int o4 = 0; o4 < 4; o4++) mma_tf32(acc[o4][p4], ah[o4], bh0, bh1);
#pragma unroll
                for (int o4 = 0; o4 < 4; o4++) mma_tf32(acc[o4][p4], ah[o4], bl0, bl1);
#pragma unroll
                for (int o4 = 0; o4 < 4; o4++) mma_tf32(acc[o4][p4], al[o4], bh0, bh1);
            }
        }
    }

    // epilogue
    const int ghout = h0 + warp;
    if (ghout < H) {
        float* dbase = dst + (size_t)n * C * SUMHW + cOFF[s] + (size_t)ghout * W + w0;
#pragma unroll
        for (int o4 = 0; o4 < 4; o4++) {
            int oc0 = ocBase + o4 * 16 + g;
            float b0v = s_bias[o4 * 16 + g];
            float b1v = s_bias[o4 * 16 + g + 8];
#pragma unroll
            for (int p4 = 0; p4 < 4; p4++) {
                int col = p4 * 8 + 2 * t;
                if (w0 + col < W) {
                    float2 v0 = make_float2(fmaxf(acc[o4][p4][0] + b0v, 0.f),
                                            fmaxf(acc[o4][p4][1] + b0v, 0.f));
                    float2 v1 = make_float2(fmaxf(acc[o4][p4][2] + b1v, 0.f),
                                            fmaxf(acc[o4][p4][3] + b1v, 0.f));
                    *(float2*)(dbase + (size_t)oc0 * SUMHW + col) = v0;
                    *(float2*)(dbase + (size_t)(oc0 + 8) * SUMHW + col) = v1;
                }
            }
        }
    }
}

// ---------------- person heads flat -----------------------------------------
__global__ __launch_bounds__(256)
void heads_p_flat(const float* __restrict__ hid,
                  const float* __restrict__ pl_w, const float* __restrict__ pl_b,
                  const float* __restrict__ pd_w, const float* __restrict__ pd_b,
                  float* __restrict__ out, float* __restrict__ cell)
{
    __shared__ float swl[A * C];
    __shared__ float swd[BOXC * C];
    const int tid = threadIdx.x;
    for (int i = tid; i < A * C; i += 256) swl[i] = pl_w[i];
    for (int i = tid; i < BOXC * C; i += 256) swd[i] = pd_w[i];
    __syncthreads();

    const int p = blockIdx.x * 256 + tid;
    const int n = blockIdx.y;
    if (p >= SUMHW) return;
    const int s = scale_of(p);
    const int ploc = p - cOFF[s];
    const int HW = cHW[s];
    const float* h = hid + (size_t)n * C * SUMHW + p;

    float accl[A], accd[BOXC];
#pragma unroll
    for (int a = 0; a < A; a++) accl[a] = pl_b[a];
#pragma unroll
    for (int j = 0; j < BOXC; j++) accd[j] = pd_b[j];

    for (int c = 0; c < C; c++) {
        float v = h[(size_t)c * SUMHW];
#pragma unroll
        for (int a = 0; a < A; a++) accl[a] += swl[a * C + c] * v;
#pragma unroll
        for (int j = 0; j < BOXC; j++) accd[j] += swd[j * C + c] * v;
    }
    float m = accl[0];
#pragma unroll
    for (int a = 0; a < A; a++) {
        out[cPLOG[s] + ((size_t)n * A + a) * HW + ploc] = accl[a];
        m = fmaxf(m, accl[a]);
    }
#pragma unroll
    for (int j = 0; j < BOXC; j++)
        out[cPDEL[s] + ((size_t)n * BOXC + j) * HW + ploc] = accd[j];
    cell[(size_t)n * SUMHW + p] = m;
}

// ---------------- object delta head flat ------------------------------------
__global__ __launch_bounds__(256)
void heads_od_flat(const float* __restrict__ hid,
                   const float* __restrict__ od_w, const float* __restrict__ od_b,
                   float* __restrict__ out)
{
    __shared__ float sw[BOXC * C];
    const int tid = threadIdx.x;
    for (int i = tid; i < BOXC * C; i += 256) sw[i] = od_w[i];
    __syncthreads();

    const int p = blockIdx.x * 256 + tid;
    const int n = blockIdx.y;
    if (p >= SUMHW) return;
    const int s = scale_of(p);
    const int ploc = p - cOFF[s];
    const int HW = cHW[s];
    const float* h = hid + (size_t)n * C * SUMHW + p;

    float acc[BOXC];
#pragma unroll
    for (int j = 0; j < BOXC; j++) acc[j] = od_b[j];
    for (int c = 0; c < C; c++) {
        float v = h[(size_t)c * SUMHW];
#pragma unroll
        for (int j = 0; j < BOXC; j++) acc[j] += sw[j * C + c] * v;
    }
#pragma unroll
    for (int j = 0; j < BOXC; j++)
        out[cODEL[s] + ((size_t)n * BOXC + j) * HW + ploc] = acc[j];
}

// ---------------- per-scale top-K (smem-cached) -----------------------------
__global__ __launch_bounds__(256)
void topk_flat(const float* __restrict__ cell, const float* __restrict__ hid,
               float* __restrict__ cand_hid, float* __restrict__ cand_sc)
{
    const int s = blockIdx.x;
    const int n = blockIdx.y;
    const int HW = cHW[s], off = cOFF[s];
    __shared__ float sc[10240];
    __shared__ float s_val[256];
    __shared__ int   s_idx[256];
    __shared__ int   sel[KTOP];
    const int tid = threadIdx.x;

    for (int i = tid; i < HW; i += 256)
        sc[i] = cell[(size_t)n * SUMHW + off + i];
    __syncthreads();

    for (int k = 0; k < KTOP; k++) {
        float best = -CUDART_INF_F;
        int bi = HW;
        for (int i = tid; i < HW; i += 256) {
            float v = sc[i];
            if (v > best) { best = v; bi = i; }
        }
        s_val[tid] = best; s_idx[tid] = bi;
        __syncthreads();
        for (int offr = 128; offr > 0; offr >>= 1) {
            if (tid < offr) {
                float v2 = s_val[tid + offr]; int i2 = s_idx[tid + offr];
                if (v2 > s_val[tid] || (v2 == s_val[tid] && i2 < s_idx[tid])) {
                    s_val[tid] = v2; s_idx[tid] = i2;
                }
            }
            __syncthreads();
        }
        if (tid == 0) {
            sel[k] = s_idx[0];
            cand_sc[(size_t)n * 80 + s * KTOP + k] = s_val[0];
            sc[s_idx[0]] = -CUDART_INF_F;
        }
        __syncthreads();
    }
    for (int idx = tid; idx < C * KTOP; idx += 256) {
        int c = idx / KTOP, k = idx % KTOP;
        cand_hid[((size_t)n * C + c) * 80 + s * KTOP + k] =
            hid[((size_t)n * C + c) * SUMHW + off + sel[k]];
    }
}

// ---------------- global top-K over 80 --------------------------------------
__global__ void topk_global_kernel(const float* __restrict__ sc, int* __restrict__ keep)
{
    const int n = blockIdx.x;
    bool used[80];
    for (int i = 0; i < 80; i++) used[i] = false;
    const float* s = sc + (size_t)n * 80;
    for (int k = 0; k < KTOP; k++) {
        float best = -CUDART_INF_F; int bi = 0;
        for (int i = 0; i < 80; i++)
            if (!used[i] && s[i] > best) { best = s[i]; bi = i; }
        used[bi] = true;
        keep[n * KTOP + k] = bi;
    }
}

// ---------------- p_proj ----------------------------------------------------
__global__ __launch_bounds__(256)
void pproj_kernel(const float* __restrict__ cand_hid, const int* __restrict__ keep,
                  const float* __restrict__ rn1_w, const float* __restrict__ rn1_b,
                  float* __restrict__ pproj)
{
    const int k = blockIdx.x, n = blockIdx.y, d = threadIdx.x;
    __shared__ float sh[C];
    const int col = keep[n * KTOP + k];
    sh[d] = cand_hid[((size_t)n * C + d) * 80 + col];
    __syncthreads();
    float acc = rn1_b[d];
    const float* wrow = rn1_w + (size_t)d * (2 * C) + C;   // Wp
    for (int c = 0; c < C; c++) acc += sh[c] * wrow[c];
    pproj[((size_t)n * KTOP + k) * D + d] = acc;
}

// ---------------- o_proj GEMM flat ------------------------------------------
__global__ __launch_bounds__(256)
void gemm_oproj_flat(const float* __restrict__ hid, const float* __restrict__ rn1_w,
                     float* __restrict__ oproj)
{
    __shared__ __align__(16) float As[16][68];
    __shared__ __align__(16) float Bs[16][68];
    const int n = blockIdx.z;
    const int s0 = blockIdx.x * 64;
    const int d0 = blockIdx.y * 64;
    const int tid = threadIdx.x;
    const int td = tid % 16, ts = tid / 16;
    float acc[4][4];
#pragma unroll
    for (int i = 0; i < 4; i++)
#pragma unroll
        for (int j = 0; j < 4; j++) acc[i][j] = 0.f;
    const float* hb = hid + (size_t)n * C * SUMHW;

    for (int cb = 0; cb < C; cb += 16) {
        for (int i = tid; i < 16 * 64; i += 256) {
            int c = i >> 6, sx = i & 63;
            int gs = s0 + sx;
            As[c][sx] = (gs < SUMHW) ? hb[(size_t)(cb + c) * SUMHW + gs] : 0.f;
        }
        for (int i = tid; i < 64 * 16; i += 256) {
            int d = i >> 4, c = i & 15;
            Bs[c][d] = rn1_w[(size_t)(d0 + d) * (2 * C) + cb + c];   // Wo
        }
        __syncthreads();
#pragma unroll
        for (int c = 0; c < 16; c++) {
            float4 a4 = *(const float4*)&As[c][ts * 4];
            float4 b4 = *(const float4*)&Bs[c][td * 4];
            float a[4] = {a4.x, a4.y, a4.z, a4.w};
            float b[4] = {b4.x, b4.y, b4.z, b4.w};
#pragma unroll
            for (int i = 0; i < 4; i++)
#pragma unroll
                for (int j = 0; j < 4; j++) acc[i][j] += a[i] * b[j];
        }
        __syncthreads();
    }
#pragma unroll
    for (int i = 0; i < 4; i++) {
        int gs = s0 + ts * 4 + i;
        if (gs < SUMHW)
#pragma unroll
            for (int j = 0; j < 4; j++)
                oproj[((size_t)n * SUMHW + gs) * D + d0 + td * 4 + j] = acc[i][j];
    }
}

// ---------------- hsum: 8 pixels per block ----------------------------------
__global__ __launch_bounds__(256)
void hsum8(const float* __restrict__ oproj, const float* __restrict__ pproj,
           float* __restrict__ hout)
{
    const int n = blockIdx.y;
    const int s0 = blockIdx.x * 8;
    const int d = threadIdx.x;
    float pp[KTOP];
#pragma unroll
    for (int k = 0; k < KTOP; k++)
        pp[k] = pproj[((size_t)n * KTOP + k) * D + d];
#pragma unroll
    for (int i = 0; i < 8; i++) {
        int sflat = s0 + i;
        float o = oproj[((size_t)n * SUMHW + sflat) * D + d];
        float acc = 0.f;
#pragma unroll
        for (int k = 0; k < KTOP; k++) acc += fmaxf(o + pp[k], 0.f);
        hout[((size_t)n * SUMHW + sflat) * D + d] = acc;
    }
}

// ---------------- rn2 GEMM flat ---------------------------------------------
__global__ __launch_bounds__(256)
void gemm_rn2_flat(const float* __restrict__ hin, const float* __restrict__ rn2_w,
                   const float* __restrict__ rn2_b, float* __restrict__ hout)
{
    __shared__ __align__(16) float As[16][68];
    __shared__ __align__(16) float Bs[16][68];
    const int n = blockIdx.z;
    const int s0 = blockIdx.x * 64;
    const int e0 = blockIdx.y * 64;
    const int tid = threadIdx.x;
    const int td = tid % 16, ts = tid / 16;
    float acc[4][4];
#pragma unroll
    for (int i = 0; i < 4; i++)
#pragma unroll
        for (int j = 0; j < 4; j++) acc[i][j] = 0.f;

    for (int db = 0; db < D; db += 16) {
        for (int i = tid; i < 64 * 16; i += 256) {
            int sx = i >> 4, c = i & 15;
            int gs = s0 + sx;
            As[c][sx] = (gs < SUMHW) ? hin[((size_t)n * SUMHW + gs) * D + db + c] : 0.f;
        }
        for (int i = tid; i < 64 * 16; i += 256) {
            int e = i >> 4, c = i & 15;
            Bs[c][e] = rn2_w[(size_t)(e0 + e) * D + db + c];
        }
        __syncthreads();
#pragma unroll
        for (int c = 0; c < 16; c++) {
            float4 a4 = *(const float4*)&As[c][ts * 4];
            float4 b4 = *(const float4*)&Bs[c][td * 4];
            float a[4] = {a4.x, a4.y, a4.z, a4.w};
            float b[4] = {b4.x, b4.y, b4.z, b4.w};
#pragma unroll
            for (int i = 0; i < 4; i++)
#pragma unroll
                for (int j = 0; j < 4; j++) acc[i][j] += a[i] * b[j];
        }
        __syncthreads();
    }
#pragma unroll
    for (int i = 0; i < 4; i++) {
        int gs = s0 + ts * 4 + i;
        if (gs < SUMHW)
#pragma unroll
            for (int j = 0; j < 4; j++) {
                int e = e0 + td * 4 + j;
                hout[((size_t)n * SUMHW + gs) * D + e] = fmaxf(acc[i][j] + rn2_b[e], 0.f);
            }
    }
}

// ---------------- ol head flat ----------------------------------------------
__global__ __launch_bounds__(256)
void ol_flat(const float* __restrict__ h2, const float* __restrict__ ol_w,
             const float* __restrict__ ol_b, float* __restrict__ out)
{
    const int tid = threadIdx.x;
    const int warp = tid >> 5, lane = tid & 31;
    const int n = blockIdx.y;
    const int p = blockIdx.x * 8 + warp;
    if (p >= SUMHW) return;
    const int s = scale_of(p);
    const int ploc = p - cOFF[s];
    const int HW = cHW[s];
    const float* h = h2 + ((size_t)n * SUMHW + p) * D;
    float a0 = 0.f, a1 = 0.f, a2 = 0.f;
    for (int d = lane; d < D; d += 32) {
        float v = h[d];
        a0 += v * ol_w[d];
        a1 += v * ol_w[D + d];
        a2 += v * ol_w[2 * D + d];
    }
#pragma unroll
    for (int off = 16; off > 0; off >>= 1) {
        a0 += __shfl_down_sync(0xFFFFFFFFu, a0, off);
        a1 += __shfl_down_sync(0xFFFFFFFFu, a1, off);
        a2 += __shfl_down_sync(0xFFFFFFFFu, a2, off);
    }
    if (lane == 0) {
        out[cOLOG[s] + ((size_t)n * A + 0) * HW + ploc] = a0 + ol_b[0];
        out[cOLOG[s] + ((size_t)n * A + 1) * HW + ploc] = a1 + ol_b[1];
        out[cOLOG[s] + ((size_t)n * A + 2) * HW + ploc] = a2 + ol_b[2];
    }
}

// ---------------------------- host orchestration ----------------------------
extern "C" void kernel_launch(void* const* d_in, const int* in_sizes, int n_in,
                              void* d_out, int out_size)
{
    const float* f0 = (const float*)d_in[0];
    const float* f1 = (const float*)d_in[1];
    const float* f2 = (const float*)d_in[2];
    const float* f3 = (const float*)d_in[3];
    const float* pc1_w = (const float*)d_in[4];
    const float* pc1_b = (const float*)d_in[5];
    const float* pc2_w = (const float*)d_in[6];
    const float* pc2_b = (const float*)d_in[7];
    const float* oc1_w = (const float*)d_in[8];
    const float* oc1_b = (const float*)d_in[9];
    const float* oc2_w = (const float*)d_in[10];
    const float* oc2_b = (const float*)d_in[11];
    const float* rn1_w = (const float*)d_in[12];
    const float* rn1_b = (const float*)d_in[13];
    const float* rn2_w = (const float*)d_in[14];
    const float* rn2_b = (const float*)d_in[15];
    const float* pl_w  = (const float*)d_in[16];
    const float* pl_b  = (const float*)d_in[17];
    const float* pd_w  = (const float*)d_in[18];
    const float* pd_b  = (const float*)d_in[19];
    const float* ol_w  = (const float*)d_in[20];
    const float* ol_b  = (const float*)d_in[21];
    const float* od_w  = (const float*)d_in[22];
    const float* od_b  = (const float*)d_in[23];
    float* out = (float*)d_out;

    float *t1, *t2, *o1, *o2, *cell, *cand_hid, *cand_sc, *pproj;
    int* keep;
    cudaGetSymbolAddress((void**)&t1, g_t1);
    cudaGetSymbolAddress((void**)&t2, g_t2);
    cudaGetSymbolAddress((void**)&o1, g_o1);
    cudaGetSymbolAddress((void**)&o2, g_o2);
    cudaGetSymbolAddress((void**)&cell, g_cell);
    cudaGetSymbolAddress((void**)&cand_hid, g_cand_hid);
    cudaGetSymbolAddress((void**)&cand_sc, g_cand_sc);
    cudaGetSymbolAddress((void**)&keep, g_keep);
    cudaGetSymbolAddress((void**)&pproj, g_pproj);

    const int convSmem = (8 * SIN_C + 72 * SW_R) * (int)sizeof(float2);  // 63488
    cudaFuncSetAttribute(conv3x3_mma,
                         cudaFuncAttributeMaxDynamicSharedMemorySize, convSmem);

    const dim3 convGrid(55, 4, NB);                // 55 px-tiles, 4 oc-groups of 64
    const dim3 headGrid((SUMHW + 255) / 256, NB);
    const dim3 gemmGrid((SUMHW + 63) / 64, D / 64, NB);

    // ---- person branch ----
    conv3x3_mma<<<convGrid, 256, convSmem>>>(f0, f1, f2, f3, pc1_w, pc1_b, t1, 1);
    conv3x3_mma<<<convGrid, 256, convSmem>>>(t1, t1, t1, t1, pc2_w, pc2_b, t2, 0);
    heads_p_flat<<<headGrid, 256>>>(t2, pl_w, pl_b, pd_w, pd_b, out, cell);
    topk_flat<<<dim3(4, NB), 256>>>(cell, t2, cand_hid, cand_sc);
    topk_global_kernel<<<NB, 1>>>(cand_sc, keep);
    pproj_kernel<<<dim3(KTOP, NB), 256>>>(cand_hid, keep, rn1_w, rn1_b, pproj);

    // ---- object branch ----
    conv3x3_mma<<<convGrid, 256, convSmem>>>(f0, f1, f2, f3, oc1_w, oc1_b, t1, 1);
    conv3x3_mma<<<convGrid, 256, convSmem>>>(t1, t1, t1, t1, oc2_w, oc2_b, t2, 0);
    heads_od_flat<<<headGrid, 256>>>(t2, od_w, od_b, out);
    gemm_oproj_flat<<<gemmGrid, 256>>>(t2, rn1_w, o1);
    hsum8<<<dim3(SUMHW / 8, NB), 256>>>(o1, pproj, o2);
    gemm_rn2_flat<<<gemmGrid, 256>>>(o2, rn2_w, rn2_b, o1);
    ol_flat<<<dim3((SUMHW + 7) / 8, NB), 256>>>(o1, ol_w, ol_b, out);

    (void)in_sizes; (void)n_in; (void)out_size;
}

// round 6
// speedup vs baseline: 5.2394x; 1.8457x over previous
#include <cuda_runtime.h>
#include <cuda_bf16.h>
#include <math_constants.h>
#include <stdint.h>

// Problem constants
#define NB   2
#define C    256
#define A    3
#define KTOP 20
#define D    256
#define BOXC 12
#define SUMHW 13600   // 10240 + 2560 + 640 + 160

// ---------------- scratch (device globals) ----------------------------------
__device__ float g_t1[NB * C * SUMHW];
__device__ float g_t2[NB * C * SUMHW];
__device__ float g_o1[NB * SUMHW * D];
__device__ float g_o2[NB * SUMHW * D];
__device__ float g_cell[NB * SUMHW];
__device__ float g_cand_hid[NB * C * 80];
__device__ float g_cand_sc[NB * 80];
__device__ int   g_keep[NB * KTOP];
__device__ float g_pproj[NB * KTOP * D];

// per-scale constants
__device__ __constant__ int cOFF[4]  = {0, 10240, 12800, 13440};
__device__ __constant__ int cHW[4]   = {10240, 2560, 640, 160};
__device__ __constant__ int cH[4]    = {80, 40, 20, 10};
__device__ __constant__ int cW[4]    = {128, 64, 32, 16};
__device__ __constant__ int cPLOG[4] = {0,      61440,  76800,  80640};
__device__ __constant__ int cPDEL[4] = {81600,  327360, 388800, 404160};
__device__ __constant__ int cOLOG[4] = {408000, 469440, 484800, 488640};
__device__ __constant__ int cODEL[4] = {489600, 735360, 796800, 812160};

__device__ __forceinline__ int scale_of(int p) {
    return (p < 10240) ? 0 : (p < 12800) ? 1 : (p < 13440) ? 2 : 3;
}

// ---------------- bf16 mma helpers ------------------------------------------
__device__ __forceinline__ void mma_bf16(float* c, const uint32_t* a, const uint32_t* b) {
    asm volatile(
        "mma.sync.aligned.m16n8k16.row.col.f32.bf16.bf16.f32 "
        "{%0,%1,%2,%3}, {%4,%5,%6,%7}, {%8,%9}, {%0,%1,%2,%3};\n"
        : "+f"(c[0]), "+f"(c[1]), "+f"(c[2]), "+f"(c[3])
        : "r"(a[0]), "r"(a[1]), "r"(a[2]), "r"(a[3]), "r"(b[0]), "r"(b[1]));
}
__device__ __forceinline__ uint32_t pack_split_hi(float v0, float v1,
                                                  uint32_t& lo_out) {
    __nv_bfloat16 h0 = __float2bfloat16(v0);
    __nv_bfloat16 h1 = __float2bfloat16(v1);
    __nv_bfloat16 l0 = __float2bfloat16(v0 - __bfloat162float(h0));
    __nv_bfloat16 l1 = __float2bfloat16(v1 - __bfloat162float(h1));
    lo_out = ((uint32_t)__bfloat16_as_ushort(l1) << 16) | (uint32_t)__bfloat16_as_ushort(l0);
    return ((uint32_t)__bfloat16_as_ushort(h1) << 16) | (uint32_t)__bfloat16_as_ushort(h0);
}

// ---------------- conv3x3 via 3-term bf16 mma (all scales) ------------------
// Block: 256 thr = 8 warps; warp = output row; block tile 64oc x (8x32)px.
// K chunk: 16 ci; per tap mma m16n8k16 (16oc x 8px x 16ci), 3 split terms.
// smem layouts chosen conflict-free (bank = 8t + g):
//   s_w[(tap*8+p)*72 + oc]   (72 % 32 == 8)
//   s_i[(p*10+r)*36 + cc]    (360 % 32 == 8)
#define WPAD 72
#define IPAD 36
#define OFF_WH 0
#define OFF_WL 5184          // 9*8*72
#define OFF_IH 10368
#define OFF_IL 13248         // + 8*10*36
#define CONV_U32 16128
#define CONV_SMEM (CONV_U32 * 4)

__global__ __launch_bounds__(256, 2)
void conv3x3_bf16(const float* __restrict__ f0, const float* __restrict__ f1,
                  const float* __restrict__ f2, const float* __restrict__ f3,
                  const float* __restrict__ w,     // [C][C][3][3]
                  const float* __restrict__ bias,
                  float* __restrict__ dst,         // [n][C][SUMHW]
                  int layer1)
{
    extern __shared__ uint32_t sm[];
    uint32_t* s_wH = sm + OFF_WH;
    uint32_t* s_wL = sm + OFF_WL;
    uint32_t* s_iH = sm + OFF_IH;
    uint32_t* s_iL = sm + OFF_IL;
    __shared__ float s_bias[64];

    const int bx = blockIdx.x;
    int s, t_;
    if (bx < 40)      { s = 0; t_ = bx; }
    else if (bx < 50) { s = 1; t_ = bx - 40; }
    else if (bx < 53) { s = 2; t_ = bx - 50; }
    else              { s = 3; t_ = bx - 53; }
    const int H = cH[s], W = cW[s];
    const int tilesX = (W >= 32) ? (W / 32) : 1;
    const int ty = t_ / tilesX, tx = t_ % tilesX;
    const int h0 = ty * 8, w0 = tx * 32;
    const int n = blockIdx.z;
    const int ocBase = blockIdx.y * 64;

    const float* srcs = (s == 0) ? f0 : (s == 1) ? f1 : (s == 2) ? f2 : f3;
    const int srcCS  = layer1 ? (H * W) : SUMHW;
    const int srcOff = layer1 ? 0 : cOFF[s];
    const float* src = srcs + (size_t)n * C * srcCS + srcOff;

    const int tid  = threadIdx.x;
    const int warp = tid >> 5;        // output row within tile
    const int lane = tid & 31;
    const int g = lane >> 2;          // groupID
    const int t = lane & 3;           // threadID_in_group

    if (tid < 64) s_bias[tid] = bias[ocBase + tid];

    float acc[4][4][4];
#pragma unroll
    for (int i = 0; i < 4; i++)
#pragma unroll
        for (int j = 0; j < 4; j++)
#pragma unroll
            for (int k = 0; k < 4; k++) acc[i][j][k] = 0.f;

    for (int cb = 0; cb < C; cb += 16) {
        __syncthreads();
        // weights: 64 oc x 9 taps x 8 ci-pairs
        for (int idx = tid; idx < 64 * 72; idx += 256) {
            int oc = idx / 72, rem = idx % 72;
            int tap = rem >> 3, p = rem & 7;
            const float* wp = w + (size_t)(ocBase + oc) * 2304 + (cb + 2 * p) * 9 + tap;
            float v0 = wp[0], v1 = wp[9];
            uint32_t lo;
            uint32_t hi = pack_split_hi(v0, v1, lo);
            s_wH[(tap * 8 + p) * WPAD + oc] = hi;
            s_wL[(tap * 8 + p) * WPAD + oc] = lo;
        }
        // input halo tile: 8 ci-pairs x 10 rows x 34 cols
        for (int idx = tid; idx < 8 * 10 * 34; idx += 256) {
            int p = idx / 340, rem = idx % 340;
            int r = rem / 34, cc = rem % 34;
            int gh = h0 + r - 1, gw = w0 + cc - 1;
            float v0 = 0.f, v1 = 0.f;
            if (gh >= 0 && gh < H && gw >= 0 && gw < W) {
                const float* sp = src + (size_t)(cb + 2 * p) * srcCS + gh * W + gw;
                v0 = sp[0];
                v1 = sp[srcCS];
            }
            uint32_t lo;
            uint32_t hi = pack_split_hi(v0, v1, lo);
            s_iH[(p * 10 + r) * IPAD + cc] = hi;
            s_iL[(p * 10 + r) * IPAD + cc] = lo;
        }
        __syncthreads();

#pragma unroll
        for (int kh = 0; kh < 3; kh++)
#pragma unroll
        for (int kw = 0; kw < 3; kw++) {
            const int tap = kh * 3 + kw;
            // B fragments (4 px groups)
            uint32_t bh[4][2], bl[4][2];
            const int ib0 = (t * 10 + warp + kh) * IPAD + kw + g;
            const int ib1 = ((t + 4) * 10 + warp + kh) * IPAD + kw + g;
#pragma unroll
            for (int p4 = 0; p4 < 4; p4++) {
                bh[p4][0] = s_iH[ib0 + p4 * 8];
                bh[p4][1] = s_iH[ib1 + p4 * 8];
                bl[p4][0] = s_iL[ib0 + p4 * 8];
                bl[p4][1] = s_iL[ib1 + p4 * 8];
            }
            const int ia0 = (tap * 8 + t) * WPAD + g;
            const int ia1 = (tap * 8 + t + 4) * WPAD + g;
#pragma unroll
            for (int o4 = 0; o4 < 4; o4++) {
                uint32_t ah[4], al[4];
                ah[0] = s_wH[ia0 + o4 * 16];     al[0] = s_wL[ia0 + o4 * 16];
                ah[1] = s_wH[ia0 + o4 * 16 + 8]; al[1] = s_wL[ia0 + o4 * 16 + 8];
                ah[2] = s_wH[ia1 + o4 * 16];     al[2] = s_wL[ia1 + o4 * 16];
                ah[3] = s_wH[ia1 + o4 * 16 + 8]; al[3] = s_wL[ia1 + o4 * 16 + 8];
#pragma unroll
                for (int p4 = 0; p4 < 4; p4++) {
                    mma_bf16(acc[o4][p4], ah, bh[p4]);
                    mma_bf16(acc[o4][p4], ah, bl[p4]);
                    mma_bf16(acc[o4][p4], al, bh[p4]);
                }
            }
        }
    }

    // epilogue: acc[o4][p4]: c0=(g,2t) c1=(g,2t+1) c2=(g+8,2t) c3=(g+8,2t+1)
    const int ghout = h0 + warp;
    if (ghout < H) {
        float* dbase = dst + (size_t)n * C * SUMHW + cOFF[s] + (size_t)ghout * W + w0;
#pragma unroll
        for (int o4 = 0; o4 < 4; o4++) {
            int oc0 = ocBase + o4 * 16 + g;
            float b0v = s_bias[o4 * 16 + g];
            float b1v = s_bias[o4 * 16 + g + 8];
#pragma unroll
            for (int p4 = 0; p4 < 4; p4++) {
                int col = p4 * 8 + 2 * t;
                if (w0 + col < W) {
                    float2 v0 = make_float2(fmaxf(acc[o4][p4][0] + b0v, 0.f),
                                            fmaxf(acc[o4][p4][1] + b0v, 0.f));
                    float2 v1 = make_float2(fmaxf(acc[o4][p4][2] + b1v, 0.f),
                                            fmaxf(acc[o4][p4][3] + b1v, 0.f));
                    *(float2*)(dbase + (size_t)(oc0 - ocBase + ocBase) * SUMHW + col) = v0;
                    *(float2*)(dbase + (size_t)(oc0 + 8) * SUMHW + col) = v1;
                }
            }
        }
    }
}

// ---------------- person heads flat -----------------------------------------
__global__ __launch_bounds__(256)
void heads_p_flat(const float* __restrict__ hid,
                  const float* __restrict__ pl_w, const float* __restrict__ pl_b,
                  const float* __restrict__ pd_w, const float* __restrict__ pd_b,
                  float* __restrict__ out, float* __restrict__ cell)
{
    __shared__ float swl[A * C];
    __shared__ float swd[BOXC * C];
    const int tid = threadIdx.x;
    for (int i = tid; i < A * C; i += 256) swl[i] = pl_w[i];
    for (int i = tid; i < BOXC * C; i += 256) swd[i] = pd_w[i];
    __syncthreads();

    const int p = blockIdx.x * 256 + tid;
    const int n = blockIdx.y;
    if (p >= SUMHW) return;
    const int s = scale_of(p);
    const int ploc = p - cOFF[s];
    const int HW = cHW[s];
    const float* h = hid + (size_t)n * C * SUMHW + p;

    float accl[A], accd[BOXC];
#pragma unroll
    for (int a = 0; a < A; a++) accl[a] = pl_b[a];
#pragma unroll
    for (int j = 0; j < BOXC; j++) accd[j] = pd_b[j];

    for (int c = 0; c < C; c++) {
        float v = h[(size_t)c * SUMHW];
#pragma unroll
        for (int a = 0; a < A; a++) accl[a] += swl[a * C + c] * v;
#pragma unroll
        for (int j = 0; j < BOXC; j++) accd[j] += swd[j * C + c] * v;
    }
    float m = accl[0];
#pragma unroll
    for (int a = 0; a < A; a++) {
        out[cPLOG[s] + ((size_t)n * A + a) * HW + ploc] = accl[a];
        m = fmaxf(m, accl[a]);
    }
#pragma unroll
    for (int j = 0; j < BOXC; j++)
        out[cPDEL[s] + ((size_t)n * BOXC + j) * HW + ploc] = accd[j];
    cell[(size_t)n * SUMHW + p] = m;
}

// ---------------- object delta head flat ------------------------------------
__global__ __launch_bounds__(256)
void heads_od_flat(const float* __restrict__ hid,
                   const float* __restrict__ od_w, const float* __restrict__ od_b,
                   float* __restrict__ out)
{
    __shared__ float sw[BOXC * C];
    const int tid = threadIdx.x;
    for (int i = tid; i < BOXC * C; i += 256) sw[i] = od_w[i];
    __syncthreads();

    const int p = blockIdx.x * 256 + tid;
    const int n = blockIdx.y;
    if (p >= SUMHW) return;
    const int s = scale_of(p);
    const int ploc = p - cOFF[s];
    const int HW = cHW[s];
    const float* h = hid + (size_t)n * C * SUMHW + p;

    float acc[BOXC];
#pragma unroll
    for (int j = 0; j < BOXC; j++) acc[j] = od_b[j];
    for (int c = 0; c < C; c++) {
        float v = h[(size_t)c * SUMHW];
#pragma unroll
        for (int j = 0; j < BOXC; j++) acc[j] += sw[j * C + c] * v;
    }
#pragma unroll
    for (int j = 0; j < BOXC; j++)
        out[cODEL[s] + ((size_t)n * BOXC + j) * HW + ploc] = acc[j];
}

// ---------------- per-scale top-K (smem-cached) -----------------------------
__global__ __launch_bounds__(256)
void topk_flat(const float* __restrict__ cell, const float* __restrict__ hid,
               float* __restrict__ cand_hid, float* __restrict__ cand_sc)
{
    const int s = blockIdx.x;
    const int n = blockIdx.y;
    const int HW = cHW[s], off = cOFF[s];
    __shared__ float sc[10240];
    __shared__ float s_val[256];
    __shared__ int   s_idx[256];
    __shared__ int   sel[KTOP];
    const int tid = threadIdx.x;

    for (int i = tid; i < HW; i += 256)
        sc[i] = cell[(size_t)n * SUMHW + off + i];
    __syncthreads();

    for (int k = 0; k < KTOP; k++) {
        float best = -CUDART_INF_F;
        int bi = HW;
        for (int i = tid; i < HW; i += 256) {
            float v = sc[i];
            if (v > best) { best = v; bi = i; }
        }
        s_val[tid] = best; s_idx[tid] = bi;
        __syncthreads();
        for (int offr = 128; offr > 0; offr >>= 1) {
            if (tid < offr) {
                float v2 = s_val[tid + offr]; int i2 = s_idx[tid + offr];
                if (v2 > s_val[tid] || (v2 == s_val[tid] && i2 < s_idx[tid])) {
                    s_val[tid] = v2; s_idx[tid] = i2;
                }
            }
            __syncthreads();
        }
        if (tid == 0) {
            sel[k] = s_idx[0];
            cand_sc[(size_t)n * 80 + s * KTOP + k] = s_val[0];
            sc[s_idx[0]] = -CUDART_INF_F;
        }
        __syncthreads();
    }
    for (int idx = tid; idx < C * KTOP; idx += 256) {
        int c = idx / KTOP, k = idx % KTOP;
        cand_hid[((size_t)n * C + c) * 80 + s * KTOP + k] =
            hid[((size_t)n * C + c) * SUMHW + off + sel[k]];
    }
}

// ---------------- global top-K over 80 --------------------------------------
__global__ void topk_global_kernel(const float* __restrict__ sc, int* __restrict__ keep)
{
    const int n = blockIdx.x;
    bool used[80];
    for (int i = 0; i < 80; i++) used[i] = false;
    const float* s = sc + (size_t)n * 80;
    for (int k = 0; k < KTOP; k++) {
        float best = -CUDART_INF_F; int bi = 0;
        for (int i = 0; i < 80; i++)
            if (!used[i] && s[i] > best) { best = s[i]; bi = i; }
        used[bi] = true;
        keep[n * KTOP + k] = bi;
    }
}

// ---------------- p_proj ----------------------------------------------------
__global__ __launch_bounds__(256)
void pproj_kernel(const float* __restrict__ cand_hid, const int* __restrict__ keep,
                  const float* __restrict__ rn1_w, const float* __restrict__ rn1_b,
                  float* __restrict__ pproj)
{
    const int k = blockIdx.x, n = blockIdx.y, d = threadIdx.x;
    __shared__ float sh[C];
    const int col = keep[n * KTOP + k];
    sh[d] = cand_hid[((size_t)n * C + d) * 80 + col];
    __syncthreads();
    float acc = rn1_b[d];
    const float* wrow = rn1_w + (size_t)d * (2 * C) + C;   // Wp
    for (int c = 0; c < C; c++) acc += sh[c] * wrow[c];
    pproj[((size_t)n * KTOP + k) * D + d] = acc;
}

// ---------------- o_proj GEMM flat ------------------------------------------
__global__ __launch_bounds__(256)
void gemm_oproj_flat(const float* __restrict__ hid, const float* __restrict__ rn1_w,
                     float* __restrict__ oproj)
{
    __shared__ __align__(16) float As[16][68];
    __shared__ __align__(16) float Bs[16][68];
    const int n = blockIdx.z;
    const int s0 = blockIdx.x * 64;
    const int d0 = blockIdx.y * 64;
    const int tid = threadIdx.x;
    const int td = tid % 16, ts = tid / 16;
    float acc[4][4];
#pragma unroll
    for (int i = 0; i < 4; i++)
#pragma unroll
        for (int j = 0; j < 4; j++) acc[i][j] = 0.f;
    const float* hb = hid + (size_t)n * C * SUMHW;

    for (int cb = 0; cb < C; cb += 16) {
        for (int i = tid; i < 16 * 64; i += 256) {
            int c = i >> 6, sx = i & 63;
            int gs = s0 + sx;
            As[c][sx] = (gs < SUMHW) ? hb[(size_t)(cb + c) * SUMHW + gs] : 0.f;
        }
        for (int i = tid; i < 64 * 16; i += 256) {
            int d = i >> 4, c = i & 15;
            Bs[c][d] = rn1_w[(size_t)(d0 + d) * (2 * C) + cb + c];   // Wo
        }
        __syncthreads();
#pragma unroll
        for (int c = 0; c < 16; c++) {
            float4 a4 = *(const float4*)&As[c][ts * 4];
            float4 b4 = *(const float4*)&Bs[c][td * 4];
            float a[4] = {a4.x, a4.y, a4.z, a4.w};
            float b[4] = {b4.x, b4.y, b4.z, b4.w};
#pragma unroll
            for (int i = 0; i < 4; i++)
#pragma unroll
                for (int j = 0; j < 4; j++) acc[i][j] += a[i] * b[j];
        }
        __syncthreads();
    }
#pragma unroll
    for (int i = 0; i < 4; i++) {
        int gs = s0 + ts * 4 + i;
        if (gs < SUMHW)
#pragma unroll
            for (int j = 0; j < 4; j++)
                oproj[((size_t)n * SUMHW + gs) * D + d0 + td * 4 + j] = acc[i][j];
    }
}

// ---------------- hsum: 8 pixels per block ----------------------------------
__global__ __launch_bounds__(256)
void hsum8(const float* __restrict__ oproj, const float* __restrict__ pproj,
           float* __restrict__ hout)
{
    const int n = blockIdx.y;
    const int s0 = blockIdx.x * 8;
    const int d = threadIdx.x;
    float pp[KTOP];
#pragma unroll
    for (int k = 0; k < KTOP; k++)
        pp[k] = pproj[((size_t)n * KTOP + k) * D + d];
#pragma unroll
    for (int i = 0; i < 8; i++) {
        int sflat = s0 + i;
        float o = oproj[((size_t)n * SUMHW + sflat) * D + d];
        float acc = 0.f;
#pragma unroll
        for (int k = 0; k < KTOP; k++) acc += fmaxf(o + pp[k], 0.f);
        hout[((size_t)n * SUMHW + sflat) * D + d] = acc;
    }
}

// ---------------- rn2 GEMM flat ---------------------------------------------
__global__ __launch_bounds__(256)
void gemm_rn2_flat(const float* __restrict__ hin, const float* __restrict__ rn2_w,
                   const float* __restrict__ rn2_b, float* __restrict__ hout)
{
    __shared__ __align__(16) float As[16][68];
    __shared__ __align__(16) float Bs[16][68];
    const int n = blockIdx.z;
    const int s0 = blockIdx.x * 64;
    const int e0 = blockIdx.y * 64;
    const int tid = threadIdx.x;
    const int td = tid % 16, ts = tid / 16;
    float acc[4][4];
#pragma unroll
    for (int i = 0; i < 4; i++)
#pragma unroll
        for (int j = 0; j < 4; j++) acc[i][j] = 0.f;

    for (int db = 0; db < D; db += 16) {
        for (int i = tid; i < 64 * 16; i += 256) {
            int sx = i >> 4, c = i & 15;
            int gs = s0 + sx;
            As[c][sx] = (gs < SUMHW) ? hin[((size_t)n * SUMHW + gs) * D + db + c] : 0.f;
        }
        for (int i = tid; i < 64 * 16; i += 256) {
            int e = i >> 4, c = i & 15;
            Bs[c][e] = rn2_w[(size_t)(e0 + e) * D + db + c];
        }
        __syncthreads();
#pragma unroll
        for (int c = 0; c < 16; c++) {
            float4 a4 = *(const float4*)&As[c][ts * 4];
            float4 b4 = *(const float4*)&Bs[c][td * 4];
            float a[4] = {a4.x, a4.y, a4.z, a4.w};
            float b[4] = {b4.x, b4.y, b4.z, b4.w};
#pragma unroll
            for (int i = 0; i < 4; i++)
#pragma unroll
                for (int j = 0; j < 4; j++) acc[i][j] += a[i] * b[j];
        }
        __syncthreads();
    }
#pragma unroll
    for (int i = 0; i < 4; i++) {
        int gs = s0 + ts * 4 + i;
        if (gs < SUMHW)
#pragma unroll
            for (int j = 0; j < 4; j++) {
                int e = e0 + td * 4 + j;
                hout[((size_t)n * SUMHW + gs) * D + e] = fmaxf(acc[i][j] + rn2_b[e], 0.f);
            }
    }
}

// ---------------- ol head flat ----------------------------------------------
__global__ __launch_bounds__(256)
void ol_flat(const float* __restrict__ h2, const float* __restrict__ ol_w,
             const float* __restrict__ ol_b, float* __restrict__ out)
{
    const int tid = threadIdx.x;
    const int warp = tid >> 5, lane = tid & 31;
    const int n = blockIdx.y;
    const int p = blockIdx.x * 8 + warp;
    if (p >= SUMHW) return;
    const int s = scale_of(p);
    const int ploc = p - cOFF[s];
    const int HW = cHW[s];
    const float* h = h2 + ((size_t)n * SUMHW + p) * D;
    float a0 = 0.f, a1 = 0.f, a2 = 0.f;
    for (int d = lane; d < D; d += 32) {
        float v = h[d];
        a0 += v * ol_w[d];
        a1 += v * ol_w[D + d];
        a2 += v * ol_w[2 * D + d];
    }
#pragma unroll
    for (int off = 16; off > 0; off >>= 1) {
        a0 += __shfl_down_sync(0xFFFFFFFFu, a0, off);
        a1 += __shfl_down_sync(0xFFFFFFFFu, a1, off);
        a2 += __shfl_down_sync(0xFFFFFFFFu, a2, off);
    }
    if (lane == 0) {
        out[cOLOG[s] + ((size_t)n * A + 0) * HW + ploc] = a0 + ol_b[0];
        out[cOLOG[s] + ((size_t)n * A + 1) * HW + ploc] = a1 + ol_b[1];
        out[cOLOG[s] + ((size_t)n * A + 2) * HW + ploc] = a2 + ol_b[2];
    }
}

// ---------------------------- host orchestration ----------------------------
extern "C" void kernel_launch(void* const* d_in, const int* in_sizes, int n_in,
                              void* d_out, int out_size)
{
    const float* f0 = (const float*)d_in[0];
    const float* f1 = (const float*)d_in[1];
    const float* f2 = (const float*)d_in[2];
    const float* f3 = (const float*)d_in[3];
    const float* pc1_w = (const float*)d_in[4];
    const float* pc1_b = (const float*)d_in[5];
    const float* pc2_w = (const float*)d_in[6];
    const float* pc2_b = (const float*)d_in[7];
    const float* oc1_w = (const float*)d_in[8];
    const float* oc1_b = (const float*)d_in[9];
    const float* oc2_w = (const float*)d_in[10];
    const float* oc2_b = (const float*)d_in[11];
    const float* rn1_w = (const float*)d_in[12];
    const float* rn1_b = (const float*)d_in[13];
    const float* rn2_w = (const float*)d_in[14];
    const float* rn2_b = (const float*)d_in[15];
    const float* pl_w  = (const float*)d_in[16];
    const float* pl_b  = (const float*)d_in[17];
    const float* pd_w  = (const float*)d_in[18];
    const float* pd_b  = (const float*)d_in[19];
    const float* ol_w  = (const float*)d_in[20];
    const float* ol_b  = (const float*)d_in[21];
    const float* od_w  = (const float*)d_in[22];
    const float* od_b  = (const float*)d_in[23];
    float* out = (float*)d_out;

    float *t1, *t2, *o1, *o2, *cell, *cand_hid, *cand_sc, *pproj;
    int* keep;
    cudaGetSymbolAddress((void**)&t1, g_t1);
    cudaGetSymbolAddress((void**)&t2, g_t2);
    cudaGetSymbolAddress((void**)&o1, g_o1);
    cudaGetSymbolAddress((void**)&o2, g_o2);
    cudaGetSymbolAddress((void**)&cell, g_cell);
    cudaGetSymbolAddress((void**)&cand_hid, g_cand_hid);
    cudaGetSymbolAddress((void**)&cand_sc, g_cand_sc);
    cudaGetSymbolAddress((void**)&keep, g_keep);
    cudaGetSymbolAddress((void**)&pproj, g_pproj);

    cudaFuncSetAttribute(conv3x3_bf16,
                         cudaFuncAttributeMaxDynamicSharedMemorySize, CONV_SMEM);

    const dim3 convGrid(55, 4, NB);                // 55 px-tiles, 4 oc-groups of 64
    const dim3 headGrid((SUMHW + 255) / 256, NB);
    const dim3 gemmGrid((SUMHW + 63) / 64, D / 64, NB);

    // ---- person branch ----
    conv3x3_bf16<<<convGrid, 256, CONV_SMEM>>>(f0, f1, f2, f3, pc1_w, pc1_b, t1, 1);
    conv3x3_bf16<<<convGrid, 256, CONV_SMEM>>>(t1, t1, t1, t1, pc2_w, pc2_b, t2, 0);
    heads_p_flat<<<headGrid, 256>>>(t2, pl_w, pl_b, pd_w, pd_b, out, cell);
    topk_flat<<<dim3(4, NB), 256>>>(cell, t2, cand_hid, cand_sc);
    topk_global_kernel<<<NB, 1>>>(cand_sc, keep);
    pproj_kernel<<<dim3(KTOP, NB), 256>>>(cand_hid, keep, rn1_w, rn1_b, pproj);

    // ---- object branch ----
    conv3x3_bf16<<<convGrid, 256, CONV_SMEM>>>(f0, f1, f2, f3, oc1_w, oc1_b, t1, 1);
    conv3x3_bf16<<<convGrid, 256, CONV_SMEM>>>(t1, t1, t1, t1, oc2_w, oc2_b, t2, 0);
    heads_od_flat<<<headGrid, 256>>>(t2, od_w, od_b, out);
    gemm_oproj_flat<<<gemmGrid, 256>>>(t2, rn1_w, o1);
    hsum8<<<dim3(SUMHW / 8, NB), 256>>>(o1, pproj, o2);
    gemm_rn2_flat<<<gemmGrid, 256>>>(o2, rn2_w, rn2_b, o1);
    ol_flat<<<dim3((SUMHW + 7) / 8, NB), 256>>>(o1, ol_w, ol_b, out);

    (void)in_sizes; (void)n_in; (void)out_size;
}

// round 7
// speedup vs baseline: 5.4732x; 1.0446x over previous
#include <cuda_runtime.h>
#include <cuda_bf16.h>
#include <math_constants.h>
#include <stdint.h>

// Problem constants
#define NB   2
#define C    256
#define A    3
#define KTOP 20
#define D    256
#define BOXC 12
#define SUMHW 13600   // 10240 + 2560 + 640 + 160
#define WSPL 294912   // per-layer split-weight u32 count: 16*9*8*256

// ---------------- scratch (device globals) ----------------------------------
__device__ float g_t2[NB * C * SUMHW];
__device__ float g_o1[NB * SUMHW * D];
__device__ float g_o2[NB * SUMHW * D];
__device__ float g_cell[NB * SUMHW];
__device__ float g_cand_hid[NB * C * 80];
__device__ float g_cand_sc[NB * 80];
__device__ int   g_keep[NB * KTOP];
__device__ float g_pproj[NB * KTOP * D];
// split activations: [n][c2=128][SUMHW] u32 (bf16x2: ci even low, odd high)
__device__ uint32_t g_sA_hi[NB * 128 * SUMHW];
__device__ uint32_t g_sA_lo[NB * 128 * SUMHW];
__device__ uint32_t g_sB_hi[NB * 128 * SUMHW];
__device__ uint32_t g_sB_lo[NB * 128 * SUMHW];
// split weights: 4 layers x WSPL
__device__ uint32_t g_wsp_hi[4 * WSPL];
__device__ uint32_t g_wsp_lo[4 * WSPL];

// per-scale constants
__device__ __constant__ int cOFF[4]  = {0, 10240, 12800, 13440};
__device__ __constant__ int cHW[4]   = {10240, 2560, 640, 160};
__device__ __constant__ int cH[4]    = {80, 40, 20, 10};
__device__ __constant__ int cW[4]    = {128, 64, 32, 16};
__device__ __constant__ int cPLOG[4] = {0,      61440,  76800,  80640};
__device__ __constant__ int cPDEL[4] = {81600,  327360, 388800, 404160};
__device__ __constant__ int cOLOG[4] = {408000, 469440, 484800, 488640};
__device__ __constant__ int cODEL[4] = {489600, 735360, 796800, 812160};

__device__ __forceinline__ int scale_of(int p) {
    return (p < 10240) ? 0 : (p < 12800) ? 1 : (p < 13440) ? 2 : 3;
}

// ---------------- bf16 helpers ----------------------------------------------
__device__ __forceinline__ void mma_bf16(float* c, const uint32_t* a, const uint32_t* b) {
    asm volatile(
        "mma.sync.aligned.m16n8k16.row.col.f32.bf16.bf16.f32 "
        "{%0,%1,%2,%3}, {%4,%5,%6,%7}, {%8,%9}, {%0,%1,%2,%3};\n"
        : "+f"(c[0]), "+f"(c[1]), "+f"(c[2]), "+f"(c[3])
        : "r"(a[0]), "r"(a[1]), "r"(a[2]), "r"(a[3]), "r"(b[0]), "r"(b[1]));
}
// pack split of (v0 low-half, v1 high-half)
__device__ __forceinline__ void split_pack(float v0, float v1,
                                           uint32_t& hi_out, uint32_t& lo_out) {
    __nv_bfloat16 h0 = __float2bfloat16(v0);
    __nv_bfloat16 h1 = __float2bfloat16(v1);
    __nv_bfloat16 l0 = __float2bfloat16(v0 - __bfloat162float(h0));
    __nv_bfloat16 l1 = __float2bfloat16(v1 - __bfloat162float(h1));
    hi_out = ((uint32_t)__bfloat16_as_ushort(h1) << 16) | (uint32_t)__bfloat16_as_ushort(h0);
    lo_out = ((uint32_t)__bfloat16_as_ushort(l1) << 16) | (uint32_t)__bfloat16_as_ushort(l0);
}

// ---------------- weight pre-split ------------------------------------------
// layout: [layer][ ((cb*9+tap)*8+p)*256 + oc ]  where ci = cb*16 + 2p (+1)
__global__ __launch_bounds__(256)
void split_w_kernel(const float* __restrict__ w0, const float* __restrict__ w1,
                    const float* __restrict__ w2, const float* __restrict__ w3,
                    uint32_t* __restrict__ outH, uint32_t* __restrict__ outL)
{
    const int i = blockIdx.x * 256 + threadIdx.x;
    if (i >= WSPL) return;
    const int layer = blockIdx.y;
    const float* w = (layer == 0) ? w0 : (layer == 1) ? w1 : (layer == 2) ? w2 : w3;
    const int oc = i & 255;
    const int r  = i >> 8;         // 0..1151
    const int p  = r & 7;
    const int r2 = r >> 3;         // 0..143
    const int tap = r2 % 9;
    const int cb  = r2 / 9;
    const int ci0 = cb * 16 + 2 * p;
    float v0 = w[(size_t)oc * 2304 + ci0 * 9 + tap];
    float v1 = w[(size_t)oc * 2304 + (ci0 + 1) * 9 + tap];
    uint32_t hi, lo;
    split_pack(v0, v1, hi, lo);
    outH[(size_t)layer * WSPL + i] = hi;
    outL[(size_t)layer * WSPL + i] = lo;
}

// ---------------- feats pre-split -------------------------------------------
__global__ __launch_bounds__(256)
void split_feats_kernel(const float* __restrict__ f0, const float* __restrict__ f1,
                        const float* __restrict__ f2, const float* __restrict__ f3,
                        uint32_t* __restrict__ outH, uint32_t* __restrict__ outL)
{
    const int px = blockIdx.x * 256 + threadIdx.x;
    if (px >= SUMHW) return;
    const int c2 = blockIdx.y;
    const int n  = blockIdx.z;
    const int s = scale_of(px);
    const int ploc = px - cOFF[s];
    const int HW = cHW[s];
    const float* f = (s == 0) ? f0 : (s == 1) ? f1 : (s == 2) ? f2 : f3;
    const float* src = f + ((size_t)n * C + 2 * c2) * HW + ploc;
    uint32_t hi, lo;
    split_pack(src[0], src[HW], hi, lo);
    const size_t o = ((size_t)n * 128 + c2) * SUMHW + px;
    outH[o] = hi;
    outL[o] = lo;
}

// ---------------- conv3x3 via 3-term bf16 mma, pre-split I/O ----------------
// Block: 256 thr = 8 warps; warp = output row; block tile 64oc x (8x32)px.
// smem layouts conflict-free (bank = 8t + g):
//   s_w[(tap*8+p)*72 + oc]   (72 % 32 == 8)
//   s_i[(p*10+r)*36 + cc]    (360 % 32 == 8)
#define WPAD 72
#define IPAD 36
#define OFF_WH 0
#define OFF_WL 5184          // 9*8*72
#define OFF_IH 10368
#define OFF_IL 13248         // + 8*10*36
#define CONV_U32 16128
#define CONV_SMEM (CONV_U32 * 4)

__global__ __launch_bounds__(256, 2)
void conv3x3_sp(const uint32_t* __restrict__ inH, const uint32_t* __restrict__ inL,
                const uint32_t* __restrict__ wH, const uint32_t* __restrict__ wL,
                const float* __restrict__ bias,
                float* __restrict__ dstF,
                uint32_t* __restrict__ dstH, uint32_t* __restrict__ dstL,
                int out_split)
{
    extern __shared__ uint32_t sm[];
    uint32_t* s_wH = sm + OFF_WH;
    uint32_t* s_wL = sm + OFF_WL;
    uint32_t* s_iH = sm + OFF_IH;
    uint32_t* s_iL = sm + OFF_IL;
    __shared__ float s_bias[64];

    const int bx = blockIdx.x;
    int s, t_;
    if (bx < 40)      { s = 0; t_ = bx; }
    else if (bx < 50) { s = 1; t_ = bx - 40; }
    else if (bx < 53) { s = 2; t_ = bx - 50; }
    else              { s = 3; t_ = bx - 53; }
    const int H = cH[s], W = cW[s];
    const int tilesX = (W >= 32) ? (W / 32) : 1;
    const int ty = t_ / tilesX, tx = t_ % tilesX;
    const int h0 = ty * 8, w0 = tx * 32;
    const int n = blockIdx.z;
    const int ocBase = blockIdx.y * 64;

    const int tid  = threadIdx.x;
    const int warp = tid >> 5;
    const int lane = tid & 31;
    const int g = lane >> 2;
    const int t = lane & 3;

    if (tid < 64) s_bias[tid] = bias[ocBase + tid];

    float acc[4][4][4];
#pragma unroll
    for (int i = 0; i < 4; i++)
#pragma unroll
        for (int j = 0; j < 4; j++)
#pragma unroll
            for (int k = 0; k < 4; k++) acc[i][j][k] = 0.f;

    for (int q = 0; q < 16; q++) {
        __syncthreads();
        // weights: pure copy, 4608 u32 per array
        {
            const uint32_t* wHq = wH + (size_t)q * 72 * 256 + ocBase;
            const uint32_t* wLq = wL + (size_t)q * 72 * 256 + ocBase;
#pragma unroll
            for (int it = 0; it < 18; it++) {
                int idx = tid + it * 256;
                int row = idx >> 6, oc = idx & 63;
                s_wH[row * WPAD + oc] = wHq[row * 256 + oc];
                s_wL[row * WPAD + oc] = wLq[row * 256 + oc];
            }
        }
        // inputs: gather u32 (8 ci-pairs x 10 rows x 34 cols)
        for (int idx = tid; idx < 8 * 10 * 34; idx += 256) {
            int p = idx / 340, rem = idx % 340;
            int r = rem / 34, cc = rem % 34;
            int gh = h0 + r - 1, gw = w0 + cc - 1;
            uint32_t vh = 0, vl = 0;
            if (gh >= 0 && gh < H && gw >= 0 && gw < W) {
                size_t off = ((size_t)n * 128 + q * 8 + p) * SUMHW + cOFF[s] + gh * W + gw;
                vh = inH[off];
                vl = inL[off];
            }
            s_iH[(p * 10 + r) * IPAD + cc] = vh;
            s_iL[(p * 10 + r) * IPAD + cc] = vl;
        }
        __syncthreads();

#pragma unroll
        for (int kh = 0; kh < 3; kh++)
#pragma unroll
        for (int kw = 0; kw < 3; kw++) {
            const int tap = kh * 3 + kw;
            uint32_t bh[4][2], bl[4][2];
            const int ib0 = (t * 10 + warp + kh) * IPAD + kw + g;
            const int ib1 = ((t + 4) * 10 + warp + kh) * IPAD + kw + g;
#pragma unroll
            for (int p4 = 0; p4 < 4; p4++) {
                bh[p4][0] = s_iH[ib0 + p4 * 8];
                bh[p4][1] = s_iH[ib1 + p4 * 8];
                bl[p4][0] = s_iL[ib0 + p4 * 8];
                bl[p4][1] = s_iL[ib1 + p4 * 8];
            }
            const int ia0 = (tap * 8 + t) * WPAD + g;
            const int ia1 = (tap * 8 + t + 4) * WPAD + g;
#pragma unroll
            for (int o4 = 0; o4 < 4; o4++) {
                uint32_t ah[4], al[4];
                ah[0] = s_wH[ia0 + o4 * 16];     al[0] = s_wL[ia0 + o4 * 16];
                ah[1] = s_wH[ia0 + o4 * 16 + 8]; al[1] = s_wL[ia0 + o4 * 16 + 8];
                ah[2] = s_wH[ia1 + o4 * 16];     al[2] = s_wL[ia1 + o4 * 16];
                ah[3] = s_wH[ia1 + o4 * 16 + 8]; al[3] = s_wL[ia1 + o4 * 16 + 8];
#pragma unroll
                for (int p4 = 0; p4 < 4; p4++) {
                    mma_bf16(acc[o4][p4], ah, bh[p4]);
                    mma_bf16(acc[o4][p4], ah, bl[p4]);
                    mma_bf16(acc[o4][p4], al, bh[p4]);
                }
            }
        }
    }

    // epilogue: C frag mapping (validated R6): c0=(oc,col) c1=(oc,col+1)
    // c2=(oc+8,col) c3=(oc+8,col+1); oc = ocBase+o4*16+g, col = p4*8+2t
    const int ghout = h0 + warp;
    if (!out_split) {
        if (ghout < H) {
            float* dbase = dstF + (size_t)n * C * SUMHW + cOFF[s] + (size_t)ghout * W + w0;
#pragma unroll
            for (int o4 = 0; o4 < 4; o4++) {
                int ocl = o4 * 16 + g;
                float b0v = s_bias[ocl];
                float b1v = s_bias[ocl + 8];
#pragma unroll
                for (int p4 = 0; p4 < 4; p4++) {
                    int col = p4 * 8 + 2 * t;
                    if (w0 + col < W) {
                        float2 v0 = make_float2(fmaxf(acc[o4][p4][0] + b0v, 0.f),
                                                fmaxf(acc[o4][p4][1] + b0v, 0.f));
                        float2 v1 = make_float2(fmaxf(acc[o4][p4][2] + b1v, 0.f),
                                                fmaxf(acc[o4][p4][3] + b1v, 0.f));
                        *(float2*)(dbase + (size_t)(ocBase + ocl) * SUMHW + col) = v0;
                        *(float2*)(dbase + (size_t)(ocBase + ocl + 8) * SUMHW + col) = v1;
                    }
                }
            }
        }
    } else {
        // split write: pair lanes (g, g^1) hold (oc, oc^1); shfl_xor(4) exchanges.
        const size_t base = ((size_t)n * 128) * SUMHW + cOFF[s] + (size_t)ghout * W + w0;
#pragma unroll
        for (int o4 = 0; o4 < 4; o4++) {
            int ocl = o4 * 16 + g;
            float b0v = s_bias[ocl];
            float b1v = s_bias[ocl + 8];
            const size_t w2a = (size_t)((ocBase + ocl) >> 1) * SUMHW;       // word row for oc
            const size_t w2b = (size_t)(((ocBase + ocl) >> 1) + 4) * SUMHW; // for oc+8
#pragma unroll
            for (int p4 = 0; p4 < 4; p4++) {
                int col = p4 * 8 + 2 * t;
                float v0 = fmaxf(acc[o4][p4][0] + b0v, 0.f);
                float v1 = fmaxf(acc[o4][p4][1] + b0v, 0.f);
                float v2 = fmaxf(acc[o4][p4][2] + b1v, 0.f);
                float v3 = fmaxf(acc[o4][p4][3] + b1v, 0.f);
                float p0 = __shfl_xor_sync(0xFFFFFFFFu, v0, 4);
                float p1 = __shfl_xor_sync(0xFFFFFFFFu, v1, 4);
                float p2 = __shfl_xor_sync(0xFFFFFFFFu, v2, 4);
                float p3 = __shfl_xor_sync(0xFFFFFFFFu, v3, 4);
                if (((g & 1) == 0) && ghout < H && (w0 + col) < W) {
                    uint32_t hw, lw;
                    split_pack(v0, p0, hw, lw);
                    dstH[base + w2a + col] = hw;  dstL[base + w2a + col] = lw;
                    split_pack(v1, p1, hw, lw);
                    dstH[base + w2a + col + 1] = hw;  dstL[base + w2a + col + 1] = lw;
                    split_pack(v2, p2, hw, lw);
                    dstH[base + w2b + col] = hw;  dstL[base + w2b + col] = lw;
                    split_pack(v3, p3, hw, lw);
                    dstH[base + w2b + col + 1] = hw;  dstL[base + w2b + col + 1] = lw;
                }
            }
        }
    }
}

// ---------------- person heads flat -----------------------------------------
__global__ __launch_bounds__(256)
void heads_p_flat(const float* __restrict__ hid,
                  const float* __restrict__ pl_w, const float* __restrict__ pl_b,
                  const float* __restrict__ pd_w, const float* __restrict__ pd_b,
                  float* __restrict__ out, float* __restrict__ cell)
{
    __shared__ float swl[A * C];
    __shared__ float swd[BOXC * C];
    const int tid = threadIdx.x;
    for (int i = tid; i < A * C; i += 256) swl[i] = pl_w[i];
    for (int i = tid; i < BOXC * C; i += 256) swd[i] = pd_w[i];
    __syncthreads();

    const int p = blockIdx.x * 256 + tid;
    const int n = blockIdx.y;
    if (p >= SUMHW) return;
    const int s = scale_of(p);
    const int ploc = p - cOFF[s];
    const int HW = cHW[s];
    const float* h = hid + (size_t)n * C * SUMHW + p;

    float accl[A], accd[BOXC];
#pragma unroll
    for (int a = 0; a < A; a++) accl[a] = pl_b[a];
#pragma unroll
    for (int j = 0; j < BOXC; j++) accd[j] = pd_b[j];

    for (int c = 0; c < C; c++) {
        float v = h[(size_t)c * SUMHW];
#pragma unroll
        for (int a = 0; a < A; a++) accl[a] += swl[a * C + c] * v;
#pragma unroll
        for (int j = 0; j < BOXC; j++) accd[j] += swd[j * C + c] * v;
    }
    float m = accl[0];
#pragma unroll
    for (int a = 0; a < A; a++) {
        out[cPLOG[s] + ((size_t)n * A + a) * HW + ploc] = accl[a];
        m = fmaxf(m, accl[a]);
    }
#pragma unroll
    for (int j = 0; j < BOXC; j++)
        out[cPDEL[s] + ((size_t)n * BOXC + j) * HW + ploc] = accd[j];
    cell[(size_t)n * SUMHW + p] = m;
}

// ---------------- object delta head flat ------------------------------------
__global__ __launch_bounds__(256)
void heads_od_flat(const float* __restrict__ hid,
                   const float* __restrict__ od_w, const float* __restrict__ od_b,
                   float* __restrict__ out)
{
    __shared__ float sw[BOXC * C];
    const int tid = threadIdx.x;
    for (int i = tid; i < BOXC * C; i += 256) sw[i] = od_w[i];
    __syncthreads();

    const int p = blockIdx.x * 256 + tid;
    const int n = blockIdx.y;
    if (p >= SUMHW) return;
    const int s = scale_of(p);
    const int ploc = p - cOFF[s];
    const int HW = cHW[s];
    const float* h = hid + (size_t)n * C * SUMHW + p;

    float acc[BOXC];
#pragma unroll
    for (int j = 0; j < BOXC; j++) acc[j] = od_b[j];
    for (int c = 0; c < C; c++) {
        float v = h[(size_t)c * SUMHW];
#pragma unroll
        for (int j = 0; j < BOXC; j++) acc[j] += sw[j * C + c] * v;
    }
#pragma unroll
    for (int j = 0; j < BOXC; j++)
        out[cODEL[s] + ((size_t)n * BOXC + j) * HW + ploc] = acc[j];
}

// ---------------- per-scale top-K (smem-cached) -----------------------------
__global__ __launch_bounds__(256)
void topk_flat(const float* __restrict__ cell, const float* __restrict__ hid,
               float* __restrict__ cand_hid, float* __restrict__ cand_sc)
{
    const int s = blockIdx.x;
    const int n = blockIdx.y;
    const int HW = cHW[s], off = cOFF[s];
    __shared__ float sc[10240];
    __shared__ float s_val[256];
    __shared__ int   s_idx[256];
    __shared__ int   sel[KTOP];
    const int tid = threadIdx.x;

    for (int i = tid; i < HW; i += 256)
        sc[i] = cell[(size_t)n * SUMHW + off + i];
    __syncthreads();

    for (int k = 0; k < KTOP; k++) {
        float best = -CUDART_INF_F;
        int bi = HW;
        for (int i = tid; i < HW; i += 256) {
            float v = sc[i];
            if (v > best) { best = v; bi = i; }
        }
        s_val[tid] = best; s_idx[tid] = bi;
        __syncthreads();
        for (int offr = 128; offr > 0; offr >>= 1) {
            if (tid < offr) {
                float v2 = s_val[tid + offr]; int i2 = s_idx[tid + offr];
                if (v2 > s_val[tid] || (v2 == s_val[tid] && i2 < s_idx[tid])) {
                    s_val[tid] = v2; s_idx[tid] = i2;
                }
            }
            __syncthreads();
        }
        if (tid == 0) {
            sel[k] = s_idx[0];
            cand_sc[(size_t)n * 80 + s * KTOP + k] = s_val[0];
            sc[s_idx[0]] = -CUDART_INF_F;
        }
        __syncthreads();
    }
    for (int idx = tid; idx < C * KTOP; idx += 256) {
        int c = idx / KTOP, k = idx % KTOP;
        cand_hid[((size_t)n * C + c) * 80 + s * KTOP + k] =
            hid[((size_t)n * C + c) * SUMHW + off + sel[k]];
    }
}

// ---------------- global top-K over 80 --------------------------------------
__global__ void topk_global_kernel(const float* __restrict__ sc, int* __restrict__ keep)
{
    const int n = blockIdx.x;
    bool used[80];
    for (int i = 0; i < 80; i++) used[i] = false;
    const float* s = sc + (size_t)n * 80;
    for (int k = 0; k < KTOP; k++) {
        float best = -CUDART_INF_F; int bi = 0;
        for (int i = 0; i < 80; i++)
            if (!used[i] && s[i] > best) { best = s[i]; bi = i; }
        used[bi] = true;
        keep[n * KTOP + k] = bi;
    }
}

// ---------------- p_proj ----------------------------------------------------
__global__ __launch_bounds__(256)
void pproj_kernel(const float* __restrict__ cand_hid, const int* __restrict__ keep,
                  const float* __restrict__ rn1_w, const float* __restrict__ rn1_b,
                  float* __restrict__ pproj)
{
    const int k = blockIdx.x, n = blockIdx.y, d = threadIdx.x;
    __shared__ float sh[C];
    const int col = keep[n * KTOP + k];
    sh[d] = cand_hid[((size_t)n * C + d) * 80 + col];
    __syncthreads();
    float acc = rn1_b[d];
    const float* wrow = rn1_w + (size_t)d * (2 * C) + C;   // Wp
    for (int c = 0; c < C; c++) acc += sh[c] * wrow[c];
    pproj[((size_t)n * KTOP + k) * D + d] = acc;
}

// ---------------- o_proj GEMM flat ------------------------------------------
__global__ __launch_bounds__(256)
void gemm_oproj_flat(const float* __restrict__ hid, const float* __restrict__ rn1_w,
                     float* __restrict__ oproj)
{
    __shared__ __align__(16) float As[16][68];
    __shared__ __align__(16) float Bs[16][68];
    const int n = blockIdx.z;
    const int s0 = blockIdx.x * 64;
    const int d0 = blockIdx.y * 64;
    const int tid = threadIdx.x;
    const int td = tid % 16, ts = tid / 16;
    float acc[4][4];
#pragma unroll
    for (int i = 0; i < 4; i++)
#pragma unroll
        for (int j = 0; j < 4; j++) acc[i][j] = 0.f;
    const float* hb = hid + (size_t)n * C * SUMHW;

    for (int cb = 0; cb < C; cb += 16) {
        for (int i = tid; i < 16 * 64; i += 256) {
            int c = i >> 6, sx = i & 63;
            int gs = s0 + sx;
            As[c][sx] = (gs < SUMHW) ? hb[(size_t)(cb + c) * SUMHW + gs] : 0.f;
        }
        for (int i = tid; i < 64 * 16; i += 256) {
            int d = i >> 4, c = i & 15;
            Bs[c][d] = rn1_w[(size_t)(d0 + d) * (2 * C) + cb + c];   // Wo
        }
        __syncthreads();
#pragma unroll
        for (int c = 0; c < 16; c++) {
            float4 a4 = *(const float4*)&As[c][ts * 4];
            float4 b4 = *(const float4*)&Bs[c][td * 4];
            float a[4] = {a4.x, a4.y, a4.z, a4.w};
            float b[4] = {b4.x, b4.y, b4.z, b4.w};
#pragma unroll
            for (int i = 0; i < 4; i++)
#pragma unroll
                for (int j = 0; j < 4; j++) acc[i][j] += a[i] * b[j];
        }
        __syncthreads();
    }
#pragma unroll
    for (int i = 0; i < 4; i++) {
        int gs = s0 + ts * 4 + i;
        if (gs < SUMHW)
#pragma unroll
            for (int j = 0; j < 4; j++)
                oproj[((size_t)n * SUMHW + gs) * D + d0 + td * 4 + j] = acc[i][j];
    }
}

// ---------------- hsum: 8 pixels per block ----------------------------------
__global__ __launch_bounds__(256)
void hsum8(const float* __restrict__ oproj, const float* __restrict__ pproj,
           float* __restrict__ hout)
{
    const int n = blockIdx.y;
    const int s0 = blockIdx.x * 8;
    const int d = threadIdx.x;
    float pp[KTOP];
#pragma unroll
    for (int k = 0; k < KTOP; k++)
        pp[k] = pproj[((size_t)n * KTOP + k) * D + d];
#pragma unroll
    for (int i = 0; i < 8; i++) {
        int sflat = s0 + i;
        float o = oproj[((size_t)n * SUMHW + sflat) * D + d];
        float acc = 0.f;
#pragma unroll
        for (int k = 0; k < KTOP; k++) acc += fmaxf(o + pp[k], 0.f);
        hout[((size_t)n * SUMHW + sflat) * D + d] = acc;
    }
}

// ---------------- rn2 GEMM flat ---------------------------------------------
__global__ __launch_bounds__(256)
void gemm_rn2_flat(const float* __restrict__ hin, const float* __restrict__ rn2_w,
                   const float* __restrict__ rn2_b, float* __restrict__ hout)
{
    __shared__ __align__(16) float As[16][68];
    __shared__ __align__(16) float Bs[16][68];
    const int n = blockIdx.z;
    const int s0 = blockIdx.x * 64;
    const int e0 = blockIdx.y * 64;
    const int tid = threadIdx.x;
    const int td = tid % 16, ts = tid / 16;
    float acc[4][4];
#pragma unroll
    for (int i = 0; i < 4; i++)
#pragma unroll
        for (int j = 0; j < 4; j++) acc[i][j] = 0.f;

    for (int db = 0; db < D; db += 16) {
        for (int i = tid; i < 64 * 16; i += 256) {
            int sx = i >> 4, c = i & 15;
            int gs = s0 + sx;
            As[c][sx] = (gs < SUMHW) ? hin[((size_t)n * SUMHW + gs) * D + db + c] : 0.f;
        }
        for (int i = tid; i < 64 * 16; i += 256) {
            int e = i >> 4, c = i & 15;
            Bs[c][e] = rn2_w[(size_t)(e0 + e) * D + db + c];
        }
        __syncthreads();
#pragma unroll
        for (int c = 0; c < 16; c++) {
            float4 a4 = *(const float4*)&As[c][ts * 4];
            float4 b4 = *(const float4*)&Bs[c][td * 4];
            float a[4] = {a4.x, a4.y, a4.z, a4.w};
            float b[4] = {b4.x, b4.y, b4.z, b4.w};
#pragma unroll
            for (int i = 0; i < 4; i++)
#pragma unroll
                for (int j = 0; j < 4; j++) acc[i][j] += a[i] * b[j];
        }
        __syncthreads();
    }
#pragma unroll
    for (int i = 0; i < 4; i++) {
        int gs = s0 + ts * 4 + i;
        if (gs < SUMHW)
#pragma unroll
            for (int j = 0; j < 4; j++) {
                int e = e0 + td * 4 + j;
                hout[((size_t)n * SUMHW + gs) * D + e] = fmaxf(acc[i][j] + rn2_b[e], 0.f);
            }
    }
}

// ---------------- ol head flat ----------------------------------------------
__global__ __launch_bounds__(256)
void ol_flat(const float* __restrict__ h2, const float* __restrict__ ol_w,
             const float* __restrict__ ol_b, float* __restrict__ out)
{
    const int tid = threadIdx.x;
    const int warp = tid >> 5, lane = tid & 31;
    const int n = blockIdx.y;
    const int p = blockIdx.x * 8 + warp;
    if (p >= SUMHW) return;
    const int s = scale_of(p);
    const int ploc = p - cOFF[s];
    const int HW = cHW[s];
    const float* h = h2 + ((size_t)n * SUMHW + p) * D;
    float a0 = 0.f, a1 = 0.f, a2 = 0.f;
    for (int d = lane; d < D; d += 32) {
        float v = h[d];
        a0 += v * ol_w[d];
        a1 += v * ol_w[D + d];
        a2 += v * ol_w[2 * D + d];
    }
#pragma unroll
    for (int off = 16; off > 0; off >>= 1) {
        a0 += __shfl_down_sync(0xFFFFFFFFu, a0, off);
        a1 += __shfl_down_sync(0xFFFFFFFFu, a1, off);
        a2 += __shfl_down_sync(0xFFFFFFFFu, a2, off);
    }
    if (lane == 0) {
        out[cOLOG[s] + ((size_t)n * A + 0) * HW + ploc] = a0 + ol_b[0];
        out[cOLOG[s] + ((size_t)n * A + 1) * HW + ploc] = a1 + ol_b[1];
        out[cOLOG[s] + ((size_t)n * A + 2) * HW + ploc] = a2 + ol_b[2];
    }
}

// ---------------------------- host orchestration ----------------------------
extern "C" void kernel_launch(void* const* d_in, const int* in_sizes, int n_in,
                              void* d_out, int out_size)
{
    const float* f0 = (const float*)d_in[0];
    const float* f1 = (const float*)d_in[1];
    const float* f2 = (const float*)d_in[2];
    const float* f3 = (const float*)d_in[3];
    const float* pc1_w = (const float*)d_in[4];
    const float* pc1_b = (const float*)d_in[5];
    const float* pc2_w = (const float*)d_in[6];
    const float* pc2_b = (const float*)d_in[7];
    const float* oc1_w = (const float*)d_in[8];
    const float* oc1_b = (const float*)d_in[9];
    const float* oc2_w = (const float*)d_in[10];
    const float* oc2_b = (const float*)d_in[11];
    const float* rn1_w = (const float*)d_in[12];
    const float* rn1_b = (const float*)d_in[13];
    const float* rn2_w = (const float*)d_in[14];
    const float* rn2_b = (const float*)d_in[15];
    const float* pl_w  = (const float*)d_in[16];
    const float* pl_b  = (const float*)d_in[17];
    const float* pd_w  = (const float*)d_in[18];
    const float* pd_b  = (const float*)d_in[19];
    const float* ol_w  = (const float*)d_in[20];
    const float* ol_b  = (const float*)d_in[21];
    const float* od_w  = (const float*)d_in[22];
    const float* od_b  = (const float*)d_in[23];
    float* out = (float*)d_out;

    float *t2, *o1, *o2, *cell, *cand_hid, *cand_sc, *pproj;
    int* keep;
    uint32_t *sAh, *sAl, *sBh, *sBl, *wsh, *wsl;
    cudaGetSymbolAddress((void**)&t2, g_t2);
    cudaGetSymbolAddress((void**)&o1, g_o1);
    cudaGetSymbolAddress((void**)&o2, g_o2);
    cudaGetSymbolAddress((void**)&cell, g_cell);
    cudaGetSymbolAddress((void**)&cand_hid, g_cand_hid);
    cudaGetSymbolAddress((void**)&cand_sc, g_cand_sc);
    cudaGetSymbolAddress((void**)&keep, g_keep);
    cudaGetSymbolAddress((void**)&pproj, g_pproj);
    cudaGetSymbolAddress((void**)&sAh, g_sA_hi);
    cudaGetSymbolAddress((void**)&sAl, g_sA_lo);
    cudaGetSymbolAddress((void**)&sBh, g_sB_hi);
    cudaGetSymbolAddress((void**)&sBl, g_sB_lo);
    cudaGetSymbolAddress((void**)&wsh, g_wsp_hi);
    cudaGetSymbolAddress((void**)&wsl, g_wsp_lo);

    cudaFuncSetAttribute(conv3x3_sp,
                         cudaFuncAttributeMaxDynamicSharedMemorySize, CONV_SMEM);

    const dim3 convGrid(55, 4, NB);
    const dim3 headGrid((SUMHW + 255) / 256, NB);
    const dim3 gemmGrid((SUMHW + 63) / 64, D / 64, NB);

    // ---- prep: split weights (4 layers) + feats ----
    split_w_kernel<<<dim3((WSPL + 255) / 256, 4), 256>>>(pc1_w, pc2_w, oc1_w, oc2_w, wsh, wsl);
    split_feats_kernel<<<dim3((SUMHW + 255) / 256, 128, NB), 256>>>(f0, f1, f2, f3, sAh, sAl);

    // ---- person branch ----
    conv3x3_sp<<<convGrid, 256, CONV_SMEM>>>(sAh, sAl, wsh, wsl, pc1_b,
                                             nullptr, sBh, sBl, 1);
    conv3x3_sp<<<convGrid, 256, CONV_SMEM>>>(sBh, sBl, wsh + WSPL, wsl + WSPL, pc2_b,
                                             t2, nullptr, nullptr, 0);
    heads_p_flat<<<headGrid, 256>>>(t2, pl_w, pl_b, pd_w, pd_b, out, cell);
    topk_flat<<<dim3(4, NB), 256>>>(cell, t2, cand_hid, cand_sc);
    topk_global_kernel<<<NB, 1>>>(cand_sc, keep);
    pproj_kernel<<<dim3(KTOP, NB), 256>>>(cand_hid, keep, rn1_w, rn1_b, pproj);

    // ---- object branch ----
    conv3x3_sp<<<convGrid, 256, CONV_SMEM>>>(sAh, sAl, wsh + 2 * WSPL, wsl + 2 * WSPL, oc1_b,
                                             nullptr, sBh, sBl, 1);
    conv3x3_sp<<<convGrid, 256, CONV_SMEM>>>(sBh, sBl, wsh + 3 * WSPL, wsl + 3 * WSPL, oc2_b,
                                             t2, nullptr, nullptr, 0);
    heads_od_flat<<<headGrid, 256>>>(t2, od_w, od_b, out);
    gemm_oproj_flat<<<gemmGrid, 256>>>(t2, rn1_w, o1);
    hsum8<<<dim3(SUMHW / 8, NB), 256>>>(o1, pproj, o2);
    gemm_rn2_flat<<<gemmGrid, 256>>>(o2, rn2_w, rn2_b, o1);
    ol_flat<<<dim3((SUMHW + 7) / 8, NB), 256>>>(o1, ol_w, ol_b, out);

    (void)in_sizes; (void)n_in; (void)out_size;
}

// round 8
// speedup vs baseline: 5.5306x; 1.0105x over previous
#include <cuda_runtime.h>
#include <cuda_bf16.h>
#include <math_constants.h>
#include <stdint.h>

// Problem constants
#define NB   2
#define C    256
#define A    3
#define KTOP 20
#define D    256
#define BOXC 12
#define SUMHW 13600   // 10240 + 2560 + 640 + 160
#define WSPL 294912   // per-layer conv split-weight u32 count
#define WDNS 32768    // dense 256x256 split-weight u32 count
#define STILE 54      // ceil(SUMHW/256)

// ---------------- scratch (device globals) ----------------------------------
__device__ float g_t2[NB * C * SUMHW];
__device__ float g_o1[NB * 256 * SUMHW];   // oproj transposed [n][d][s]
__device__ float g_h2[NB * 256 * SUMHW];   // rn2 out [n][e][s]
__device__ float g_cell[NB * SUMHW];
__device__ float g_cand_hid[NB * C * 80];
__device__ float g_cand_sc[NB * 80];
__device__ int   g_keep[NB * KTOP];
__device__ float g_pproj[NB * KTOP * D];
// split activations: [n][pair=128][SUMHW] u32 (even ci low half, odd high)
__device__ uint32_t g_sA_hi[NB * 128 * SUMHW];
__device__ uint32_t g_sA_lo[NB * 128 * SUMHW];
__device__ uint32_t g_sB_hi[NB * 128 * SUMHW];
__device__ uint32_t g_sB_lo[NB * 128 * SUMHW];
__device__ uint32_t g_sC_hi[NB * 128 * SUMHW];
__device__ uint32_t g_sC_lo[NB * 128 * SUMHW];
__device__ uint32_t g_hs_hi[NB * 128 * SUMHW];
__device__ uint32_t g_hs_lo[NB * 128 * SUMHW];
// split weights (fragment order)
__device__ uint32_t g_wsp_hi[4 * WSPL];
__device__ uint32_t g_wsp_lo[4 * WSPL];
__device__ uint32_t g_wd_hi[2 * WDNS];     // 0: Wo, 1: rn2
__device__ uint32_t g_wd_lo[2 * WDNS];

// per-scale constants
__device__ __constant__ int cOFF[4]  = {0, 10240, 12800, 13440};
__device__ __constant__ int cHW[4]   = {10240, 2560, 640, 160};
__device__ __constant__ int cH[4]    = {80, 40, 20, 10};
__device__ __constant__ int cW[4]    = {128, 64, 32, 16};
__device__ __constant__ int cPLOG[4] = {0,      61440,  76800,  80640};
__device__ __constant__ int cPDEL[4] = {81600,  327360, 388800, 404160};
__device__ __constant__ int cOLOG[4] = {408000, 469440, 484800, 488640};
__device__ __constant__ int cODEL[4] = {489600, 735360, 796800, 812160};

__device__ __forceinline__ int scale_of(int p) {
    return (p < 10240) ? 0 : (p < 12800) ? 1 : (p < 13440) ? 2 : 3;
}

// ---------------- bf16 helpers ----------------------------------------------
__device__ __forceinline__ void mma_bf16(float* c, const uint32_t* a, const uint32_t* b) {
    asm volatile(
        "mma.sync.aligned.m16n8k16.row.col.f32.bf16.bf16.f32 "
        "{%0,%1,%2,%3}, {%4,%5,%6,%7}, {%8,%9}, {%0,%1,%2,%3};\n"
        : "+f"(c[0]), "+f"(c[1]), "+f"(c[2]), "+f"(c[3])
        : "r"(a[0]), "r"(a[1]), "r"(a[2]), "r"(a[3]), "r"(b[0]), "r"(b[1]));
}
__device__ __forceinline__ void split_pack(float v0, float v1,
                                           uint32_t& hi_out, uint32_t& lo_out) {
    __nv_bfloat16 h0 = __float2bfloat16(v0);
    __nv_bfloat16 h1 = __float2bfloat16(v1);
    __nv_bfloat16 l0 = __float2bfloat16(v0 - __bfloat162float(h0));
    __nv_bfloat16 l1 = __float2bfloat16(v1 - __bfloat162float(h1));
    hi_out = ((uint32_t)__bfloat16_as_ushort(h1) << 16) | (uint32_t)__bfloat16_as_ushort(h0);
    lo_out = ((uint32_t)__bfloat16_as_ushort(l1) << 16) | (uint32_t)__bfloat16_as_ushort(l0);
}

// ---------------- conv weight pre-split (fragment order) --------------------
// u32 index: ((((q*4+ocg)*9+tap)*4+o4)*32 + slot)*4 + e
// slot = (g>>1)*8 + t*2 + (g&1); e: bit0 -> oc+8, bit1 -> pair t+4
__global__ __launch_bounds__(256)
void split_w_conv(const float* __restrict__ w0, const float* __restrict__ w1,
                  const float* __restrict__ w2, const float* __restrict__ w3,
                  uint32_t* __restrict__ outH, uint32_t* __restrict__ outL)
{
    const int i = blockIdx.x * 256 + threadIdx.x;
    if (i >= WSPL) return;
    const int layer = blockIdx.y;
    const float* w = (layer == 0) ? w0 : (layer == 1) ? w1 : (layer == 2) ? w2 : w3;
    const int e = i & 3;
    int j = i >> 2;
    const int slot = j & 31; j >>= 5;
    const int o4 = j & 3; j >>= 2;
    const int tap = j % 9; j /= 9;
    const int ocg = j & 3;
    const int q = j >> 2;
    const int g = ((slot >> 3) << 1) | (slot & 1);
    const int t = (slot >> 1) & 3;
    const int oc = ocg * 64 + o4 * 16 + g + (e & 1) * 8;
    const int p = t + ((e >> 1) << 2);
    const int ci0 = q * 16 + 2 * p;
    float v0 = w[(size_t)oc * 2304 + ci0 * 9 + tap];
    float v1 = w[(size_t)oc * 2304 + (ci0 + 1) * 9 + tap];
    uint32_t hi, lo;
    split_pack(v0, v1, hi, lo);
    outH[(size_t)layer * WSPL + i] = hi;
    outL[(size_t)layer * WSPL + i] = lo;
}

// ---------------- dense weight pre-split (fragment order) -------------------
// u32 index: (((q*4+mg)*4+o4)*32 + slot)*4 + e ; W[m][k], stride given
__global__ __launch_bounds__(256)
void split_w_dense(const float* __restrict__ wA, const float* __restrict__ wB,
                   int strideA, int strideB,
                   uint32_t* __restrict__ outH, uint32_t* __restrict__ outL)
{
    const int i = blockIdx.x * 256 + threadIdx.x;
    if (i >= WDNS) return;
    const int which = blockIdx.y;
    const float* w = which ? wB : wA;
    const int stride = which ? strideB : strideA;
    const int e = i & 3;
    int j = i >> 2;
    const int slot = j & 31; j >>= 5;
    const int o4 = j & 3; j >>= 2;
    const int mg = j & 3;
    const int q = j >> 2;
    const int g = ((slot >> 3) << 1) | (slot & 1);
    const int t = (slot >> 1) & 3;
    const int m = mg * 64 + o4 * 16 + g + (e & 1) * 8;
    const int p = t + ((e >> 1) << 2);
    const int k0 = q * 16 + 2 * p;
    float v0 = w[(size_t)m * stride + k0];
    float v1 = w[(size_t)m * stride + k0 + 1];
    uint32_t hi, lo;
    split_pack(v0, v1, hi, lo);
    outH[(size_t)which * WDNS + i] = hi;
    outL[(size_t)which * WDNS + i] = lo;
}

// ---------------- feats pre-split -------------------------------------------
__global__ __launch_bounds__(256)
void split_feats_kernel(const float* __restrict__ f0, const float* __restrict__ f1,
                        const float* __restrict__ f2, const float* __restrict__ f3,
                        uint32_t* __restrict__ outH, uint32_t* __restrict__ outL)
{
    const int px = blockIdx.x * 256 + threadIdx.x;
    if (px >= SUMHW) return;
    const int c2 = blockIdx.y;
    const int n  = blockIdx.z;
    const int s = scale_of(px);
    const int ploc = px - cOFF[s];
    const int HW = cHW[s];
    const float* f = (s == 0) ? f0 : (s == 1) ? f1 : (s == 2) ? f2 : f3;
    const float* src = f + ((size_t)n * C + 2 * c2) * HW + ploc;
    uint32_t hi, lo;
    split_pack(src[0], src[HW], hi, lo);
    const size_t o = ((size_t)n * 128 + c2) * SUMHW + px;
    outH[o] = hi;
    outL[o] = lo;
}

// ---------------- conv3x3: 3-term bf16 mma, fragment-order weights ----------
#define IPAD 36
#define U_WH4 0          // uint4 offsets
#define U_WL4 1152
#define U_IH  9216       // u32 offset
#define U_IL  12096
#define CONV_SMEM ((9216 + 5760) * 4)   // 59904 bytes

__global__ __launch_bounds__(256, 2)
void conv3x3_sp(const uint32_t* __restrict__ inH, const uint32_t* __restrict__ inL,
                const uint32_t* __restrict__ wH, const uint32_t* __restrict__ wL,
                const float* __restrict__ bias,
                float* __restrict__ dstF,
                uint32_t* __restrict__ dstH, uint32_t* __restrict__ dstL)
{
    extern __shared__ __align__(16) uint4 smem4[];
    uint4* s_w4H = smem4 + U_WH4;
    uint4* s_w4L = smem4 + U_WL4;
    uint32_t* smu = (uint32_t*)smem4;
    uint32_t* s_iH = smu + U_IH;
    uint32_t* s_iL = smu + U_IL;
    __shared__ float s_bias[64];

    const int bx = blockIdx.x;
    int s, t_;
    if (bx < 40)      { s = 0; t_ = bx; }
    else if (bx < 50) { s = 1; t_ = bx - 40; }
    else if (bx < 53) { s = 2; t_ = bx - 50; }
    else              { s = 3; t_ = bx - 53; }
    const int H = cH[s], W = cW[s];
    const int tilesX = (W >= 32) ? (W / 32) : 1;
    const int ty = t_ / tilesX, tx = t_ % tilesX;
    const int h0 = ty * 8, w0 = tx * 32;
    const int n = blockIdx.z;
    const int ocg = blockIdx.y;
    const int ocBase = ocg * 64;

    const int tid  = threadIdx.x;
    const int warp = tid >> 5;
    const int lane = tid & 31;
    const int g = lane >> 2;
    const int t = lane & 3;
    const int slot = ((g >> 1) << 3) | (t << 1) | (g & 1);

    if (tid < 64) s_bias[tid] = bias[ocBase + tid];

    float acc[4][4][4];
#pragma unroll
    for (int i = 0; i < 4; i++)
#pragma unroll
        for (int j = 0; j < 4; j++)
#pragma unroll
            for (int k = 0; k < 4; k++) acc[i][j][k] = 0.f;

    for (int q = 0; q < 16; q++) {
        __syncthreads();
        // weights: pure uint4 copy (fragment order)
        {
            const uint4* wH4 = (const uint4*)wH + (size_t)(q * 4 + ocg) * 1152;
            const uint4* wL4 = (const uint4*)wL + (size_t)(q * 4 + ocg) * 1152;
            for (int j = tid; j < 1152; j += 256) {
                s_w4H[j] = wH4[j];
                s_w4L[j] = wL4[j];
            }
        }
        // inputs: gather u32 (8 ci-pairs x 10 rows x 34 cols)
        for (int idx = tid; idx < 8 * 10 * 34; idx += 256) {
            int p = idx / 340, rem = idx % 340;
            int r = rem / 34, cc = rem % 34;
            int gh = h0 + r - 1, gw = w0 + cc - 1;
            uint32_t vh = 0, vl = 0;
            if (gh >= 0 && gh < H && gw >= 0 && gw < W) {
                size_t off = ((size_t)n * 128 + q * 8 + p) * SUMHW + cOFF[s] + gh * W + gw;
                vh = inH[off];
                vl = inL[off];
            }
            s_iH[(p * 10 + r) * IPAD + cc] = vh;
            s_iL[(p * 10 + r) * IPAD + cc] = vl;
        }
        __syncthreads();

#pragma unroll
        for (int kh = 0; kh < 3; kh++)
#pragma unroll
        for (int kw = 0; kw < 3; kw++) {
            const int tap = kh * 3 + kw;
            uint32_t bh[4][2], bl[4][2];
            const int ib0 = (t * 10 + warp + kh) * IPAD + kw + g;
            const int ib1 = ((t + 4) * 10 + warp + kh) * IPAD + kw + g;
#pragma unroll
            for (int p4 = 0; p4 < 4; p4++) {
                bh[p4][0] = s_iH[ib0 + p4 * 8];
                bh[p4][1] = s_iH[ib1 + p4 * 8];
                bl[p4][0] = s_iL[ib0 + p4 * 8];
                bl[p4][1] = s_iL[ib1 + p4 * 8];
            }
#pragma unroll
            for (int o4 = 0; o4 < 4; o4++) {
                uint4 a4 = s_w4H[(tap * 4 + o4) * 32 + slot];
                uint4 b4 = s_w4L[(tap * 4 + o4) * 32 + slot];
                uint32_t ah[4] = {a4.x, a4.y, a4.z, a4.w};
                uint32_t al[4] = {b4.x, b4.y, b4.z, b4.w};
#pragma unroll
                for (int p4 = 0; p4 < 4; p4++) {
                    mma_bf16(acc[o4][p4], ah, bh[p4]);
                    mma_bf16(acc[o4][p4], ah, bl[p4]);
                    mma_bf16(acc[o4][p4], al, bh[p4]);
                }
            }
        }
    }

    // epilogue (validated mapping): c0=(oc,col) c1=(oc,col+1) c2=(oc+8,col) c3=(oc+8,col+1)
    const int ghout = h0 + warp;
    if (dstF && ghout < H) {
        float* dbase = dstF + (size_t)n * C * SUMHW + cOFF[s] + (size_t)ghout * W + w0;
#pragma unroll
        for (int o4 = 0; o4 < 4; o4++) {
            int ocl = o4 * 16 + g;
            float b0v = s_bias[ocl];
            float b1v = s_bias[ocl + 8];
#pragma unroll
            for (int p4 = 0; p4 < 4; p4++) {
                int col = p4 * 8 + 2 * t;
                if (w0 + col < W) {
                    float2 v0 = make_float2(fmaxf(acc[o4][p4][0] + b0v, 0.f),
                                            fmaxf(acc[o4][p4][1] + b0v, 0.f));
                    float2 v1 = make_float2(fmaxf(acc[o4][p4][2] + b1v, 0.f),
                                            fmaxf(acc[o4][p4][3] + b1v, 0.f));
                    *(float2*)(dbase + (size_t)(ocBase + ocl) * SUMHW + col) = v0;
                    *(float2*)(dbase + (size_t)(ocBase + ocl + 8) * SUMHW + col) = v1;
                }
            }
        }
    }
    if (dstH) {
        const size_t base = ((size_t)n * 128) * SUMHW + cOFF[s] + (size_t)ghout * W + w0;
#pragma unroll
        for (int o4 = 0; o4 < 4; o4++) {
            int ocl = o4 * 16 + g;
            float b0v = s_bias[ocl];
            float b1v = s_bias[ocl + 8];
            const size_t w2a = (size_t)((ocBase + ocl) >> 1) * SUMHW;
            const size_t w2b = (size_t)(((ocBase + ocl) >> 1) + 4) * SUMHW;
#pragma unroll
            for (int p4 = 0; p4 < 4; p4++) {
                int col = p4 * 8 + 2 * t;
                float v0 = fmaxf(acc[o4][p4][0] + b0v, 0.f);
                float v1 = fmaxf(acc[o4][p4][1] + b0v, 0.f);
                float v2 = fmaxf(acc[o4][p4][2] + b1v, 0.f);
                float v3 = fmaxf(acc[o4][p4][3] + b1v, 0.f);
                float p0 = __shfl_xor_sync(0xFFFFFFFFu, v0, 4);
                float p1 = __shfl_xor_sync(0xFFFFFFFFu, v1, 4);
                float p2 = __shfl_xor_sync(0xFFFFFFFFu, v2, 4);
                float p3 = __shfl_xor_sync(0xFFFFFFFFu, v3, 4);
                if (((g & 1) == 0) && ghout < H && (w0 + col) < W) {
                    uint32_t hw, lw;
                    split_pack(v0, p0, hw, lw);
                    dstH[base + w2a + col] = hw;  dstL[base + w2a + col] = lw;
                    split_pack(v1, p1, hw, lw);
                    dstH[base + w2a + col + 1] = hw;  dstL[base + w2a + col + 1] = lw;
                    split_pack(v2, p2, hw, lw);
                    dstH[base + w2b + col] = hw;  dstL[base + w2b + col] = lw;
                    split_pack(v3, p3, hw, lw);
                    dstH[base + w2b + col + 1] = hw;  dstL[base + w2b + col + 1] = lw;
                }
            }
        }
    }
}

// ---------------- dense GEMM via 3-term bf16 mma ----------------------------
// out[n][m][s] (+bias, relu opt), M=256 (mg 0..3 of 64), K=256, N-tile 256 px.
#define GIPAD 264
__global__ __launch_bounds__(256, 2)
void gemm_mma(const uint32_t* __restrict__ wH, const uint32_t* __restrict__ wL,
              const uint32_t* __restrict__ bHg, const uint32_t* __restrict__ bLg,
              const float* __restrict__ bias, float* __restrict__ outp,
              int relu_flag)
{
    __shared__ uint4 s_aH4[128];
    __shared__ uint4 s_aL4[128];
    __shared__ uint32_t s_iH[8 * GIPAD];
    __shared__ uint32_t s_iL[8 * GIPAD];

    const int s0 = blockIdx.x * 256;
    const int mg = blockIdx.y;
    const int n  = blockIdx.z;
    const int tid = threadIdx.x;
    const int warp = tid >> 5;
    const int lane = tid & 31;
    const int g = lane >> 2;
    const int t = lane & 3;
    const int slot = ((g >> 1) << 3) | (t << 1) | (g & 1);
    const bool sok = (s0 + tid) < SUMHW;

    float acc[4][4][4];
#pragma unroll
    for (int i = 0; i < 4; i++)
#pragma unroll
        for (int j = 0; j < 4; j++)
#pragma unroll
            for (int k = 0; k < 4; k++) acc[i][j][k] = 0.f;

    for (int q = 0; q < 16; q++) {
        __syncthreads();
        if (tid < 128) {
            s_aH4[tid] = ((const uint4*)wH)[(size_t)(q * 4 + mg) * 128 + tid];
        } else {
            s_aL4[tid - 128] = ((const uint4*)wL)[(size_t)(q * 4 + mg) * 128 + tid - 128];
        }
#pragma unroll
        for (int p = 0; p < 8; p++) {
            size_t off = ((size_t)n * 128 + q * 8 + p) * SUMHW + s0 + tid;
            s_iH[p * GIPAD + tid] = sok ? bHg[off] : 0u;
            s_iL[p * GIPAD + tid] = sok ? bLg[off] : 0u;
        }
        __syncthreads();

        uint32_t bh[4][2], bl[4][2];
        const int ib0 = t * GIPAD + warp * 32 + g;
        const int ib1 = (t + 4) * GIPAD + warp * 32 + g;
#pragma unroll
        for (int p4 = 0; p4 < 4; p4++) {
            bh[p4][0] = s_iH[ib0 + p4 * 8];
            bh[p4][1] = s_iH[ib1 + p4 * 8];
            bl[p4][0] = s_iL[ib0 + p4 * 8];
            bl[p4][1] = s_iL[ib1 + p4 * 8];
        }
#pragma unroll
        for (int o4 = 0; o4 < 4; o4++) {
            uint4 a4 = s_aH4[o4 * 32 + slot];
            uint4 b4 = s_aL4[o4 * 32 + slot];
            uint32_t ah[4] = {a4.x, a4.y, a4.z, a4.w};
            uint32_t al[4] = {b4.x, b4.y, b4.z, b4.w};
#pragma unroll
            for (int p4 = 0; p4 < 4; p4++) {
                mma_bf16(acc[o4][p4], ah, bh[p4]);
                mma_bf16(acc[o4][p4], ah, bl[p4]);
                mma_bf16(acc[o4][p4], al, bh[p4]);
            }
        }
    }

    // epilogue: m = mg*64 + o4*16 + g (+8); s = s0 + warp*32 + p4*8 + 2t (+1)
#pragma unroll
    for (int o4 = 0; o4 < 4; o4++) {
        int m0 = mg * 64 + o4 * 16 + g;
        float b0v = bias ? bias[m0] : 0.f;
        float b1v = bias ? bias[m0 + 8] : 0.f;
#pragma unroll
        for (int p4 = 0; p4 < 4; p4++) {
            int sx = s0 + warp * 32 + p4 * 8 + 2 * t;
            if (sx < SUMHW) {
                float v0 = acc[o4][p4][0] + b0v;
                float v1 = acc[o4][p4][1] + b0v;
                float v2 = acc[o4][p4][2] + b1v;
                float v3 = acc[o4][p4][3] + b1v;
                if (relu_flag) {
                    v0 = fmaxf(v0, 0.f); v1 = fmaxf(v1, 0.f);
                    v2 = fmaxf(v2, 0.f); v3 = fmaxf(v3, 0.f);
                }
                *(float2*)(outp + ((size_t)n * 256 + m0) * SUMHW + sx) = make_float2(v0, v1);
                *(float2*)(outp + ((size_t)n * 256 + m0 + 8) * SUMHW + sx) = make_float2(v2, v3);
            }
        }
    }
}

// ---------------- person heads flat -----------------------------------------
__global__ __launch_bounds__(256)
void heads_p_flat(const float* __restrict__ hid,
                  const float* __restrict__ pl_w, const float* __restrict__ pl_b,
                  const float* __restrict__ pd_w, const float* __restrict__ pd_b,
                  float* __restrict__ out, float* __restrict__ cell)
{
    __shared__ float swl[A * C];
    __shared__ float swd[BOXC * C];
    const int tid = threadIdx.x;
    for (int i = tid; i < A * C; i += 256) swl[i] = pl_w[i];
    for (int i = tid; i < BOXC * C; i += 256) swd[i] = pd_w[i];
    __syncthreads();

    const int p = blockIdx.x * 256 + tid;
    const int n = blockIdx.y;
    if (p >= SUMHW) return;
    const int s = scale_of(p);
    const int ploc = p - cOFF[s];
    const int HW = cHW[s];
    const float* h = hid + (size_t)n * C * SUMHW + p;

    float accl[A], accd[BOXC];
#pragma unroll
    for (int a = 0; a < A; a++) accl[a] = pl_b[a];
#pragma unroll
    for (int j = 0; j < BOXC; j++) accd[j] = pd_b[j];

    for (int c = 0; c < C; c++) {
        float v = h[(size_t)c * SUMHW];
#pragma unroll
        for (int a = 0; a < A; a++) accl[a] += swl[a * C + c] * v;
#pragma unroll
        for (int j = 0; j < BOXC; j++) accd[j] += swd[j * C + c] * v;
    }
    float m = accl[0];
#pragma unroll
    for (int a = 0; a < A; a++) {
        out[cPLOG[s] + ((size_t)n * A + a) * HW + ploc] = accl[a];
        m = fmaxf(m, accl[a]);
    }
#pragma unroll
    for (int j = 0; j < BOXC; j++)
        out[cPDEL[s] + ((size_t)n * BOXC + j) * HW + ploc] = accd[j];
    cell[(size_t)n * SUMHW + p] = m;
}

// ---------------- object delta head flat ------------------------------------
__global__ __launch_bounds__(256)
void heads_od_flat(const float* __restrict__ hid,
                   const float* __restrict__ od_w, const float* __restrict__ od_b,
                   float* __restrict__ out)
{
    __shared__ float sw[BOXC * C];
    const int tid = threadIdx.x;
    for (int i = tid; i < BOXC * C; i += 256) sw[i] = od_w[i];
    __syncthreads();

    const int p = blockIdx.x * 256 + tid;
    const int n = blockIdx.y;
    if (p >= SUMHW) return;
    const int s = scale_of(p);
    const int ploc = p - cOFF[s];
    const int HW = cHW[s];
    const float* h = hid + (size_t)n * C * SUMHW + p;

    float acc[BOXC];
#pragma unroll
    for (int j = 0; j < BOXC; j++) acc[j] = od_b[j];
    for (int c = 0; c < C; c++) {
        float v = h[(size_t)c * SUMHW];
#pragma unroll
        for (int j = 0; j < BOXC; j++) acc[j] += sw[j * C + c] * v;
    }
#pragma unroll
    for (int j = 0; j < BOXC; j++)
        out[cODEL[s] + ((size_t)n * BOXC + j) * HW + ploc] = acc[j];
}

// ---------------- per-scale top-K (smem-cached) -----------------------------
__global__ __launch_bounds__(256)
void topk_flat(const float* __restrict__ cell, const float* __restrict__ hid,
               float* __restrict__ cand_hid, float* __restrict__ cand_sc)
{
    const int s = blockIdx.x;
    const int n = blockIdx.y;
    const int HW = cHW[s], off = cOFF[s];
    __shared__ float sc[10240];
    __shared__ float s_val[256];
    __shared__ int   s_idx[256];
    __shared__ int   sel[KTOP];
    const int tid = threadIdx.x;

    for (int i = tid; i < HW; i += 256)
        sc[i] = cell[(size_t)n * SUMHW + off + i];
    __syncthreads();

    for (int k = 0; k < KTOP; k++) {
        float best = -CUDART_INF_F;
        int bi = HW;
        for (int i = tid; i < HW; i += 256) {
            float v = sc[i];
            if (v > best) { best = v; bi = i; }
        }
        s_val[tid] = best; s_idx[tid] = bi;
        __syncthreads();
        for (int offr = 128; offr > 0; offr >>= 1) {
            if (tid < offr) {
                float v2 = s_val[tid + offr]; int i2 = s_idx[tid + offr];
                if (v2 > s_val[tid] || (v2 == s_val[tid] && i2 < s_idx[tid])) {
                    s_val[tid] = v2; s_idx[tid] = i2;
                }
            }
            __syncthreads();
        }
        if (tid == 0) {
            sel[k] = s_idx[0];
            cand_sc[(size_t)n * 80 + s * KTOP + k] = s_val[0];
            sc[s_idx[0]] = -CUDART_INF_F;
        }
        __syncthreads();
    }
    for (int idx = tid; idx < C * KTOP; idx += 256) {
        int c = idx / KTOP, k = idx % KTOP;
        cand_hid[((size_t)n * C + c) * 80 + s * KTOP + k] =
            hid[((size_t)n * C + c) * SUMHW + off + sel[k]];
    }
}

// ---------------- global top-K over 80 --------------------------------------
__global__ void topk_global_kernel(const float* __restrict__ sc, int* __restrict__ keep)
{
    const int n = blockIdx.x;
    bool used[80];
    for (int i = 0; i < 80; i++) used[i] = false;
    const float* s = sc + (size_t)n * 80;
    for (int k = 0; k < KTOP; k++) {
        float best = -CUDART_INF_F; int bi = 0;
        for (int i = 0; i < 80; i++)
            if (!used[i] && s[i] > best) { best = s[i]; bi = i; }
        used[bi] = true;
        keep[n * KTOP + k] = bi;
    }
}

// ---------------- p_proj ----------------------------------------------------
__global__ __launch_bounds__(256)
void pproj_kernel(const float* __restrict__ cand_hid, const int* __restrict__ keep,
                  const float* __restrict__ rn1_w, const float* __restrict__ rn1_b,
                  float* __restrict__ pproj)
{
    const int k = blockIdx.x, n = blockIdx.y, d = threadIdx.x;
    __shared__ float sh[C];
    const int col = keep[n * KTOP + k];
    sh[d] = cand_hid[((size_t)n * C + d) * 80 + col];
    __syncthreads();
    float acc = rn1_b[d];
    const float* wrow = rn1_w + (size_t)d * (2 * C) + C;   // Wp
    for (int c = 0; c < C; c++) acc += sh[c] * wrow[c];
    pproj[((size_t)n * KTOP + k) * D + d] = acc;
}

// ---------------- hsum (transposed): reads o1 [n][d][s] ---------------------
__global__ __launch_bounds__(256)
void hsum_t(const float* __restrict__ oproj, const float* __restrict__ pproj,
            uint32_t* __restrict__ hsH, uint32_t* __restrict__ hsL)
{
    __shared__ float spp[KTOP * 256];
    const int n = blockIdx.y;
    const int tid = threadIdx.x;
    for (int i = tid; i < KTOP * 256; i += 256) {
        int k = i >> 8, d = i & 255;
        spp[i] = pproj[((size_t)n * KTOP + k) * D + d];
    }
    __syncthreads();
    const int s = blockIdx.x * 256 + tid;
    if (s >= SUMHW) return;
    for (int dp = 0; dp < 128; dp++) {
        float o0 = oproj[((size_t)n * 256 + 2 * dp) * SUMHW + s];
        float o1v = oproj[((size_t)n * 256 + 2 * dp + 1) * SUMHW + s];
        float a0 = 0.f, a1 = 0.f;
#pragma unroll 4
        for (int k = 0; k < KTOP; k++) {
            a0 += fmaxf(o0 + spp[k * 256 + 2 * dp], 0.f);
            a1 += fmaxf(o1v + spp[k * 256 + 2 * dp + 1], 0.f);
        }
        uint32_t hi, lo;
        split_pack(a0, a1, hi, lo);
        hsH[((size_t)n * 128 + dp) * SUMHW + s] = hi;
        hsL[((size_t)n * 128 + dp) * SUMHW + s] = lo;
    }
}

// ---------------- ol head (transposed h2 [n][e][s]) -------------------------
__global__ __launch_bounds__(256)
void ol_t(const float* __restrict__ h2, const float* __restrict__ ol_w,
          const float* __restrict__ ol_b, float* __restrict__ out)
{
    __shared__ float sw[A * 256];
    const int n = blockIdx.y;
    const int tid = threadIdx.x;
    for (int i = tid; i < A * 256; i += 256) sw[i] = ol_w[i];
    __syncthreads();
    const int s = blockIdx.x * 256 + tid;
    if (s >= SUMHW) return;
    float a0 = 0.f, a1 = 0.f, a2 = 0.f;
    for (int e = 0; e < 256; e++) {
        float v = h2[((size_t)n * 256 + e) * SUMHW + s];
        a0 += v * sw[e];
        a1 += v * sw[256 + e];
        a2 += v * sw[512 + e];
    }
    const int sc = scale_of(s);
    const int ploc = s - cOFF[sc];
    const int HW = cHW[sc];
    out[cOLOG[sc] + ((size_t)n * A + 0) * HW + ploc] = a0 + ol_b[0];
    out[cOLOG[sc] + ((size_t)n * A + 1) * HW + ploc] = a1 + ol_b[1];
    out[cOLOG[sc] + ((size_t)n * A + 2) * HW + ploc] = a2 + ol_b[2];
}

// ---------------------------- host orchestration ----------------------------
extern "C" void kernel_launch(void* const* d_in, const int* in_sizes, int n_in,
                              void* d_out, int out_size)
{
    const float* f0 = (const float*)d_in[0];
    const float* f1 = (const float*)d_in[1];
    const float* f2 = (const float*)d_in[2];
    const float* f3 = (const float*)d_in[3];
    const float* pc1_w = (const float*)d_in[4];
    const float* pc1_b = (const float*)d_in[5];
    const float* pc2_w = (const float*)d_in[6];
    const float* pc2_b = (const float*)d_in[7];
    const float* oc1_w = (const float*)d_in[8];
    const float* oc1_b = (const float*)d_in[9];
    const float* oc2_w = (const float*)d_in[10];
    const float* oc2_b = (const float*)d_in[11];
    const float* rn1_w = (const float*)d_in[12];
    const float* rn1_b = (const float*)d_in[13];
    const float* rn2_w = (const float*)d_in[14];
    const float* rn2_b = (const float*)d_in[15];
    const float* pl_w  = (const float*)d_in[16];
    const float* pl_b  = (const float*)d_in[17];
    const float* pd_w  = (const float*)d_in[18];
    const float* pd_b  = (const float*)d_in[19];
    const float* ol_w  = (const float*)d_in[20];
    const float* ol_b  = (const float*)d_in[21];
    const float* od_w  = (const float*)d_in[22];
    const float* od_b  = (const float*)d_in[23];
    float* out = (float*)d_out;

    float *t2, *o1, *h2, *cell, *cand_hid, *cand_sc, *pproj;
    int* keep;
    uint32_t *sAh, *sAl, *sBh, *sBl, *sCh, *sCl, *hsh, *hsl, *wsh, *wsl, *wdh, *wdl;
    cudaGetSymbolAddress((void**)&t2, g_t2);
    cudaGetSymbolAddress((void**)&o1, g_o1);
    cudaGetSymbolAddress((void**)&h2, g_h2);
    cudaGetSymbolAddress((void**)&cell, g_cell);
    cudaGetSymbolAddress((void**)&cand_hid, g_cand_hid);
    cudaGetSymbolAddress((void**)&cand_sc, g_cand_sc);
    cudaGetSymbolAddress((void**)&keep, g_keep);
    cudaGetSymbolAddress((void**)&pproj, g_pproj);
    cudaGetSymbolAddress((void**)&sAh, g_sA_hi);
    cudaGetSymbolAddress((void**)&sAl, g_sA_lo);
    cudaGetSymbolAddress((void**)&sBh, g_sB_hi);
    cudaGetSymbolAddress((void**)&sBl, g_sB_lo);
    cudaGetSymbolAddress((void**)&sCh, g_sC_hi);
    cudaGetSymbolAddress((void**)&sCl, g_sC_lo);
    cudaGetSymbolAddress((void**)&hsh, g_hs_hi);
    cudaGetSymbolAddress((void**)&hsl, g_hs_lo);
    cudaGetSymbolAddress((void**)&wsh, g_wsp_hi);
    cudaGetSymbolAddress((void**)&wsl, g_wsp_lo);
    cudaGetSymbolAddress((void**)&wdh, g_wd_hi);
    cudaGetSymbolAddress((void**)&wdl, g_wd_lo);

    cudaFuncSetAttribute(conv3x3_sp,
                         cudaFuncAttributeMaxDynamicSharedMemorySize, CONV_SMEM);

    const dim3 convGrid(55, 4, NB);
    const dim3 headGrid((SUMHW + 255) / 256, NB);
    const dim3 gemmGrid(STILE, 4, NB);

    // ---- prep: split weights + feats ----
    split_w_conv<<<dim3((WSPL + 255) / 256, 4), 256>>>(pc1_w, pc2_w, oc1_w, oc2_w, wsh, wsl);
    split_w_dense<<<dim3((WDNS + 255) / 256, 2), 256>>>(rn1_w, rn2_w, 2 * C, D, wdh, wdl);
    split_feats_kernel<<<dim3((SUMHW + 255) / 256, 128, NB), 256>>>(f0, f1, f2, f3, sAh, sAl);

    // ---- person branch ----
    conv3x3_sp<<<convGrid, 256, CONV_SMEM>>>(sAh, sAl, wsh, wsl, pc1_b,
                                             nullptr, sBh, sBl);
    conv3x3_sp<<<convGrid, 256, CONV_SMEM>>>(sBh, sBl, wsh + WSPL, wsl + WSPL, pc2_b,
                                             t2, nullptr, nullptr);
    heads_p_flat<<<headGrid, 256>>>(t2, pl_w, pl_b, pd_w, pd_b, out, cell);
    topk_flat<<<dim3(4, NB), 256>>>(cell, t2, cand_hid, cand_sc);
    topk_global_kernel<<<NB, 1>>>(cand_sc, keep);
    pproj_kernel<<<dim3(KTOP, NB), 256>>>(cand_hid, keep, rn1_w, rn1_b, pproj);

    // ---- object branch ----
    conv3x3_sp<<<convGrid, 256, CONV_SMEM>>>(sAh, sAl, wsh + 2 * WSPL, wsl + 2 * WSPL, oc1_b,
                                             nullptr, sBh, sBl);
    conv3x3_sp<<<convGrid, 256, CONV_SMEM>>>(sBh, sBl, wsh + 3 * WSPL, wsl + 3 * WSPL, oc2_b,
                                             t2, sCh, sCl);
    heads_od_flat<<<headGrid, 256>>>(t2, od_w, od_b, out);
    // o_proj: A = Wo frags, B = sC -> o1 [n][d][s]
    gemm_mma<<<gemmGrid, 256>>>(wdh, wdl, sCh, sCl, nullptr, o1, 0);
    hsum_t<<<dim3(STILE, NB), 256>>>(o1, pproj, hsh, hsl);
    // rn2: A = rn2 frags, B = hs -> h2 [n][e][s], +bias +relu
    gemm_mma<<<gemmGrid, 256>>>(wdh + WDNS, wdl + WDNS, hsh, hsl, rn2_b, h2, 1);
    ol_t<<<dim3(STILE, NB), 256>>>(h2, ol_w, ol_b, out);

    (void)in_sizes; (void)n_in; (void)out_size;
}

// round 9
// speedup vs baseline: 6.5038x; 1.1760x over previous
#include <cuda_runtime.h>
#include <cuda_bf16.h>
#include <math_constants.h>
#include <stdint.h>

// Problem constants
#define NB   2
#define C    256
#define A    3
#define KTOP 20
#define D    256
#define BOXC 12
#define SUMHW 13600   // 10240 + 2560 + 640 + 160
#define WSPL 294912   // per-layer conv split-weight u32 count
#define WDNS 32768    // dense 256x256 split-weight u32 count
#define STILE 54      // ceil(SUMHW/256)

// ---------------- scratch (device globals) ----------------------------------
__device__ float g_t2[NB * C * SUMHW];
__device__ float g_o1[NB * 256 * SUMHW];   // oproj transposed [n][d][s]
__device__ float g_h2[NB * 256 * SUMHW];   // rn2 out [n][e][s]
__device__ float g_cell[NB * SUMHW];
__device__ float g_cand_hid[NB * C * 80];
__device__ float g_cand_sc[NB * 80];
__device__ int   g_keep[NB * KTOP];
__device__ float g_pproj[NB * KTOP * D];
// split activations: [n][pair=128][SUMHW] u32 (even ci low half, odd high)
__device__ uint32_t g_sA_hi[NB * 128 * SUMHW];
__device__ uint32_t g_sA_lo[NB * 128 * SUMHW];
__device__ uint32_t g_sB_hi[NB * 128 * SUMHW];
__device__ uint32_t g_sB_lo[NB * 128 * SUMHW];
__device__ uint32_t g_sC_hi[NB * 128 * SUMHW];
__device__ uint32_t g_sC_lo[NB * 128 * SUMHW];
__device__ uint32_t g_hs_hi[NB * 128 * SUMHW];
__device__ uint32_t g_hs_lo[NB * 128 * SUMHW];
// split weights (fragment order)
__device__ uint32_t g_wsp_hi[4 * WSPL];
__device__ uint32_t g_wsp_lo[4 * WSPL];
__device__ uint32_t g_wd_hi[2 * WDNS];     // 0: Wo, 1: rn2
__device__ uint32_t g_wd_lo[2 * WDNS];

// per-scale constants
__device__ __constant__ int cOFF[4]  = {0, 10240, 12800, 13440};
__device__ __constant__ int cHW[4]   = {10240, 2560, 640, 160};
__device__ __constant__ int cH[4]    = {80, 40, 20, 10};
__device__ __constant__ int cW[4]    = {128, 64, 32, 16};
__device__ __constant__ int cPLOG[4] = {0,      61440,  76800,  80640};
__device__ __constant__ int cPDEL[4] = {81600,  327360, 388800, 404160};
__device__ __constant__ int cOLOG[4] = {408000, 469440, 484800, 488640};
__device__ __constant__ int cODEL[4] = {489600, 735360, 796800, 812160};

__device__ __forceinline__ int scale_of(int p) {
    return (p < 10240) ? 0 : (p < 12800) ? 1 : (p < 13440) ? 2 : 3;
}

// ---------------- bf16 / async helpers --------------------------------------
__device__ __forceinline__ void mma_bf16(float* c, const uint32_t* a, const uint32_t* b) {
    asm volatile(
        "mma.sync.aligned.m16n8k16.row.col.f32.bf16.bf16.f32 "
        "{%0,%1,%2,%3}, {%4,%5,%6,%7}, {%8,%9}, {%0,%1,%2,%3};\n"
        : "+f"(c[0]), "+f"(c[1]), "+f"(c[2]), "+f"(c[3])
        : "r"(a[0]), "r"(a[1]), "r"(a[2]), "r"(a[3]), "r"(b[0]), "r"(b[1]));
}
__device__ __forceinline__ void split_pack(float v0, float v1,
                                           uint32_t& hi_out, uint32_t& lo_out) {
    __nv_bfloat16 h0 = __float2bfloat16(v0);
    __nv_bfloat16 h1 = __float2bfloat16(v1);
    __nv_bfloat16 l0 = __float2bfloat16(v0 - __bfloat162float(h0));
    __nv_bfloat16 l1 = __float2bfloat16(v1 - __bfloat162float(h1));
    hi_out = ((uint32_t)__bfloat16_as_ushort(h1) << 16) | (uint32_t)__bfloat16_as_ushort(h0);
    lo_out = ((uint32_t)__bfloat16_as_ushort(l1) << 16) | (uint32_t)__bfloat16_as_ushort(l0);
}
__device__ __forceinline__ uint32_t smem_addr_of(const void* p) {
    return (uint32_t)__cvta_generic_to_shared(p);
}
__device__ __forceinline__ void cp16(uint32_t dst, const void* src, bool pred) {
    asm volatile("cp.async.cg.shared.global [%0], [%1], 16, %2;"
                 :: "r"(dst), "l"(src), "r"(pred ? 16 : 0));
}
__device__ __forceinline__ void cp4(uint32_t dst, const void* src, bool pred) {
    asm volatile("cp.async.ca.shared.global [%0], [%1], 4, %2;"
                 :: "r"(dst), "l"(src), "r"(pred ? 4 : 0));
}
#define CP_COMMIT() asm volatile("cp.async.commit_group;" ::: "memory")
#define CP_WAIT(n)  asm volatile("cp.async.wait_group %0;" :: "n"(n) : "memory")

// ---------------- conv weight pre-split (fragment order) --------------------
__global__ __launch_bounds__(256)
void split_w_conv(const float* __restrict__ w0, const float* __restrict__ w1,
                  const float* __restrict__ w2, const float* __restrict__ w3,
                  uint32_t* __restrict__ outH, uint32_t* __restrict__ outL)
{
    const int i = blockIdx.x * 256 + threadIdx.x;
    if (i >= WSPL) return;
    const int layer = blockIdx.y;
    const float* w = (layer == 0) ? w0 : (layer == 1) ? w1 : (layer == 2) ? w2 : w3;
    const int e = i & 3;
    int j = i >> 2;
    const int slot = j & 31; j >>= 5;
    const int o4 = j & 3; j >>= 2;
    const int tap = j % 9; j /= 9;
    const int ocg = j & 3;
    const int q = j >> 2;
    const int g = ((slot >> 3) << 1) | (slot & 1);
    const int t = (slot >> 1) & 3;
    const int oc = ocg * 64 + o4 * 16 + g + (e & 1) * 8;
    const int p = t + ((e >> 1) << 2);
    const int ci0 = q * 16 + 2 * p;
    float v0 = w[(size_t)oc * 2304 + ci0 * 9 + tap];
    float v1 = w[(size_t)oc * 2304 + (ci0 + 1) * 9 + tap];
    uint32_t hi, lo;
    split_pack(v0, v1, hi, lo);
    outH[(size_t)layer * WSPL + i] = hi;
    outL[(size_t)layer * WSPL + i] = lo;
}

// ---------------- dense weight pre-split (fragment order) -------------------
__global__ __launch_bounds__(256)
void split_w_dense(const float* __restrict__ wA, const float* __restrict__ wB,
                   int strideA, int strideB,
                   uint32_t* __restrict__ outH, uint32_t* __restrict__ outL)
{
    const int i = blockIdx.x * 256 + threadIdx.x;
    if (i >= WDNS) return;
    const int which = blockIdx.y;
    const float* w = which ? wB : wA;
    const int stride = which ? strideB : strideA;
    const int e = i & 3;
    int j = i >> 2;
    const int slot = j & 31; j >>= 5;
    const int o4 = j & 3; j >>= 2;
    const int mg = j & 3;
    const int q = j >> 2;
    const int g = ((slot >> 3) << 1) | (slot & 1);
    const int t = (slot >> 1) & 3;
    const int m = mg * 64 + o4 * 16 + g + (e & 1) * 8;
    const int p = t + ((e >> 1) << 2);
    const int k0 = q * 16 + 2 * p;
    float v0 = w[(size_t)m * stride + k0];
    float v1 = w[(size_t)m * stride + k0 + 1];
    uint32_t hi, lo;
    split_pack(v0, v1, hi, lo);
    outH[(size_t)which * WDNS + i] = hi;
    outL[(size_t)which * WDNS + i] = lo;
}

// ---------------- feats pre-split -------------------------------------------
__global__ __launch_bounds__(256)
void split_feats_kernel(const float* __restrict__ f0, const float* __restrict__ f1,
                        const float* __restrict__ f2, const float* __restrict__ f3,
                        uint32_t* __restrict__ outH, uint32_t* __restrict__ outL)
{
    const int px = blockIdx.x * 256 + threadIdx.x;
    if (px >= SUMHW) return;
    const int c2 = blockIdx.y;
    const int n  = blockIdx.z;
    const int s = scale_of(px);
    const int ploc = px - cOFF[s];
    const int HW = cHW[s];
    const float* f = (s == 0) ? f0 : (s == 1) ? f1 : (s == 2) ? f2 : f3;
    const float* src = f + ((size_t)n * C + 2 * c2) * HW + ploc;
    uint32_t hi, lo;
    split_pack(src[0], src[HW], hi, lo);
    const size_t o = ((size_t)n * 128 + c2) * SUMHW + px;
    outH[o] = hi;
    outL[o] = lo;
}

// ---------------- conv3x3: pipelined 3-term bf16 mma ------------------------
// Stage layout (u32): WH4 uint4[1152] @0 | WL4 uint4[1152] @4608 | IH[3520] @9216 | IL[3520] @12736
// IPAD = 44 (10*44 % 32 == 24 -> conflict-free fragment loads; cols 16B-aligned)
#define IPAD 44
#define ST_IH 9216
#define ST_IL 12736
#define STG_U32 16256
#define CONV_SMEM (2 * STG_U32 * 4)   // 130048 B

__global__ __launch_bounds__(256, 2)
void conv3x3_sp(const uint32_t* __restrict__ inH, const uint32_t* __restrict__ inL,
                const uint32_t* __restrict__ wH, const uint32_t* __restrict__ wL,
                const float* __restrict__ bias,
                float* __restrict__ dstF,
                uint32_t* __restrict__ dstH, uint32_t* __restrict__ dstL)
{
    extern __shared__ __align__(16) uint32_t smu[];
    __shared__ float s_bias[64];

    const int bx = blockIdx.x;
    int s, t_;
    if (bx < 40)      { s = 0; t_ = bx; }
    else if (bx < 50) { s = 1; t_ = bx - 40; }
    else if (bx < 53) { s = 2; t_ = bx - 50; }
    else              { s = 3; t_ = bx - 53; }
    const int H = cH[s], W = cW[s];
    const int tilesX = (W >= 32) ? (W / 32) : 1;
    const int ty = t_ / tilesX, tx = t_ % tilesX;
    const int h0 = ty * 8, w0 = tx * 32;
    const int n = blockIdx.z;
    const int ocg = blockIdx.y;
    const int ocBase = ocg * 64;

    const int tid  = threadIdx.x;
    const int warp = tid >> 5;
    const int lane = tid & 31;
    const int g = lane >> 2;
    const int t = lane & 3;
    const int slot = ((g >> 1) << 3) | (t << 1) | (g & 1);

    if (tid < 64) s_bias[tid] = bias[ocBase + tid];

    float acc[4][4][4];
#pragma unroll
    for (int i = 0; i < 4; i++)
#pragma unroll
        for (int j = 0; j < 4; j++)
#pragma unroll
            for (int k = 0; k < 4; k++) acc[i][j][k] = 0.f;

    const uint32_t smbase = smem_addr_of(smu);

    // fill one chunk's stage with cp.async
    auto fill = [&](int q, int st) {
        const uint32_t sb = smbase + (uint32_t)st * STG_U32 * 4;
        // weights: 2304 uint4 pure copy
        const uint4* wH4 = (const uint4*)wH + (size_t)(q * 4 + ocg) * 1152;
        const uint4* wL4 = (const uint4*)wL + (size_t)(q * 4 + ocg) * 1152;
        for (int j = tid; j < 2304; j += 256) {
            const uint4* src = (j < 1152) ? (wH4 + j) : (wL4 + (j - 1152));
            cp16(sb + j * 16, src, true);
        }
        // inputs: 80 (p,r) rows x 2 arrays x 10 slots (8x16B interior + 2x4B halo)
        for (int j = tid; j < 1600; j += 256) {
            int slotc = j % 10;
            int rest = j / 10;
            int arr = rest & 1;
            int pr = rest >> 1;
            int p = pr / 10, r = pr % 10;
            int gh = h0 + r - 1;
            bool rowok = (gh >= 0) && (gh < H);
            int ghc = min(max(gh, 0), H - 1);
            size_t rowoff = ((size_t)n * 128 + q * 8 + p) * SUMHW + cOFF[s] + (size_t)ghc * W;
            const uint32_t* gsrc = arr ? inL : inH;
            uint32_t dstrow = sb + (uint32_t)((arr ? ST_IL : ST_IH) + (p * 10 + r) * IPAD) * 4;
            if (slotc < 8) {
                int c0 = slotc * 4;
                bool ok = rowok && (w0 + c0 < W);
                cp16(dstrow + (uint32_t)(4 + c0) * 4, gsrc + rowoff + w0 + (ok ? c0 : 0), ok);
            } else if (slotc == 8) {
                bool ok = rowok && (w0 > 0);
                cp4(dstrow + 3 * 4, gsrc + rowoff + (ok ? (w0 - 1) : w0), ok);
            } else {
                bool ok = rowok && (w0 + 32 < W);
                cp4(dstrow + 36 * 4, gsrc + rowoff + w0 + (ok ? 32 : 0), ok);
            }
        }
    };

    fill(0, 0);
    CP_COMMIT();

    for (int q = 0; q < 16; q++) {
        if (q < 15) { fill(q + 1, (q + 1) & 1); CP_COMMIT(); CP_WAIT(1); }
        else        { CP_WAIT(0); }
        __syncthreads();

        const uint32_t* sb = smu + (q & 1) * STG_U32;
        const uint4* s_w4H = (const uint4*)sb;
        const uint4* s_w4L = s_w4H + 1152;
        const uint32_t* s_iH = sb + ST_IH;
        const uint32_t* s_iL = sb + ST_IL;

#pragma unroll
        for (int kh = 0; kh < 3; kh++)
#pragma unroll
        for (int kw = 0; kw < 3; kw++) {
            const int tap = kh * 3 + kw;
            uint32_t bh[4][2], bl[4][2];
            const int ib0 = (t * 10 + warp + kh) * IPAD + kw + 3 + g;
            const int ib1 = ((t + 4) * 10 + warp + kh) * IPAD + kw + 3 + g;
#pragma unroll
            for (int p4 = 0; p4 < 4; p4++) {
                bh[p4][0] = s_iH[ib0 + p4 * 8];
                bh[p4][1] = s_iH[ib1 + p4 * 8];
                bl[p4][0] = s_iL[ib0 + p4 * 8];
                bl[p4][1] = s_iL[ib1 + p4 * 8];
            }
#pragma unroll
            for (int o4 = 0; o4 < 4; o4++) {
                uint4 a4 = s_w4H[(tap * 4 + o4) * 32 + slot];
                uint4 b4 = s_w4L[(tap * 4 + o4) * 32 + slot];
                uint32_t ah[4] = {a4.x, a4.y, a4.z, a4.w};
                uint32_t al[4] = {b4.x, b4.y, b4.z, b4.w};
#pragma unroll
                for (int p4 = 0; p4 < 4; p4++) {
                    mma_bf16(acc[o4][p4], ah, bh[p4]);
                    mma_bf16(acc[o4][p4], ah, bl[p4]);
                    mma_bf16(acc[o4][p4], al, bh[p4]);
                }
            }
        }
        __syncthreads();
    }

    // epilogue (validated mapping): c0=(oc,col) c1=(oc,col+1) c2=(oc+8,col) c3=(oc+8,col+1)
    const int ghout = h0 + warp;
    if (dstF && ghout < H) {
        float* dbase = dstF + (size_t)n * C * SUMHW + cOFF[s] + (size_t)ghout * W + w0;
#pragma unroll
        for (int o4 = 0; o4 < 4; o4++) {
            int ocl = o4 * 16 + g;
            float b0v = s_bias[ocl];
            float b1v = s_bias[ocl + 8];
#pragma unroll
            for (int p4 = 0; p4 < 4; p4++) {
                int col = p4 * 8 + 2 * t;
                if (w0 + col < W) {
                    float2 v0 = make_float2(fmaxf(acc[o4][p4][0] + b0v, 0.f),
                                            fmaxf(acc[o4][p4][1] + b0v, 0.f));
                    float2 v1 = make_float2(fmaxf(acc[o4][p4][2] + b1v, 0.f),
                                            fmaxf(acc[o4][p4][3] + b1v, 0.f));
                    *(float2*)(dbase + (size_t)(ocBase + ocl) * SUMHW + col) = v0;
                    *(float2*)(dbase + (size_t)(ocBase + ocl + 8) * SUMHW + col) = v1;
                }
            }
        }
    }
    if (dstH) {
        const size_t base = ((size_t)n * 128) * SUMHW + cOFF[s] + (size_t)ghout * W + w0;
#pragma unroll
        for (int o4 = 0; o4 < 4; o4++) {
            int ocl = o4 * 16 + g;
            float b0v = s_bias[ocl];
            float b1v = s_bias[ocl + 8];
            const size_t w2a = (size_t)((ocBase + ocl) >> 1) * SUMHW;
            const size_t w2b = (size_t)(((ocBase + ocl) >> 1) + 4) * SUMHW;
#pragma unroll
            for (int p4 = 0; p4 < 4; p4++) {
                int col = p4 * 8 + 2 * t;
                float v0 = fmaxf(acc[o4][p4][0] + b0v, 0.f);
                float v1 = fmaxf(acc[o4][p4][1] + b0v, 0.f);
                float v2 = fmaxf(acc[o4][p4][2] + b1v, 0.f);
                float v3 = fmaxf(acc[o4][p4][3] + b1v, 0.f);
                float p0 = __shfl_xor_sync(0xFFFFFFFFu, v0, 4);
                float p1 = __shfl_xor_sync(0xFFFFFFFFu, v1, 4);
                float p2 = __shfl_xor_sync(0xFFFFFFFFu, v2, 4);
                float p3 = __shfl_xor_sync(0xFFFFFFFFu, v3, 4);
                if (((g & 1) == 0) && ghout < H && (w0 + col) < W) {
                    uint32_t hw, lw;
                    split_pack(v0, p0, hw, lw);
                    dstH[base + w2a + col] = hw;  dstL[base + w2a + col] = lw;
                    split_pack(v1, p1, hw, lw);
                    dstH[base + w2a + col + 1] = hw;  dstL[base + w2a + col + 1] = lw;
                    split_pack(v2, p2, hw, lw);
                    dstH[base + w2b + col] = hw;  dstL[base + w2b + col] = lw;
                    split_pack(v3, p3, hw, lw);
                    dstH[base + w2b + col + 1] = hw;  dstL[base + w2b + col + 1] = lw;
                }
            }
        }
    }
}

// ---------------- dense GEMM via pipelined 3-term bf16 mma ------------------
// Stage (u32): WH4 uint4[128] @0 | WL4 uint4[128] @512 | IH[8*264] @1024 | IL @3136
#define GIPAD 264
#define GST_U32 5248

__global__ __launch_bounds__(256, 2)
void gemm_mma(const uint32_t* __restrict__ wH, const uint32_t* __restrict__ wL,
              const uint32_t* __restrict__ bHg, const uint32_t* __restrict__ bLg,
              const float* __restrict__ bias, float* __restrict__ outp,
              int relu_flag)
{
    __shared__ __align__(16) uint32_t gsm[2 * GST_U32];

    const int s0 = blockIdx.x * 256;
    const int mg = blockIdx.y;
    const int n  = blockIdx.z;
    const int tid = threadIdx.x;
    const int warp = tid >> 5;
    const int lane = tid & 31;
    const int g = lane >> 2;
    const int t = lane & 3;
    const int slot = ((g >> 1) << 3) | (t << 1) | (g & 1);

    float acc[4][4][4];
#pragma unroll
    for (int i = 0; i < 4; i++)
#pragma unroll
        for (int j = 0; j < 4; j++)
#pragma unroll
            for (int k = 0; k < 4; k++) acc[i][j][k] = 0.f;

    const uint32_t smbase = smem_addr_of(gsm);

    auto fill = [&](int q, int st) {
        const uint32_t sb = smbase + (uint32_t)st * GST_U32 * 4;
        // weights: 256 uint4
        const uint4* wH4 = (const uint4*)wH + (size_t)(q * 4 + mg) * 128;
        const uint4* wL4 = (const uint4*)wL + (size_t)(q * 4 + mg) * 128;
        {
            int j = tid;
            if (j < 256) {
                const uint4* src = (j < 128) ? (wH4 + j) : (wL4 + (j - 128));
                cp16(sb + j * 16, src, true);
            }
        }
        // inputs: 8 p x 2 arrays x 64 16B-chunks
        for (int j = tid; j < 1024; j += 256) {
            int c = j & 63;
            int rest = j >> 6;
            int arr = rest & 1;
            int p = rest >> 1;
            int sx = s0 + c * 4;
            bool ok = sx < SUMHW;
            size_t off = ((size_t)n * 128 + q * 8 + p) * SUMHW + (ok ? sx : 0);
            const uint32_t* gsrc = arr ? bLg : bHg;
            uint32_t dst = sb + (uint32_t)(1024 + arr * 2112 + p * GIPAD + c * 4) * 4;
            cp16(dst, gsrc + off, ok);
        }
    };

    fill(0, 0);
    CP_COMMIT();

    for (int q = 0; q < 16; q++) {
        if (q < 15) { fill(q + 1, (q + 1) & 1); CP_COMMIT(); CP_WAIT(1); }
        else        { CP_WAIT(0); }
        __syncthreads();

        const uint32_t* sb = gsm + (q & 1) * GST_U32;
        const uint4* s_aH4 = (const uint4*)sb;
        const uint4* s_aL4 = s_aH4 + 128;
        const uint32_t* s_iH = sb + 1024;
        const uint32_t* s_iL = sb + 3136;

        uint32_t bh[4][2], bl[4][2];
        const int ib0 = t * GIPAD + warp * 32 + g;
        const int ib1 = (t + 4) * GIPAD + warp * 32 + g;
#pragma unroll
        for (int p4 = 0; p4 < 4; p4++) {
            bh[p4][0] = s_iH[ib0 + p4 * 8];
            bh[p4][1] = s_iH[ib1 + p4 * 8];
            bl[p4][0] = s_iL[ib0 + p4 * 8];
            bl[p4][1] = s_iL[ib1 + p4 * 8];
        }
#pragma unroll
        for (int o4 = 0; o4 < 4; o4++) {
            uint4 a4 = s_aH4[o4 * 32 + slot];
            uint4 b4 = s_aL4[o4 * 32 + slot];
            uint32_t ah[4] = {a4.x, a4.y, a4.z, a4.w};
            uint32_t al[4] = {b4.x, b4.y, b4.z, b4.w};
#pragma unroll
            for (int p4 = 0; p4 < 4; p4++) {
                mma_bf16(acc[o4][p4], ah, bh[p4]);
                mma_bf16(acc[o4][p4], ah, bl[p4]);
                mma_bf16(acc[o4][p4], al, bh[p4]);
            }
        }
        __syncthreads();
    }

    // epilogue: m = mg*64 + o4*16 + g (+8); s = s0 + warp*32 + p4*8 + 2t (+1)
#pragma unroll
    for (int o4 = 0; o4 < 4; o4++) {
        int m0 = mg * 64 + o4 * 16 + g;
        float b0v = bias ? bias[m0] : 0.f;
        float b1v = bias ? bias[m0 + 8] : 0.f;
#pragma unroll
        for (int p4 = 0; p4 < 4; p4++) {
            int sx = s0 + warp * 32 + p4 * 8 + 2 * t;
            if (sx < SUMHW) {
                float v0 = acc[o4][p4][0] + b0v;
                float v1 = acc[o4][p4][1] + b0v;
                float v2 = acc[o4][p4][2] + b1v;
                float v3 = acc[o4][p4][3] + b1v;
                if (relu_flag) {
                    v0 = fmaxf(v0, 0.f); v1 = fmaxf(v1, 0.f);
                    v2 = fmaxf(v2, 0.f); v3 = fmaxf(v3, 0.f);
                }
                *(float2*)(outp + ((size_t)n * 256 + m0) * SUMHW + sx) = make_float2(v0, v1);
                *(float2*)(outp + ((size_t)n * 256 + m0 + 8) * SUMHW + sx) = make_float2(v2, v3);
            }
        }
    }
}

// ---------------- person heads flat -----------------------------------------
__global__ __launch_bounds__(256)
void heads_p_flat(const float* __restrict__ hid,
                  const float* __restrict__ pl_w, const float* __restrict__ pl_b,
                  const float* __restrict__ pd_w, const float* __restrict__ pd_b,
                  float* __restrict__ out, float* __restrict__ cell)
{
    __shared__ float swl[A * C];
    __shared__ float swd[BOXC * C];
    const int tid = threadIdx.x;
    for (int i = tid; i < A * C; i += 256) swl[i] = pl_w[i];
    for (int i = tid; i < BOXC * C; i += 256) swd[i] = pd_w[i];
    __syncthreads();

    const int p = blockIdx.x * 256 + tid;
    const int n = blockIdx.y;
    if (p >= SUMHW) return;
    const int s = scale_of(p);
    const int ploc = p - cOFF[s];
    const int HW = cHW[s];
    const float* h = hid + (size_t)n * C * SUMHW + p;

    float accl[A], accd[BOXC];
#pragma unroll
    for (int a = 0; a < A; a++) accl[a] = pl_b[a];
#pragma unroll
    for (int j = 0; j < BOXC; j++) accd[j] = pd_b[j];

    for (int c = 0; c < C; c++) {
        float v = h[(size_t)c * SUMHW];
#pragma unroll
        for (int a = 0; a < A; a++) accl[a] += swl[a * C + c] * v;
#pragma unroll
        for (int j = 0; j < BOXC; j++) accd[j] += swd[j * C + c] * v;
    }
    float m = accl[0];
#pragma unroll
    for (int a = 0; a < A; a++) {
        out[cPLOG[s] + ((size_t)n * A + a) * HW + ploc] = accl[a];
        m = fmaxf(m, accl[a]);
    }
#pragma unroll
    for (int j = 0; j < BOXC; j++)
        out[cPDEL[s] + ((size_t)n * BOXC + j) * HW + ploc] = accd[j];
    cell[(size_t)n * SUMHW + p] = m;
}

// ---------------- object delta head flat ------------------------------------
__global__ __launch_bounds__(256)
void heads_od_flat(const float* __restrict__ hid,
                   const float* __restrict__ od_w, const float* __restrict__ od_b,
                   float* __restrict__ out)
{
    __shared__ float sw[BOXC * C];
    const int tid = threadIdx.x;
    for (int i = tid; i < BOXC * C; i += 256) sw[i] = od_w[i];
    __syncthreads();

    const int p = blockIdx.x * 256 + tid;
    const int n = blockIdx.y;
    if (p >= SUMHW) return;
    const int s = scale_of(p);
    const int ploc = p - cOFF[s];
    const int HW = cHW[s];
    const float* h = hid + (size_t)n * C * SUMHW + p;

    float acc[BOXC];
#pragma unroll
    for (int j = 0; j < BOXC; j++) acc[j] = od_b[j];
    for (int c = 0; c < C; c++) {
        float v = h[(size_t)c * SUMHW];
#pragma unroll
        for (int j = 0; j < BOXC; j++) acc[j] += sw[j * C + c] * v;
    }
#pragma unroll
    for (int j = 0; j < BOXC; j++)
        out[cODEL[s] + ((size_t)n * BOXC + j) * HW + ploc] = acc[j];
}

// ---------------- per-scale top-K (smem-cached) -----------------------------
__global__ __launch_bounds__(256)
void topk_flat(const float* __restrict__ cell, const float* __restrict__ hid,
               float* __restrict__ cand_hid, float* __restrict__ cand_sc)
{
    const int s = blockIdx.x;
    const int n = blockIdx.y;
    const int HW = cHW[s], off = cOFF[s];
    __shared__ float sc[10240];
    __shared__ float s_val[256];
    __shared__ int   s_idx[256];
    __shared__ int   sel[KTOP];
    const int tid = threadIdx.x;

    for (int i = tid; i < HW; i += 256)
        sc[i] = cell[(size_t)n * SUMHW + off + i];
    __syncthreads();

    for (int k = 0; k < KTOP; k++) {
        float best = -CUDART_INF_F;
        int bi = HW;
        for (int i = tid; i < HW; i += 256) {
            float v = sc[i];
            if (v > best) { best = v; bi = i; }
        }
        s_val[tid] = best; s_idx[tid] = bi;
        __syncthreads();
        for (int offr = 128; offr > 0; offr >>= 1) {
            if (tid < offr) {
                float v2 = s_val[tid + offr]; int i2 = s_idx[tid + offr];
                if (v2 > s_val[tid] || (v2 == s_val[tid] && i2 < s_idx[tid])) {
                    s_val[tid] = v2; s_idx[tid] = i2;
                }
            }
            __syncthreads();
        }
        if (tid == 0) {
            sel[k] = s_idx[0];
            cand_sc[(size_t)n * 80 + s * KTOP + k] = s_val[0];
            sc[s_idx[0]] = -CUDART_INF_F;
        }
        __syncthreads();
    }
    for (int idx = tid; idx < C * KTOP; idx += 256) {
        int c = idx / KTOP, k = idx % KTOP;
        cand_hid[((size_t)n * C + c) * 80 + s * KTOP + k] =
            hid[((size_t)n * C + c) * SUMHW + off + sel[k]];
    }
}

// ---------------- global top-K over 80 --------------------------------------
__global__ void topk_global_kernel(const float* __restrict__ sc, int* __restrict__ keep)
{
    const int n = blockIdx.x;
    bool used[80];
    for (int i = 0; i < 80; i++) used[i] = false;
    const float* s = sc + (size_t)n * 80;
    for (int k = 0; k < KTOP; k++) {
        float best = -CUDART_INF_F; int bi = 0;
        for (int i = 0; i < 80; i++)
            if (!used[i] && s[i] > best) { best = s[i]; bi = i; }
        used[bi] = true;
        keep[n * KTOP + k] = bi;
    }
}

// ---------------- p_proj ----------------------------------------------------
__global__ __launch_bounds__(256)
void pproj_kernel(const float* __restrict__ cand_hid, const int* __restrict__ keep,
                  const float* __restrict__ rn1_w, const float* __restrict__ rn1_b,
                  float* __restrict__ pproj)
{
    const int k = blockIdx.x, n = blockIdx.y, d = threadIdx.x;
    __shared__ float sh[C];
    const int col = keep[n * KTOP + k];
    sh[d] = cand_hid[((size_t)n * C + d) * 80 + col];
    __syncthreads();
    float acc = rn1_b[d];
    const float* wrow = rn1_w + (size_t)d * (2 * C) + C;   // Wp
    for (int c = 0; c < C; c++) acc += sh[c] * wrow[c];
    pproj[((size_t)n * KTOP + k) * D + d] = acc;
}

// ---------------- hsum (transposed): reads o1 [n][d][s] ---------------------
__global__ __launch_bounds__(256)
void hsum_t(const float* __restrict__ oproj, const float* __restrict__ pproj,
            uint32_t* __restrict__ hsH, uint32_t* __restrict__ hsL)
{
    __shared__ float spp[KTOP * 256];
    const int n = blockIdx.y;
    const int tid = threadIdx.x;
    for (int i = tid; i < KTOP * 256; i += 256) {
        int k = i >> 8, d = i & 255;
        spp[i] = pproj[((size_t)n * KTOP + k) * D + d];
    }
    __syncthreads();
    const int s = blockIdx.x * 256 + tid;
    if (s >= SUMHW) return;
    for (int dp = 0; dp < 128; dp++) {
        float o0 = oproj[((size_t)n * 256 + 2 * dp) * SUMHW + s];
        float o1v = oproj[((size_t)n * 256 + 2 * dp + 1) * SUMHW + s];
        float a0 = 0.f, a1 = 0.f;
#pragma unroll 4
        for (int k = 0; k < KTOP; k++) {
            a0 += fmaxf(o0 + spp[k * 256 + 2 * dp], 0.f);
            a1 += fmaxf(o1v + spp[k * 256 + 2 * dp + 1], 0.f);
        }
        uint32_t hi, lo;
        split_pack(a0, a1, hi, lo);
        hsH[((size_t)n * 128 + dp) * SUMHW + s] = hi;
        hsL[((size_t)n * 128 + dp) * SUMHW + s] = lo;
    }
}

// ---------------- ol head (transposed h2 [n][e][s]) -------------------------
__global__ __launch_bounds__(256)
void ol_t(const float* __restrict__ h2, const float* __restrict__ ol_w,
          const float* __restrict__ ol_b, float* __restrict__ out)
{
    __shared__ float sw[A * 256];
    const int n = blockIdx.y;
    const int tid = threadIdx.x;
    for (int i = tid; i < A * 256; i += 256) sw[i] = ol_w[i];
    __syncthreads();
    const int s = blockIdx.x * 256 + tid;
    if (s >= SUMHW) return;
    float a0 = 0.f, a1 = 0.f, a2 = 0.f;
    for (int e = 0; e < 256; e++) {
        float v = h2[((size_t)n * 256 + e) * SUMHW + s];
        a0 += v * sw[e];
        a1 += v * sw[256 + e];
        a2 += v * sw[512 + e];
    }
    const int sc = scale_of(s);
    const int ploc = s - cOFF[sc];
    const int HW = cHW[sc];
    out[cOLOG[sc] + ((size_t)n * A + 0) * HW + ploc] = a0 + ol_b[0];
    out[cOLOG[sc] + ((size_t)n * A + 1) * HW + ploc] = a1 + ol_b[1];
    out[cOLOG[sc] + ((size_t)n * A + 2) * HW + ploc] = a2 + ol_b[2];
}

// ---------------------------- host orchestration ----------------------------
extern "C" void kernel_launch(void* const* d_in, const int* in_sizes, int n_in,
                              void* d_out, int out_size)
{
    const float* f0 = (const float*)d_in[0];
    const float* f1 = (const float*)d_in[1];
    const float* f2 = (const float*)d_in[2];
    const float* f3 = (const float*)d_in[3];
    const float* pc1_w = (const float*)d_in[4];
    const float* pc1_b = (const float*)d_in[5];
    const float* pc2_w = (const float*)d_in[6];
    const float* pc2_b = (const float*)d_in[7];
    const float* oc1_w = (const float*)d_in[8];
    const float* oc1_b = (const float*)d_in[9];
    const float* oc2_w = (const float*)d_in[10];
    const float* oc2_b = (const float*)d_in[11];
    const float* rn1_w = (const float*)d_in[12];
    const float* rn1_b = (const float*)d_in[13];
    const float* rn2_w = (const float*)d_in[14];
    const float* rn2_b = (const float*)d_in[15];
    const float* pl_w  = (const float*)d_in[16];
    const float* pl_b  = (const float*)d_in[17];
    const float* pd_w  = (const float*)d_in[18];
    const float* pd_b  = (const float*)d_in[19];
    const float* ol_w  = (const float*)d_in[20];
    const float* ol_b  = (const float*)d_in[21];
    const float* od_w  = (const float*)d_in[22];
    const float* od_b  = (const float*)d_in[23];
    float* out = (float*)d_out;

    float *t2, *o1, *h2, *cell, *cand_hid, *cand_sc, *pproj;
    int* keep;
    uint32_t *sAh, *sAl, *sBh, *sBl, *sCh, *sCl, *hsh, *hsl, *wsh, *wsl, *wdh, *wdl;
    cudaGetSymbolAddress((void**)&t2, g_t2);
    cudaGetSymbolAddress((void**)&o1, g_o1);
    cudaGetSymbolAddress((void**)&h2, g_h2);
    cudaGetSymbolAddress((void**)&cell, g_cell);
    cudaGetSymbolAddress((void**)&cand_hid, g_cand_hid);
    cudaGetSymbolAddress((void**)&cand_sc, g_cand_sc);
    cudaGetSymbolAddress((void**)&keep, g_keep);
    cudaGetSymbolAddress((void**)&pproj, g_pproj);
    cudaGetSymbolAddress((void**)&sAh, g_sA_hi);
    cudaGetSymbolAddress((void**)&sAl, g_sA_lo);
    cudaGetSymbolAddress((void**)&sBh, g_sB_hi);
    cudaGetSymbolAddress((void**)&sBl, g_sB_lo);
    cudaGetSymbolAddress((void**)&sCh, g_sC_hi);
    cudaGetSymbolAddress((void**)&sCl, g_sC_lo);
    cudaGetSymbolAddress((void**)&hsh, g_hs_hi);
    cudaGetSymbolAddress((void**)&hsl, g_hs_lo);
    cudaGetSymbolAddress((void**)&wsh, g_wsp_hi);
    cudaGetSymbolAddress((void**)&wsl, g_wsp_lo);
    cudaGetSymbolAddress((void**)&wdh, g_wd_hi);
    cudaGetSymbolAddress((void**)&wdl, g_wd_lo);

    cudaFuncSetAttribute(conv3x3_sp,
                         cudaFuncAttributeMaxDynamicSharedMemorySize, CONV_SMEM);

    const dim3 convGrid(55, 4, NB);
    const dim3 headGrid((SUMHW + 255) / 256, NB);
    const dim3 gemmGrid(STILE, 4, NB);

    // ---- prep: split weights + feats ----
    split_w_conv<<<dim3((WSPL + 255) / 256, 4), 256>>>(pc1_w, pc2_w, oc1_w, oc2_w, wsh, wsl);
    split_w_dense<<<dim3((WDNS + 255) / 256, 2), 256>>>(rn1_w, rn2_w, 2 * C, D, wdh, wdl);
    split_feats_kernel<<<dim3((SUMHW + 255) / 256, 128, NB), 256>>>(f0, f1, f2, f3, sAh, sAl);

    // ---- person branch ----
    conv3x3_sp<<<convGrid, 256, CONV_SMEM>>>(sAh, sAl, wsh, wsl, pc1_b,
                                             nullptr, sBh, sBl);
    conv3x3_sp<<<convGrid, 256, CONV_SMEM>>>(sBh, sBl, wsh + WSPL, wsl + WSPL, pc2_b,
                                             t2, nullptr, nullptr);
    heads_p_flat<<<headGrid, 256>>>(t2, pl_w, pl_b, pd_w, pd_b, out, cell);
    topk_flat<<<dim3(4, NB), 256>>>(cell, t2, cand_hid, cand_sc);
    topk_global_kernel<<<NB, 1>>>(cand_sc, keep);
    pproj_kernel<<<dim3(KTOP, NB), 256>>>(cand_hid, keep, rn1_w, rn1_b, pproj);

    // ---- object branch ----
    conv3x3_sp<<<convGrid, 256, CONV_SMEM>>>(sAh, sAl, wsh + 2 * WSPL, wsl + 2 * WSPL, oc1_b,
                                             nullptr, sBh, sBl);
    conv3x3_sp<<<convGrid, 256, CONV_SMEM>>>(sBh, sBl, wsh + 3 * WSPL, wsl + 3 * WSPL, oc2_b,
                                             t2, sCh, sCl);
    heads_od_flat<<<headGrid, 256>>>(t2, od_w, od_b, out);
    gemm_mma<<<gemmGrid, 256>>>(wdh, wdl, sCh, sCl, nullptr, o1, 0);
    hsum_t<<<dim3(STILE, NB), 256>>>(o1, pproj, hsh, hsl);
    gemm_mma<<<gemmGrid, 256>>>(wdh + WDNS, wdl + WDNS, hsh, hsl, rn2_b, h2, 1);
    ol_t<<<dim3(STILE, NB), 256>>>(h2, ol_w, ol_b, out);

    (void)in_sizes; (void)n_in; (void)out_size;
}

// round 10
// speedup vs baseline: 6.8158x; 1.0480x over previous
#include <cuda_runtime.h>
#include <cuda_bf16.h>
#include <math_constants.h>
#include <stdint.h>

// Problem constants
#define NB   2
#define C    256
#define A    3
#define KTOP 20
#define D    256
#define BOXC 12
#define SUMHW 13600   // 10240 + 2560 + 640 + 160
#define WSPL 294912   // per-layer conv split-weight u32 count
#define WDNS 32768    // dense 256x256 split-weight u32 count
#define STILE 54      // ceil(SUMHW/256)

// ---------------- scratch (device globals) ----------------------------------
__device__ float g_t2[NB * C * SUMHW];
__device__ float g_o1[NB * 256 * SUMHW];   // oproj transposed [n][d][s]
__device__ float g_h2[NB * 256 * SUMHW];   // rn2 out [n][e][s]
__device__ float g_cell[NB * SUMHW];
__device__ float g_cand_hid[NB * C * 80];
__device__ float g_cand_sc[NB * 80];
__device__ int   g_keep[NB * KTOP];
__device__ float g_pproj[NB * KTOP * D];
// split activations: [n][pair=128][SUMHW] u32 (even ci low half, odd high)
__device__ uint32_t g_sA_hi[NB * 128 * SUMHW];
__device__ uint32_t g_sA_lo[NB * 128 * SUMHW];
__device__ uint32_t g_sB_hi[NB * 128 * SUMHW];
__device__ uint32_t g_sB_lo[NB * 128 * SUMHW];
__device__ uint32_t g_sC_hi[NB * 128 * SUMHW];
__device__ uint32_t g_sC_lo[NB * 128 * SUMHW];
__device__ uint32_t g_hs_hi[NB * 128 * SUMHW];
__device__ uint32_t g_hs_lo[NB * 128 * SUMHW];
// split weights (fragment order)
__device__ uint32_t g_wsp_hi[4 * WSPL];
__device__ uint32_t g_wsp_lo[4 * WSPL];
__device__ uint32_t g_wd_hi[2 * WDNS];     // 0: Wo, 1: rn2
__device__ uint32_t g_wd_lo[2 * WDNS];

// per-scale constants
__device__ __constant__ int cOFF[4]  = {0, 10240, 12800, 13440};
__device__ __constant__ int cHW[4]   = {10240, 2560, 640, 160};
__device__ __constant__ int cH[4]    = {80, 40, 20, 10};
__device__ __constant__ int cW[4]    = {128, 64, 32, 16};
__device__ __constant__ int cPLOG[4] = {0,      61440,  76800,  80640};
__device__ __constant__ int cPDEL[4] = {81600,  327360, 388800, 404160};
__device__ __constant__ int cOLOG[4] = {408000, 469440, 484800, 488640};
__device__ __constant__ int cODEL[4] = {489600, 735360, 796800, 812160};

__device__ __forceinline__ int scale_of(int p) {
    return (p < 10240) ? 0 : (p < 12800) ? 1 : (p < 13440) ? 2 : 3;
}

// ---------------- bf16 / async helpers --------------------------------------
__device__ __forceinline__ void mma_bf16(float* c, const uint32_t* a, const uint32_t* b) {
    asm volatile(
        "mma.sync.aligned.m16n8k16.row.col.f32.bf16.bf16.f32 "
        "{%0,%1,%2,%3}, {%4,%5,%6,%7}, {%8,%9}, {%0,%1,%2,%3};\n"
        : "+f"(c[0]), "+f"(c[1]), "+f"(c[2]), "+f"(c[3])
        : "r"(a[0]), "r"(a[1]), "r"(a[2]), "r"(a[3]), "r"(b[0]), "r"(b[1]));
}
__device__ __forceinline__ void split_pack(float v0, float v1,
                                           uint32_t& hi_out, uint32_t& lo_out) {
    __nv_bfloat16 h0 = __float2bfloat16(v0);
    __nv_bfloat16 h1 = __float2bfloat16(v1);
    __nv_bfloat16 l0 = __float2bfloat16(v0 - __bfloat162float(h0));
    __nv_bfloat16 l1 = __float2bfloat16(v1 - __bfloat162float(h1));
    hi_out = ((uint32_t)__bfloat16_as_ushort(h1) << 16) | (uint32_t)__bfloat16_as_ushort(h0);
    lo_out = ((uint32_t)__bfloat16_as_ushort(l1) << 16) | (uint32_t)__bfloat16_as_ushort(l0);
}
__device__ __forceinline__ uint32_t smem_addr_of(const void* p) {
    return (uint32_t)__cvta_generic_to_shared(p);
}
__device__ __forceinline__ void cp16(uint32_t dst, const void* src, bool pred) {
    asm volatile("cp.async.cg.shared.global [%0], [%1], 16, %2;"
                 :: "r"(dst), "l"(src), "r"(pred ? 16 : 0));
}
__device__ __forceinline__ void cp4(uint32_t dst, const void* src, bool pred) {
    asm volatile("cp.async.ca.shared.global [%0], [%1], 4, %2;"
                 :: "r"(dst), "l"(src), "r"(pred ? 4 : 0));
}
#define CP_COMMIT() asm volatile("cp.async.commit_group;" ::: "memory")
#define CP_WAIT(n)  asm volatile("cp.async.wait_group %0;" :: "n"(n) : "memory")

// ---------------- conv weight pre-split (fragment order) --------------------
__global__ __launch_bounds__(256)
void split_w_conv(const float* __restrict__ w0, const float* __restrict__ w1,
                  const float* __restrict__ w2, const float* __restrict__ w3,
                  uint32_t* __restrict__ outH, uint32_t* __restrict__ outL)
{
    const int i = blockIdx.x * 256 + threadIdx.x;
    if (i >= WSPL) return;
    const int layer = blockIdx.y;
    const float* w = (layer == 0) ? w0 : (layer == 1) ? w1 : (layer == 2) ? w2 : w3;
    const int e = i & 3;
    int j = i >> 2;
    const int slot = j & 31; j >>= 5;
    const int o4 = j & 3; j >>= 2;
    const int tap = j % 9; j /= 9;
    const int ocg = j & 3;
    const int q = j >> 2;
    const int g = ((slot >> 3) << 1) | (slot & 1);
    const int t = (slot >> 1) & 3;
    const int oc = ocg * 64 + o4 * 16 + g + (e & 1) * 8;
    const int p = t + ((e >> 1) << 2);
    const int ci0 = q * 16 + 2 * p;
    float v0 = w[(size_t)oc * 2304 + ci0 * 9 + tap];
    float v1 = w[(size_t)oc * 2304 + (ci0 + 1) * 9 + tap];
    uint32_t hi, lo;
    split_pack(v0, v1, hi, lo);
    outH[(size_t)layer * WSPL + i] = hi;
    outL[(size_t)layer * WSPL + i] = lo;
}

// ---------------- dense weight pre-split (fragment order) -------------------
__global__ __launch_bounds__(256)
void split_w_dense(const float* __restrict__ wA, const float* __restrict__ wB,
                   int strideA, int strideB,
                   uint32_t* __restrict__ outH, uint32_t* __restrict__ outL)
{
    const int i = blockIdx.x * 256 + threadIdx.x;
    if (i >= WDNS) return;
    const int which = blockIdx.y;
    const float* w = which ? wB : wA;
    const int stride = which ? strideB : strideA;
    const int e = i & 3;
    int j = i >> 2;
    const int slot = j & 31; j >>= 5;
    const int o4 = j & 3; j >>= 2;
    const int mg = j & 3;
    const int q = j >> 2;
    const int g = ((slot >> 3) << 1) | (slot & 1);
    const int t = (slot >> 1) & 3;
    const int m = mg * 64 + o4 * 16 + g + (e & 1) * 8;
    const int p = t + ((e >> 1) << 2);
    const int k0 = q * 16 + 2 * p;
    float v0 = w[(size_t)m * stride + k0];
    float v1 = w[(size_t)m * stride + k0 + 1];
    uint32_t hi, lo;
    split_pack(v0, v1, hi, lo);
    outH[(size_t)which * WDNS + i] = hi;
    outL[(size_t)which * WDNS + i] = lo;
}

// ---------------- feats pre-split -------------------------------------------
__global__ __launch_bounds__(256)
void split_feats_kernel(const float* __restrict__ f0, const float* __restrict__ f1,
                        const float* __restrict__ f2, const float* __restrict__ f3,
                        uint32_t* __restrict__ outH, uint32_t* __restrict__ outL)
{
    const int px = blockIdx.x * 256 + threadIdx.x;
    if (px >= SUMHW) return;
    const int c2 = blockIdx.y;
    const int n  = blockIdx.z;
    const int s = scale_of(px);
    const int ploc = px - cOFF[s];
    const int HW = cHW[s];
    const float* f = (s == 0) ? f0 : (s == 1) ? f1 : (s == 2) ? f2 : f3;
    const float* src = f + ((size_t)n * C + 2 * c2) * HW + ploc;
    uint32_t hi, lo;
    split_pack(src[0], src[HW], hi, lo);
    const size_t o = ((size_t)n * 128 + c2) * SUMHW + px;
    outH[o] = hi;
    outL[o] = lo;
}

// ---------------- conv3x3: pipelined 3-term bf16 mma, 8x16 px tile ----------
// Stage (u32): WH4 uint4[1152] @0 | WL4 uint4[1152] @4608 | IH[2240] @9216 | IL[2240] @11456
// IPAD = 28 (10*28 % 32 == 24 -> bank 24t+g all-distinct); interior cols at u32 off 4 (16B aligned)
#define IPAD 28
#define ST_IH 9216
#define ST_IL 11456
#define STG_U32 13696
#define CONV_SMEM (2 * STG_U32 * 4)   // 109568 B

__global__ __launch_bounds__(256, 2)
void conv3x3_sp(const uint32_t* __restrict__ inH, const uint32_t* __restrict__ inL,
                const uint32_t* __restrict__ wH, const uint32_t* __restrict__ wL,
                const float* __restrict__ bias,
                float* __restrict__ dstF,
                uint32_t* __restrict__ dstH, uint32_t* __restrict__ dstL)
{
    extern __shared__ __align__(16) uint32_t smu[];
    __shared__ float s_bias[64];

    const int bx = blockIdx.x;
    int s, t_;
    if (bx < 80)       { s = 0; t_ = bx; }
    else if (bx < 100) { s = 1; t_ = bx - 80; }
    else if (bx < 106) { s = 2; t_ = bx - 100; }
    else               { s = 3; t_ = bx - 106; }
    const int H = cH[s], W = cW[s];
    const int tilesX = W >> 4;
    const int ty = t_ / tilesX, tx = t_ % tilesX;
    const int h0 = ty * 8, w0 = tx * 16;
    const int n = blockIdx.z;
    const int ocg = blockIdx.y;
    const int ocBase = ocg * 64;

    const int tid  = threadIdx.x;
    const int warp = tid >> 5;
    const int lane = tid & 31;
    const int g = lane >> 2;
    const int t = lane & 3;
    const int slot = ((g >> 1) << 3) | (t << 1) | (g & 1);

    if (tid < 64) s_bias[tid] = bias[ocBase + tid];

    float acc[4][2][4];
#pragma unroll
    for (int i = 0; i < 4; i++)
#pragma unroll
        for (int j = 0; j < 2; j++)
#pragma unroll
            for (int k = 0; k < 4; k++) acc[i][j][k] = 0.f;

    const uint32_t smbase = smem_addr_of(smu);

    // fill one chunk's stage with cp.async
    auto fill = [&](int q, int st) {
        const uint32_t sb = smbase + (uint32_t)st * STG_U32 * 4;
        // weights: 2304 uint4 pure copy
        const uint4* wH4 = (const uint4*)wH + (size_t)(q * 4 + ocg) * 1152;
        const uint4* wL4 = (const uint4*)wL + (size_t)(q * 4 + ocg) * 1152;
        for (int j = tid; j < 2304; j += 256) {
            const uint4* src = (j < 1152) ? (wH4 + j) : (wL4 + (j - 1152));
            cp16(sb + j * 16, src, true);
        }
        // inputs: 80 (p,r) rows x 2 arrays x 6 slots (4x16B interior + 2x4B halo)
        for (int j = tid; j < 960; j += 256) {
            int slotc = j % 6;
            int rest = j / 6;
            int arr = rest & 1;
            int pr = rest >> 1;
            int p = pr / 10, r = pr % 10;
            int gh = h0 + r - 1;
            bool rowok = (gh >= 0) && (gh < H);
            int ghc = min(max(gh, 0), H - 1);
            size_t rowoff = ((size_t)n * 128 + q * 8 + p) * SUMHW + cOFF[s] + (size_t)ghc * W;
            const uint32_t* gsrc = arr ? inL : inH;
            uint32_t dstrow = sb + (uint32_t)((arr ? ST_IL : ST_IH) + (p * 10 + r) * IPAD) * 4;
            if (slotc < 4) {
                int c0 = slotc * 4;
                cp16(dstrow + (uint32_t)(4 + c0) * 4, gsrc + rowoff + w0 + c0, rowok);
            } else if (slotc == 4) {
                bool ok = rowok && (w0 > 0);
                cp4(dstrow + 3 * 4, gsrc + rowoff + (ok ? (w0 - 1) : w0), ok);
            } else {
                bool ok = rowok && (w0 + 16 < W);
                cp4(dstrow + 20 * 4, gsrc + rowoff + w0 + (ok ? 16 : 0), ok);
            }
        }
    };

    fill(0, 0);
    CP_COMMIT();

    for (int q = 0; q < 16; q++) {
        if (q < 15) { fill(q + 1, (q + 1) & 1); CP_COMMIT(); CP_WAIT(1); }
        else        { CP_WAIT(0); }
        __syncthreads();

        const uint32_t* sb = smu + (q & 1) * STG_U32;
        const uint4* s_w4H = (const uint4*)sb;
        const uint4* s_w4L = s_w4H + 1152;
        const uint32_t* s_iH = sb + ST_IH;
        const uint32_t* s_iL = sb + ST_IL;

#pragma unroll
        for (int kh = 0; kh < 3; kh++)
#pragma unroll
        for (int kw = 0; kw < 3; kw++) {
            const int tap = kh * 3 + kw;
            uint32_t bh[2][2], bl[2][2];
            const int ib0 = (t * 10 + warp + kh) * IPAD + kw + 3 + g;
            const int ib1 = ((t + 4) * 10 + warp + kh) * IPAD + kw + 3 + g;
#pragma unroll
            for (int p4 = 0; p4 < 2; p4++) {
                bh[p4][0] = s_iH[ib0 + p4 * 8];
                bh[p4][1] = s_iH[ib1 + p4 * 8];
                bl[p4][0] = s_iL[ib0 + p4 * 8];
                bl[p4][1] = s_iL[ib1 + p4 * 8];
            }
#pragma unroll
            for (int o4 = 0; o4 < 4; o4++) {
                uint4 a4 = s_w4H[(tap * 4 + o4) * 32 + slot];
                uint4 b4 = s_w4L[(tap * 4 + o4) * 32 + slot];
                uint32_t ah[4] = {a4.x, a4.y, a4.z, a4.w};
                uint32_t al[4] = {b4.x, b4.y, b4.z, b4.w};
#pragma unroll
                for (int p4 = 0; p4 < 2; p4++) {
                    mma_bf16(acc[o4][p4], ah, bh[p4]);
                    mma_bf16(acc[o4][p4], ah, bl[p4]);
                    mma_bf16(acc[o4][p4], al, bh[p4]);
                }
            }
        }
        __syncthreads();
    }

    // epilogue (validated mapping): c0=(oc,col) c1=(oc,col+1) c2=(oc+8,col) c3=(oc+8,col+1)
    const int ghout = h0 + warp;
    if (dstF && ghout < H) {
        float* dbase = dstF + (size_t)n * C * SUMHW + cOFF[s] + (size_t)ghout * W + w0;
#pragma unroll
        for (int o4 = 0; o4 < 4; o4++) {
            int ocl = o4 * 16 + g;
            float b0v = s_bias[ocl];
            float b1v = s_bias[ocl + 8];
#pragma unroll
            for (int p4 = 0; p4 < 2; p4++) {
                int col = p4 * 8 + 2 * t;
                float2 v0 = make_float2(fmaxf(acc[o4][p4][0] + b0v, 0.f),
                                        fmaxf(acc[o4][p4][1] + b0v, 0.f));
                float2 v1 = make_float2(fmaxf(acc[o4][p4][2] + b1v, 0.f),
                                        fmaxf(acc[o4][p4][3] + b1v, 0.f));
                *(float2*)(dbase + (size_t)(ocBase + ocl) * SUMHW + col) = v0;
                *(float2*)(dbase + (size_t)(ocBase + ocl + 8) * SUMHW + col) = v1;
            }
        }
    }
    if (dstH) {
        const size_t base = ((size_t)n * 128) * SUMHW + cOFF[s] + (size_t)ghout * W + w0;
#pragma unroll
        for (int o4 = 0; o4 < 4; o4++) {
            int ocl = o4 * 16 + g;
            float b0v = s_bias[ocl];
            float b1v = s_bias[ocl + 8];
            const size_t w2a = (size_t)((ocBase + ocl) >> 1) * SUMHW;
            const size_t w2b = (size_t)(((ocBase + ocl) >> 1) + 4) * SUMHW;
#pragma unroll
            for (int p4 = 0; p4 < 2; p4++) {
                int col = p4 * 8 + 2 * t;
                float v0 = fmaxf(acc[o4][p4][0] + b0v, 0.f);
                float v1 = fmaxf(acc[o4][p4][1] + b0v, 0.f);
                float v2 = fmaxf(acc[o4][p4][2] + b1v, 0.f);
                float v3 = fmaxf(acc[o4][p4][3] + b1v, 0.f);
                float p0 = __shfl_xor_sync(0xFFFFFFFFu, v0, 4);
                float p1 = __shfl_xor_sync(0xFFFFFFFFu, v1, 4);
                float p2 = __shfl_xor_sync(0xFFFFFFFFu, v2, 4);
                float p3 = __shfl_xor_sync(0xFFFFFFFFu, v3, 4);
                if (((g & 1) == 0) && ghout < H) {
                    uint32_t hw, lw;
                    split_pack(v0, p0, hw, lw);
                    dstH[base + w2a + col] = hw;  dstL[base + w2a + col] = lw;
                    split_pack(v1, p1, hw, lw);
                    dstH[base + w2a + col + 1] = hw;  dstL[base + w2a + col + 1] = lw;
                    split_pack(v2, p2, hw, lw);
                    dstH[base + w2b + col] = hw;  dstL[base + w2b + col] = lw;
                    split_pack(v3, p3, hw, lw);
                    dstH[base + w2b + col + 1] = hw;  dstL[base + w2b + col + 1] = lw;
                }
            }
        }
    }
}

// ---------------- dense GEMM via pipelined 3-term bf16 mma ------------------
#define GIPAD 264
#define GST_U32 5248

__global__ __launch_bounds__(256, 2)
void gemm_mma(const uint32_t* __restrict__ wH, const uint32_t* __restrict__ wL,
              const uint32_t* __restrict__ bHg, const uint32_t* __restrict__ bLg,
              const float* __restrict__ bias, float* __restrict__ outp,
              int relu_flag)
{
    __shared__ __align__(16) uint32_t gsm[2 * GST_U32];

    const int s0 = blockIdx.x * 256;
    const int mg = blockIdx.y;
    const int n  = blockIdx.z;
    const int tid = threadIdx.x;
    const int warp = tid >> 5;
    const int lane = tid & 31;
    const int g = lane >> 2;
    const int t = lane & 3;
    const int slot = ((g >> 1) << 3) | (t << 1) | (g & 1);

    float acc[4][4][4];
#pragma unroll
    for (int i = 0; i < 4; i++)
#pragma unroll
        for (int j = 0; j < 4; j++)
#pragma unroll
            for (int k = 0; k < 4; k++) acc[i][j][k] = 0.f;

    const uint32_t smbase = smem_addr_of(gsm);

    auto fill = [&](int q, int st) {
        const uint32_t sb = smbase + (uint32_t)st * GST_U32 * 4;
        const uint4* wH4 = (const uint4*)wH + (size_t)(q * 4 + mg) * 128;
        const uint4* wL4 = (const uint4*)wL + (size_t)(q * 4 + mg) * 128;
        {
            int j = tid;
            if (j < 256) {
                const uint4* src = (j < 128) ? (wH4 + j) : (wL4 + (j - 128));
                cp16(sb + j * 16, src, true);
            }
        }
        for (int j = tid; j < 1024; j += 256) {
            int c = j & 63;
            int rest = j >> 6;
            int arr = rest & 1;
            int p = rest >> 1;
            int sx = s0 + c * 4;
            bool ok = sx < SUMHW;
            size_t off = ((size_t)n * 128 + q * 8 + p) * SUMHW + (ok ? sx : 0);
            const uint32_t* gsrc = arr ? bLg : bHg;
            uint32_t dst = sb + (uint32_t)(1024 + arr * 2112 + p * GIPAD + c * 4) * 4;
            cp16(dst, gsrc + off, ok);
        }
    };

    fill(0, 0);
    CP_COMMIT();

    for (int q = 0; q < 16; q++) {
        if (q < 15) { fill(q + 1, (q + 1) & 1); CP_COMMIT(); CP_WAIT(1); }
        else        { CP_WAIT(0); }
        __syncthreads();

        const uint32_t* sb = gsm + (q & 1) * GST_U32;
        const uint4* s_aH4 = (const uint4*)sb;
        const uint4* s_aL4 = s_aH4 + 128;
        const uint32_t* s_iH = sb + 1024;
        const uint32_t* s_iL = sb + 3136;

        uint32_t bh[4][2], bl[4][2];
        const int ib0 = t * GIPAD + warp * 32 + g;
        const int ib1 = (t + 4) * GIPAD + warp * 32 + g;
#pragma unroll
        for (int p4 = 0; p4 < 4; p4++) {
            bh[p4][0] = s_iH[ib0 + p4 * 8];
            bh[p4][1] = s_iH[ib1 + p4 * 8];
            bl[p4][0] = s_iL[ib0 + p4 * 8];
            bl[p4][1] = s_iL[ib1 + p4 * 8];
        }
#pragma unroll
        for (int o4 = 0; o4 < 4; o4++) {
            uint4 a4 = s_aH4[o4 * 32 + slot];
            uint4 b4 = s_aL4[o4 * 32 + slot];
            uint32_t ah[4] = {a4.x, a4.y, a4.z, a4.w};
            uint32_t al[4] = {b4.x, b4.y, b4.z, b4.w};
#pragma unroll
            for (int p4 = 0; p4 < 4; p4++) {
                mma_bf16(acc[o4][p4], ah, bh[p4]);
                mma_bf16(acc[o4][p4], ah, bl[p4]);
                mma_bf16(acc[o4][p4], al, bh[p4]);
            }
        }
        __syncthreads();
    }

#pragma unroll
    for (int o4 = 0; o4 < 4; o4++) {
        int m0 = mg * 64 + o4 * 16 + g;
        float b0v = bias ? bias[m0] : 0.f;
        float b1v = bias ? bias[m0 + 8] : 0.f;
#pragma unroll
        for (int p4 = 0; p4 < 4; p4++) {
            int sx = s0 + warp * 32 + p4 * 8 + 2 * t;
            if (sx < SUMHW) {
                float v0 = acc[o4][p4][0] + b0v;
                float v1 = acc[o4][p4][1] + b0v;
                float v2 = acc[o4][p4][2] + b1v;
                float v3 = acc[o4][p4][3] + b1v;
                if (relu_flag) {
                    v0 = fmaxf(v0, 0.f); v1 = fmaxf(v1, 0.f);
                    v2 = fmaxf(v2, 0.f); v3 = fmaxf(v3, 0.f);
                }
                *(float2*)(outp + ((size_t)n * 256 + m0) * SUMHW + sx) = make_float2(v0, v1);
                *(float2*)(outp + ((size_t)n * 256 + m0 + 8) * SUMHW + sx) = make_float2(v2, v3);
            }
        }
    }
}

// ---------------- person heads flat -----------------------------------------
__global__ __launch_bounds__(256)
void heads_p_flat(const float* __restrict__ hid,
                  const float* __restrict__ pl_w, const float* __restrict__ pl_b,
                  const float* __restrict__ pd_w, const float* __restrict__ pd_b,
                  float* __restrict__ out, float* __restrict__ cell)
{
    __shared__ float swl[A * C];
    __shared__ float swd[BOXC * C];
    const int tid = threadIdx.x;
    for (int i = tid; i < A * C; i += 256) swl[i] = pl_w[i];
    for (int i = tid; i < BOXC * C; i += 256) swd[i] = pd_w[i];
    __syncthreads();

    const int p = blockIdx.x * 256 + tid;
    const int n = blockIdx.y;
    if (p >= SUMHW) return;
    const int s = scale_of(p);
    const int ploc = p - cOFF[s];
    const int HW = cHW[s];
    const float* h = hid + (size_t)n * C * SUMHW + p;

    float accl[A], accd[BOXC];
#pragma unroll
    for (int a = 0; a < A; a++) accl[a] = pl_b[a];
#pragma unroll
    for (int j = 0; j < BOXC; j++) accd[j] = pd_b[j];

    for (int c = 0; c < C; c++) {
        float v = h[(size_t)c * SUMHW];
#pragma unroll
        for (int a = 0; a < A; a++) accl[a] += swl[a * C + c] * v;
#pragma unroll
        for (int j = 0; j < BOXC; j++) accd[j] += swd[j * C + c] * v;
    }
    float m = accl[0];
#pragma unroll
    for (int a = 0; a < A; a++) {
        out[cPLOG[s] + ((size_t)n * A + a) * HW + ploc] = accl[a];
        m = fmaxf(m, accl[a]);
    }
#pragma unroll
    for (int j = 0; j < BOXC; j++)
        out[cPDEL[s] + ((size_t)n * BOXC + j) * HW + ploc] = accd[j];
    cell[(size_t)n * SUMHW + p] = m;
}

// ---------------- object delta head flat ------------------------------------
__global__ __launch_bounds__(256)
void heads_od_flat(const float* __restrict__ hid,
                   const float* __restrict__ od_w, const float* __restrict__ od_b,
                   float* __restrict__ out)
{
    __shared__ float sw[BOXC * C];
    const int tid = threadIdx.x;
    for (int i = tid; i < BOXC * C; i += 256) sw[i] = od_w[i];
    __syncthreads();

    const int p = blockIdx.x * 256 + tid;
    const int n = blockIdx.y;
    if (p >= SUMHW) return;
    const int s = scale_of(p);
    const int ploc = p - cOFF[s];
    const int HW = cHW[s];
    const float* h = hid + (size_t)n * C * SUMHW + p;

    float acc[BOXC];
#pragma unroll
    for (int j = 0; j < BOXC; j++) acc[j] = od_b[j];
    for (int c = 0; c < C; c++) {
        float v = h[(size_t)c * SUMHW];
#pragma unroll
        for (int j = 0; j < BOXC; j++) acc[j] += sw[j * C + c] * v;
    }
#pragma unroll
    for (int j = 0; j < BOXC; j++)
        out[cODEL[s] + ((size_t)n * BOXC + j) * HW + ploc] = acc[j];
}

// ---------------- per-scale top-K (smem-cached) -----------------------------
__global__ __launch_bounds__(256)
void topk_flat(const float* __restrict__ cell, const float* __restrict__ hid,
               float* __restrict__ cand_hid, float* __restrict__ cand_sc)
{
    const int s = blockIdx.x;
    const int n = blockIdx.y;
    const int HW = cHW[s], off = cOFF[s];
    __shared__ float sc[10240];
    __shared__ float s_val[256];
    __shared__ int   s_idx[256];
    __shared__ int   sel[KTOP];
    const int tid = threadIdx.x;

    for (int i = tid; i < HW; i += 256)
        sc[i] = cell[(size_t)n * SUMHW + off + i];
    __syncthreads();

    for (int k = 0; k < KTOP; k++) {
        float best = -CUDART_INF_F;
        int bi = HW;
        for (int i = tid; i < HW; i += 256) {
            float v = sc[i];
            if (v > best) { best = v; bi = i; }
        }
        s_val[tid] = best; s_idx[tid] = bi;
        __syncthreads();
        for (int offr = 128; offr > 0; offr >>= 1) {
            if (tid < offr) {
                float v2 = s_val[tid + offr]; int i2 = s_idx[tid + offr];
                if (v2 > s_val[tid] || (v2 == s_val[tid] && i2 < s_idx[tid])) {
                    s_val[tid] = v2; s_idx[tid] = i2;
                }
            }
            __syncthreads();
        }
        if (tid == 0) {
            sel[k] = s_idx[0];
            cand_sc[(size_t)n * 80 + s * KTOP + k] = s_val[0];
            sc[s_idx[0]] = -CUDART_INF_F;
        }
        __syncthreads();
    }
    for (int idx = tid; idx < C * KTOP; idx += 256) {
        int c = idx / KTOP, k = idx % KTOP;
        cand_hid[((size_t)n * C + c) * 80 + s * KTOP + k] =
            hid[((size_t)n * C + c) * SUMHW + off + sel[k]];
    }
}

// ---------------- global top-K over 80 --------------------------------------
__global__ void topk_global_kernel(const float* __restrict__ sc, int* __restrict__ keep)
{
    const int n = blockIdx.x;
    bool used[80];
    for (int i = 0; i < 80; i++) used[i] = false;
    const float* s = sc + (size_t)n * 80;
    for (int k = 0; k < KTOP; k++) {
        float best = -CUDART_INF_F; int bi = 0;
        for (int i = 0; i < 80; i++)
            if (!used[i] && s[i] > best) { best = s[i]; bi = i; }
        used[bi] = true;
        keep[n * KTOP + k] = bi;
    }
}

// ---------------- p_proj ----------------------------------------------------
__global__ __launch_bounds__(256)
void pproj_kernel(const float* __restrict__ cand_hid, const int* __restrict__ keep,
                  const float* __restrict__ rn1_w, const float* __restrict__ rn1_b,
                  float* __restrict__ pproj)
{
    const int k = blockIdx.x, n = blockIdx.y, d = threadIdx.x;
    __shared__ float sh[C];
    const int col = keep[n * KTOP + k];
    sh[d] = cand_hid[((size_t)n * C + d) * 80 + col];
    __syncthreads();
    float acc = rn1_b[d];
    const float* wrow = rn1_w + (size_t)d * (2 * C) + C;   // Wp
    for (int c = 0; c < C; c++) acc += sh[c] * wrow[c];
    pproj[((size_t)n * KTOP + k) * D + d] = acc;
}

// ---------------- hsum (transposed): reads o1 [n][d][s] ---------------------
__global__ __launch_bounds__(256)
void hsum_t(const float* __restrict__ oproj, const float* __restrict__ pproj,
            uint32_t* __restrict__ hsH, uint32_t* __restrict__ hsL)
{
    __shared__ float spp[KTOP * 256];
    const int n = blockIdx.y;
    const int tid = threadIdx.x;
    for (int i = tid; i < KTOP * 256; i += 256) {
        int k = i >> 8, d = i & 255;
        spp[i] = pproj[((size_t)n * KTOP + k) * D + d];
    }
    __syncthreads();
    const int s = blockIdx.x * 256 + tid;
    if (s >= SUMHW) return;
    for (int dp = 0; dp < 128; dp++) {
        float o0 = oproj[((size_t)n * 256 + 2 * dp) * SUMHW + s];
        float o1v = oproj[((size_t)n * 256 + 2 * dp + 1) * SUMHW + s];
        float a0 = 0.f, a1 = 0.f;
#pragma unroll 4
        for (int k = 0; k < KTOP; k++) {
            a0 += fmaxf(o0 + spp[k * 256 + 2 * dp], 0.f);
            a1 += fmaxf(o1v + spp[k * 256 + 2 * dp + 1], 0.f);
        }
        uint32_t hi, lo;
        split_pack(a0, a1, hi, lo);
        hsH[((size_t)n * 128 + dp) * SUMHW + s] = hi;
        hsL[((size_t)n * 128 + dp) * SUMHW + s] = lo;
    }
}

// ---------------- ol head (transposed h2 [n][e][s]) -------------------------
__global__ __launch_bounds__(256)
void ol_t(const float* __restrict__ h2, const float* __restrict__ ol_w,
          const float* __restrict__ ol_b, float* __restrict__ out)
{
    __shared__ float sw[A * 256];
    const int n = blockIdx.y;
    const int tid = threadIdx.x;
    for (int i = tid; i < A * 256; i += 256) sw[i] = ol_w[i];
    __syncthreads();
    const int s = blockIdx.x * 256 + tid;
    if (s >= SUMHW) return;
    float a0 = 0.f, a1 = 0.f, a2 = 0.f;
    for (int e = 0; e < 256; e++) {
        float v = h2[((size_t)n * 256 + e) * SUMHW + s];
        a0 += v * sw[e];
        a1 += v * sw[256 + e];
        a2 += v * sw[512 + e];
    }
    const int sc = scale_of(s);
    const int ploc = s - cOFF[sc];
    const int HW = cHW[sc];
    out[cOLOG[sc] + ((size_t)n * A + 0) * HW + ploc] = a0 + ol_b[0];
    out[cOLOG[sc] + ((size_t)n * A + 1) * HW + ploc] = a1 + ol_b[1];
    out[cOLOG[sc] + ((size_t)n * A + 2) * HW + ploc] = a2 + ol_b[2];
}

// ---------------------------- host orchestration ----------------------------
extern "C" void kernel_launch(void* const* d_in, const int* in_sizes, int n_in,
                              void* d_out, int out_size)
{
    const float* f0 = (const float*)d_in[0];
    const float* f1 = (const float*)d_in[1];
    const float* f2 = (const float*)d_in[2];
    const float* f3 = (const float*)d_in[3];
    const float* pc1_w = (const float*)d_in[4];
    const float* pc1_b = (const float*)d_in[5];
    const float* pc2_w = (const float*)d_in[6];
    const float* pc2_b = (const float*)d_in[7];
    const float* oc1_w = (const float*)d_in[8];
    const float* oc1_b = (const float*)d_in[9];
    const float* oc2_w = (const float*)d_in[10];
    const float* oc2_b = (const float*)d_in[11];
    const float* rn1_w = (const float*)d_in[12];
    const float* rn1_b = (const float*)d_in[13];
    const float* rn2_w = (const float*)d_in[14];
    const float* rn2_b = (const float*)d_in[15];
    const float* pl_w  = (const float*)d_in[16];
    const float* pl_b  = (const float*)d_in[17];
    const float* pd_w  = (const float*)d_in[18];
    const float* pd_b  = (const float*)d_in[19];
    const float* ol_w  = (const float*)d_in[20];
    const float* ol_b  = (const float*)d_in[21];
    const float* od_w  = (const float*)d_in[22];
    const float* od_b  = (const float*)d_in[23];
    float* out = (float*)d_out;

    float *t2, *o1, *h2, *cell, *cand_hid, *cand_sc, *pproj;
    int* keep;
    uint32_t *sAh, *sAl, *sBh, *sBl, *sCh, *sCl, *hsh, *hsl, *wsh, *wsl, *wdh, *wdl;
    cudaGetSymbolAddress((void**)&t2, g_t2);
    cudaGetSymbolAddress((void**)&o1, g_o1);
    cudaGetSymbolAddress((void**)&h2, g_h2);
    cudaGetSymbolAddress((void**)&cell, g_cell);
    cudaGetSymbolAddress((void**)&cand_hid, g_cand_hid);
    cudaGetSymbolAddress((void**)&cand_sc, g_cand_sc);
    cudaGetSymbolAddress((void**)&keep, g_keep);
    cudaGetSymbolAddress((void**)&pproj, g_pproj);
    cudaGetSymbolAddress((void**)&sAh, g_sA_hi);
    cudaGetSymbolAddress((void**)&sAl, g_sA_lo);
    cudaGetSymbolAddress((void**)&sBh, g_sB_hi);
    cudaGetSymbolAddress((void**)&sBl, g_sB_lo);
    cudaGetSymbolAddress((void**)&sCh, g_sC_hi);
    cudaGetSymbolAddress((void**)&sCl, g_sC_lo);
    cudaGetSymbolAddress((void**)&hsh, g_hs_hi);
    cudaGetSymbolAddress((void**)&hsl, g_hs_lo);
    cudaGetSymbolAddress((void**)&wsh, g_wsp_hi);
    cudaGetSymbolAddress((void**)&wsl, g_wsp_lo);
    cudaGetSymbolAddress((void**)&wdh, g_wd_hi);
    cudaGetSymbolAddress((void**)&wdl, g_wd_lo);

    cudaFuncSetAttribute(conv3x3_sp,
                         cudaFuncAttributeMaxDynamicSharedMemorySize, CONV_SMEM);

    const dim3 convGrid(108, 4, NB);
    const dim3 headGrid((SUMHW + 255) / 256, NB);
    const dim3 gemmGrid(STILE, 4, NB);

    // ---- prep: split weights + feats ----
    split_w_conv<<<dim3((WSPL + 255) / 256, 4), 256>>>(pc1_w, pc2_w, oc1_w, oc2_w, wsh, wsl);
    split_w_dense<<<dim3((WDNS + 255) / 256, 2), 256>>>(rn1_w, rn2_w, 2 * C, D, wdh, wdl);
    split_feats_kernel<<<dim3((SUMHW + 255) / 256, 128, NB), 256>>>(f0, f1, f2, f3, sAh, sAl);

    // ---- person branch ----
    conv3x3_sp<<<convGrid, 256, CONV_SMEM>>>(sAh, sAl, wsh, wsl, pc1_b,
                                             nullptr, sBh, sBl);
    conv3x3_sp<<<convGrid, 256, CONV_SMEM>>>(sBh, sBl, wsh + WSPL, wsl + WSPL, pc2_b,
                                             t2, nullptr, nullptr);
    heads_p_flat<<<headGrid, 256>>>(t2, pl_w, pl_b, pd_w, pd_b, out, cell);
    topk_flat<<<dim3(4, NB), 256>>>(cell, t2, cand_hid, cand_sc);
    topk_global_kernel<<<NB, 1>>>(cand_sc, keep);
    pproj_kernel<<<dim3(KTOP, NB), 256>>>(cand_hid, keep, rn1_w, rn1_b, pproj);

    // ---- object branch ----
    conv3x3_sp<<<convGrid, 256, CONV_SMEM>>>(sAh, sAl, wsh + 2 * WSPL, wsl + 2 * WSPL, oc1_b,
                                             nullptr, sBh, sBl);
    conv3x3_sp<<<convGrid, 256, CONV_SMEM>>>(sBh, sBl, wsh + 3 * WSPL, wsl + 3 * WSPL, oc2_b,
                                             t2, sCh, sCl);
    heads_od_flat<<<headGrid, 256>>>(t2, od_w, od_b, out);
    gemm_mma<<<gemmGrid, 256>>>(wdh, wdl, sCh, sCl, nullptr, o1, 0);
    hsum_t<<<dim3(STILE, NB), 256>>>(o1, pproj, hsh, hsl);
    gemm_mma<<<gemmGrid, 256>>>(wdh + WDNS, wdl + WDNS, hsh, hsl, rn2_b, h2, 1);
    ol_t<<<dim3(STILE, NB), 256>>>(h2, ol_w, ol_b, out);

    (void)in_sizes; (void)n_in; (void)out_size;
}

// round 11
// speedup vs baseline: 7.2322x; 1.0611x over previous
#include <cuda_runtime.h>
#include <cuda_bf16.h>
#include <math_constants.h>
#include <stdint.h>

// Problem constants
#define NB   2
#define C    256
#define A    3
#define KTOP 20
#define D    256
#define BOXC 12
#define SUMHW 13600   // 10240 + 2560 + 640 + 160
#define WSPL 294912   // per-layer conv split-weight u32 count
#define WDNS 32768    // dense 256x256 split-weight u32 count
#define STILE 54      // ceil(SUMHW/256)

// ---------------- scratch (device globals) ----------------------------------
__device__ float g_t2p[NB * C * SUMHW];
__device__ float g_t2o[NB * C * SUMHW];
__device__ float g_h2[NB * 256 * SUMHW];   // rn2 out [n][e][s]
__device__ float g_cell[NB * SUMHW];
__device__ float g_cand_hid[NB * C * 80];
__device__ float g_cand_sc[NB * 80];
__device__ int   g_keep[NB * KTOP];
__device__ float g_pproj[NB * KTOP * D];
// split activations: [n][pair=128][SUMHW] u32 (even ci low half, odd high)
__device__ uint32_t g_sA_hi[NB * 128 * SUMHW];
__device__ uint32_t g_sA_lo[NB * 128 * SUMHW];
__device__ uint32_t g_sB_hi[NB * 128 * SUMHW];   // person conv1 out
__device__ uint32_t g_sB_lo[NB * 128 * SUMHW];
__device__ uint32_t g_sD_hi[NB * 128 * SUMHW];   // object conv1 out
__device__ uint32_t g_sD_lo[NB * 128 * SUMHW];
__device__ uint32_t g_sC_hi[NB * 128 * SUMHW];   // object conv2 split out
__device__ uint32_t g_sC_lo[NB * 128 * SUMHW];
__device__ uint32_t g_hs_hi[NB * 128 * SUMHW];
__device__ uint32_t g_hs_lo[NB * 128 * SUMHW];
// split weights (fragment order)
__device__ uint32_t g_wsp_hi[4 * WSPL];
__device__ uint32_t g_wsp_lo[4 * WSPL];
__device__ uint32_t g_wd_hi[2 * WDNS];     // 0: Wo, 1: rn2
__device__ uint32_t g_wd_lo[2 * WDNS];

// per-scale constants
__device__ __constant__ int cOFF[4]  = {0, 10240, 12800, 13440};
__device__ __constant__ int cHW[4]   = {10240, 2560, 640, 160};
__device__ __constant__ int cH[4]    = {80, 40, 20, 10};
__device__ __constant__ int cW[4]    = {128, 64, 32, 16};
__device__ __constant__ int cPLOG[4] = {0,      61440,  76800,  80640};
__device__ __constant__ int cPDEL[4] = {81600,  327360, 388800, 404160};
__device__ __constant__ int cOLOG[4] = {408000, 469440, 484800, 488640};
__device__ __constant__ int cODEL[4] = {489600, 735360, 796800, 812160};

__device__ __forceinline__ int scale_of(int p) {
    return (p < 10240) ? 0 : (p < 12800) ? 1 : (p < 13440) ? 2 : 3;
}

// ---------------- bf16 / async helpers --------------------------------------
__device__ __forceinline__ void mma_bf16(float* c, const uint32_t* a, const uint32_t* b) {
    asm volatile(
        "mma.sync.aligned.m16n8k16.row.col.f32.bf16.bf16.f32 "
        "{%0,%1,%2,%3}, {%4,%5,%6,%7}, {%8,%9}, {%0,%1,%2,%3};\n"
        : "+f"(c[0]), "+f"(c[1]), "+f"(c[2]), "+f"(c[3])
        : "r"(a[0]), "r"(a[1]), "r"(a[2]), "r"(a[3]), "r"(b[0]), "r"(b[1]));
}
__device__ __forceinline__ void split_pack(float v0, float v1,
                                           uint32_t& hi_out, uint32_t& lo_out) {
    __nv_bfloat16 h0 = __float2bfloat16(v0);
    __nv_bfloat16 h1 = __float2bfloat16(v1);
    __nv_bfloat16 l0 = __float2bfloat16(v0 - __bfloat162float(h0));
    __nv_bfloat16 l1 = __float2bfloat16(v1 - __bfloat162float(h1));
    hi_out = ((uint32_t)__bfloat16_as_ushort(h1) << 16) | (uint32_t)__bfloat16_as_ushort(h0);
    lo_out = ((uint32_t)__bfloat16_as_ushort(l1) << 16) | (uint32_t)__bfloat16_as_ushort(l0);
}
__device__ __forceinline__ uint32_t smem_addr_of(const void* p) {
    return (uint32_t)__cvta_generic_to_shared(p);
}
__device__ __forceinline__ void cp16(uint32_t dst, const void* src, bool pred) {
    asm volatile("cp.async.cg.shared.global [%0], [%1], 16, %2;"
                 :: "r"(dst), "l"(src), "r"(pred ? 16 : 0));
}
__device__ __forceinline__ void cp4(uint32_t dst, const void* src, bool pred) {
    asm volatile("cp.async.ca.shared.global [%0], [%1], 4, %2;"
                 :: "r"(dst), "l"(src), "r"(pred ? 4 : 0));
}
#define CP_COMMIT() asm volatile("cp.async.commit_group;" ::: "memory")
#define CP_WAIT(n)  asm volatile("cp.async.wait_group %0;" :: "n"(n) : "memory")

// ---------------- conv weight pre-split (fragment order) --------------------
__global__ __launch_bounds__(256)
void split_w_conv(const float* __restrict__ w0, const float* __restrict__ w1,
                  const float* __restrict__ w2, const float* __restrict__ w3,
                  uint32_t* __restrict__ outH, uint32_t* __restrict__ outL)
{
    const int i = blockIdx.x * 256 + threadIdx.x;
    if (i >= WSPL) return;
    const int layer = blockIdx.y;
    const float* w = (layer == 0) ? w0 : (layer == 1) ? w1 : (layer == 2) ? w2 : w3;
    const int e = i & 3;
    int j = i >> 2;
    const int slot = j & 31; j >>= 5;
    const int o4 = j & 3; j >>= 2;
    const int tap = j % 9; j /= 9;
    const int ocg = j & 3;
    const int q = j >> 2;
    const int g = ((slot >> 3) << 1) | (slot & 1);
    const int t = (slot >> 1) & 3;
    const int oc = ocg * 64 + o4 * 16 + g + (e & 1) * 8;
    const int p = t + ((e >> 1) << 2);
    const int ci0 = q * 16 + 2 * p;
    float v0 = w[(size_t)oc * 2304 + ci0 * 9 + tap];
    float v1 = w[(size_t)oc * 2304 + (ci0 + 1) * 9 + tap];
    uint32_t hi, lo;
    split_pack(v0, v1, hi, lo);
    outH[(size_t)layer * WSPL + i] = hi;
    outL[(size_t)layer * WSPL + i] = lo;
}

// ---------------- dense weight pre-split (fragment order) -------------------
__global__ __launch_bounds__(256)
void split_w_dense(const float* __restrict__ wA, const float* __restrict__ wB,
                   int strideA, int strideB,
                   uint32_t* __restrict__ outH, uint32_t* __restrict__ outL)
{
    const int i = blockIdx.x * 256 + threadIdx.x;
    if (i >= WDNS) return;
    const int which = blockIdx.y;
    const float* w = which ? wB : wA;
    const int stride = which ? strideB : strideA;
    const int e = i & 3;
    int j = i >> 2;
    const int slot = j & 31; j >>= 5;
    const int o4 = j & 3; j >>= 2;
    const int mg = j & 3;
    const int q = j >> 2;
    const int g = ((slot >> 3) << 1) | (slot & 1);
    const int t = (slot >> 1) & 3;
    const int m = mg * 64 + o4 * 16 + g + (e & 1) * 8;
    const int p = t + ((e >> 1) << 2);
    const int k0 = q * 16 + 2 * p;
    float v0 = w[(size_t)m * stride + k0];
    float v1 = w[(size_t)m * stride + k0 + 1];
    uint32_t hi, lo;
    split_pack(v0, v1, hi, lo);
    outH[(size_t)which * WDNS + i] = hi;
    outL[(size_t)which * WDNS + i] = lo;
}

// ---------------- feats pre-split -------------------------------------------
__global__ __launch_bounds__(256)
void split_feats_kernel(const float* __restrict__ f0, const float* __restrict__ f1,
                        const float* __restrict__ f2, const float* __restrict__ f3,
                        uint32_t* __restrict__ outH, uint32_t* __restrict__ outL)
{
    const int px = blockIdx.x * 256 + threadIdx.x;
    if (px >= SUMHW) return;
    const int c2 = blockIdx.y;
    const int n  = blockIdx.z;
    const int s = scale_of(px);
    const int ploc = px - cOFF[s];
    const int HW = cHW[s];
    const float* f = (s == 0) ? f0 : (s == 1) ? f1 : (s == 2) ? f2 : f3;
    const float* src = f + ((size_t)n * C + 2 * c2) * HW + ploc;
    uint32_t hi, lo;
    split_pack(src[0], src[HW], hi, lo);
    const size_t o = ((size_t)n * 128 + c2) * SUMHW + px;
    outH[o] = hi;
    outL[o] = lo;
}

// ---------------- conv3x3 dual-branch: pipelined 3-term bf16 mma ------------
#define IPAD 28
#define ST_IH 9216
#define ST_IL 11456
#define STG_U32 13696
#define CONV_SMEM (2 * STG_U32 * 4)   // 109568 B

__global__ __launch_bounds__(256, 2)
void conv3x3_dual(const uint32_t* __restrict__ in0H, const uint32_t* __restrict__ in0L,
                  const uint32_t* __restrict__ in1H, const uint32_t* __restrict__ in1L,
                  const uint32_t* __restrict__ wH0, const uint32_t* __restrict__ wL0,
                  const uint32_t* __restrict__ wH1, const uint32_t* __restrict__ wL1,
                  const float* __restrict__ bias0, const float* __restrict__ bias1,
                  float* __restrict__ dF0, uint32_t* __restrict__ dH0, uint32_t* __restrict__ dL0,
                  float* __restrict__ dF1, uint32_t* __restrict__ dH1, uint32_t* __restrict__ dL1)
{
    extern __shared__ __align__(16) uint32_t smu[];
    __shared__ float s_bias[64];

    const int branch = blockIdx.z & 1;
    const int n = blockIdx.z >> 1;
    const uint32_t* inH = branch ? in1H : in0H;
    const uint32_t* inL = branch ? in1L : in0L;
    const uint32_t* wH  = branch ? wH1 : wH0;
    const uint32_t* wL  = branch ? wL1 : wL0;
    const float* bias   = branch ? bias1 : bias0;
    float* dstF    = branch ? dF1 : dF0;
    uint32_t* dstH = branch ? dH1 : dH0;
    uint32_t* dstL = branch ? dL1 : dL0;

    const int bx = blockIdx.x;
    int s, t_;
    if (bx < 80)       { s = 0; t_ = bx; }
    else if (bx < 100) { s = 1; t_ = bx - 80; }
    else if (bx < 106) { s = 2; t_ = bx - 100; }
    else               { s = 3; t_ = bx - 106; }
    const int H = cH[s], W = cW[s];
    const int tilesX = W >> 4;
    const int ty = t_ / tilesX, tx = t_ % tilesX;
    const int h0 = ty * 8, w0 = tx * 16;
    const int ocg = blockIdx.y;
    const int ocBase = ocg * 64;

    const int tid  = threadIdx.x;
    const int warp = tid >> 5;
    const int lane = tid & 31;
    const int g = lane >> 2;
    const int t = lane & 3;
    const int slot = ((g >> 1) << 3) | (t << 1) | (g & 1);

    if (tid < 64) s_bias[tid] = bias[ocBase + tid];

    float acc[4][2][4];
#pragma unroll
    for (int i = 0; i < 4; i++)
#pragma unroll
        for (int j = 0; j < 2; j++)
#pragma unroll
            for (int k = 0; k < 4; k++) acc[i][j][k] = 0.f;

    const uint32_t smbase = smem_addr_of(smu);

    auto fill = [&](int q, int st) {
        const uint32_t sb = smbase + (uint32_t)st * STG_U32 * 4;
        const uint4* wH4 = (const uint4*)wH + (size_t)(q * 4 + ocg) * 1152;
        const uint4* wL4 = (const uint4*)wL + (size_t)(q * 4 + ocg) * 1152;
        for (int j = tid; j < 2304; j += 256) {
            const uint4* src = (j < 1152) ? (wH4 + j) : (wL4 + (j - 1152));
            cp16(sb + j * 16, src, true);
        }
        for (int j = tid; j < 960; j += 256) {
            int slotc = j % 6;
            int rest = j / 6;
            int arr = rest & 1;
            int pr = rest >> 1;
            int p = pr / 10, r = pr % 10;
            int gh = h0 + r - 1;
            bool rowok = (gh >= 0) && (gh < H);
            int ghc = min(max(gh, 0), H - 1);
            size_t rowoff = ((size_t)n * 128 + q * 8 + p) * SUMHW + cOFF[s] + (size_t)ghc * W;
            const uint32_t* gsrc = arr ? inL : inH;
            uint32_t dstrow = sb + (uint32_t)((arr ? ST_IL : ST_IH) + (p * 10 + r) * IPAD) * 4;
            if (slotc < 4) {
                int c0 = slotc * 4;
                cp16(dstrow + (uint32_t)(4 + c0) * 4, gsrc + rowoff + w0 + c0, rowok);
            } else if (slotc == 4) {
                bool ok = rowok && (w0 > 0);
                cp4(dstrow + 3 * 4, gsrc + rowoff + (ok ? (w0 - 1) : w0), ok);
            } else {
                bool ok = rowok && (w0 + 16 < W);
                cp4(dstrow + 20 * 4, gsrc + rowoff + w0 + (ok ? 16 : 0), ok);
            }
        }
    };

    fill(0, 0);
    CP_COMMIT();

    for (int q = 0; q < 16; q++) {
        if (q < 15) { fill(q + 1, (q + 1) & 1); CP_COMMIT(); CP_WAIT(1); }
        else        { CP_WAIT(0); }
        __syncthreads();

        const uint32_t* sb = smu + (q & 1) * STG_U32;
        const uint4* s_w4H = (const uint4*)sb;
        const uint4* s_w4L = s_w4H + 1152;
        const uint32_t* s_iH = sb + ST_IH;
        const uint32_t* s_iL = sb + ST_IL;

#pragma unroll
        for (int kh = 0; kh < 3; kh++)
#pragma unroll
        for (int kw = 0; kw < 3; kw++) {
            const int tap = kh * 3 + kw;
            uint32_t bh[2][2], bl[2][2];
            const int ib0 = (t * 10 + warp + kh) * IPAD + kw + 3 + g;
            const int ib1 = ((t + 4) * 10 + warp + kh) * IPAD + kw + 3 + g;
#pragma unroll
            for (int p4 = 0; p4 < 2; p4++) {
                bh[p4][0] = s_iH[ib0 + p4 * 8];
                bh[p4][1] = s_iH[ib1 + p4 * 8];
                bl[p4][0] = s_iL[ib0 + p4 * 8];
                bl[p4][1] = s_iL[ib1 + p4 * 8];
            }
#pragma unroll
            for (int o4 = 0; o4 < 4; o4++) {
                uint4 a4 = s_w4H[(tap * 4 + o4) * 32 + slot];
                uint4 b4 = s_w4L[(tap * 4 + o4) * 32 + slot];
                uint32_t ah[4] = {a4.x, a4.y, a4.z, a4.w};
                uint32_t al[4] = {b4.x, b4.y, b4.z, b4.w};
#pragma unroll
                for (int p4 = 0; p4 < 2; p4++) {
                    mma_bf16(acc[o4][p4], ah, bh[p4]);
                    mma_bf16(acc[o4][p4], ah, bl[p4]);
                    mma_bf16(acc[o4][p4], al, bh[p4]);
                }
            }
        }
        __syncthreads();
    }

    // epilogue (validated mapping)
    const int ghout = h0 + warp;
    if (dstF && ghout < H) {
        float* dbase = dstF + (size_t)n * C * SUMHW + cOFF[s] + (size_t)ghout * W + w0;
#pragma unroll
        for (int o4 = 0; o4 < 4; o4++) {
            int ocl = o4 * 16 + g;
            float b0v = s_bias[ocl];
            float b1v = s_bias[ocl + 8];
#pragma unroll
            for (int p4 = 0; p4 < 2; p4++) {
                int col = p4 * 8 + 2 * t;
                float2 v0 = make_float2(fmaxf(acc[o4][p4][0] + b0v, 0.f),
                                        fmaxf(acc[o4][p4][1] + b0v, 0.f));
                float2 v1 = make_float2(fmaxf(acc[o4][p4][2] + b1v, 0.f),
                                        fmaxf(acc[o4][p4][3] + b1v, 0.f));
                *(float2*)(dbase + (size_t)(ocBase + ocl) * SUMHW + col) = v0;
                *(float2*)(dbase + (size_t)(ocBase + ocl + 8) * SUMHW + col) = v1;
            }
        }
    }
    if (dstH) {
        const size_t base = ((size_t)n * 128) * SUMHW + cOFF[s] + (size_t)ghout * W + w0;
#pragma unroll
        for (int o4 = 0; o4 < 4; o4++) {
            int ocl = o4 * 16 + g;
            float b0v = s_bias[ocl];
            float b1v = s_bias[ocl + 8];
            const size_t w2a = (size_t)((ocBase + ocl) >> 1) * SUMHW;
            const size_t w2b = (size_t)(((ocBase + ocl) >> 1) + 4) * SUMHW;
#pragma unroll
            for (int p4 = 0; p4 < 2; p4++) {
                int col = p4 * 8 + 2 * t;
                float v0 = fmaxf(acc[o4][p4][0] + b0v, 0.f);
                float v1 = fmaxf(acc[o4][p4][1] + b0v, 0.f);
                float v2 = fmaxf(acc[o4][p4][2] + b1v, 0.f);
                float v3 = fmaxf(acc[o4][p4][3] + b1v, 0.f);
                float p0 = __shfl_xor_sync(0xFFFFFFFFu, v0, 4);
                float p1 = __shfl_xor_sync(0xFFFFFFFFu, v1, 4);
                float p2 = __shfl_xor_sync(0xFFFFFFFFu, v2, 4);
                float p3 = __shfl_xor_sync(0xFFFFFFFFu, v3, 4);
                if (((g & 1) == 0) && ghout < H) {
                    uint32_t hw, lw;
                    split_pack(v0, p0, hw, lw);
                    dstH[base + w2a + col] = hw;  dstL[base + w2a + col] = lw;
                    split_pack(v1, p1, hw, lw);
                    dstH[base + w2a + col + 1] = hw;  dstL[base + w2a + col + 1] = lw;
                    split_pack(v2, p2, hw, lw);
                    dstH[base + w2b + col] = hw;  dstL[base + w2b + col] = lw;
                    split_pack(v3, p3, hw, lw);
                    dstH[base + w2b + col + 1] = hw;  dstL[base + w2b + col + 1] = lw;
                }
            }
        }
    }
}

// ---------------- dense GEMM core macro pieces ------------------------------
#define GIPAD 264
#define GST_U32 5248

// rn2 GEMM: out[n][m][s] = relu(W hs + bias)
__global__ __launch_bounds__(256, 2)
void gemm_mma(const uint32_t* __restrict__ wH, const uint32_t* __restrict__ wL,
              const uint32_t* __restrict__ bHg, const uint32_t* __restrict__ bLg,
              const float* __restrict__ bias, float* __restrict__ outp)
{
    __shared__ __align__(16) uint32_t gsm[2 * GST_U32];

    const int s0 = blockIdx.x * 256;
    const int mg = blockIdx.y;
    const int n  = blockIdx.z;
    const int tid = threadIdx.x;
    const int warp = tid >> 5;
    const int lane = tid & 31;
    const int g = lane >> 2;
    const int t = lane & 3;
    const int slot = ((g >> 1) << 3) | (t << 1) | (g & 1);

    float acc[4][4][4];
#pragma unroll
    for (int i = 0; i < 4; i++)
#pragma unroll
        for (int j = 0; j < 4; j++)
#pragma unroll
            for (int k = 0; k < 4; k++) acc[i][j][k] = 0.f;

    const uint32_t smbase = smem_addr_of(gsm);

    auto fill = [&](int q, int st) {
        const uint32_t sb = smbase + (uint32_t)st * GST_U32 * 4;
        const uint4* wH4 = (const uint4*)wH + (size_t)(q * 4 + mg) * 128;
        const uint4* wL4 = (const uint4*)wL + (size_t)(q * 4 + mg) * 128;
        if (tid < 256) {
            const uint4* src = (tid < 128) ? (wH4 + tid) : (wL4 + (tid - 128));
            cp16(sb + tid * 16, src, true);
        }
        for (int j = tid; j < 1024; j += 256) {
            int c = j & 63;
            int rest = j >> 6;
            int arr = rest & 1;
            int p = rest >> 1;
            int sx = s0 + c * 4;
            bool ok = sx < SUMHW;
            size_t off = ((size_t)n * 128 + q * 8 + p) * SUMHW + (ok ? sx : 0);
            const uint32_t* gsrc = arr ? bLg : bHg;
            uint32_t dst = sb + (uint32_t)(1024 + arr * 2112 + p * GIPAD + c * 4) * 4;
            cp16(dst, gsrc + off, ok);
        }
    };

    fill(0, 0);
    CP_COMMIT();

    for (int q = 0; q < 16; q++) {
        if (q < 15) { fill(q + 1, (q + 1) & 1); CP_COMMIT(); CP_WAIT(1); }
        else        { CP_WAIT(0); }
        __syncthreads();

        const uint32_t* sb = gsm + (q & 1) * GST_U32;
        const uint4* s_aH4 = (const uint4*)sb;
        const uint4* s_aL4 = s_aH4 + 128;
        const uint32_t* s_iH = sb + 1024;
        const uint32_t* s_iL = sb + 3136;

        uint32_t bh[4][2], bl[4][2];
        const int ib0 = t * GIPAD + warp * 32 + g;
        const int ib1 = (t + 4) * GIPAD + warp * 32 + g;
#pragma unroll
        for (int p4 = 0; p4 < 4; p4++) {
            bh[p4][0] = s_iH[ib0 + p4 * 8];
            bh[p4][1] = s_iH[ib1 + p4 * 8];
            bl[p4][0] = s_iL[ib0 + p4 * 8];
            bl[p4][1] = s_iL[ib1 + p4 * 8];
        }
#pragma unroll
        for (int o4 = 0; o4 < 4; o4++) {
            uint4 a4 = s_aH4[o4 * 32 + slot];
            uint4 b4 = s_aL4[o4 * 32 + slot];
            uint32_t ah[4] = {a4.x, a4.y, a4.z, a4.w};
            uint32_t al[4] = {b4.x, b4.y, b4.z, b4.w};
#pragma unroll
            for (int p4 = 0; p4 < 4; p4++) {
                mma_bf16(acc[o4][p4], ah, bh[p4]);
                mma_bf16(acc[o4][p4], ah, bl[p4]);
                mma_bf16(acc[o4][p4], al, bh[p4]);
            }
        }
        __syncthreads();
    }

#pragma unroll
    for (int o4 = 0; o4 < 4; o4++) {
        int m0 = mg * 64 + o4 * 16 + g;
        float b0v = bias[m0];
        float b1v = bias[m0 + 8];
#pragma unroll
        for (int p4 = 0; p4 < 4; p4++) {
            int sx = s0 + warp * 32 + p4 * 8 + 2 * t;
            if (sx < SUMHW) {
                float v0 = fmaxf(acc[o4][p4][0] + b0v, 0.f);
                float v1 = fmaxf(acc[o4][p4][1] + b0v, 0.f);
                float v2 = fmaxf(acc[o4][p4][2] + b1v, 0.f);
                float v3 = fmaxf(acc[o4][p4][3] + b1v, 0.f);
                *(float2*)(outp + ((size_t)n * 256 + m0) * SUMHW + sx) = make_float2(v0, v1);
                *(float2*)(outp + ((size_t)n * 256 + m0 + 8) * SUMHW + sx) = make_float2(v2, v3);
            }
        }
    }
}

// o_proj GEMM fused with hsum: writes split hs directly (no o1 roundtrip)
__global__ __launch_bounds__(256, 2)
void gemm_oproj_hsum(const uint32_t* __restrict__ wH, const uint32_t* __restrict__ wL,
                     const uint32_t* __restrict__ bHg, const uint32_t* __restrict__ bLg,
                     const float* __restrict__ pproj,
                     uint32_t* __restrict__ hsH, uint32_t* __restrict__ hsL)
{
    __shared__ __align__(16) uint32_t gsm[2 * GST_U32];
    __shared__ float spp[KTOP * 64];

    const int s0 = blockIdx.x * 256;
    const int mg = blockIdx.y;
    const int n  = blockIdx.z;
    const int tid = threadIdx.x;
    const int warp = tid >> 5;
    const int lane = tid & 31;
    const int g = lane >> 2;
    const int t = lane & 3;
    const int slot = ((g >> 1) << 3) | (t << 1) | (g & 1);

    // load pproj slice for this mg: spp[k*64 + dl], d = mg*64 + dl
    for (int i = tid; i < KTOP * 64; i += 256) {
        int k = i >> 6, dl = i & 63;
        spp[i] = pproj[((size_t)n * KTOP + k) * D + mg * 64 + dl];
    }

    float acc[4][4][4];
#pragma unroll
    for (int i = 0; i < 4; i++)
#pragma unroll
        for (int j = 0; j < 4; j++)
#pragma unroll
            for (int k = 0; k < 4; k++) acc[i][j][k] = 0.f;

    const uint32_t smbase = smem_addr_of(gsm);

    auto fill = [&](int q, int st) {
        const uint32_t sb = smbase + (uint32_t)st * GST_U32 * 4;
        const uint4* wH4 = (const uint4*)wH + (size_t)(q * 4 + mg) * 128;
        const uint4* wL4 = (const uint4*)wL + (size_t)(q * 4 + mg) * 128;
        if (tid < 256) {
            const uint4* src = (tid < 128) ? (wH4 + tid) : (wL4 + (tid - 128));
            cp16(sb + tid * 16, src, true);
        }
        for (int j = tid; j < 1024; j += 256) {
            int c = j & 63;
            int rest = j >> 6;
            int arr = rest & 1;
            int p = rest >> 1;
            int sx = s0 + c * 4;
            bool ok = sx < SUMHW;
            size_t off = ((size_t)n * 128 + q * 8 + p) * SUMHW + (ok ? sx : 0);
            const uint32_t* gsrc = arr ? bLg : bHg;
            uint32_t dst = sb + (uint32_t)(1024 + arr * 2112 + p * GIPAD + c * 4) * 4;
            cp16(dst, gsrc + off, ok);
        }
    };

    fill(0, 0);
    CP_COMMIT();

    for (int q = 0; q < 16; q++) {
        if (q < 15) { fill(q + 1, (q + 1) & 1); CP_COMMIT(); CP_WAIT(1); }
        else        { CP_WAIT(0); }
        __syncthreads();

        const uint32_t* sb = gsm + (q & 1) * GST_U32;
        const uint4* s_aH4 = (const uint4*)sb;
        const uint4* s_aL4 = s_aH4 + 128;
        const uint32_t* s_iH = sb + 1024;
        const uint32_t* s_iL = sb + 3136;

        uint32_t bh[4][2], bl[4][2];
        const int ib0 = t * GIPAD + warp * 32 + g;
        const int ib1 = (t + 4) * GIPAD + warp * 32 + g;
#pragma unroll
        for (int p4 = 0; p4 < 4; p4++) {
            bh[p4][0] = s_iH[ib0 + p4 * 8];
            bh[p4][1] = s_iH[ib1 + p4 * 8];
            bl[p4][0] = s_iL[ib0 + p4 * 8];
            bl[p4][1] = s_iL[ib1 + p4 * 8];
        }
#pragma unroll
        for (int o4 = 0; o4 < 4; o4++) {
            uint4 a4 = s_aH4[o4 * 32 + slot];
            uint4 b4 = s_aL4[o4 * 32 + slot];
            uint32_t ah[4] = {a4.x, a4.y, a4.z, a4.w};
            uint32_t al[4] = {b4.x, b4.y, b4.z, b4.w};
#pragma unroll
            for (int p4 = 0; p4 < 4; p4++) {
                mma_bf16(acc[o4][p4], ah, bh[p4]);
                mma_bf16(acc[o4][p4], ah, bl[p4]);
                mma_bf16(acc[o4][p4], al, bh[p4]);
            }
        }
        __syncthreads();
    }

    // fused epilogue: o -> hsum over KTOP -> split-pack (shfl pairing, like conv)
#pragma unroll
    for (int o4 = 0; o4 < 4; o4++) {
        const int m0l = o4 * 16 + g;          // local d for c0/c1
        const int m0  = mg * 64 + m0l;
        float pp0[KTOP], pp1[KTOP];
#pragma unroll
        for (int k = 0; k < KTOP; k++) {
            pp0[k] = spp[k * 64 + m0l];
            pp1[k] = spp[k * 64 + m0l + 8];
        }
        const size_t w2a = (size_t)(m0 >> 1) * SUMHW;
        const size_t w2b = (size_t)((m0 >> 1) + 4) * SUMHW;
        const size_t nb = (size_t)n * 128 * SUMHW;
#pragma unroll
        for (int p4 = 0; p4 < 4; p4++) {
            int sx = s0 + warp * 32 + p4 * 8 + 2 * t;
            float a0 = 0.f, a1 = 0.f, a2 = 0.f, a3 = 0.f;
#pragma unroll 4
            for (int k = 0; k < KTOP; k++) {
                a0 += fmaxf(acc[o4][p4][0] + pp0[k], 0.f);
                a1 += fmaxf(acc[o4][p4][1] + pp0[k], 0.f);
                a2 += fmaxf(acc[o4][p4][2] + pp1[k], 0.f);
                a3 += fmaxf(acc[o4][p4][3] + pp1[k], 0.f);
            }
            float q0 = __shfl_xor_sync(0xFFFFFFFFu, a0, 4);
            float q1 = __shfl_xor_sync(0xFFFFFFFFu, a1, 4);
            float q2 = __shfl_xor_sync(0xFFFFFFFFu, a2, 4);
            float q3 = __shfl_xor_sync(0xFFFFFFFFu, a3, 4);
            if (((g & 1) == 0) && sx < SUMHW) {
                uint32_t hw, lw;
                split_pack(a0, q0, hw, lw);
                hsH[nb + w2a + sx] = hw;      hsL[nb + w2a + sx] = lw;
                split_pack(a1, q1, hw, lw);
                hsH[nb + w2a + sx + 1] = hw;  hsL[nb + w2a + sx + 1] = lw;
                split_pack(a2, q2, hw, lw);
                hsH[nb + w2b + sx] = hw;      hsL[nb + w2b + sx] = lw;
                split_pack(a3, q3, hw, lw);
                hsH[nb + w2b + sx + 1] = hw;  hsL[nb + w2b + sx + 1] = lw;
            }
        }
    }
}

// ---------------- merged heads (person + object delta) ----------------------
__global__ __launch_bounds__(256)
void heads_all(const float* __restrict__ t2p, const float* __restrict__ t2o,
               const float* __restrict__ pl_w, const float* __restrict__ pl_b,
               const float* __restrict__ pd_w, const float* __restrict__ pd_b,
               const float* __restrict__ od_w, const float* __restrict__ od_b,
               float* __restrict__ out, float* __restrict__ cell)
{
    const int branch = blockIdx.y & 1;
    const int n = blockIdx.y >> 1;
    const int tid = threadIdx.x;
    __shared__ float swl[A * C];
    __shared__ float swd[BOXC * C];
    if (branch == 0) {
        for (int i = tid; i < A * C; i += 256) swl[i] = pl_w[i];
        for (int i = tid; i < BOXC * C; i += 256) swd[i] = pd_w[i];
    } else {
        for (int i = tid; i < BOXC * C; i += 256) swd[i] = od_w[i];
    }
    __syncthreads();

    const int p = blockIdx.x * 256 + tid;
    if (p >= SUMHW) return;
    const int s = scale_of(p);
    const int ploc = p - cOFF[s];
    const int HW = cHW[s];

    if (branch == 0) {
        const float* h = t2p + (size_t)n * C * SUMHW + p;
        float accl[A], accd[BOXC];
#pragma unroll
        for (int a = 0; a < A; a++) accl[a] = pl_b[a];
#pragma unroll
        for (int j = 0; j < BOXC; j++) accd[j] = pd_b[j];
        for (int c = 0; c < C; c++) {
            float v = h[(size_t)c * SUMHW];
#pragma unroll
            for (int a = 0; a < A; a++) accl[a] += swl[a * C + c] * v;
#pragma unroll
            for (int j = 0; j < BOXC; j++) accd[j] += swd[j * C + c] * v;
        }
        float m = accl[0];
#pragma unroll
        for (int a = 0; a < A; a++) {
            out[cPLOG[s] + ((size_t)n * A + a) * HW + ploc] = accl[a];
            m = fmaxf(m, accl[a]);
        }
#pragma unroll
        for (int j = 0; j < BOXC; j++)
            out[cPDEL[s] + ((size_t)n * BOXC + j) * HW + ploc] = accd[j];
        cell[(size_t)n * SUMHW + p] = m;
    } else {
        const float* h = t2o + (size_t)n * C * SUMHW + p;
        float accd[BOXC];
#pragma unroll
        for (int j = 0; j < BOXC; j++) accd[j] = od_b[j];
        for (int c = 0; c < C; c++) {
            float v = h[(size_t)c * SUMHW];
#pragma unroll
            for (int j = 0; j < BOXC; j++) accd[j] += swd[j * C + c] * v;
        }
#pragma unroll
        for (int j = 0; j < BOXC; j++)
            out[cODEL[s] + ((size_t)n * BOXC + j) * HW + ploc] = accd[j];
    }
}

// ---------------- per-scale top-K (smem-cached) -----------------------------
__global__ __launch_bounds__(256)
void topk_flat(const float* __restrict__ cell, const float* __restrict__ hid,
               float* __restrict__ cand_hid, float* __restrict__ cand_sc)
{
    const int s = blockIdx.x;
    const int n = blockIdx.y;
    const int HW = cHW[s], off = cOFF[s];
    __shared__ float sc[10240];
    __shared__ float s_val[256];
    __shared__ int   s_idx[256];
    __shared__ int   sel[KTOP];
    const int tid = threadIdx.x;

    for (int i = tid; i < HW; i += 256)
        sc[i] = cell[(size_t)n * SUMHW + off + i];
    __syncthreads();

    for (int k = 0; k < KTOP; k++) {
        float best = -CUDART_INF_F;
        int bi = HW;
        for (int i = tid; i < HW; i += 256) {
            float v = sc[i];
            if (v > best) { best = v; bi = i; }
        }
        s_val[tid] = best; s_idx[tid] = bi;
        __syncthreads();
        for (int offr = 128; offr > 0; offr >>= 1) {
            if (tid < offr) {
                float v2 = s_val[tid + offr]; int i2 = s_idx[tid + offr];
                if (v2 > s_val[tid] || (v2 == s_val[tid] && i2 < s_idx[tid])) {
                    s_val[tid] = v2; s_idx[tid] = i2;
                }
            }
            __syncthreads();
        }
        if (tid == 0) {
            sel[k] = s_idx[0];
            cand_sc[(size_t)n * 80 + s * KTOP + k] = s_val[0];
            sc[s_idx[0]] = -CUDART_INF_F;
        }
        __syncthreads();
    }
    for (int idx = tid; idx < C * KTOP; idx += 256) {
        int c = idx / KTOP, k = idx % KTOP;
        cand_hid[((size_t)n * C + c) * 80 + s * KTOP + k] =
            hid[((size_t)n * C + c) * SUMHW + off + sel[k]];
    }
}

// ---------------- global top-K over 80 --------------------------------------
__global__ void topk_global_kernel(const float* __restrict__ sc, int* __restrict__ keep)
{
    const int n = blockIdx.x;
    bool used[80];
    for (int i = 0; i < 80; i++) used[i] = false;
    const float* s = sc + (size_t)n * 80;
    for (int k = 0; k < KTOP; k++) {
        float best = -CUDART_INF_F; int bi = 0;
        for (int i = 0; i < 80; i++)
            if (!used[i] && s[i] > best) { best = s[i]; bi = i; }
        used[bi] = true;
        keep[n * KTOP + k] = bi;
    }
}

// ---------------- p_proj ----------------------------------------------------
__global__ __launch_bounds__(256)
void pproj_kernel(const float* __restrict__ cand_hid, const int* __restrict__ keep,
                  const float* __restrict__ rn1_w, const float* __restrict__ rn1_b,
                  float* __restrict__ pproj)
{
    const int k = blockIdx.x, n = blockIdx.y, d = threadIdx.x;
    __shared__ float sh[C];
    const int col = keep[n * KTOP + k];
    sh[d] = cand_hid[((size_t)n * C + d) * 80 + col];
    __syncthreads();
    float acc = rn1_b[d];
    const float* wrow = rn1_w + (size_t)d * (2 * C) + C;   // Wp
    for (int c = 0; c < C; c++) acc += sh[c] * wrow[c];
    pproj[((size_t)n * KTOP + k) * D + d] = acc;
}

// ---------------- ol head (transposed h2 [n][e][s]) -------------------------
__global__ __launch_bounds__(256)
void ol_t(const float* __restrict__ h2, const float* __restrict__ ol_w,
          const float* __restrict__ ol_b, float* __restrict__ out)
{
    __shared__ float sw[A * 256];
    const int n = blockIdx.y;
    const int tid = threadIdx.x;
    for (int i = tid; i < A * 256; i += 256) sw[i] = ol_w[i];
    __syncthreads();
    const int s = blockIdx.x * 256 + tid;
    if (s >= SUMHW) return;
    float a0 = 0.f, a1 = 0.f, a2 = 0.f;
    for (int e = 0; e < 256; e++) {
        float v = h2[((size_t)n * 256 + e) * SUMHW + s];
        a0 += v * sw[e];
        a1 += v * sw[256 + e];
        a2 += v * sw[512 + e];
    }
    const int sc = scale_of(s);
    const int ploc = s - cOFF[sc];
    const int HW = cHW[sc];
    out[cOLOG[sc] + ((size_t)n * A + 0) * HW + ploc] = a0 + ol_b[0];
    out[cOLOG[sc] + ((size_t)n * A + 1) * HW + ploc] = a1 + ol_b[1];
    out[cOLOG[sc] + ((size_t)n * A + 2) * HW + ploc] = a2 + ol_b[2];
}

// ---------------------------- host orchestration ----------------------------
extern "C" void kernel_launch(void* const* d_in, const int* in_sizes, int n_in,
                              void* d_out, int out_size)
{
    const float* f0 = (const float*)d_in[0];
    const float* f1 = (const float*)d_in[1];
    const float* f2 = (const float*)d_in[2];
    const float* f3 = (const float*)d_in[3];
    const float* pc1_w = (const float*)d_in[4];
    const float* pc1_b = (const float*)d_in[5];
    const float* pc2_w = (const float*)d_in[6];
    const float* pc2_b = (const float*)d_in[7];
    const float* oc1_w = (const float*)d_in[8];
    const float* oc1_b = (const float*)d_in[9];
    const float* oc2_w = (const float*)d_in[10];
    const float* oc2_b = (const float*)d_in[11];
    const float* rn1_w = (const float*)d_in[12];
    const float* rn1_b = (const float*)d_in[13];
    const float* rn2_w = (const float*)d_in[14];
    const float* rn2_b = (const float*)d_in[15];
    const float* pl_w  = (const float*)d_in[16];
    const float* pl_b  = (const float*)d_in[17];
    const float* pd_w  = (const float*)d_in[18];
    const float* pd_b  = (const float*)d_in[19];
    const float* ol_w  = (const float*)d_in[20];
    const float* ol_b  = (const float*)d_in[21];
    const float* od_w  = (const float*)d_in[22];
    const float* od_b  = (const float*)d_in[23];
    float* out = (float*)d_out;

    float *t2p, *t2o, *h2, *cell, *cand_hid, *cand_sc, *pproj;
    int* keep;
    uint32_t *sAh, *sAl, *sBh, *sBl, *sDh, *sDl, *sCh, *sCl, *hsh, *hsl, *wsh, *wsl, *wdh, *wdl;
    cudaGetSymbolAddress((void**)&t2p, g_t2p);
    cudaGetSymbolAddress((void**)&t2o, g_t2o);
    cudaGetSymbolAddress((void**)&h2, g_h2);
    cudaGetSymbolAddress((void**)&cell, g_cell);
    cudaGetSymbolAddress((void**)&cand_hid, g_cand_hid);
    cudaGetSymbolAddress((void**)&cand_sc, g_cand_sc);
    cudaGetSymbolAddress((void**)&keep, g_keep);
    cudaGetSymbolAddress((void**)&pproj, g_pproj);
    cudaGetSymbolAddress((void**)&sAh, g_sA_hi);
    cudaGetSymbolAddress((void**)&sAl, g_sA_lo);
    cudaGetSymbolAddress((void**)&sBh, g_sB_hi);
    cudaGetSymbolAddress((void**)&sBl, g_sB_lo);
    cudaGetSymbolAddress((void**)&sDh, g_sD_hi);
    cudaGetSymbolAddress((void**)&sDl, g_sD_lo);
    cudaGetSymbolAddress((void**)&sCh, g_sC_hi);
    cudaGetSymbolAddress((void**)&sCl, g_sC_lo);
    cudaGetSymbolAddress((void**)&hsh, g_hs_hi);
    cudaGetSymbolAddress((void**)&hsl, g_hs_lo);
    cudaGetSymbolAddress((void**)&wsh, g_wsp_hi);
    cudaGetSymbolAddress((void**)&wsl, g_wsp_lo);
    cudaGetSymbolAddress((void**)&wdh, g_wd_hi);
    cudaGetSymbolAddress((void**)&wdl, g_wd_lo);

    cudaFuncSetAttribute(conv3x3_dual,
                         cudaFuncAttributeMaxDynamicSharedMemorySize, CONV_SMEM);

    const dim3 convGrid(108, 4, NB * 2);
    const dim3 headGrid((SUMHW + 255) / 256, NB * 2);
    const dim3 gemmGrid(STILE, 4, NB);

    // ---- prep: split weights + feats ----
    split_w_conv<<<dim3((WSPL + 255) / 256, 4), 256>>>(pc1_w, pc2_w, oc1_w, oc2_w, wsh, wsl);
    split_w_dense<<<dim3((WDNS + 255) / 256, 2), 256>>>(rn1_w, rn2_w, 2 * C, D, wdh, wdl);
    split_feats_kernel<<<dim3((SUMHW + 255) / 256, 128, NB), 256>>>(f0, f1, f2, f3, sAh, sAl);

    // ---- layer 1 (both branches) ----
    conv3x3_dual<<<convGrid, 256, CONV_SMEM>>>(
        sAh, sAl, sAh, sAl,
        wsh, wsl, wsh + 2 * WSPL, wsl + 2 * WSPL,
        pc1_b, oc1_b,
        nullptr, sBh, sBl,
        nullptr, sDh, sDl);
    // ---- layer 2 (both branches) ----
    conv3x3_dual<<<convGrid, 256, CONV_SMEM>>>(
        sBh, sBl, sDh, sDl,
        wsh + WSPL, wsl + WSPL, wsh + 3 * WSPL, wsl + 3 * WSPL,
        pc2_b, oc2_b,
        t2p, nullptr, nullptr,
        t2o, sCh, sCl);

    // ---- heads (both branches) ----
    heads_all<<<headGrid, 256>>>(t2p, t2o, pl_w, pl_b, pd_w, pd_b, od_w, od_b, out, cell);

    // ---- person relational path ----
    topk_flat<<<dim3(4, NB), 256>>>(cell, t2p, cand_hid, cand_sc);
    topk_global_kernel<<<NB, 1>>>(cand_sc, keep);
    pproj_kernel<<<dim3(KTOP, NB), 256>>>(cand_hid, keep, rn1_w, rn1_b, pproj);

    // ---- object relational path ----
    gemm_oproj_hsum<<<gemmGrid, 256>>>(wdh, wdl, sCh, sCl, pproj, hsh, hsl);
    gemm_mma<<<gemmGrid, 256>>>(wdh + WDNS, wdl + WDNS, hsh, hsl, rn2_b, h2);
    ol_t<<<dim3(STILE, NB), 256>>>(h2, ol_w, ol_b, out);

    (void)in_sizes; (void)n_in; (void)out_size;
}

// round 12
// speedup vs baseline: 7.3190x; 1.0120x over previous
#include <cuda_runtime.h>
#include <cuda_bf16.h>
#include <math_constants.h>
#include <stdint.h>

// Problem constants
#define NB   2
#define C    256
#define A    3
#define KTOP 20
#define D    256
#define BOXC 12
#define SUMHW 13600   // 10240 + 2560 + 640 + 160
#define WSPL 294912   // per-layer conv split-weight u32 count
#define WDNS 32768    // dense 256x256 split-weight u32 count
#define STILE 54      // ceil(SUMHW/256)

// ---------------- scratch (device globals) ----------------------------------
__device__ float g_t2p[NB * C * SUMHW];
__device__ float g_t2o[NB * C * SUMHW];
__device__ float g_h2[NB * 256 * SUMHW];   // rn2 out [n][e][s]
__device__ float g_cell[NB * SUMHW];
__device__ float g_cand_hid[NB * C * 80];
__device__ float g_cand_sc[NB * 80];
__device__ int   g_keep[NB * KTOP];
__device__ float g_pproj[NB * KTOP * D];
// split activations: [n][pair=128][SUMHW] u32 (even ci low half, odd high)
__device__ uint32_t g_sA_hi[NB * 128 * SUMHW];
__device__ uint32_t g_sA_lo[NB * 128 * SUMHW];
__device__ uint32_t g_sB_hi[NB * 128 * SUMHW];   // person conv1 out
__device__ uint32_t g_sB_lo[NB * 128 * SUMHW];
__device__ uint32_t g_sD_hi[NB * 128 * SUMHW];   // object conv1 out
__device__ uint32_t g_sD_lo[NB * 128 * SUMHW];
__device__ uint32_t g_sC_hi[NB * 128 * SUMHW];   // object conv2 split out
__device__ uint32_t g_sC_lo[NB * 128 * SUMHW];
__device__ uint32_t g_hs_hi[NB * 128 * SUMHW];
__device__ uint32_t g_hs_lo[NB * 128 * SUMHW];
// split weights (fragment order)
__device__ uint32_t g_wsp_hi[4 * WSPL];
__device__ uint32_t g_wsp_lo[4 * WSPL];
__device__ uint32_t g_wd_hi[2 * WDNS];     // 0: Wo, 1: rn2
__device__ uint32_t g_wd_lo[2 * WDNS];

// per-scale constants
__device__ __constant__ int cOFF[4]  = {0, 10240, 12800, 13440};
__device__ __constant__ int cHW[4]   = {10240, 2560, 640, 160};
__device__ __constant__ int cH[4]    = {80, 40, 20, 10};
__device__ __constant__ int cW[4]    = {128, 64, 32, 16};
__device__ __constant__ int cPLOG[4] = {0,      61440,  76800,  80640};
__device__ __constant__ int cPDEL[4] = {81600,  327360, 388800, 404160};
__device__ __constant__ int cOLOG[4] = {408000, 469440, 484800, 488640};
__device__ __constant__ int cODEL[4] = {489600, 735360, 796800, 812160};

__device__ __forceinline__ int scale_of(int p) {
    return (p < 10240) ? 0 : (p < 12800) ? 1 : (p < 13440) ? 2 : 3;
}

// ---------------- bf16 / async helpers --------------------------------------
__device__ __forceinline__ void mma_bf16(float* c, const uint32_t* a, const uint32_t* b) {
    asm volatile(
        "mma.sync.aligned.m16n8k16.row.col.f32.bf16.bf16.f32 "
        "{%0,%1,%2,%3}, {%4,%5,%6,%7}, {%8,%9}, {%0,%1,%2,%3};\n"
        : "+f"(c[0]), "+f"(c[1]), "+f"(c[2]), "+f"(c[3])
        : "r"(a[0]), "r"(a[1]), "r"(a[2]), "r"(a[3]), "r"(b[0]), "r"(b[1]));
}
__device__ __forceinline__ void split_pack(float v0, float v1,
                                           uint32_t& hi_out, uint32_t& lo_out) {
    __nv_bfloat16 h0 = __float2bfloat16(v0);
    __nv_bfloat16 h1 = __float2bfloat16(v1);
    __nv_bfloat16 l0 = __float2bfloat16(v0 - __bfloat162float(h0));
    __nv_bfloat16 l1 = __float2bfloat16(v1 - __bfloat162float(h1));
    hi_out = ((uint32_t)__bfloat16_as_ushort(h1) << 16) | (uint32_t)__bfloat16_as_ushort(h0);
    lo_out = ((uint32_t)__bfloat16_as_ushort(l1) << 16) | (uint32_t)__bfloat16_as_ushort(l0);
}
__device__ __forceinline__ uint32_t smem_addr_of(const void* p) {
    return (uint32_t)__cvta_generic_to_shared(p);
}
__device__ __forceinline__ void cp16(uint32_t dst, const void* src, bool pred) {
    asm volatile("cp.async.cg.shared.global [%0], [%1], 16, %2;"
                 :: "r"(dst), "l"(src), "r"(pred ? 16 : 0));
}
__device__ __forceinline__ void cp4(uint32_t dst, const void* src, bool pred) {
    asm volatile("cp.async.ca.shared.global [%0], [%1], 4, %2;"
                 :: "r"(dst), "l"(src), "r"(pred ? 4 : 0));
}
#define CP_COMMIT() asm volatile("cp.async.commit_group;" ::: "memory")
#define CP_WAIT(n)  asm volatile("cp.async.wait_group %0;" :: "n"(n) : "memory")

// ---------------- conv weight pre-split (fragment order) --------------------
__global__ __launch_bounds__(256)
void split_w_conv(const float* __restrict__ w0, const float* __restrict__ w1,
                  const float* __restrict__ w2, const float* __restrict__ w3,
                  uint32_t* __restrict__ outH, uint32_t* __restrict__ outL)
{
    const int i = blockIdx.x * 256 + threadIdx.x;
    if (i >= WSPL) return;
    const int layer = blockIdx.y;
    const float* w = (layer == 0) ? w0 : (layer == 1) ? w1 : (layer == 2) ? w2 : w3;
    const int e = i & 3;
    int j = i >> 2;
    const int slot = j & 31; j >>= 5;
    const int o4 = j & 3; j >>= 2;
    const int tap = j % 9; j /= 9;
    const int ocg = j & 3;
    const int q = j >> 2;
    const int g = ((slot >> 3) << 1) | (slot & 1);
    const int t = (slot >> 1) & 3;
    const int oc = ocg * 64 + o4 * 16 + g + (e & 1) * 8;
    const int p = t + ((e >> 1) << 2);
    const int ci0 = q * 16 + 2 * p;
    float v0 = w[(size_t)oc * 2304 + ci0 * 9 + tap];
    float v1 = w[(size_t)oc * 2304 + (ci0 + 1) * 9 + tap];
    uint32_t hi, lo;
    split_pack(v0, v1, hi, lo);
    outH[(size_t)layer * WSPL + i] = hi;
    outL[(size_t)layer * WSPL + i] = lo;
}

// ---------------- dense weight pre-split (fragment order) -------------------
__global__ __launch_bounds__(256)
void split_w_dense(const float* __restrict__ wA, const float* __restrict__ wB,
                   int strideA, int strideB,
                   uint32_t* __restrict__ outH, uint32_t* __restrict__ outL)
{
    const int i = blockIdx.x * 256 + threadIdx.x;
    if (i >= WDNS) return;
    const int which = blockIdx.y;
    const float* w = which ? wB : wA;
    const int stride = which ? strideB : strideA;
    const int e = i & 3;
    int j = i >> 2;
    const int slot = j & 31; j >>= 5;
    const int o4 = j & 3; j >>= 2;
    const int mg = j & 3;
    const int q = j >> 2;
    const int g = ((slot >> 3) << 1) | (slot & 1);
    const int t = (slot >> 1) & 3;
    const int m = mg * 64 + o4 * 16 + g + (e & 1) * 8;
    const int p = t + ((e >> 1) << 2);
    const int k0 = q * 16 + 2 * p;
    float v0 = w[(size_t)m * stride + k0];
    float v1 = w[(size_t)m * stride + k0 + 1];
    uint32_t hi, lo;
    split_pack(v0, v1, hi, lo);
    outH[(size_t)which * WDNS + i] = hi;
    outL[(size_t)which * WDNS + i] = lo;
}

// ---------------- feats pre-split -------------------------------------------
__global__ __launch_bounds__(256)
void split_feats_kernel(const float* __restrict__ f0, const float* __restrict__ f1,
                        const float* __restrict__ f2, const float* __restrict__ f3,
                        uint32_t* __restrict__ outH, uint32_t* __restrict__ outL)
{
    const int px = blockIdx.x * 256 + threadIdx.x;
    if (px >= SUMHW) return;
    const int c2 = blockIdx.y;
    const int n  = blockIdx.z;
    const int s = scale_of(px);
    const int ploc = px - cOFF[s];
    const int HW = cHW[s];
    const float* f = (s == 0) ? f0 : (s == 1) ? f1 : (s == 2) ? f2 : f3;
    const float* src = f + ((size_t)n * C + 2 * c2) * HW + ploc;
    uint32_t hi, lo;
    split_pack(src[0], src[HW], hi, lo);
    const size_t o = ((size_t)n * 128 + c2) * SUMHW + px;
    outH[o] = hi;
    outL[o] = lo;
}

// ---------------- conv3x3 dual-branch: pipelined 3-term bf16 mma ------------
// Warp remap: warp -> (oh = warp&1: which 32-oc half, rw = warp>>1: row pair)
// Warp tile: 32 oc x 2 rows x 16 px. A-fragment LDS halved vs row-per-warp.
#define IPAD 28
#define ST_IH 9216
#define ST_IL 11456
#define STG_U32 13696
#define CONV_SMEM (2 * STG_U32 * 4)   // 109568 B

__global__ __launch_bounds__(256, 2)
void conv3x3_dual(const uint32_t* __restrict__ in0H, const uint32_t* __restrict__ in0L,
                  const uint32_t* __restrict__ in1H, const uint32_t* __restrict__ in1L,
                  const uint32_t* __restrict__ wH0, const uint32_t* __restrict__ wL0,
                  const uint32_t* __restrict__ wH1, const uint32_t* __restrict__ wL1,
                  const float* __restrict__ bias0, const float* __restrict__ bias1,
                  float* __restrict__ dF0, uint32_t* __restrict__ dH0, uint32_t* __restrict__ dL0,
                  float* __restrict__ dF1, uint32_t* __restrict__ dH1, uint32_t* __restrict__ dL1)
{
    extern __shared__ __align__(16) uint32_t smu[];
    __shared__ float s_bias[64];

    const int branch = blockIdx.z & 1;
    const int n = blockIdx.z >> 1;
    const uint32_t* inH = branch ? in1H : in0H;
    const uint32_t* inL = branch ? in1L : in0L;
    const uint32_t* wH  = branch ? wH1 : wH0;
    const uint32_t* wL  = branch ? wL1 : wL0;
    const float* bias   = branch ? bias1 : bias0;
    float* dstF    = branch ? dF1 : dF0;
    uint32_t* dstH = branch ? dH1 : dH0;
    uint32_t* dstL = branch ? dL1 : dL0;

    const int bx = blockIdx.x;
    int s, t_;
    if (bx < 80)       { s = 0; t_ = bx; }
    else if (bx < 100) { s = 1; t_ = bx - 80; }
    else if (bx < 106) { s = 2; t_ = bx - 100; }
    else               { s = 3; t_ = bx - 106; }
    const int H = cH[s], W = cW[s];
    const int tilesX = W >> 4;
    const int ty = t_ / tilesX, tx = t_ % tilesX;
    const int h0 = ty * 8, w0 = tx * 16;
    const int ocg = blockIdx.y;
    const int ocBase = ocg * 64;

    const int tid  = threadIdx.x;
    const int warp = tid >> 5;
    const int oh = warp & 1;         // which pair of o4 groups
    const int rw = warp >> 1;        // row pair index (0..3)
    const int lane = tid & 31;
    const int g = lane >> 2;
    const int t = lane & 3;
    const int slot = ((g >> 1) << 3) | (t << 1) | (g & 1);

    if (tid < 64) s_bias[tid] = bias[ocBase + tid];

    float acc[2][2][2][4];   // [o4l][rr][p4][4]
#pragma unroll
    for (int i = 0; i < 2; i++)
#pragma unroll
        for (int j = 0; j < 2; j++)
#pragma unroll
            for (int k = 0; k < 2; k++)
#pragma unroll
                for (int l = 0; l < 4; l++) acc[i][j][k][l] = 0.f;

    const uint32_t smbase = smem_addr_of(smu);

    auto fill = [&](int q, int st) {
        const uint32_t sb = smbase + (uint32_t)st * STG_U32 * 4;
        const uint4* wH4 = (const uint4*)wH + (size_t)(q * 4 + ocg) * 1152;
        const uint4* wL4 = (const uint4*)wL + (size_t)(q * 4 + ocg) * 1152;
        for (int j = tid; j < 2304; j += 256) {
            const uint4* src = (j < 1152) ? (wH4 + j) : (wL4 + (j - 1152));
            cp16(sb + j * 16, src, true);
        }
        for (int j = tid; j < 960; j += 256) {
            int slotc = j % 6;
            int rest = j / 6;
            int arr = rest & 1;
            int pr = rest >> 1;
            int p = pr / 10, r = pr % 10;
            int gh = h0 + r - 1;
            bool rowok = (gh >= 0) && (gh < H);
            int ghc = min(max(gh, 0), H - 1);
            size_t rowoff = ((size_t)n * 128 + q * 8 + p) * SUMHW + cOFF[s] + (size_t)ghc * W;
            const uint32_t* gsrc = arr ? inL : inH;
            uint32_t dstrow = sb + (uint32_t)((arr ? ST_IL : ST_IH) + (p * 10 + r) * IPAD) * 4;
            if (slotc < 4) {
                int c0 = slotc * 4;
                cp16(dstrow + (uint32_t)(4 + c0) * 4, gsrc + rowoff + w0 + c0, rowok);
            } else if (slotc == 4) {
                bool ok = rowok && (w0 > 0);
                cp4(dstrow + 3 * 4, gsrc + rowoff + (ok ? (w0 - 1) : w0), ok);
            } else {
                bool ok = rowok && (w0 + 16 < W);
                cp4(dstrow + 20 * 4, gsrc + rowoff + w0 + (ok ? 16 : 0), ok);
            }
        }
    };

    fill(0, 0);
    CP_COMMIT();

    for (int q = 0; q < 16; q++) {
        if (q < 15) { fill(q + 1, (q + 1) & 1); CP_COMMIT(); CP_WAIT(1); }
        else        { CP_WAIT(0); }
        __syncthreads();

        const uint32_t* sb = smu + (q & 1) * STG_U32;
        const uint4* s_w4H = (const uint4*)sb;
        const uint4* s_w4L = s_w4H + 1152;
        const uint32_t* s_iH = sb + ST_IH;
        const uint32_t* s_iL = sb + ST_IL;

#pragma unroll
        for (int kh = 0; kh < 3; kh++)
#pragma unroll
        for (int kw = 0; kw < 3; kw++) {
            const int tap = kh * 3 + kw;
            // B fragments for 2 rows
            uint32_t bh[2][2][2], bl[2][2][2];   // [rr][p4][reg]
#pragma unroll
            for (int rr = 0; rr < 2; rr++) {
                const int row = 2 * rw + rr;
                const int ib0 = (t * 10 + row + kh) * IPAD + kw + 3 + g;
                const int ib1 = ((t + 4) * 10 + row + kh) * IPAD + kw + 3 + g;
#pragma unroll
                for (int p4 = 0; p4 < 2; p4++) {
                    bh[rr][p4][0] = s_iH[ib0 + p4 * 8];
                    bh[rr][p4][1] = s_iH[ib1 + p4 * 8];
                    bl[rr][p4][0] = s_iL[ib0 + p4 * 8];
                    bl[rr][p4][1] = s_iL[ib1 + p4 * 8];
                }
            }
#pragma unroll
            for (int o4l = 0; o4l < 2; o4l++) {
                const int o4g = oh * 2 + o4l;
                uint4 a4 = s_w4H[(tap * 4 + o4g) * 32 + slot];
                uint4 b4 = s_w4L[(tap * 4 + o4g) * 32 + slot];
                uint32_t ah[4] = {a4.x, a4.y, a4.z, a4.w};
                uint32_t al[4] = {b4.x, b4.y, b4.z, b4.w};
#pragma unroll
                for (int rr = 0; rr < 2; rr++)
#pragma unroll
                    for (int p4 = 0; p4 < 2; p4++) {
                        mma_bf16(acc[o4l][rr][p4], ah, bh[rr][p4]);
                        mma_bf16(acc[o4l][rr][p4], ah, bl[rr][p4]);
                        mma_bf16(acc[o4l][rr][p4], al, bh[rr][p4]);
                    }
            }
        }
        __syncthreads();
    }

    // epilogue (validated C mapping): c0=(oc,col) c1=(oc,col+1) c2=(oc+8,col) c3=(oc+8,col+1)
    if (dstF) {
#pragma unroll
        for (int rr = 0; rr < 2; rr++) {
            const int ghout = h0 + 2 * rw + rr;
            if (ghout >= H) continue;
            float* dbase = dstF + (size_t)n * C * SUMHW + cOFF[s] + (size_t)ghout * W + w0;
#pragma unroll
            for (int o4l = 0; o4l < 2; o4l++) {
                int ocl = (oh * 2 + o4l) * 16 + g;
                float b0v = s_bias[ocl];
                float b1v = s_bias[ocl + 8];
#pragma unroll
                for (int p4 = 0; p4 < 2; p4++) {
                    int col = p4 * 8 + 2 * t;
                    float2 v0 = make_float2(fmaxf(acc[o4l][rr][p4][0] + b0v, 0.f),
                                            fmaxf(acc[o4l][rr][p4][1] + b0v, 0.f));
                    float2 v1 = make_float2(fmaxf(acc[o4l][rr][p4][2] + b1v, 0.f),
                                            fmaxf(acc[o4l][rr][p4][3] + b1v, 0.f));
                    *(float2*)(dbase + (size_t)(ocBase + ocl) * SUMHW + col) = v0;
                    *(float2*)(dbase + (size_t)(ocBase + ocl + 8) * SUMHW + col) = v1;
                }
            }
        }
    }
    if (dstH) {
#pragma unroll
        for (int rr = 0; rr < 2; rr++) {
            const int ghout = h0 + 2 * rw + rr;
            const size_t base = ((size_t)n * 128) * SUMHW + cOFF[s] + (size_t)ghout * W + w0;
#pragma unroll
            for (int o4l = 0; o4l < 2; o4l++) {
                int ocl = (oh * 2 + o4l) * 16 + g;
                float b0v = s_bias[ocl];
                float b1v = s_bias[ocl + 8];
                const size_t w2a = (size_t)((ocBase + ocl) >> 1) * SUMHW;
                const size_t w2b = (size_t)(((ocBase + ocl) >> 1) + 4) * SUMHW;
#pragma unroll
                for (int p4 = 0; p4 < 2; p4++) {
                    int col = p4 * 8 + 2 * t;
                    float v0 = fmaxf(acc[o4l][rr][p4][0] + b0v, 0.f);
                    float v1 = fmaxf(acc[o4l][rr][p4][1] + b0v, 0.f);
                    float v2 = fmaxf(acc[o4l][rr][p4][2] + b1v, 0.f);
                    float v3 = fmaxf(acc[o4l][rr][p4][3] + b1v, 0.f);
                    float p0 = __shfl_xor_sync(0xFFFFFFFFu, v0, 4);
                    float p1 = __shfl_xor_sync(0xFFFFFFFFu, v1, 4);
                    float p2 = __shfl_xor_sync(0xFFFFFFFFu, v2, 4);
                    float p3 = __shfl_xor_sync(0xFFFFFFFFu, v3, 4);
                    if (((g & 1) == 0) && ghout < H) {
                        uint32_t hw, lw;
                        split_pack(v0, p0, hw, lw);
                        dstH[base + w2a + col] = hw;  dstL[base + w2a + col] = lw;
                        split_pack(v1, p1, hw, lw);
                        dstH[base + w2a + col + 1] = hw;  dstL[base + w2a + col + 1] = lw;
                        split_pack(v2, p2, hw, lw);
                        dstH[base + w2b + col] = hw;  dstL[base + w2b + col] = lw;
                        split_pack(v3, p3, hw, lw);
                        dstH[base + w2b + col + 1] = hw;  dstL[base + w2b + col + 1] = lw;
                    }
                }
            }
        }
    }
}

// ---------------- dense GEMM core -------------------------------------------
#define GIPAD 264
#define GST_U32 5248

// rn2 GEMM: out[n][m][s] = relu(W hs + bias)
__global__ __launch_bounds__(256, 2)
void gemm_mma(const uint32_t* __restrict__ wH, const uint32_t* __restrict__ wL,
              const uint32_t* __restrict__ bHg, const uint32_t* __restrict__ bLg,
              const float* __restrict__ bias, float* __restrict__ outp)
{
    __shared__ __align__(16) uint32_t gsm[2 * GST_U32];

    const int s0 = blockIdx.x * 256;
    const int mg = blockIdx.y;
    const int n  = blockIdx.z;
    const int tid = threadIdx.x;
    const int warp = tid >> 5;
    const int lane = tid & 31;
    const int g = lane >> 2;
    const int t = lane & 3;
    const int slot = ((g >> 1) << 3) | (t << 1) | (g & 1);

    float acc[4][4][4];
#pragma unroll
    for (int i = 0; i < 4; i++)
#pragma unroll
        for (int j = 0; j < 4; j++)
#pragma unroll
            for (int k = 0; k < 4; k++) acc[i][j][k] = 0.f;

    const uint32_t smbase = smem_addr_of(gsm);

    auto fill = [&](int q, int st) {
        const uint32_t sb = smbase + (uint32_t)st * GST_U32 * 4;
        const uint4* wH4 = (const uint4*)wH + (size_t)(q * 4 + mg) * 128;
        const uint4* wL4 = (const uint4*)wL + (size_t)(q * 4 + mg) * 128;
        if (tid < 256) {
            const uint4* src = (tid < 128) ? (wH4 + tid) : (wL4 + (tid - 128));
            cp16(sb + tid * 16, src, true);
        }
        for (int j = tid; j < 1024; j += 256) {
            int c = j & 63;
            int rest = j >> 6;
            int arr = rest & 1;
            int p = rest >> 1;
            int sx = s0 + c * 4;
            bool ok = sx < SUMHW;
            size_t off = ((size_t)n * 128 + q * 8 + p) * SUMHW + (ok ? sx : 0);
            const uint32_t* gsrc = arr ? bLg : bHg;
            uint32_t dst = sb + (uint32_t)(1024 + arr * 2112 + p * GIPAD + c * 4) * 4;
            cp16(dst, gsrc + off, ok);
        }
    };

    fill(0, 0);
    CP_COMMIT();

    for (int q = 0; q < 16; q++) {
        if (q < 15) { fill(q + 1, (q + 1) & 1); CP_COMMIT(); CP_WAIT(1); }
        else        { CP_WAIT(0); }
        __syncthreads();

        const uint32_t* sb = gsm + (q & 1) * GST_U32;
        const uint4* s_aH4 = (const uint4*)sb;
        const uint4* s_aL4 = s_aH4 + 128;
        const uint32_t* s_iH = sb + 1024;
        const uint32_t* s_iL = sb + 3136;

        uint32_t bh[4][2], bl[4][2];
        const int ib0 = t * GIPAD + warp * 32 + g;
        const int ib1 = (t + 4) * GIPAD + warp * 32 + g;
#pragma unroll
        for (int p4 = 0; p4 < 4; p4++) {
            bh[p4][0] = s_iH[ib0 + p4 * 8];
            bh[p4][1] = s_iH[ib1 + p4 * 8];
            bl[p4][0] = s_iL[ib0 + p4 * 8];
            bl[p4][1] = s_iL[ib1 + p4 * 8];
        }
#pragma unroll
        for (int o4 = 0; o4 < 4; o4++) {
            uint4 a4 = s_aH4[o4 * 32 + slot];
            uint4 b4 = s_aL4[o4 * 32 + slot];
            uint32_t ah[4] = {a4.x, a4.y, a4.z, a4.w};
            uint32_t al[4] = {b4.x, b4.y, b4.z, b4.w};
#pragma unroll
            for (int p4 = 0; p4 < 4; p4++) {
                mma_bf16(acc[o4][p4], ah, bh[p4]);
                mma_bf16(acc[o4][p4], ah, bl[p4]);
                mma_bf16(acc[o4][p4], al, bh[p4]);
            }
        }
        __syncthreads();
    }

#pragma unroll
    for (int o4 = 0; o4 < 4; o4++) {
        int m0 = mg * 64 + o4 * 16 + g;
        float b0v = bias[m0];
        float b1v = bias[m0 + 8];
#pragma unroll
        for (int p4 = 0; p4 < 4; p4++) {
            int sx = s0 + warp * 32 + p4 * 8 + 2 * t;
            if (sx < SUMHW) {
                float v0 = fmaxf(acc[o4][p4][0] + b0v, 0.f);
                float v1 = fmaxf(acc[o4][p4][1] + b0v, 0.f);
                float v2 = fmaxf(acc[o4][p4][2] + b1v, 0.f);
                float v3 = fmaxf(acc[o4][p4][3] + b1v, 0.f);
                *(float2*)(outp + ((size_t)n * 256 + m0) * SUMHW + sx) = make_float2(v0, v1);
                *(float2*)(outp + ((size_t)n * 256 + m0 + 8) * SUMHW + sx) = make_float2(v2, v3);
            }
        }
    }
}

// o_proj GEMM fused with hsum: writes split hs directly
__global__ __launch_bounds__(256, 2)
void gemm_oproj_hsum(const uint32_t* __restrict__ wH, const uint32_t* __restrict__ wL,
                     const uint32_t* __restrict__ bHg, const uint32_t* __restrict__ bLg,
                     const float* __restrict__ pproj,
                     uint32_t* __restrict__ hsH, uint32_t* __restrict__ hsL)
{
    __shared__ __align__(16) uint32_t gsm[2 * GST_U32];
    __shared__ float spp[KTOP * 64];

    const int s0 = blockIdx.x * 256;
    const int mg = blockIdx.y;
    const int n  = blockIdx.z;
    const int tid = threadIdx.x;
    const int warp = tid >> 5;
    const int lane = tid & 31;
    const int g = lane >> 2;
    const int t = lane & 3;
    const int slot = ((g >> 1) << 3) | (t << 1) | (g & 1);

    for (int i = tid; i < KTOP * 64; i += 256) {
        int k = i >> 6, dl = i & 63;
        spp[i] = pproj[((size_t)n * KTOP + k) * D + mg * 64 + dl];
    }

    float acc[4][4][4];
#pragma unroll
    for (int i = 0; i < 4; i++)
#pragma unroll
        for (int j = 0; j < 4; j++)
#pragma unroll
            for (int k = 0; k < 4; k++) acc[i][j][k] = 0.f;

    const uint32_t smbase = smem_addr_of(gsm);

    auto fill = [&](int q, int st) {
        const uint32_t sb = smbase + (uint32_t)st * GST_U32 * 4;
        const uint4* wH4 = (const uint4*)wH + (size_t)(q * 4 + mg) * 128;
        const uint4* wL4 = (const uint4*)wL + (size_t)(q * 4 + mg) * 128;
        if (tid < 256) {
            const uint4* src = (tid < 128) ? (wH4 + tid) : (wL4 + (tid - 128));
            cp16(sb + tid * 16, src, true);
        }
        for (int j = tid; j < 1024; j += 256) {
            int c = j & 63;
            int rest = j >> 6;
            int arr = rest & 1;
            int p = rest >> 1;
            int sx = s0 + c * 4;
            bool ok = sx < SUMHW;
            size_t off = ((size_t)n * 128 + q * 8 + p) * SUMHW + (ok ? sx : 0);
            const uint32_t* gsrc = arr ? bLg : bHg;
            uint32_t dst = sb + (uint32_t)(1024 + arr * 2112 + p * GIPAD + c * 4) * 4;
            cp16(dst, gsrc + off, ok);
        }
    };

    fill(0, 0);
    CP_COMMIT();

    for (int q = 0; q < 16; q++) {
        if (q < 15) { fill(q + 1, (q + 1) & 1); CP_COMMIT(); CP_WAIT(1); }
        else        { CP_WAIT(0); }
        __syncthreads();

        const uint32_t* sb = gsm + (q & 1) * GST_U32;
        const uint4* s_aH4 = (const uint4*)sb;
        const uint4* s_aL4 = s_aH4 + 128;
        const uint32_t* s_iH = sb + 1024;
        const uint32_t* s_iL = sb + 3136;

        uint32_t bh[4][2], bl[4][2];
        const int ib0 = t * GIPAD + warp * 32 + g;
        const int ib1 = (t + 4) * GIPAD + warp * 32 + g;
#pragma unroll
        for (int p4 = 0; p4 < 4; p4++) {
            bh[p4][0] = s_iH[ib0 + p4 * 8];
            bh[p4][1] = s_iH[ib1 + p4 * 8];
            bl[p4][0] = s_iL[ib0 + p4 * 8];
            bl[p4][1] = s_iL[ib1 + p4 * 8];
        }
#pragma unroll
        for (int o4 = 0; o4 < 4; o4++) {
            uint4 a4 = s_aH4[o4 * 32 + slot];
            uint4 b4 = s_aL4[o4 * 32 + slot];
            uint32_t ah[4] = {a4.x, a4.y, a4.z, a4.w};
            uint32_t al[4] = {b4.x, b4.y, b4.z, b4.w};
#pragma unroll
            for (int p4 = 0; p4 < 4; p4++) {
                mma_bf16(acc[o4][p4], ah, bh[p4]);
                mma_bf16(acc[o4][p4], ah, bl[p4]);
                mma_bf16(acc[o4][p4], al, bh[p4]);
            }
        }
        __syncthreads();
    }

#pragma unroll
    for (int o4 = 0; o4 < 4; o4++) {
        const int m0l = o4 * 16 + g;
        const int m0  = mg * 64 + m0l;
        float pp0[KTOP], pp1[KTOP];
#pragma unroll
        for (int k = 0; k < KTOP; k++) {
            pp0[k] = spp[k * 64 + m0l];
            pp1[k] = spp[k * 64 + m0l + 8];
        }
        const size_t w2a = (size_t)(m0 >> 1) * SUMHW;
        const size_t w2b = (size_t)((m0 >> 1) + 4) * SUMHW;
        const size_t nb = (size_t)n * 128 * SUMHW;
#pragma unroll
        for (int p4 = 0; p4 < 4; p4++) {
            int sx = s0 + warp * 32 + p4 * 8 + 2 * t;
            float a0 = 0.f, a1 = 0.f, a2 = 0.f, a3 = 0.f;
#pragma unroll 4
            for (int k = 0; k < KTOP; k++) {
                a0 += fmaxf(acc[o4][p4][0] + pp0[k], 0.f);
                a1 += fmaxf(acc[o4][p4][1] + pp0[k], 0.f);
                a2 += fmaxf(acc[o4][p4][2] + pp1[k], 0.f);
                a3 += fmaxf(acc[o4][p4][3] + pp1[k], 0.f);
            }
            float q0 = __shfl_xor_sync(0xFFFFFFFFu, a0, 4);
            float q1 = __shfl_xor_sync(0xFFFFFFFFu, a1, 4);
            float q2 = __shfl_xor_sync(0xFFFFFFFFu, a2, 4);
            float q3 = __shfl_xor_sync(0xFFFFFFFFu, a3, 4);
            if (((g & 1) == 0) && sx < SUMHW) {
                uint32_t hw, lw;
                split_pack(a0, q0, hw, lw);
                hsH[nb + w2a + sx] = hw;      hsL[nb + w2a + sx] = lw;
                split_pack(a1, q1, hw, lw);
                hsH[nb + w2a + sx + 1] = hw;  hsL[nb + w2a + sx + 1] = lw;
                split_pack(a2, q2, hw, lw);
                hsH[nb + w2b + sx] = hw;      hsL[nb + w2b + sx] = lw;
                split_pack(a3, q3, hw, lw);
                hsH[nb + w2b + sx + 1] = hw;  hsL[nb + w2b + sx + 1] = lw;
            }
        }
    }
}

// ---------------- merged heads (person + object delta) ----------------------
__global__ __launch_bounds__(256)
void heads_all(const float* __restrict__ t2p, const float* __restrict__ t2o,
               const float* __restrict__ pl_w, const float* __restrict__ pl_b,
               const float* __restrict__ pd_w, const float* __restrict__ pd_b,
               const float* __restrict__ od_w, const float* __restrict__ od_b,
               float* __restrict__ out, float* __restrict__ cell)
{
    const int branch = blockIdx.y & 1;
    const int n = blockIdx.y >> 1;
    const int tid = threadIdx.x;
    __shared__ float swl[A * C];
    __shared__ float swd[BOXC * C];
    if (branch == 0) {
        for (int i = tid; i < A * C; i += 256) swl[i] = pl_w[i];
        for (int i = tid; i < BOXC * C; i += 256) swd[i] = pd_w[i];
    } else {
        for (int i = tid; i < BOXC * C; i += 256) swd[i] = od_w[i];
    }
    __syncthreads();

    const int p = blockIdx.x * 256 + tid;
    if (p >= SUMHW) return;
    const int s = scale_of(p);
    const int ploc = p - cOFF[s];
    const int HW = cHW[s];

    if (branch == 0) {
        const float* h = t2p + (size_t)n * C * SUMHW + p;
        float accl[A], accd[BOXC];
#pragma unroll
        for (int a = 0; a < A; a++) accl[a] = pl_b[a];
#pragma unroll
        for (int j = 0; j < BOXC; j++) accd[j] = pd_b[j];
        for (int c = 0; c < C; c++) {
            float v = h[(size_t)c * SUMHW];
#pragma unroll
            for (int a = 0; a < A; a++) accl[a] += swl[a * C + c] * v;
#pragma unroll
            for (int j = 0; j < BOXC; j++) accd[j] += swd[j * C + c] * v;
        }
        float m = accl[0];
#pragma unroll
        for (int a = 0; a < A; a++) {
            out[cPLOG[s] + ((size_t)n * A + a) * HW + ploc] = accl[a];
            m = fmaxf(m, accl[a]);
        }
#pragma unroll
        for (int j = 0; j < BOXC; j++)
            out[cPDEL[s] + ((size_t)n * BOXC + j) * HW + ploc] = accd[j];
        cell[(size_t)n * SUMHW + p] = m;
    } else {
        const float* h = t2o + (size_t)n * C * SUMHW + p;
        float accd[BOXC];
#pragma unroll
        for (int j = 0; j < BOXC; j++) accd[j] = od_b[j];
        for (int c = 0; c < C; c++) {
            float v = h[(size_t)c * SUMHW];
#pragma unroll
            for (int j = 0; j < BOXC; j++) accd[j] += swd[j * C + c] * v;
        }
#pragma unroll
        for (int j = 0; j < BOXC; j++)
            out[cODEL[s] + ((size_t)n * BOXC + j) * HW + ploc] = accd[j];
    }
}

// ---------------- per-scale top-K (smem-cached) -----------------------------
__global__ __launch_bounds__(256)
void topk_flat(const float* __restrict__ cell, const float* __restrict__ hid,
               float* __restrict__ cand_hid, float* __restrict__ cand_sc)
{
    const int s = blockIdx.x;
    const int n = blockIdx.y;
    const int HW = cHW[s], off = cOFF[s];
    __shared__ float sc[10240];
    __shared__ float s_val[256];
    __shared__ int   s_idx[256];
    __shared__ int   sel[KTOP];
    const int tid = threadIdx.x;

    for (int i = tid; i < HW; i += 256)
        sc[i] = cell[(size_t)n * SUMHW + off + i];
    __syncthreads();

    for (int k = 0; k < KTOP; k++) {
        float best = -CUDART_INF_F;
        int bi = HW;
        for (int i = tid; i < HW; i += 256) {
            float v = sc[i];
            if (v > best) { best = v; bi = i; }
        }
        s_val[tid] = best; s_idx[tid] = bi;
        __syncthreads();
        for (int offr = 128; offr > 0; offr >>= 1) {
            if (tid < offr) {
                float v2 = s_val[tid + offr]; int i2 = s_idx[tid + offr];
                if (v2 > s_val[tid] || (v2 == s_val[tid] && i2 < s_idx[tid])) {
                    s_val[tid] = v2; s_idx[tid] = i2;
                }
            }
            __syncthreads();
        }
        if (tid == 0) {
            sel[k] = s_idx[0];
            cand_sc[(size_t)n * 80 + s * KTOP + k] = s_val[0];
            sc[s_idx[0]] = -CUDART_INF_F;
        }
        __syncthreads();
    }
    for (int idx = tid; idx < C * KTOP; idx += 256) {
        int c = idx / KTOP, k = idx % KTOP;
        cand_hid[((size_t)n * C + c) * 80 + s * KTOP + k] =
            hid[((size_t)n * C + c) * SUMHW + off + sel[k]];
    }
}

// ---------------- global top-K over 80 --------------------------------------
__global__ void topk_global_kernel(const float* __restrict__ sc, int* __restrict__ keep)
{
    const int n = blockIdx.x;
    bool used[80];
    for (int i = 0; i < 80; i++) used[i] = false;
    const float* s = sc + (size_t)n * 80;
    for (int k = 0; k < KTOP; k++) {
        float best = -CUDART_INF_F; int bi = 0;
        for (int i = 0; i < 80; i++)
            if (!used[i] && s[i] > best) { best = s[i]; bi = i; }
        used[bi] = true;
        keep[n * KTOP + k] = bi;
    }
}

// ---------------- p_proj ----------------------------------------------------
__global__ __launch_bounds__(256)
void pproj_kernel(const float* __restrict__ cand_hid, const int* __restrict__ keep,
                  const float* __restrict__ rn1_w, const float* __restrict__ rn1_b,
                  float* __restrict__ pproj)
{
    const int k = blockIdx.x, n = blockIdx.y, d = threadIdx.x;
    __shared__ float sh[C];
    const int col = keep[n * KTOP + k];
    sh[d] = cand_hid[((size_t)n * C + d) * 80 + col];
    __syncthreads();
    float acc = rn1_b[d];
    const float* wrow = rn1_w + (size_t)d * (2 * C) + C;   // Wp
    for (int c = 0; c < C; c++) acc += sh[c] * wrow[c];
    pproj[((size_t)n * KTOP + k) * D + d] = acc;
}

// ---------------- ol head (transposed h2 [n][e][s]) -------------------------
__global__ __launch_bounds__(256)
void ol_t(const float* __restrict__ h2, const float* __restrict__ ol_w,
          const float* __restrict__ ol_b, float* __restrict__ out)
{
    __shared__ float sw[A * 256];
    const int n = blockIdx.y;
    const int tid = threadIdx.x;
    for (int i = tid; i < A * 256; i += 256) sw[i] = ol_w[i];
    __syncthreads();
    const int s = blockIdx.x * 256 + tid;
    if (s >= SUMHW) return;
    float a0 = 0.f, a1 = 0.f, a2 = 0.f;
    for (int e = 0; e < 256; e++) {
        float v = h2[((size_t)n * 256 + e) * SUMHW + s];
        a0 += v * sw[e];
        a1 += v * sw[256 + e];
        a2 += v * sw[512 + e];
    }
    const int sc = scale_of(s);
    const int ploc = s - cOFF[sc];
    const int HW = cHW[sc];
    out[cOLOG[sc] + ((size_t)n * A + 0) * HW + ploc] = a0 + ol_b[0];
    out[cOLOG[sc] + ((size_t)n * A + 1) * HW + ploc] = a1 + ol_b[1];
    out[cOLOG[sc] + ((size_t)n * A + 2) * HW + ploc] = a2 + ol_b[2];
}

// ---------------------------- host orchestration ----------------------------
extern "C" void kernel_launch(void* const* d_in, const int* in_sizes, int n_in,
                              void* d_out, int out_size)
{
    const float* f0 = (const float*)d_in[0];
    const float* f1 = (const float*)d_in[1];
    const float* f2 = (const float*)d_in[2];
    const float* f3 = (const float*)d_in[3];
    const float* pc1_w = (const float*)d_in[4];
    const float* pc1_b = (const float*)d_in[5];
    const float* pc2_w = (const float*)d_in[6];
    const float* pc2_b = (const float*)d_in[7];
    const float* oc1_w = (const float*)d_in[8];
    const float* oc1_b = (const float*)d_in[9];
    const float* oc2_w = (const float*)d_in[10];
    const float* oc2_b = (const float*)d_in[11];
    const float* rn1_w = (const float*)d_in[12];
    const float* rn1_b = (const float*)d_in[13];
    const float* rn2_w = (const float*)d_in[14];
    const float* rn2_b = (const float*)d_in[15];
    const float* pl_w  = (const float*)d_in[16];
    const float* pl_b  = (const float*)d_in[17];
    const float* pd_w  = (const float*)d_in[18];
    const float* pd_b  = (const float*)d_in[19];
    const float* ol_w  = (const float*)d_in[20];
    const float* ol_b  = (const float*)d_in[21];
    const float* od_w  = (const float*)d_in[22];
    const float* od_b  = (const float*)d_in[23];
    float* out = (float*)d_out;

    float *t2p, *t2o, *h2, *cell, *cand_hid, *cand_sc, *pproj;
    int* keep;
    uint32_t *sAh, *sAl, *sBh, *sBl, *sDh, *sDl, *sCh, *sCl, *hsh, *hsl, *wsh, *wsl, *wdh, *wdl;
    cudaGetSymbolAddress((void**)&t2p, g_t2p);
    cudaGetSymbolAddress((void**)&t2o, g_t2o);
    cudaGetSymbolAddress((void**)&h2, g_h2);
    cudaGetSymbolAddress((void**)&cell, g_cell);
    cudaGetSymbolAddress((void**)&cand_hid, g_cand_hid);
    cudaGetSymbolAddress((void**)&cand_sc, g_cand_sc);
    cudaGetSymbolAddress((void**)&keep, g_keep);
    cudaGetSymbolAddress((void**)&pproj, g_pproj);
    cudaGetSymbolAddress((void**)&sAh, g_sA_hi);
    cudaGetSymbolAddress((void**)&sAl, g_sA_lo);
    cudaGetSymbolAddress((void**)&sBh, g_sB_hi);
    cudaGetSymbolAddress((void**)&sBl, g_sB_lo);
    cudaGetSymbolAddress((void**)&sDh, g_sD_hi);
    cudaGetSymbolAddress((void**)&sDl, g_sD_lo);
    cudaGetSymbolAddress((void**)&sCh, g_sC_hi);
    cudaGetSymbolAddress((void**)&sCl, g_sC_lo);
    cudaGetSymbolAddress((void**)&hsh, g_hs_hi);
    cudaGetSymbolAddress((void**)&hsl, g_hs_lo);
    cudaGetSymbolAddress((void**)&wsh, g_wsp_hi);
    cudaGetSymbolAddress((void**)&wsl, g_wsp_lo);
    cudaGetSymbolAddress((void**)&wdh, g_wd_hi);
    cudaGetSymbolAddress((void**)&wdl, g_wd_lo);

    cudaFuncSetAttribute(conv3x3_dual,
                         cudaFuncAttributeMaxDynamicSharedMemorySize, CONV_SMEM);

    const dim3 convGrid(108, 4, NB * 2);
    const dim3 headGrid((SUMHW + 255) / 256, NB * 2);
    const dim3 gemmGrid(STILE, 4, NB);

    // ---- prep: split weights + feats ----
    split_w_conv<<<dim3((WSPL + 255) / 256, 4), 256>>>(pc1_w, pc2_w, oc1_w, oc2_w, wsh, wsl);
    split_w_dense<<<dim3((WDNS + 255) / 256, 2), 256>>>(rn1_w, rn2_w, 2 * C, D, wdh, wdl);
    split_feats_kernel<<<dim3((SUMHW + 255) / 256, 128, NB), 256>>>(f0, f1, f2, f3, sAh, sAl);

    // ---- layer 1 (both branches) ----
    conv3x3_dual<<<convGrid, 256, CONV_SMEM>>>(
        sAh, sAl, sAh, sAl,
        wsh, wsl, wsh + 2 * WSPL, wsl + 2 * WSPL,
        pc1_b, oc1_b,
        nullptr, sBh, sBl,
        nullptr, sDh, sDl);
    // ---- layer 2 (both branches) ----
    conv3x3_dual<<<convGrid, 256, CONV_SMEM>>>(
        sBh, sBl, sDh, sDl,
        wsh + WSPL, wsl + WSPL, wsh + 3 * WSPL, wsl + 3 * WSPL,
        pc2_b, oc2_b,
        t2p, nullptr, nullptr,
        t2o, sCh, sCl);

    // ---- heads (both branches) ----
    heads_all<<<headGrid, 256>>>(t2p, t2o, pl_w, pl_b, pd_w, pd_b, od_w, od_b, out, cell);

    // ---- person relational path ----
    topk_flat<<<dim3(4, NB), 256>>>(cell, t2p, cand_hid, cand_sc);
    topk_global_kernel<<<NB, 1>>>(cand_sc, keep);
    pproj_kernel<<<dim3(KTOP, NB), 256>>>(cand_hid, keep, rn1_w, rn1_b, pproj);

    // ---- object relational path ----
    gemm_oproj_hsum<<<gemmGrid, 256>>>(wdh, wdl, sCh, sCl, pproj, hsh, hsl);
    gemm_mma<<<gemmGrid, 256>>>(wdh + WDNS, wdl + WDNS, hsh, hsl, rn2_b, h2);
    ol_t<<<dim3(STILE, NB), 256>>>(h2, ol_w, ol_b, out);

    (void)in_sizes; (void)n_in; (void)out_size;
}

// round 13
// speedup vs baseline: 8.1766x; 1.1172x over previous
#include <cuda_runtime.h>
#include <cuda_bf16.h>
#include <cuda_fp16.h>
#include <math_constants.h>
#include <stdint.h>

// Problem constants
#define NB   2
#define C    256
#define A    3
#define KTOP 20
#define D    256
#define BOXC 12
#define SUMHW 13600   // 10240 + 2560 + 640 + 160
#define WSPL 294912   // per-layer conv split-weight u32 count
#define WDNS 32768    // dense 256x256 split-weight u32 count
#define STILE 54      // ceil(SUMHW/256)

// ---------------- scratch (device globals) ----------------------------------
__device__ float g_t2p[NB * C * SUMHW];
__device__ float g_t2o[NB * C * SUMHW];
__device__ float g_h2[NB * 256 * SUMHW];
__device__ float g_cell[NB * SUMHW];
__device__ float g_cand_hid[NB * C * 80];
__device__ float g_cand_sc[NB * 80];
__device__ int   g_keep[NB * KTOP];
__device__ float g_pproj[NB * KTOP * D];
// split activations: [n][pair=128][SUMHW] u32
__device__ uint32_t g_sA_hi[NB * 128 * SUMHW];    // feats bf16 split (person)
__device__ uint32_t g_sA_lo[NB * 128 * SUMHW];
__device__ uint32_t g_sAf_hi[NB * 128 * SUMHW];   // feats fp16 split (object)
__device__ uint32_t g_sAf_lo[NB * 128 * SUMHW];
__device__ uint32_t g_sB_hi[NB * 128 * SUMHW];    // person conv1 out (bf16)
__device__ uint32_t g_sB_lo[NB * 128 * SUMHW];
__device__ uint32_t g_sD_hi[NB * 128 * SUMHW];    // object conv1 out (fp16)
__device__ uint32_t g_sD_lo[NB * 128 * SUMHW];
__device__ uint32_t g_sC_hi[NB * 128 * SUMHW];    // object conv2 out (bf16, for gemm)
__device__ uint32_t g_sC_lo[NB * 128 * SUMHW];
__device__ uint32_t g_hs_hi[NB * 128 * SUMHW];
__device__ uint32_t g_hs_lo[NB * 128 * SUMHW];
// split weights (fragment order)
__device__ uint32_t g_wsp_hi[4 * WSPL];   // layers 0,1 bf16 ; layers 2,3 fp16
__device__ uint32_t g_wsp_lo[4 * WSPL];
__device__ uint32_t g_wd_hi[2 * WDNS];
__device__ uint32_t g_wd_lo[2 * WDNS];

// per-scale constants
__device__ __constant__ int cOFF[4]  = {0, 10240, 12800, 13440};
__device__ __constant__ int cHW[4]   = {10240, 2560, 640, 160};
__device__ __constant__ int cH[4]    = {80, 40, 20, 10};
__device__ __constant__ int cW[4]    = {128, 64, 32, 16};
__device__ __constant__ int cPLOG[4] = {0,      61440,  76800,  80640};
__device__ __constant__ int cPDEL[4] = {81600,  327360, 388800, 404160};
__device__ __constant__ int cOLOG[4] = {408000, 469440, 484800, 488640};
__device__ __constant__ int cODEL[4] = {489600, 735360, 796800, 812160};

__device__ __forceinline__ int scale_of(int p) {
    return (p < 10240) ? 0 : (p < 12800) ? 1 : (p < 13440) ? 2 : 3;
}

// ---------------- mma / split helpers ---------------------------------------
__device__ __forceinline__ void mma_bf16(float* c, const uint32_t* a, const uint32_t* b) {
    asm volatile(
        "mma.sync.aligned.m16n8k16.row.col.f32.bf16.bf16.f32 "
        "{%0,%1,%2,%3}, {%4,%5,%6,%7}, {%8,%9}, {%0,%1,%2,%3};\n"
        : "+f"(c[0]), "+f"(c[1]), "+f"(c[2]), "+f"(c[3])
        : "r"(a[0]), "r"(a[1]), "r"(a[2]), "r"(a[3]), "r"(b[0]), "r"(b[1]));
}
__device__ __forceinline__ void mma_f16(float* c, const uint32_t* a, const uint32_t* b) {
    asm volatile(
        "mma.sync.aligned.m16n8k16.row.col.f32.f16.f16.f32 "
        "{%0,%1,%2,%3}, {%4,%5,%6,%7}, {%8,%9}, {%0,%1,%2,%3};\n"
        : "+f"(c[0]), "+f"(c[1]), "+f"(c[2]), "+f"(c[3])
        : "r"(a[0]), "r"(a[1]), "r"(a[2]), "r"(a[3]), "r"(b[0]), "r"(b[1]));
}
// bf16 hi/lo split pack
__device__ __forceinline__ void split_pack(float v0, float v1,
                                           uint32_t& hi_out, uint32_t& lo_out) {
    __nv_bfloat16 h0 = __float2bfloat16(v0);
    __nv_bfloat16 h1 = __float2bfloat16(v1);
    __nv_bfloat16 l0 = __float2bfloat16(v0 - __bfloat162float(h0));
    __nv_bfloat16 l1 = __float2bfloat16(v1 - __bfloat162float(h1));
    hi_out = ((uint32_t)__bfloat16_as_ushort(h1) << 16) | (uint32_t)__bfloat16_as_ushort(h0);
    lo_out = ((uint32_t)__bfloat16_as_ushort(l1) << 16) | (uint32_t)__bfloat16_as_ushort(l0);
}
// fp16 hi/lo split pack
__device__ __forceinline__ void split_pack_h(float v0, float v1,
                                             uint32_t& hi_out, uint32_t& lo_out) {
    __half h0 = __float2half(v0);
    __half h1 = __float2half(v1);
    __half l0 = __float2half(v0 - __half2float(h0));
    __half l1 = __float2half(v1 - __half2float(h1));
    hi_out = ((uint32_t)__half_as_ushort(h1) << 16) | (uint32_t)__half_as_ushort(h0);
    lo_out = ((uint32_t)__half_as_ushort(l1) << 16) | (uint32_t)__half_as_ushort(l0);
}
__device__ __forceinline__ uint32_t smem_addr_of(const void* p) {
    return (uint32_t)__cvta_generic_to_shared(p);
}
__device__ __forceinline__ void cp16(uint32_t dst, const void* src, bool pred) {
    asm volatile("cp.async.cg.shared.global [%0], [%1], 16, %2;"
                 :: "r"(dst), "l"(src), "r"(pred ? 16 : 0));
}
__device__ __forceinline__ void cp4(uint32_t dst, const void* src, bool pred) {
    asm volatile("cp.async.ca.shared.global [%0], [%1], 4, %2;"
                 :: "r"(dst), "l"(src), "r"(pred ? 4 : 0));
}
#define CP_COMMIT() asm volatile("cp.async.commit_group;" ::: "memory")
#define CP_WAIT(n)  asm volatile("cp.async.wait_group %0;" :: "n"(n) : "memory")

// ---------------- conv weight pre-split (fragment order) --------------------
// layers 0,1: bf16 split (person); layers 2,3: fp16 split (object)
__global__ __launch_bounds__(256)
void split_w_conv(const float* __restrict__ w0, const float* __restrict__ w1,
                  const float* __restrict__ w2, const float* __restrict__ w3,
                  uint32_t* __restrict__ outH, uint32_t* __restrict__ outL)
{
    const int i = blockIdx.x * 256 + threadIdx.x;
    if (i >= WSPL) return;
    const int layer = blockIdx.y;
    const float* w = (layer == 0) ? w0 : (layer == 1) ? w1 : (layer == 2) ? w2 : w3;
    const int e = i & 3;
    int j = i >> 2;
    const int slot = j & 31; j >>= 5;
    const int o4 = j & 3; j >>= 2;
    const int tap = j % 9; j /= 9;
    const int ocg = j & 3;
    const int q = j >> 2;
    const int g = ((slot >> 3) << 1) | (slot & 1);
    const int t = (slot >> 1) & 3;
    const int oc = ocg * 64 + o4 * 16 + g + (e & 1) * 8;
    const int p = t + ((e >> 1) << 2);
    const int ci0 = q * 16 + 2 * p;
    float v0 = w[(size_t)oc * 2304 + ci0 * 9 + tap];
    float v1 = w[(size_t)oc * 2304 + (ci0 + 1) * 9 + tap];
    uint32_t hi, lo;
    if (layer < 2) split_pack(v0, v1, hi, lo);
    else           split_pack_h(v0, v1, hi, lo);
    outH[(size_t)layer * WSPL + i] = hi;
    outL[(size_t)layer * WSPL + i] = lo;
}

// ---------------- dense weight pre-split (bf16, fragment order) -------------
__global__ __launch_bounds__(256)
void split_w_dense(const float* __restrict__ wA, const float* __restrict__ wB,
                   int strideA, int strideB,
                   uint32_t* __restrict__ outH, uint32_t* __restrict__ outL)
{
    const int i = blockIdx.x * 256 + threadIdx.x;
    if (i >= WDNS) return;
    const int which = blockIdx.y;
    const float* w = which ? wB : wA;
    const int stride = which ? strideB : strideA;
    const int e = i & 3;
    int j = i >> 2;
    const int slot = j & 31; j >>= 5;
    const int o4 = j & 3; j >>= 2;
    const int mg = j & 3;
    const int q = j >> 2;
    const int g = ((slot >> 3) << 1) | (slot & 1);
    const int t = (slot >> 1) & 3;
    const int m = mg * 64 + o4 * 16 + g + (e & 1) * 8;
    const int p = t + ((e >> 1) << 2);
    const int k0 = q * 16 + 2 * p;
    float v0 = w[(size_t)m * stride + k0];
    float v1 = w[(size_t)m * stride + k0 + 1];
    uint32_t hi, lo;
    split_pack(v0, v1, hi, lo);
    outH[(size_t)which * WDNS + i] = hi;
    outL[(size_t)which * WDNS + i] = lo;
}

// ---------------- feats pre-split (both formats) ----------------------------
__global__ __launch_bounds__(256)
void split_feats_kernel(const float* __restrict__ f0, const float* __restrict__ f1,
                        const float* __restrict__ f2, const float* __restrict__ f3,
                        uint32_t* __restrict__ outHb, uint32_t* __restrict__ outLb,
                        uint32_t* __restrict__ outHf, uint32_t* __restrict__ outLf)
{
    const int px = blockIdx.x * 256 + threadIdx.x;
    if (px >= SUMHW) return;
    const int c2 = blockIdx.y;
    const int n  = blockIdx.z;
    const int s = scale_of(px);
    const int ploc = px - cOFF[s];
    const int HW = cHW[s];
    const float* f = (s == 0) ? f0 : (s == 1) ? f1 : (s == 2) ? f2 : f3;
    const float* src = f + ((size_t)n * C + 2 * c2) * HW + ploc;
    float v0 = src[0], v1 = src[HW];
    const size_t o = ((size_t)n * 128 + c2) * SUMHW + px;
    uint32_t hi, lo;
    split_pack(v0, v1, hi, lo);
    outHb[o] = hi; outLb[o] = lo;
    split_pack_h(v0, v1, hi, lo);
    outHf[o] = hi; outLf[o] = lo;
}

// ---------------- conv3x3 dual-branch: pipelined mma ------------------------
// flags bit0: fp16 2-term compute; bit1: split output packed as fp16
#define IPAD 28
#define ST_IH 9216
#define ST_IL 11456
#define STG_U32 13696
#define CONV_SMEM (2 * STG_U32 * 4)   // 109568 B

__global__ __launch_bounds__(256, 2)
void conv3x3_dual(const uint32_t* __restrict__ in0H, const uint32_t* __restrict__ in0L,
                  const uint32_t* __restrict__ in1H, const uint32_t* __restrict__ in1L,
                  const uint32_t* __restrict__ wH0, const uint32_t* __restrict__ wL0,
                  const uint32_t* __restrict__ wH1, const uint32_t* __restrict__ wL1,
                  const float* __restrict__ bias0, const float* __restrict__ bias1,
                  float* __restrict__ dF0, uint32_t* __restrict__ dH0, uint32_t* __restrict__ dL0,
                  float* __restrict__ dF1, uint32_t* __restrict__ dH1, uint32_t* __restrict__ dL1,
                  int flags0, int flags1)
{
    extern __shared__ __align__(16) uint32_t smu[];
    __shared__ float s_bias[64];

    const int branch = blockIdx.z & 1;
    const int n = blockIdx.z >> 1;
    const uint32_t* inH = branch ? in1H : in0H;
    const uint32_t* inL = branch ? in1L : in0L;
    const uint32_t* wH  = branch ? wH1 : wH0;
    const uint32_t* wL  = branch ? wL1 : wL0;
    const float* bias   = branch ? bias1 : bias0;
    float* dstF    = branch ? dF1 : dF0;
    uint32_t* dstH = branch ? dH1 : dH0;
    uint32_t* dstL = branch ? dL1 : dL0;
    const int flags = branch ? flags1 : flags0;
    const bool f16c = (flags & 1) != 0;
    const bool sp16 = (flags & 2) != 0;

    const int bx = blockIdx.x;
    int s, t_;
    if (bx < 80)       { s = 0; t_ = bx; }
    else if (bx < 100) { s = 1; t_ = bx - 80; }
    else if (bx < 106) { s = 2; t_ = bx - 100; }
    else               { s = 3; t_ = bx - 106; }
    const int H = cH[s], W = cW[s];
    const int tilesX = W >> 4;
    const int ty = t_ / tilesX, tx = t_ % tilesX;
    const int h0 = ty * 8, w0 = tx * 16;
    const int ocg = blockIdx.y;
    const int ocBase = ocg * 64;

    const int tid  = threadIdx.x;
    const int warp = tid >> 5;
    const int oh = warp & 1;
    const int rw = warp >> 1;
    const int lane = tid & 31;
    const int g = lane >> 2;
    const int t = lane & 3;
    const int slot = ((g >> 1) << 3) | (t << 1) | (g & 1);

    if (tid < 64) s_bias[tid] = bias[ocBase + tid];

    float acc[2][2][2][4];
#pragma unroll
    for (int i = 0; i < 2; i++)
#pragma unroll
        for (int j = 0; j < 2; j++)
#pragma unroll
            for (int k = 0; k < 2; k++)
#pragma unroll
                for (int l = 0; l < 4; l++) acc[i][j][k][l] = 0.f;

    const uint32_t smbase = smem_addr_of(smu);
    const int wcnt = f16c ? 1152 : 2304;   // fp16 2-term skips weight-lo

    auto fill = [&](int q, int st) {
        const uint32_t sb = smbase + (uint32_t)st * STG_U32 * 4;
        const uint4* wH4 = (const uint4*)wH + (size_t)(q * 4 + ocg) * 1152;
        const uint4* wL4 = (const uint4*)wL + (size_t)(q * 4 + ocg) * 1152;
        for (int j = tid; j < wcnt; j += 256) {
            const uint4* src = (j < 1152) ? (wH4 + j) : (wL4 + (j - 1152));
            cp16(sb + j * 16, src, true);
        }
        for (int j = tid; j < 960; j += 256) {
            int slotc = j % 6;
            int rest = j / 6;
            int arr = rest & 1;
            int pr = rest >> 1;
            int p = pr / 10, r = pr % 10;
            int gh = h0 + r - 1;
            bool rowok = (gh >= 0) && (gh < H);
            int ghc = min(max(gh, 0), H - 1);
            size_t rowoff = ((size_t)n * 128 + q * 8 + p) * SUMHW + cOFF[s] + (size_t)ghc * W;
            const uint32_t* gsrc = arr ? inL : inH;
            uint32_t dstrow = sb + (uint32_t)((arr ? ST_IL : ST_IH) + (p * 10 + r) * IPAD) * 4;
            if (slotc < 4) {
                int c0 = slotc * 4;
                cp16(dstrow + (uint32_t)(4 + c0) * 4, gsrc + rowoff + w0 + c0, rowok);
            } else if (slotc == 4) {
                bool ok = rowok && (w0 > 0);
                cp4(dstrow + 3 * 4, gsrc + rowoff + (ok ? (w0 - 1) : w0), ok);
            } else {
                bool ok = rowok && (w0 + 16 < W);
                cp4(dstrow + 20 * 4, gsrc + rowoff + w0 + (ok ? 16 : 0), ok);
            }
        }
    };

    fill(0, 0);
    CP_COMMIT();

    for (int q = 0; q < 16; q++) {
        if (q < 15) { fill(q + 1, (q + 1) & 1); CP_COMMIT(); CP_WAIT(1); }
        else        { CP_WAIT(0); }
        __syncthreads();

        const uint32_t* sb = smu + (q & 1) * STG_U32;
        const uint4* s_w4H = (const uint4*)sb;
        const uint4* s_w4L = s_w4H + 1152;
        const uint32_t* s_iH = sb + ST_IH;
        const uint32_t* s_iL = sb + ST_IL;

#pragma unroll
        for (int kh = 0; kh < 3; kh++)
#pragma unroll
        for (int kw = 0; kw < 3; kw++) {
            const int tap = kh * 3 + kw;
            uint32_t bh[2][2][2], bl[2][2][2];
#pragma unroll
            for (int rr = 0; rr < 2; rr++) {
                const int row = 2 * rw + rr;
                const int ib0 = (t * 10 + row + kh) * IPAD + kw + 3 + g;
                const int ib1 = ((t + 4) * 10 + row + kh) * IPAD + kw + 3 + g;
#pragma unroll
                for (int p4 = 0; p4 < 2; p4++) {
                    bh[rr][p4][0] = s_iH[ib0 + p4 * 8];
                    bh[rr][p4][1] = s_iH[ib1 + p4 * 8];
                    bl[rr][p4][0] = s_iL[ib0 + p4 * 8];
                    bl[rr][p4][1] = s_iL[ib1 + p4 * 8];
                }
            }
#pragma unroll
            for (int o4l = 0; o4l < 2; o4l++) {
                const int o4g = oh * 2 + o4l;
                uint4 a4 = s_w4H[(tap * 4 + o4g) * 32 + slot];
                uint32_t ah[4] = {a4.x, a4.y, a4.z, a4.w};
                if (!f16c) {
                    uint4 b4 = s_w4L[(tap * 4 + o4g) * 32 + slot];
                    uint32_t al[4] = {b4.x, b4.y, b4.z, b4.w};
#pragma unroll
                    for (int rr = 0; rr < 2; rr++)
#pragma unroll
                        for (int p4 = 0; p4 < 2; p4++) {
                            mma_bf16(acc[o4l][rr][p4], ah, bh[rr][p4]);
                            mma_bf16(acc[o4l][rr][p4], ah, bl[rr][p4]);
                            mma_bf16(acc[o4l][rr][p4], al, bh[rr][p4]);
                        }
                } else {
#pragma unroll
                    for (int rr = 0; rr < 2; rr++)
#pragma unroll
                        for (int p4 = 0; p4 < 2; p4++) {
                            mma_f16(acc[o4l][rr][p4], ah, bh[rr][p4]);
                            mma_f16(acc[o4l][rr][p4], ah, bl[rr][p4]);
                        }
                }
            }
        }
        __syncthreads();
    }

    // epilogue (validated C mapping)
    if (dstF) {
#pragma unroll
        for (int rr = 0; rr < 2; rr++) {
            const int ghout = h0 + 2 * rw + rr;
            if (ghout >= H) continue;
            float* dbase = dstF + (size_t)n * C * SUMHW + cOFF[s] + (size_t)ghout * W + w0;
#pragma unroll
            for (int o4l = 0; o4l < 2; o4l++) {
                int ocl = (oh * 2 + o4l) * 16 + g;
                float b0v = s_bias[ocl];
                float b1v = s_bias[ocl + 8];
#pragma unroll
                for (int p4 = 0; p4 < 2; p4++) {
                    int col = p4 * 8 + 2 * t;
                    float2 v0 = make_float2(fmaxf(acc[o4l][rr][p4][0] + b0v, 0.f),
                                            fmaxf(acc[o4l][rr][p4][1] + b0v, 0.f));
                    float2 v1 = make_float2(fmaxf(acc[o4l][rr][p4][2] + b1v, 0.f),
                                            fmaxf(acc[o4l][rr][p4][3] + b1v, 0.f));
                    *(float2*)(dbase + (size_t)(ocBase + ocl) * SUMHW + col) = v0;
                    *(float2*)(dbase + (size_t)(ocBase + ocl + 8) * SUMHW + col) = v1;
                }
            }
        }
    }
    if (dstH) {
#pragma unroll
        for (int rr = 0; rr < 2; rr++) {
            const int ghout = h0 + 2 * rw + rr;
            const size_t base = ((size_t)n * 128) * SUMHW + cOFF[s] + (size_t)ghout * W + w0;
#pragma unroll
            for (int o4l = 0; o4l < 2; o4l++) {
                int ocl = (oh * 2 + o4l) * 16 + g;
                float b0v = s_bias[ocl];
                float b1v = s_bias[ocl + 8];
                const size_t w2a = (size_t)((ocBase + ocl) >> 1) * SUMHW;
                const size_t w2b = (size_t)(((ocBase + ocl) >> 1) + 4) * SUMHW;
#pragma unroll
                for (int p4 = 0; p4 < 2; p4++) {
                    int col = p4 * 8 + 2 * t;
                    float v0 = fmaxf(acc[o4l][rr][p4][0] + b0v, 0.f);
                    float v1 = fmaxf(acc[o4l][rr][p4][1] + b0v, 0.f);
                    float v2 = fmaxf(acc[o4l][rr][p4][2] + b1v, 0.f);
                    float v3 = fmaxf(acc[o4l][rr][p4][3] + b1v, 0.f);
                    float p0 = __shfl_xor_sync(0xFFFFFFFFu, v0, 4);
                    float p1 = __shfl_xor_sync(0xFFFFFFFFu, v1, 4);
                    float p2 = __shfl_xor_sync(0xFFFFFFFFu, v2, 4);
                    float p3 = __shfl_xor_sync(0xFFFFFFFFu, v3, 4);
                    if (((g & 1) == 0) && ghout < H) {
                        uint32_t hw, lw;
                        if (sp16) split_pack_h(v0, p0, hw, lw);
                        else      split_pack(v0, p0, hw, lw);
                        dstH[base + w2a + col] = hw;  dstL[base + w2a + col] = lw;
                        if (sp16) split_pack_h(v1, p1, hw, lw);
                        else      split_pack(v1, p1, hw, lw);
                        dstH[base + w2a + col + 1] = hw;  dstL[base + w2a + col + 1] = lw;
                        if (sp16) split_pack_h(v2, p2, hw, lw);
                        else      split_pack(v2, p2, hw, lw);
                        dstH[base + w2b + col] = hw;  dstL[base + w2b + col] = lw;
                        if (sp16) split_pack_h(v3, p3, hw, lw);
                        else      split_pack(v3, p3, hw, lw);
                        dstH[base + w2b + col + 1] = hw;  dstL[base + w2b + col + 1] = lw;
                    }
                }
            }
        }
    }
}

// ---------------- dense GEMM core (bf16 3-term, validated) ------------------
#define GIPAD 264
#define GST_U32 5248

__global__ __launch_bounds__(256, 2)
void gemm_mma(const uint32_t* __restrict__ wH, const uint32_t* __restrict__ wL,
              const uint32_t* __restrict__ bHg, const uint32_t* __restrict__ bLg,
              const float* __restrict__ bias, float* __restrict__ outp)
{
    __shared__ __align__(16) uint32_t gsm[2 * GST_U32];

    const int s0 = blockIdx.x * 256;
    const int mg = blockIdx.y;
    const int n  = blockIdx.z;
    const int tid = threadIdx.x;
    const int warp = tid >> 5;
    const int lane = tid & 31;
    const int g = lane >> 2;
    const int t = lane & 3;
    const int slot = ((g >> 1) << 3) | (t << 1) | (g & 1);

    float acc[4][4][4];
#pragma unroll
    for (int i = 0; i < 4; i++)
#pragma unroll
        for (int j = 0; j < 4; j++)
#pragma unroll
            for (int k = 0; k < 4; k++) acc[i][j][k] = 0.f;

    const uint32_t smbase = smem_addr_of(gsm);

    auto fill = [&](int q, int st) {
        const uint32_t sb = smbase + (uint32_t)st * GST_U32 * 4;
        const uint4* wH4 = (const uint4*)wH + (size_t)(q * 4 + mg) * 128;
        const uint4* wL4 = (const uint4*)wL + (size_t)(q * 4 + mg) * 128;
        if (tid < 256) {
            const uint4* src = (tid < 128) ? (wH4 + tid) : (wL4 + (tid - 128));
            cp16(sb + tid * 16, src, true);
        }
        for (int j = tid; j < 1024; j += 256) {
            int c = j & 63;
            int rest = j >> 6;
            int arr = rest & 1;
            int p = rest >> 1;
            int sx = s0 + c * 4;
            bool ok = sx < SUMHW;
            size_t off = ((size_t)n * 128 + q * 8 + p) * SUMHW + (ok ? sx : 0);
            const uint32_t* gsrc = arr ? bLg : bHg;
            uint32_t dst = sb + (uint32_t)(1024 + arr * 2112 + p * GIPAD + c * 4) * 4;
            cp16(dst, gsrc + off, ok);
        }
    };

    fill(0, 0);
    CP_COMMIT();

    for (int q = 0; q < 16; q++) {
        if (q < 15) { fill(q + 1, (q + 1) & 1); CP_COMMIT(); CP_WAIT(1); }
        else        { CP_WAIT(0); }
        __syncthreads();

        const uint32_t* sb = gsm + (q & 1) * GST_U32;
        const uint4* s_aH4 = (const uint4*)sb;
        const uint4* s_aL4 = s_aH4 + 128;
        const uint32_t* s_iH = sb + 1024;
        const uint32_t* s_iL = sb + 3136;

        uint32_t bh[4][2], bl[4][2];
        const int ib0 = t * GIPAD + warp * 32 + g;
        const int ib1 = (t + 4) * GIPAD + warp * 32 + g;
#pragma unroll
        for (int p4 = 0; p4 < 4; p4++) {
            bh[p4][0] = s_iH[ib0 + p4 * 8];
            bh[p4][1] = s_iH[ib1 + p4 * 8];
            bl[p4][0] = s_iL[ib0 + p4 * 8];
            bl[p4][1] = s_iL[ib1 + p4 * 8];
        }
#pragma unroll
        for (int o4 = 0; o4 < 4; o4++) {
            uint4 a4 = s_aH4[o4 * 32 + slot];
            uint4 b4 = s_aL4[o4 * 32 + slot];
            uint32_t ah[4] = {a4.x, a4.y, a4.z, a4.w};
            uint32_t al[4] = {b4.x, b4.y, b4.z, b4.w};
#pragma unroll
            for (int p4 = 0; p4 < 4; p4++) {
                mma_bf16(acc[o4][p4], ah, bh[p4]);
                mma_bf16(acc[o4][p4], ah, bl[p4]);
                mma_bf16(acc[o4][p4], al, bh[p4]);
            }
        }
        __syncthreads();
    }

#pragma unroll
    for (int o4 = 0; o4 < 4; o4++) {
        int m0 = mg * 64 + o4 * 16 + g;
        float b0v = bias[m0];
        float b1v = bias[m0 + 8];
#pragma unroll
        for (int p4 = 0; p4 < 4; p4++) {
            int sx = s0 + warp * 32 + p4 * 8 + 2 * t;
            if (sx < SUMHW) {
                float v0 = fmaxf(acc[o4][p4][0] + b0v, 0.f);
                float v1 = fmaxf(acc[o4][p4][1] + b0v, 0.f);
                float v2 = fmaxf(acc[o4][p4][2] + b1v, 0.f);
                float v3 = fmaxf(acc[o4][p4][3] + b1v, 0.f);
                *(float2*)(outp + ((size_t)n * 256 + m0) * SUMHW + sx) = make_float2(v0, v1);
                *(float2*)(outp + ((size_t)n * 256 + m0 + 8) * SUMHW + sx) = make_float2(v2, v3);
            }
        }
    }
}

// o_proj GEMM fused with hsum
__global__ __launch_bounds__(256, 2)
void gemm_oproj_hsum(const uint32_t* __restrict__ wH, const uint32_t* __restrict__ wL,
                     const uint32_t* __restrict__ bHg, const uint32_t* __restrict__ bLg,
                     const float* __restrict__ pproj,
                     uint32_t* __restrict__ hsH, uint32_t* __restrict__ hsL)
{
    __shared__ __align__(16) uint32_t gsm[2 * GST_U32];
    __shared__ float spp[KTOP * 64];

    const int s0 = blockIdx.x * 256;
    const int mg = blockIdx.y;
    const int n  = blockIdx.z;
    const int tid = threadIdx.x;
    const int warp = tid >> 5;
    const int lane = tid & 31;
    const int g = lane >> 2;
    const int t = lane & 3;
    const int slot = ((g >> 1) << 3) | (t << 1) | (g & 1);

    for (int i = tid; i < KTOP * 64; i += 256) {
        int k = i >> 6, dl = i & 63;
        spp[i] = pproj[((size_t)n * KTOP + k) * D + mg * 64 + dl];
    }

    float acc[4][4][4];
#pragma unroll
    for (int i = 0; i < 4; i++)
#pragma unroll
        for (int j = 0; j < 4; j++)
#pragma unroll
            for (int k = 0; k < 4; k++) acc[i][j][k] = 0.f;

    const uint32_t smbase = smem_addr_of(gsm);

    auto fill = [&](int q, int st) {
        const uint32_t sb = smbase + (uint32_t)st * GST_U32 * 4;
        const uint4* wH4 = (const uint4*)wH + (size_t)(q * 4 + mg) * 128;
        const uint4* wL4 = (const uint4*)wL + (size_t)(q * 4 + mg) * 128;
        if (tid < 256) {
            const uint4* src = (tid < 128) ? (wH4 + tid) : (wL4 + (tid - 128));
            cp16(sb + tid * 16, src, true);
        }
        for (int j = tid; j < 1024; j += 256) {
            int c = j & 63;
            int rest = j >> 6;
            int arr = rest & 1;
            int p = rest >> 1;
            int sx = s0 + c * 4;
            bool ok = sx < SUMHW;
            size_t off = ((size_t)n * 128 + q * 8 + p) * SUMHW + (ok ? sx : 0);
            const uint32_t* gsrc = arr ? bLg : bHg;
            uint32_t dst = sb + (uint32_t)(1024 + arr * 2112 + p * GIPAD + c * 4) * 4;
            cp16(dst, gsrc + off, ok);
        }
    };

    fill(0, 0);
    CP_COMMIT();

    for (int q = 0; q < 16; q++) {
        if (q < 15) { fill(q + 1, (q + 1) & 1); CP_COMMIT(); CP_WAIT(1); }
        else        { CP_WAIT(0); }
        __syncthreads();

        const uint32_t* sb = gsm + (q & 1) * GST_U32;
        const uint4* s_aH4 = (const uint4*)sb;
        const uint4* s_aL4 = s_aH4 + 128;
        const uint32_t* s_iH = sb + 1024;
        const uint32_t* s_iL = sb + 3136;

        uint32_t bh[4][2], bl[4][2];
        const int ib0 = t * GIPAD + warp * 32 + g;
        const int ib1 = (t + 4) * GIPAD + warp * 32 + g;
#pragma unroll
        for (int p4 = 0; p4 < 4; p4++) {
            bh[p4][0] = s_iH[ib0 + p4 * 8];
            bh[p4][1] = s_iH[ib1 + p4 * 8];
            bl[p4][0] = s_iL[ib0 + p4 * 8];
            bl[p4][1] = s_iL[ib1 + p4 * 8];
        }
#pragma unroll
        for (int o4 = 0; o4 < 4; o4++) {
            uint4 a4 = s_aH4[o4 * 32 + slot];
            uint4 b4 = s_aL4[o4 * 32 + slot];
            uint32_t ah[4] = {a4.x, a4.y, a4.z, a4.w};
            uint32_t al[4] = {b4.x, b4.y, b4.z, b4.w};
#pragma unroll
            for (int p4 = 0; p4 < 4; p4++) {
                mma_bf16(acc[o4][p4], ah, bh[p4]);
                mma_bf16(acc[o4][p4], ah, bl[p4]);
                mma_bf16(acc[o4][p4], al, bh[p4]);
            }
        }
        __syncthreads();
    }

#pragma unroll
    for (int o4 = 0; o4 < 4; o4++) {
        const int m0l = o4 * 16 + g;
        const int m0  = mg * 64 + m0l;
        float pp0[KTOP], pp1[KTOP];
#pragma unroll
        for (int k = 0; k < KTOP; k++) {
            pp0[k] = spp[k * 64 + m0l];
            pp1[k] = spp[k * 64 + m0l + 8];
        }
        const size_t w2a = (size_t)(m0 >> 1) * SUMHW;
        const size_t w2b = (size_t)((m0 >> 1) + 4) * SUMHW;
        const size_t nb = (size_t)n * 128 * SUMHW;
#pragma unroll
        for (int p4 = 0; p4 < 4; p4++) {
            int sx = s0 + warp * 32 + p4 * 8 + 2 * t;
            float a0 = 0.f, a1 = 0.f, a2 = 0.f, a3 = 0.f;
#pragma unroll 4
            for (int k = 0; k < KTOP; k++) {
                a0 += fmaxf(acc[o4][p4][0] + pp0[k], 0.f);
                a1 += fmaxf(acc[o4][p4][1] + pp0[k], 0.f);
                a2 += fmaxf(acc[o4][p4][2] + pp1[k], 0.f);
                a3 += fmaxf(acc[o4][p4][3] + pp1[k], 0.f);
            }
            float q0 = __shfl_xor_sync(0xFFFFFFFFu, a0, 4);
            float q1 = __shfl_xor_sync(0xFFFFFFFFu, a1, 4);
            float q2 = __shfl_xor_sync(0xFFFFFFFFu, a2, 4);
            float q3 = __shfl_xor_sync(0xFFFFFFFFu, a3, 4);
            if (((g & 1) == 0) && sx < SUMHW) {
                uint32_t hw, lw;
                split_pack(a0, q0, hw, lw);
                hsH[nb + w2a + sx] = hw;      hsL[nb + w2a + sx] = lw;
                split_pack(a1, q1, hw, lw);
                hsH[nb + w2a + sx + 1] = hw;  hsL[nb + w2a + sx + 1] = lw;
                split_pack(a2, q2, hw, lw);
                hsH[nb + w2b + sx] = hw;      hsL[nb + w2b + sx] = lw;
                split_pack(a3, q3, hw, lw);
                hsH[nb + w2b + sx + 1] = hw;  hsL[nb + w2b + sx + 1] = lw;
            }
        }
    }
}

// ---------------- merged heads (person + object delta) ----------------------
__global__ __launch_bounds__(256)
void heads_all(const float* __restrict__ t2p, const float* __restrict__ t2o,
               const float* __restrict__ pl_w, const float* __restrict__ pl_b,
               const float* __restrict__ pd_w, const float* __restrict__ pd_b,
               const float* __restrict__ od_w, const float* __restrict__ od_b,
               float* __restrict__ out, float* __restrict__ cell)
{
    const int branch = blockIdx.y & 1;
    const int n = blockIdx.y >> 1;
    const int tid = threadIdx.x;
    __shared__ float swl[A * C];
    __shared__ float swd[BOXC * C];
    if (branch == 0) {
        for (int i = tid; i < A * C; i += 256) swl[i] = pl_w[i];
        for (int i = tid; i < BOXC * C; i += 256) swd[i] = pd_w[i];
    } else {
        for (int i = tid; i < BOXC * C; i += 256) swd[i] = od_w[i];
    }
    __syncthreads();

    const int p = blockIdx.x * 256 + tid;
    if (p >= SUMHW) return;
    const int s = scale_of(p);
    const int ploc = p - cOFF[s];
    const int HW = cHW[s];

    if (branch == 0) {
        const float* h = t2p + (size_t)n * C * SUMHW + p;
        float accl[A], accd[BOXC];
#pragma unroll
        for (int a = 0; a < A; a++) accl[a] = pl_b[a];
#pragma unroll
        for (int j = 0; j < BOXC; j++) accd[j] = pd_b[j];
        for (int c = 0; c < C; c++) {
            float v = h[(size_t)c * SUMHW];
#pragma unroll
            for (int a = 0; a < A; a++) accl[a] += swl[a * C + c] * v;
#pragma unroll
            for (int j = 0; j < BOXC; j++) accd[j] += swd[j * C + c] * v;
        }
        float m = accl[0];
#pragma unroll
        for (int a = 0; a < A; a++) {
            out[cPLOG[s] + ((size_t)n * A + a) * HW + ploc] = accl[a];
            m = fmaxf(m, accl[a]);
        }
#pragma unroll
        for (int j = 0; j < BOXC; j++)
            out[cPDEL[s] + ((size_t)n * BOXC + j) * HW + ploc] = accd[j];
        cell[(size_t)n * SUMHW + p] = m;
    } else {
        const float* h = t2o + (size_t)n * C * SUMHW + p;
        float accd[BOXC];
#pragma unroll
        for (int j = 0; j < BOXC; j++) accd[j] = od_b[j];
        for (int c = 0; c < C; c++) {
            float v = h[(size_t)c * SUMHW];
#pragma unroll
            for (int j = 0; j < BOXC; j++) accd[j] += swd[j * C + c] * v;
        }
#pragma unroll
        for (int j = 0; j < BOXC; j++)
            out[cODEL[s] + ((size_t)n * BOXC + j) * HW + ploc] = accd[j];
    }
}

// ---------------- per-scale top-K (1024 threads, warp-shuffle reduce) -------
__global__ __launch_bounds__(1024)
void topk_flat(const float* __restrict__ cell, const float* __restrict__ hid,
               float* __restrict__ cand_hid, float* __restrict__ cand_sc)
{
    const int s = blockIdx.x;
    const int n = blockIdx.y;
    const int HW = cHW[s], off = cOFF[s];
    __shared__ float sc[10240];
    __shared__ float w_val[32];
    __shared__ int   w_idx[32];
    __shared__ int   sel[KTOP];
    const int tid = threadIdx.x;
    const int lane = tid & 31, wid = tid >> 5;

    for (int i = tid; i < HW; i += 1024)
        sc[i] = cell[(size_t)n * SUMHW + off + i];
    __syncthreads();

    for (int k = 0; k < KTOP; k++) {
        float best = -CUDART_INF_F;
        int bi = HW;
        for (int i = tid; i < HW; i += 1024) {
            float v = sc[i];
            if (v > best) { best = v; bi = i; }   // ascending scan: strict > keeps smallest idx
        }
#pragma unroll
        for (int o = 16; o > 0; o >>= 1) {
            float v2 = __shfl_down_sync(0xFFFFFFFFu, best, o);
            int   i2 = __shfl_down_sync(0xFFFFFFFFu, bi, o);
            if (v2 > best || (v2 == best && i2 < bi)) { best = v2; bi = i2; }
        }
        if (lane == 0) { w_val[wid] = best; w_idx[wid] = bi; }
        __syncthreads();
        if (wid == 0) {
            best = w_val[lane]; bi = w_idx[lane];
#pragma unroll
            for (int o = 16; o > 0; o >>= 1) {
                float v2 = __shfl_down_sync(0xFFFFFFFFu, best, o);
                int   i2 = __shfl_down_sync(0xFFFFFFFFu, bi, o);
                if (v2 > best || (v2 == best && i2 < bi)) { best = v2; bi = i2; }
            }
            if (lane == 0) {
                sel[k] = bi;
                cand_sc[(size_t)n * 80 + s * KTOP + k] = best;
                sc[bi] = -CUDART_INF_F;
            }
        }
        __syncthreads();
    }
    for (int idx = tid; idx < C * KTOP; idx += 1024) {
        int c = idx / KTOP, k = idx % KTOP;
        cand_hid[((size_t)n * C + c) * 80 + s * KTOP + k] =
            hid[((size_t)n * C + c) * SUMHW + off + sel[k]];
    }
}

// ---------------- global top-K over 80 --------------------------------------
__global__ void topk_global_kernel(const float* __restrict__ sc, int* __restrict__ keep)
{
    const int n = blockIdx.x;
    bool used[80];
    for (int i = 0; i < 80; i++) used[i] = false;
    const float* s = sc + (size_t)n * 80;
    for (int k = 0; k < KTOP; k++) {
        float best = -CUDART_INF_F; int bi = 0;
        for (int i = 0; i < 80; i++)
            if (!used[i] && s[i] > best) { best = s[i]; bi = i; }
        used[bi] = true;
        keep[n * KTOP + k] = bi;
    }
}

// ---------------- p_proj ----------------------------------------------------
__global__ __launch_bounds__(256)
void pproj_kernel(const float* __restrict__ cand_hid, const int* __restrict__ keep,
                  const float* __restrict__ rn1_w, const float* __restrict__ rn1_b,
                  float* __restrict__ pproj)
{
    const int k = blockIdx.x, n = blockIdx.y, d = threadIdx.x;
    __shared__ float sh[C];
    const int col = keep[n * KTOP + k];
    sh[d] = cand_hid[((size_t)n * C + d) * 80 + col];
    __syncthreads();
    float acc = rn1_b[d];
    const float* wrow = rn1_w + (size_t)d * (2 * C) + C;   // Wp
    for (int c = 0; c < C; c++) acc += sh[c] * wrow[c];
    pproj[((size_t)n * KTOP + k) * D + d] = acc;
}

// ---------------- ol head (transposed h2 [n][e][s]) -------------------------
__global__ __launch_bounds__(256)
void ol_t(const float* __restrict__ h2, const float* __restrict__ ol_w,
          const float* __restrict__ ol_b, float* __restrict__ out)
{
    __shared__ float sw[A * 256];
    const int n = blockIdx.y;
    const int tid = threadIdx.x;
    for (int i = tid; i < A * 256; i += 256) sw[i] = ol_w[i];
    __syncthreads();
    const int s = blockIdx.x * 256 + tid;
    if (s >= SUMHW) return;
    float a0 = 0.f, a1 = 0.f, a2 = 0.f;
    for (int e = 0; e < 256; e++) {
        float v = h2[((size_t)n * 256 + e) * SUMHW + s];
        a0 += v * sw[e];
        a1 += v * sw[256 + e];
        a2 += v * sw[512 + e];
    }
    const int sc = scale_of(s);
    const int ploc = s - cOFF[sc];
    const int HW = cHW[sc];
    out[cOLOG[sc] + ((size_t)n * A + 0) * HW + ploc] = a0 + ol_b[0];
    out[cOLOG[sc] + ((size_t)n * A + 1) * HW + ploc] = a1 + ol_b[1];
    out[cOLOG[sc] + ((size_t)n * A + 2) * HW + ploc] = a2 + ol_b[2];
}

// ---------------------------- host orchestration ----------------------------
extern "C" void kernel_launch(void* const* d_in, const int* in_sizes, int n_in,
                              void* d_out, int out_size)
{
    const float* f0 = (const float*)d_in[0];
    const float* f1 = (const float*)d_in[1];
    const float* f2 = (const float*)d_in[2];
    const float* f3 = (const float*)d_in[3];
    const float* pc1_w = (const float*)d_in[4];
    const float* pc1_b = (const float*)d_in[5];
    const float* pc2_w = (const float*)d_in[6];
    const float* pc2_b = (const float*)d_in[7];
    const float* oc1_w = (const float*)d_in[8];
    const float* oc1_b = (const float*)d_in[9];
    const float* oc2_w = (const float*)d_in[10];
    const float* oc2_b = (const float*)d_in[11];
    const float* rn1_w = (const float*)d_in[12];
    const float* rn1_b = (const float*)d_in[13];
    const float* rn2_w = (const float*)d_in[14];
    const float* rn2_b = (const float*)d_in[15];
    const float* pl_w  = (const float*)d_in[16];
    const float* pl_b  = (const float*)d_in[17];
    const float* pd_w  = (const float*)d_in[18];
    const float* pd_b  = (const float*)d_in[19];
    const float* ol_w  = (const float*)d_in[20];
    const float* ol_b  = (const float*)d_in[21];
    const float* od_w  = (const float*)d_in[22];
    const float* od_b  = (const float*)d_in[23];
    float* out = (float*)d_out;

    float *t2p, *t2o, *h2, *cell, *cand_hid, *cand_sc, *pproj;
    int* keep;
    uint32_t *sAh, *sAl, *sAfh, *sAfl, *sBh, *sBl, *sDh, *sDl, *sCh, *sCl,
             *hsh, *hsl, *wsh, *wsl, *wdh, *wdl;
    cudaGetSymbolAddress((void**)&t2p, g_t2p);
    cudaGetSymbolAddress((void**)&t2o, g_t2o);
    cudaGetSymbolAddress((void**)&h2, g_h2);
    cudaGetSymbolAddress((void**)&cell, g_cell);
    cudaGetSymbolAddress((void**)&cand_hid, g_cand_hid);
    cudaGetSymbolAddress((void**)&cand_sc, g_cand_sc);
    cudaGetSymbolAddress((void**)&keep, g_keep);
    cudaGetSymbolAddress((void**)&pproj, g_pproj);
    cudaGetSymbolAddress((void**)&sAh, g_sA_hi);
    cudaGetSymbolAddress((void**)&sAl, g_sA_lo);
    cudaGetSymbolAddress((void**)&sAfh, g_sAf_hi);
    cudaGetSymbolAddress((void**)&sAfl, g_sAf_lo);
    cudaGetSymbolAddress((void**)&sBh, g_sB_hi);
    cudaGetSymbolAddress((void**)&sBl, g_sB_lo);
    cudaGetSymbolAddress((void**)&sDh, g_sD_hi);
    cudaGetSymbolAddress((void**)&sDl, g_sD_lo);
    cudaGetSymbolAddress((void**)&sCh, g_sC_hi);
    cudaGetSymbolAddress((void**)&sCl, g_sC_lo);
    cudaGetSymbolAddress((void**)&hsh, g_hs_hi);
    cudaGetSymbolAddress((void**)&hsl, g_hs_lo);
    cudaGetSymbolAddress((void**)&wsh, g_wsp_hi);
    cudaGetSymbolAddress((void**)&wsl, g_wsp_lo);
    cudaGetSymbolAddress((void**)&wdh, g_wd_hi);
    cudaGetSymbolAddress((void**)&wdl, g_wd_lo);

    cudaFuncSetAttribute(conv3x3_dual,
                         cudaFuncAttributeMaxDynamicSharedMemorySize, CONV_SMEM);

    const dim3 convGrid(108, 4, NB * 2);
    const dim3 headGrid((SUMHW + 255) / 256, NB * 2);
    const dim3 gemmGrid(STILE, 4, NB);

    // ---- prep: split weights + feats ----
    split_w_conv<<<dim3((WSPL + 255) / 256, 4), 256>>>(pc1_w, pc2_w, oc1_w, oc2_w, wsh, wsl);
    split_w_dense<<<dim3((WDNS + 255) / 256, 2), 256>>>(rn1_w, rn2_w, 2 * C, D, wdh, wdl);
    split_feats_kernel<<<dim3((SUMHW + 255) / 256, 128, NB), 256>>>(
        f0, f1, f2, f3, sAh, sAl, sAfh, sAfl);

    // ---- layer 1: person bf16 3-term -> sB(bf16); object fp16 2-term -> sD(fp16)
    conv3x3_dual<<<convGrid, 256, CONV_SMEM>>>(
        sAh, sAl, sAfh, sAfl,
        wsh, wsl, wsh + 2 * WSPL, wsl + 2 * WSPL,
        pc1_b, oc1_b,
        nullptr, sBh, sBl,
        nullptr, sDh, sDl,
        /*flags0=*/0, /*flags1=*/3);
    // ---- layer 2: person bf16 -> t2p; object fp16 -> t2o + sC(bf16)
    conv3x3_dual<<<convGrid, 256, CONV_SMEM>>>(
        sBh, sBl, sDh, sDl,
        wsh + WSPL, wsl + WSPL, wsh + 3 * WSPL, wsl + 3 * WSPL,
        pc2_b, oc2_b,
        t2p, nullptr, nullptr,
        t2o, sCh, sCl,
        /*flags0=*/0, /*flags1=*/1);

    // ---- heads (both branches) ----
    heads_all<<<headGrid, 256>>>(t2p, t2o, pl_w, pl_b, pd_w, pd_b, od_w, od_b, out, cell);

    // ---- person relational path ----
    topk_flat<<<dim3(4, NB), 1024>>>(cell, t2p, cand_hid, cand_sc);
    topk_global_kernel<<<NB, 1>>>(cand_sc, keep);
    pproj_kernel<<<dim3(KTOP, NB), 256>>>(cand_hid, keep, rn1_w, rn1_b, pproj);

    // ---- object relational path ----
    gemm_oproj_hsum<<<gemmGrid, 256>>>(wdh, wdl, sCh, sCl, pproj, hsh, hsl);
    gemm_mma<<<gemmGrid, 256>>>(wdh + WDNS, wdl + WDNS, hsh, hsl, rn2_b, h2);
    ol_t<<<dim3(STILE, NB), 256>>>(h2, ol_w, ol_b, out);

    (void)in_sizes; (void)n_in; (void)out_size;
}

// round 14
// speedup vs baseline: 8.1909x; 1.0018x over previous
#include <cuda_runtime.h>
#include <cuda_bf16.h>
#include <cuda_fp16.h>
#include <math_constants.h>
#include <stdint.h>

// Problem constants
#define NB   2
#define C    256
#define A    3
#define KTOP 20
#define D    256
#define BOXC 12
#define SUMHW 13600   // 10240 + 2560 + 640 + 160
#define WSPL 294912   // per-layer conv split-weight u32 count
#define WDNS 32768    // dense 256x256 split-weight u32 count
#define STILE 54      // ceil(SUMHW/256)

// ---------------- scratch (device globals) ----------------------------------
__device__ float g_t2p[NB * C * SUMHW];
__device__ float g_t2o[NB * C * SUMHW];
__device__ float g_h2[NB * 256 * SUMHW];
__device__ float g_cell[NB * SUMHW];
__device__ float g_cand_hid[NB * C * 80];
__device__ float g_cand_sc[NB * 80];
__device__ float g_pproj[NB * KTOP * D];
// split activations: [n][pair=128][SUMHW] u32
__device__ uint32_t g_sA_hi[NB * 128 * SUMHW];    // feats bf16 split (person)
__device__ uint32_t g_sA_lo[NB * 128 * SUMHW];
__device__ uint32_t g_sAf_hi[NB * 128 * SUMHW];   // feats fp16 split (object)
__device__ uint32_t g_sAf_lo[NB * 128 * SUMHW];
__device__ uint32_t g_sB_hi[NB * 128 * SUMHW];    // person conv1 out (bf16)
__device__ uint32_t g_sB_lo[NB * 128 * SUMHW];
__device__ uint32_t g_sD_hi[NB * 128 * SUMHW];    // object conv1 out (fp16)
__device__ uint32_t g_sD_lo[NB * 128 * SUMHW];
__device__ uint32_t g_sC_hi[NB * 128 * SUMHW];    // object conv2 out (fp16, for gemm)
__device__ uint32_t g_sC_lo[NB * 128 * SUMHW];
__device__ uint32_t g_hs_hi[NB * 128 * SUMHW];    // hsum out (fp16)
__device__ uint32_t g_hs_lo[NB * 128 * SUMHW];
// split weights (fragment order)
__device__ uint32_t g_wsp_hi[4 * WSPL];   // layers 0,1 bf16 ; layers 2,3 fp16
__device__ uint32_t g_wsp_lo[4 * WSPL];
__device__ uint32_t g_wd_hi[2 * WDNS];    // fp16: 0: Wo, 1: rn2
__device__ uint32_t g_wd_lo[2 * WDNS];

// per-scale constants
__device__ __constant__ int cOFF[4]  = {0, 10240, 12800, 13440};
__device__ __constant__ int cHW[4]   = {10240, 2560, 640, 160};
__device__ __constant__ int cH[4]    = {80, 40, 20, 10};
__device__ __constant__ int cW[4]    = {128, 64, 32, 16};
__device__ __constant__ int cPLOG[4] = {0,      61440,  76800,  80640};
__device__ __constant__ int cPDEL[4] = {81600,  327360, 388800, 404160};
__device__ __constant__ int cOLOG[4] = {408000, 469440, 484800, 488640};
__device__ __constant__ int cODEL[4] = {489600, 735360, 796800, 812160};

__device__ __forceinline__ int scale_of(int p) {
    return (p < 10240) ? 0 : (p < 12800) ? 1 : (p < 13440) ? 2 : 3;
}

// ---------------- mma / split helpers ---------------------------------------
__device__ __forceinline__ void mma_bf16(float* c, const uint32_t* a, const uint32_t* b) {
    asm volatile(
        "mma.sync.aligned.m16n8k16.row.col.f32.bf16.bf16.f32 "
        "{%0,%1,%2,%3}, {%4,%5,%6,%7}, {%8,%9}, {%0,%1,%2,%3};\n"
        : "+f"(c[0]), "+f"(c[1]), "+f"(c[2]), "+f"(c[3])
        : "r"(a[0]), "r"(a[1]), "r"(a[2]), "r"(a[3]), "r"(b[0]), "r"(b[1]));
}
__device__ __forceinline__ void mma_f16(float* c, const uint32_t* a, const uint32_t* b) {
    asm volatile(
        "mma.sync.aligned.m16n8k16.row.col.f32.f16.f16.f32 "
        "{%0,%1,%2,%3}, {%4,%5,%6,%7}, {%8,%9}, {%0,%1,%2,%3};\n"
        : "+f"(c[0]), "+f"(c[1]), "+f"(c[2]), "+f"(c[3])
        : "r"(a[0]), "r"(a[1]), "r"(a[2]), "r"(a[3]), "r"(b[0]), "r"(b[1]));
}
__device__ __forceinline__ void split_pack(float v0, float v1,
                                           uint32_t& hi_out, uint32_t& lo_out) {
    __nv_bfloat16 h0 = __float2bfloat16(v0);
    __nv_bfloat16 h1 = __float2bfloat16(v1);
    __nv_bfloat16 l0 = __float2bfloat16(v0 - __bfloat162float(h0));
    __nv_bfloat16 l1 = __float2bfloat16(v1 - __bfloat162float(h1));
    hi_out = ((uint32_t)__bfloat16_as_ushort(h1) << 16) | (uint32_t)__bfloat16_as_ushort(h0);
    lo_out = ((uint32_t)__bfloat16_as_ushort(l1) << 16) | (uint32_t)__bfloat16_as_ushort(l0);
}
__device__ __forceinline__ void split_pack_h(float v0, float v1,
                                             uint32_t& hi_out, uint32_t& lo_out) {
    __half h0 = __float2half(v0);
    __half h1 = __float2half(v1);
    __half l0 = __float2half(v0 - __half2float(h0));
    __half l1 = __float2half(v1 - __half2float(h1));
    hi_out = ((uint32_t)__half_as_ushort(h1) << 16) | (uint32_t)__half_as_ushort(h0);
    lo_out = ((uint32_t)__half_as_ushort(l1) << 16) | (uint32_t)__half_as_ushort(l0);
}
__device__ __forceinline__ uint32_t smem_addr_of(const void* p) {
    return (uint32_t)__cvta_generic_to_shared(p);
}
__device__ __forceinline__ void cp16(uint32_t dst, const void* src, bool pred) {
    asm volatile("cp.async.cg.shared.global [%0], [%1], 16, %2;"
                 :: "r"(dst), "l"(src), "r"(pred ? 16 : 0));
}
__device__ __forceinline__ void cp4(uint32_t dst, const void* src, bool pred) {
    asm volatile("cp.async.ca.shared.global [%0], [%1], 4, %2;"
                 :: "r"(dst), "l"(src), "r"(pred ? 4 : 0));
}
#define CP_COMMIT() asm volatile("cp.async.commit_group;" ::: "memory")
#define CP_WAIT(n)  asm volatile("cp.async.wait_group %0;" :: "n"(n) : "memory")

// ---------------- conv weight pre-split (fragment order) --------------------
__global__ __launch_bounds__(256)
void split_w_conv(const float* __restrict__ w0, const float* __restrict__ w1,
                  const float* __restrict__ w2, const float* __restrict__ w3,
                  uint32_t* __restrict__ outH, uint32_t* __restrict__ outL)
{
    const int i = blockIdx.x * 256 + threadIdx.x;
    if (i >= WSPL) return;
    const int layer = blockIdx.y;
    const float* w = (layer == 0) ? w0 : (layer == 1) ? w1 : (layer == 2) ? w2 : w3;
    const int e = i & 3;
    int j = i >> 2;
    const int slot = j & 31; j >>= 5;
    const int o4 = j & 3; j >>= 2;
    const int tap = j % 9; j /= 9;
    const int ocg = j & 3;
    const int q = j >> 2;
    const int g = ((slot >> 3) << 1) | (slot & 1);
    const int t = (slot >> 1) & 3;
    const int oc = ocg * 64 + o4 * 16 + g + (e & 1) * 8;
    const int p = t + ((e >> 1) << 2);
    const int ci0 = q * 16 + 2 * p;
    float v0 = w[(size_t)oc * 2304 + ci0 * 9 + tap];
    float v1 = w[(size_t)oc * 2304 + (ci0 + 1) * 9 + tap];
    uint32_t hi, lo;
    if (layer < 2) split_pack(v0, v1, hi, lo);
    else           split_pack_h(v0, v1, hi, lo);
    outH[(size_t)layer * WSPL + i] = hi;
    outL[(size_t)layer * WSPL + i] = lo;
}

// ---------------- dense weight pre-split (fp16, fragment order) -------------
__global__ __launch_bounds__(256)
void split_w_dense(const float* __restrict__ wA, const float* __restrict__ wB,
                   int strideA, int strideB,
                   uint32_t* __restrict__ outH, uint32_t* __restrict__ outL)
{
    const int i = blockIdx.x * 256 + threadIdx.x;
    if (i >= WDNS) return;
    const int which = blockIdx.y;
    const float* w = which ? wB : wA;
    const int stride = which ? strideB : strideA;
    const int e = i & 3;
    int j = i >> 2;
    const int slot = j & 31; j >>= 5;
    const int o4 = j & 3; j >>= 2;
    const int mg = j & 3;
    const int q = j >> 2;
    const int g = ((slot >> 3) << 1) | (slot & 1);
    const int t = (slot >> 1) & 3;
    const int m = mg * 64 + o4 * 16 + g + (e & 1) * 8;
    const int p = t + ((e >> 1) << 2);
    const int k0 = q * 16 + 2 * p;
    float v0 = w[(size_t)m * stride + k0];
    float v1 = w[(size_t)m * stride + k0 + 1];
    uint32_t hi, lo;
    split_pack_h(v0, v1, hi, lo);
    outH[(size_t)which * WDNS + i] = hi;
    outL[(size_t)which * WDNS + i] = lo;
}

// ---------------- feats pre-split (both formats) ----------------------------
__global__ __launch_bounds__(256)
void split_feats_kernel(const float* __restrict__ f0, const float* __restrict__ f1,
                        const float* __restrict__ f2, const float* __restrict__ f3,
                        uint32_t* __restrict__ outHb, uint32_t* __restrict__ outLb,
                        uint32_t* __restrict__ outHf, uint32_t* __restrict__ outLf)
{
    const int px = blockIdx.x * 256 + threadIdx.x;
    if (px >= SUMHW) return;
    const int c2 = blockIdx.y;
    const int n  = blockIdx.z;
    const int s = scale_of(px);
    const int ploc = px - cOFF[s];
    const int HW = cHW[s];
    const float* f = (s == 0) ? f0 : (s == 1) ? f1 : (s == 2) ? f2 : f3;
    const float* src = f + ((size_t)n * C + 2 * c2) * HW + ploc;
    float v0 = src[0], v1 = src[HW];
    const size_t o = ((size_t)n * 128 + c2) * SUMHW + px;
    uint32_t hi, lo;
    split_pack(v0, v1, hi, lo);
    outHb[o] = hi; outLb[o] = lo;
    split_pack_h(v0, v1, hi, lo);
    outHf[o] = hi; outLf[o] = lo;
}

// ---------------- conv3x3 dual-branch (validated R13 core) ------------------
// flags bit0: fp16 2-term compute; bit1: split output packed as fp16
#define IPAD 28
#define ST_IH 9216
#define ST_IL 11456
#define STG_U32 13696
#define CONV_SMEM (2 * STG_U32 * 4)   // 109568 B

__global__ __launch_bounds__(256, 2)
void conv3x3_dual(const uint32_t* __restrict__ in0H, const uint32_t* __restrict__ in0L,
                  const uint32_t* __restrict__ in1H, const uint32_t* __restrict__ in1L,
                  const uint32_t* __restrict__ wH0, const uint32_t* __restrict__ wL0,
                  const uint32_t* __restrict__ wH1, const uint32_t* __restrict__ wL1,
                  const float* __restrict__ bias0, const float* __restrict__ bias1,
                  float* __restrict__ dF0, uint32_t* __restrict__ dH0, uint32_t* __restrict__ dL0,
                  float* __restrict__ dF1, uint32_t* __restrict__ dH1, uint32_t* __restrict__ dL1,
                  int flags0, int flags1)
{
    extern __shared__ __align__(16) uint32_t smu[];
    __shared__ float s_bias[64];

    const int branch = blockIdx.z & 1;
    const int n = blockIdx.z >> 1;
    const uint32_t* inH = branch ? in1H : in0H;
    const uint32_t* inL = branch ? in1L : in0L;
    const uint32_t* wH  = branch ? wH1 : wH0;
    const uint32_t* wL  = branch ? wL1 : wL0;
    const float* bias   = branch ? bias1 : bias0;
    float* dstF    = branch ? dF1 : dF0;
    uint32_t* dstH = branch ? dH1 : dH0;
    uint32_t* dstL = branch ? dL1 : dL0;
    const int flags = branch ? flags1 : flags0;
    const bool f16c = (flags & 1) != 0;
    const bool sp16 = (flags & 2) != 0;

    const int bx = blockIdx.x;
    int s, t_;
    if (bx < 80)       { s = 0; t_ = bx; }
    else if (bx < 100) { s = 1; t_ = bx - 80; }
    else if (bx < 106) { s = 2; t_ = bx - 100; }
    else               { s = 3; t_ = bx - 106; }
    const int H = cH[s], W = cW[s];
    const int tilesX = W >> 4;
    const int ty = t_ / tilesX, tx = t_ % tilesX;
    const int h0 = ty * 8, w0 = tx * 16;
    const int ocg = blockIdx.y;
    const int ocBase = ocg * 64;

    const int tid  = threadIdx.x;
    const int warp = tid >> 5;
    const int oh = warp & 1;
    const int rw = warp >> 1;
    const int lane = tid & 31;
    const int g = lane >> 2;
    const int t = lane & 3;
    const int slot = ((g >> 1) << 3) | (t << 1) | (g & 1);

    if (tid < 64) s_bias[tid] = bias[ocBase + tid];

    float acc[2][2][2][4];
#pragma unroll
    for (int i = 0; i < 2; i++)
#pragma unroll
        for (int j = 0; j < 2; j++)
#pragma unroll
            for (int k = 0; k < 2; k++)
#pragma unroll
                for (int l = 0; l < 4; l++) acc[i][j][k][l] = 0.f;

    const uint32_t smbase = smem_addr_of(smu);
    const int wcnt = f16c ? 1152 : 2304;

    auto fill = [&](int q, int st) {
        const uint32_t sb = smbase + (uint32_t)st * STG_U32 * 4;
        const uint4* wH4 = (const uint4*)wH + (size_t)(q * 4 + ocg) * 1152;
        const uint4* wL4 = (const uint4*)wL + (size_t)(q * 4 + ocg) * 1152;
        for (int j = tid; j < wcnt; j += 256) {
            const uint4* src = (j < 1152) ? (wH4 + j) : (wL4 + (j - 1152));
            cp16(sb + j * 16, src, true);
        }
        for (int j = tid; j < 960; j += 256) {
            int slotc = j % 6;
            int rest = j / 6;
            int arr = rest & 1;
            int pr = rest >> 1;
            int p = pr / 10, r = pr % 10;
            int gh = h0 + r - 1;
            bool rowok = (gh >= 0) && (gh < H);
            int ghc = min(max(gh, 0), H - 1);
            size_t rowoff = ((size_t)n * 128 + q * 8 + p) * SUMHW + cOFF[s] + (size_t)ghc * W;
            const uint32_t* gsrc = arr ? inL : inH;
            uint32_t dstrow = sb + (uint32_t)((arr ? ST_IL : ST_IH) + (p * 10 + r) * IPAD) * 4;
            if (slotc < 4) {
                int c0 = slotc * 4;
                cp16(dstrow + (uint32_t)(4 + c0) * 4, gsrc + rowoff + w0 + c0, rowok);
            } else if (slotc == 4) {
                bool ok = rowok && (w0 > 0);
                cp4(dstrow + 3 * 4, gsrc + rowoff + (ok ? (w0 - 1) : w0), ok);
            } else {
                bool ok = rowok && (w0 + 16 < W);
                cp4(dstrow + 20 * 4, gsrc + rowoff + w0 + (ok ? 16 : 0), ok);
            }
        }
    };

    fill(0, 0);
    CP_COMMIT();

    for (int q = 0; q < 16; q++) {
        if (q < 15) { fill(q + 1, (q + 1) & 1); CP_COMMIT(); CP_WAIT(1); }
        else        { CP_WAIT(0); }
        __syncthreads();

        const uint32_t* sb = smu + (q & 1) * STG_U32;
        const uint4* s_w4H = (const uint4*)sb;
        const uint4* s_w4L = s_w4H + 1152;
        const uint32_t* s_iH = sb + ST_IH;
        const uint32_t* s_iL = sb + ST_IL;

#pragma unroll
        for (int kh = 0; kh < 3; kh++)
#pragma unroll
        for (int kw = 0; kw < 3; kw++) {
            const int tap = kh * 3 + kw;
            uint32_t bh[2][2][2], bl[2][2][2];
#pragma unroll
            for (int rr = 0; rr < 2; rr++) {
                const int row = 2 * rw + rr;
                const int ib0 = (t * 10 + row + kh) * IPAD + kw + 3 + g;
                const int ib1 = ((t + 4) * 10 + row + kh) * IPAD + kw + 3 + g;
#pragma unroll
                for (int p4 = 0; p4 < 2; p4++) {
                    bh[rr][p4][0] = s_iH[ib0 + p4 * 8];
                    bh[rr][p4][1] = s_iH[ib1 + p4 * 8];
                    bl[rr][p4][0] = s_iL[ib0 + p4 * 8];
                    bl[rr][p4][1] = s_iL[ib1 + p4 * 8];
                }
            }
#pragma unroll
            for (int o4l = 0; o4l < 2; o4l++) {
                const int o4g = oh * 2 + o4l;
                uint4 a4 = s_w4H[(tap * 4 + o4g) * 32 + slot];
                uint32_t ah[4] = {a4.x, a4.y, a4.z, a4.w};
                if (!f16c) {
                    uint4 b4 = s_w4L[(tap * 4 + o4g) * 32 + slot];
                    uint32_t al[4] = {b4.x, b4.y, b4.z, b4.w};
#pragma unroll
                    for (int rr = 0; rr < 2; rr++)
#pragma unroll
                        for (int p4 = 0; p4 < 2; p4++) {
                            mma_bf16(acc[o4l][rr][p4], ah, bh[rr][p4]);
                            mma_bf16(acc[o4l][rr][p4], ah, bl[rr][p4]);
                            mma_bf16(acc[o4l][rr][p4], al, bh[rr][p4]);
                        }
                } else {
#pragma unroll
                    for (int rr = 0; rr < 2; rr++)
#pragma unroll
                        for (int p4 = 0; p4 < 2; p4++) {
                            mma_f16(acc[o4l][rr][p4], ah, bh[rr][p4]);
                            mma_f16(acc[o4l][rr][p4], ah, bl[rr][p4]);
                        }
                }
            }
        }
        __syncthreads();
    }

    if (dstF) {
#pragma unroll
        for (int rr = 0; rr < 2; rr++) {
            const int ghout = h0 + 2 * rw + rr;
            if (ghout >= H) continue;
            float* dbase = dstF + (size_t)n * C * SUMHW + cOFF[s] + (size_t)ghout * W + w0;
#pragma unroll
            for (int o4l = 0; o4l < 2; o4l++) {
                int ocl = (oh * 2 + o4l) * 16 + g;
                float b0v = s_bias[ocl];
                float b1v = s_bias[ocl + 8];
#pragma unroll
                for (int p4 = 0; p4 < 2; p4++) {
                    int col = p4 * 8 + 2 * t;
                    float2 v0 = make_float2(fmaxf(acc[o4l][rr][p4][0] + b0v, 0.f),
                                            fmaxf(acc[o4l][rr][p4][1] + b0v, 0.f));
                    float2 v1 = make_float2(fmaxf(acc[o4l][rr][p4][2] + b1v, 0.f),
                                            fmaxf(acc[o4l][rr][p4][3] + b1v, 0.f));
                    *(float2*)(dbase + (size_t)(ocBase + ocl) * SUMHW + col) = v0;
                    *(float2*)(dbase + (size_t)(ocBase + ocl + 8) * SUMHW + col) = v1;
                }
            }
        }
    }
    if (dstH) {
#pragma unroll
        for (int rr = 0; rr < 2; rr++) {
            const int ghout = h0 + 2 * rw + rr;
            const size_t base = ((size_t)n * 128) * SUMHW + cOFF[s] + (size_t)ghout * W + w0;
#pragma unroll
            for (int o4l = 0; o4l < 2; o4l++) {
                int ocl = (oh * 2 + o4l) * 16 + g;
                float b0v = s_bias[ocl];
                float b1v = s_bias[ocl + 8];
                const size_t w2a = (size_t)((ocBase + ocl) >> 1) * SUMHW;
                const size_t w2b = (size_t)(((ocBase + ocl) >> 1) + 4) * SUMHW;
#pragma unroll
                for (int p4 = 0; p4 < 2; p4++) {
                    int col = p4 * 8 + 2 * t;
                    float v0 = fmaxf(acc[o4l][rr][p4][0] + b0v, 0.f);
                    float v1 = fmaxf(acc[o4l][rr][p4][1] + b0v, 0.f);
                    float v2 = fmaxf(acc[o4l][rr][p4][2] + b1v, 0.f);
                    float v3 = fmaxf(acc[o4l][rr][p4][3] + b1v, 0.f);
                    float p0 = __shfl_xor_sync(0xFFFFFFFFu, v0, 4);
                    float p1 = __shfl_xor_sync(0xFFFFFFFFu, v1, 4);
                    float p2 = __shfl_xor_sync(0xFFFFFFFFu, v2, 4);
                    float p3 = __shfl_xor_sync(0xFFFFFFFFu, v3, 4);
                    if (((g & 1) == 0) && ghout < H) {
                        uint32_t hw, lw;
                        if (sp16) split_pack_h(v0, p0, hw, lw);
                        else      split_pack(v0, p0, hw, lw);
                        dstH[base + w2a + col] = hw;  dstL[base + w2a + col] = lw;
                        if (sp16) split_pack_h(v1, p1, hw, lw);
                        else      split_pack(v1, p1, hw, lw);
                        dstH[base + w2a + col + 1] = hw;  dstL[base + w2a + col + 1] = lw;
                        if (sp16) split_pack_h(v2, p2, hw, lw);
                        else      split_pack(v2, p2, hw, lw);
                        dstH[base + w2b + col] = hw;  dstL[base + w2b + col] = lw;
                        if (sp16) split_pack_h(v3, p3, hw, lw);
                        else      split_pack(v3, p3, hw, lw);
                        dstH[base + w2b + col + 1] = hw;  dstL[base + w2b + col + 1] = lw;
                    }
                }
            }
        }
    }
}

// ---------------- dense GEMM core (fp16 2-term) ------------------------------
#define GIPAD 264
#define GST_U32 5248

// rn2 GEMM: out[n][m][s] = relu(W hs + bias), fp16 2-term
__global__ __launch_bounds__(256, 2)
void gemm_mma(const uint32_t* __restrict__ wH,
              const uint32_t* __restrict__ bHg, const uint32_t* __restrict__ bLg,
              const float* __restrict__ bias, float* __restrict__ outp)
{
    __shared__ __align__(16) uint32_t gsm[2 * GST_U32];

    const int s0 = blockIdx.x * 256;
    const int mg = blockIdx.y;
    const int n  = blockIdx.z;
    const int tid = threadIdx.x;
    const int warp = tid >> 5;
    const int lane = tid & 31;
    const int g = lane >> 2;
    const int t = lane & 3;
    const int slot = ((g >> 1) << 3) | (t << 1) | (g & 1);

    float acc[4][4][4];
#pragma unroll
    for (int i = 0; i < 4; i++)
#pragma unroll
        for (int j = 0; j < 4; j++)
#pragma unroll
            for (int k = 0; k < 4; k++) acc[i][j][k] = 0.f;

    const uint32_t smbase = smem_addr_of(gsm);

    auto fill = [&](int q, int st) {
        const uint32_t sb = smbase + (uint32_t)st * GST_U32 * 4;
        const uint4* wH4 = (const uint4*)wH + (size_t)(q * 4 + mg) * 128;
        if (tid < 128) cp16(sb + tid * 16, wH4 + tid, true);
        for (int j = tid; j < 1024; j += 256) {
            int c = j & 63;
            int rest = j >> 6;
            int arr = rest & 1;
            int p = rest >> 1;
            int sx = s0 + c * 4;
            bool ok = sx < SUMHW;
            size_t off = ((size_t)n * 128 + q * 8 + p) * SUMHW + (ok ? sx : 0);
            const uint32_t* gsrc = arr ? bLg : bHg;
            uint32_t dst = sb + (uint32_t)(1024 + arr * 2112 + p * GIPAD + c * 4) * 4;
            cp16(dst, gsrc + off, ok);
        }
    };

    fill(0, 0);
    CP_COMMIT();

    for (int q = 0; q < 16; q++) {
        if (q < 15) { fill(q + 1, (q + 1) & 1); CP_COMMIT(); CP_WAIT(1); }
        else        { CP_WAIT(0); }
        __syncthreads();

        const uint32_t* sb = gsm + (q & 1) * GST_U32;
        const uint4* s_aH4 = (const uint4*)sb;
        const uint32_t* s_iH = sb + 1024;
        const uint32_t* s_iL = sb + 3136;

        uint32_t bh[4][2], bl[4][2];
        const int ib0 = t * GIPAD + warp * 32 + g;
        const int ib1 = (t + 4) * GIPAD + warp * 32 + g;
#pragma unroll
        for (int p4 = 0; p4 < 4; p4++) {
            bh[p4][0] = s_iH[ib0 + p4 * 8];
            bh[p4][1] = s_iH[ib1 + p4 * 8];
            bl[p4][0] = s_iL[ib0 + p4 * 8];
            bl[p4][1] = s_iL[ib1 + p4 * 8];
        }
#pragma unroll
        for (int o4 = 0; o4 < 4; o4++) {
            uint4 a4 = s_aH4[o4 * 32 + slot];
            uint32_t ah[4] = {a4.x, a4.y, a4.z, a4.w};
#pragma unroll
            for (int p4 = 0; p4 < 4; p4++) {
                mma_f16(acc[o4][p4], ah, bh[p4]);
                mma_f16(acc[o4][p4], ah, bl[p4]);
            }
        }
        __syncthreads();
    }

#pragma unroll
    for (int o4 = 0; o4 < 4; o4++) {
        int m0 = mg * 64 + o4 * 16 + g;
        float b0v = bias[m0];
        float b1v = bias[m0 + 8];
#pragma unroll
        for (int p4 = 0; p4 < 4; p4++) {
            int sx = s0 + warp * 32 + p4 * 8 + 2 * t;
            if (sx < SUMHW) {
                float v0 = fmaxf(acc[o4][p4][0] + b0v, 0.f);
                float v1 = fmaxf(acc[o4][p4][1] + b0v, 0.f);
                float v2 = fmaxf(acc[o4][p4][2] + b1v, 0.f);
                float v3 = fmaxf(acc[o4][p4][3] + b1v, 0.f);
                *(float2*)(outp + ((size_t)n * 256 + m0) * SUMHW + sx) = make_float2(v0, v1);
                *(float2*)(outp + ((size_t)n * 256 + m0 + 8) * SUMHW + sx) = make_float2(v2, v3);
            }
        }
    }
}

// o_proj GEMM fused with hsum (fp16 2-term, hs out fp16)
__global__ __launch_bounds__(256, 2)
void gemm_oproj_hsum(const uint32_t* __restrict__ wH,
                     const uint32_t* __restrict__ bHg, const uint32_t* __restrict__ bLg,
                     const float* __restrict__ pproj,
                     uint32_t* __restrict__ hsH, uint32_t* __restrict__ hsL)
{
    __shared__ __align__(16) uint32_t gsm[2 * GST_U32];
    __shared__ float spp[KTOP * 64];

    const int s0 = blockIdx.x * 256;
    const int mg = blockIdx.y;
    const int n  = blockIdx.z;
    const int tid = threadIdx.x;
    const int warp = tid >> 5;
    const int lane = tid & 31;
    const int g = lane >> 2;
    const int t = lane & 3;
    const int slot = ((g >> 1) << 3) | (t << 1) | (g & 1);

    for (int i = tid; i < KTOP * 64; i += 256) {
        int k = i >> 6, dl = i & 63;
        spp[i] = pproj[((size_t)n * KTOP + k) * D + mg * 64 + dl];
    }

    float acc[4][4][4];
#pragma unroll
    for (int i = 0; i < 4; i++)
#pragma unroll
        for (int j = 0; j < 4; j++)
#pragma unroll
            for (int k = 0; k < 4; k++) acc[i][j][k] = 0.f;

    const uint32_t smbase = smem_addr_of(gsm);

    auto fill = [&](int q, int st) {
        const uint32_t sb = smbase + (uint32_t)st * GST_U32 * 4;
        const uint4* wH4 = (const uint4*)wH + (size_t)(q * 4 + mg) * 128;
        if (tid < 128) cp16(sb + tid * 16, wH4 + tid, true);
        for (int j = tid; j < 1024; j += 256) {
            int c = j & 63;
            int rest = j >> 6;
            int arr = rest & 1;
            int p = rest >> 1;
            int sx = s0 + c * 4;
            bool ok = sx < SUMHW;
            size_t off = ((size_t)n * 128 + q * 8 + p) * SUMHW + (ok ? sx : 0);
            const uint32_t* gsrc = arr ? bLg : bHg;
            uint32_t dst = sb + (uint32_t)(1024 + arr * 2112 + p * GIPAD + c * 4) * 4;
            cp16(dst, gsrc + off, ok);
        }
    };

    fill(0, 0);
    CP_COMMIT();

    for (int q = 0; q < 16; q++) {
        if (q < 15) { fill(q + 1, (q + 1) & 1); CP_COMMIT(); CP_WAIT(1); }
        else        { CP_WAIT(0); }
        __syncthreads();

        const uint32_t* sb = gsm + (q & 1) * GST_U32;
        const uint4* s_aH4 = (const uint4*)sb;
        const uint32_t* s_iH = sb + 1024;
        const uint32_t* s_iL = sb + 3136;

        uint32_t bh[4][2], bl[4][2];
        const int ib0 = t * GIPAD + warp * 32 + g;
        const int ib1 = (t + 4) * GIPAD + warp * 32 + g;
#pragma unroll
        for (int p4 = 0; p4 < 4; p4++) {
            bh[p4][0] = s_iH[ib0 + p4 * 8];
            bh[p4][1] = s_iH[ib1 + p4 * 8];
            bl[p4][0] = s_iL[ib0 + p4 * 8];
            bl[p4][1] = s_iL[ib1 + p4 * 8];
        }
#pragma unroll
        for (int o4 = 0; o4 < 4; o4++) {
            uint4 a4 = s_aH4[o4 * 32 + slot];
            uint32_t ah[4] = {a4.x, a4.y, a4.z, a4.w};
#pragma unroll
            for (int p4 = 0; p4 < 4; p4++) {
                mma_f16(acc[o4][p4], ah, bh[p4]);
                mma_f16(acc[o4][p4], ah, bl[p4]);
            }
        }
        __syncthreads();
    }

#pragma unroll
    for (int o4 = 0; o4 < 4; o4++) {
        const int m0l = o4 * 16 + g;
        const int m0  = mg * 64 + m0l;
        float pp0[KTOP], pp1[KTOP];
#pragma unroll
        for (int k = 0; k < KTOP; k++) {
            pp0[k] = spp[k * 64 + m0l];
            pp1[k] = spp[k * 64 + m0l + 8];
        }
        const size_t w2a = (size_t)(m0 >> 1) * SUMHW;
        const size_t w2b = (size_t)((m0 >> 1) + 4) * SUMHW;
        const size_t nb = (size_t)n * 128 * SUMHW;
#pragma unroll
        for (int p4 = 0; p4 < 4; p4++) {
            int sx = s0 + warp * 32 + p4 * 8 + 2 * t;
            float a0 = 0.f, a1 = 0.f, a2 = 0.f, a3 = 0.f;
#pragma unroll 4
            for (int k = 0; k < KTOP; k++) {
                a0 += fmaxf(acc[o4][p4][0] + pp0[k], 0.f);
                a1 += fmaxf(acc[o4][p4][1] + pp0[k], 0.f);
                a2 += fmaxf(acc[o4][p4][2] + pp1[k], 0.f);
                a3 += fmaxf(acc[o4][p4][3] + pp1[k], 0.f);
            }
            float q0 = __shfl_xor_sync(0xFFFFFFFFu, a0, 4);
            float q1 = __shfl_xor_sync(0xFFFFFFFFu, a1, 4);
            float q2 = __shfl_xor_sync(0xFFFFFFFFu, a2, 4);
            float q3 = __shfl_xor_sync(0xFFFFFFFFu, a3, 4);
            if (((g & 1) == 0) && sx < SUMHW) {
                uint32_t hw, lw;
                split_pack_h(a0, q0, hw, lw);
                hsH[nb + w2a + sx] = hw;      hsL[nb + w2a + sx] = lw;
                split_pack_h(a1, q1, hw, lw);
                hsH[nb + w2a + sx + 1] = hw;  hsL[nb + w2a + sx + 1] = lw;
                split_pack_h(a2, q2, hw, lw);
                hsH[nb + w2b + sx] = hw;      hsL[nb + w2b + sx] = lw;
                split_pack_h(a3, q3, hw, lw);
                hsH[nb + w2b + sx + 1] = hw;  hsL[nb + w2b + sx + 1] = lw;
            }
        }
    }
}

// ---------------- merged heads (person + object delta) ----------------------
__global__ __launch_bounds__(256)
void heads_all(const float* __restrict__ t2p, const float* __restrict__ t2o,
               const float* __restrict__ pl_w, const float* __restrict__ pl_b,
               const float* __restrict__ pd_w, const float* __restrict__ pd_b,
               const float* __restrict__ od_w, const float* __restrict__ od_b,
               float* __restrict__ out, float* __restrict__ cell)
{
    const int branch = blockIdx.y & 1;
    const int n = blockIdx.y >> 1;
    const int tid = threadIdx.x;
    __shared__ float swl[A * C];
    __shared__ float swd[BOXC * C];
    if (branch == 0) {
        for (int i = tid; i < A * C; i += 256) swl[i] = pl_w[i];
        for (int i = tid; i < BOXC * C; i += 256) swd[i] = pd_w[i];
    } else {
        for (int i = tid; i < BOXC * C; i += 256) swd[i] = od_w[i];
    }
    __syncthreads();

    const int p = blockIdx.x * 256 + tid;
    if (p >= SUMHW) return;
    const int s = scale_of(p);
    const int ploc = p - cOFF[s];
    const int HW = cHW[s];

    if (branch == 0) {
        const float* h = t2p + (size_t)n * C * SUMHW + p;
        float accl[A], accd[BOXC];
#pragma unroll
        for (int a = 0; a < A; a++) accl[a] = pl_b[a];
#pragma unroll
        for (int j = 0; j < BOXC; j++) accd[j] = pd_b[j];
        for (int c = 0; c < C; c++) {
            float v = h[(size_t)c * SUMHW];
#pragma unroll
            for (int a = 0; a < A; a++) accl[a] += swl[a * C + c] * v;
#pragma unroll
            for (int j = 0; j < BOXC; j++) accd[j] += swd[j * C + c] * v;
        }
        float m = accl[0];
#pragma unroll
        for (int a = 0; a < A; a++) {
            out[cPLOG[s] + ((size_t)n * A + a) * HW + ploc] = accl[a];
            m = fmaxf(m, accl[a]);
        }
#pragma unroll
        for (int j = 0; j < BOXC; j++)
            out[cPDEL[s] + ((size_t)n * BOXC + j) * HW + ploc] = accd[j];
        cell[(size_t)n * SUMHW + p] = m;
    } else {
        const float* h = t2o + (size_t)n * C * SUMHW + p;
        float accd[BOXC];
#pragma unroll
        for (int j = 0; j < BOXC; j++) accd[j] = od_b[j];
        for (int c = 0; c < C; c++) {
            float v = h[(size_t)c * SUMHW];
#pragma unroll
            for (int j = 0; j < BOXC; j++) accd[j] += swd[j * C + c] * v;
        }
#pragma unroll
        for (int j = 0; j < BOXC; j++)
            out[cODEL[s] + ((size_t)n * BOXC + j) * HW + ploc] = accd[j];
    }
}

// ---------------- per-scale top-K (1024 threads, warp-shuffle reduce) -------
__global__ __launch_bounds__(1024)
void topk_flat(const float* __restrict__ cell, const float* __restrict__ hid,
               float* __restrict__ cand_hid, float* __restrict__ cand_sc)
{
    const int s = blockIdx.x;
    const int n = blockIdx.y;
    const int HW = cHW[s], off = cOFF[s];
    __shared__ float sc[10240];
    __shared__ float w_val[32];
    __shared__ int   w_idx[32];
    __shared__ int   sel[KTOP];
    const int tid = threadIdx.x;
    const int lane = tid & 31, wid = tid >> 5;

    for (int i = tid; i < HW; i += 1024)
        sc[i] = cell[(size_t)n * SUMHW + off + i];
    __syncthreads();

    for (int k = 0; k < KTOP; k++) {
        float best = -CUDART_INF_F;
        int bi = HW;
        for (int i = tid; i < HW; i += 1024) {
            float v = sc[i];
            if (v > best) { best = v; bi = i; }
        }
#pragma unroll
        for (int o = 16; o > 0; o >>= 1) {
            float v2 = __shfl_down_sync(0xFFFFFFFFu, best, o);
            int   i2 = __shfl_down_sync(0xFFFFFFFFu, bi, o);
            if (v2 > best || (v2 == best && i2 < bi)) { best = v2; bi = i2; }
        }
        if (lane == 0) { w_val[wid] = best; w_idx[wid] = bi; }
        __syncthreads();
        if (wid == 0) {
            best = w_val[lane]; bi = w_idx[lane];
#pragma unroll
            for (int o = 16; o > 0; o >>= 1) {
                float v2 = __shfl_down_sync(0xFFFFFFFFu, best, o);
                int   i2 = __shfl_down_sync(0xFFFFFFFFu, bi, o);
                if (v2 > best || (v2 == best && i2 < bi)) { best = v2; bi = i2; }
            }
            if (lane == 0) {
                sel[k] = bi;
                cand_sc[(size_t)n * 80 + s * KTOP + k] = best;
                sc[bi] = -CUDART_INF_F;
            }
        }
        __syncthreads();
    }
    for (int idx = tid; idx < C * KTOP; idx += 1024) {
        int c = idx / KTOP, k = idx % KTOP;
        cand_hid[((size_t)n * C + c) * 80 + s * KTOP + k] =
            hid[((size_t)n * C + c) * SUMHW + off + sel[k]];
    }
}

// ---------------- p_proj (inlines global top-K) ------------------------------
__global__ __launch_bounds__(256)
void pproj_kernel(const float* __restrict__ cand_hid, const float* __restrict__ cand_sc,
                  const float* __restrict__ rn1_w, const float* __restrict__ rn1_b,
                  float* __restrict__ pproj)
{
    const int k = blockIdx.x, n = blockIdx.y, d = threadIdx.x;
    __shared__ float sh[C];
    __shared__ int s_col;
    if (d == 0) {
        // deterministic 20-of-80 selection, same as lax.top_k tie-break
        const float* sl = cand_sc + (size_t)n * 80;
        bool used[80];
        for (int i = 0; i < 80; i++) used[i] = false;
        int bi = 0;
        for (int kk = 0; kk <= k; kk++) {
            float best = -CUDART_INF_F; bi = 0;
            for (int i = 0; i < 80; i++)
                if (!used[i] && sl[i] > best) { best = sl[i]; bi = i; }
            used[bi] = true;
        }
        s_col = bi;
    }
    __syncthreads();
    const int col = s_col;
    sh[d] = cand_hid[((size_t)n * C + d) * 80 + col];
    __syncthreads();
    float acc = rn1_b[d];
    const float* wrow = rn1_w + (size_t)d * (2 * C) + C;   // Wp
    for (int c = 0; c < C; c++) acc += sh[c] * wrow[c];
    pproj[((size_t)n * KTOP + k) * D + d] = acc;
}

// ---------------- ol head (transposed h2 [n][e][s]) -------------------------
__global__ __launch_bounds__(256)
void ol_t(const float* __restrict__ h2, const float* __restrict__ ol_w,
          const float* __restrict__ ol_b, float* __restrict__ out)
{
    __shared__ float sw[A * 256];
    const int n = blockIdx.y;
    const int tid = threadIdx.x;
    for (int i = tid; i < A * 256; i += 256) sw[i] = ol_w[i];
    __syncthreads();
    const int s = blockIdx.x * 256 + tid;
    if (s >= SUMHW) return;
    float a0 = 0.f, a1 = 0.f, a2 = 0.f;
    for (int e = 0; e < 256; e++) {
        float v = h2[((size_t)n * 256 + e) * SUMHW + s];
        a0 += v * sw[e];
        a1 += v * sw[256 + e];
        a2 += v * sw[512 + e];
    }
    const int sc = scale_of(s);
    const int ploc = s - cOFF[sc];
    const int HW = cHW[sc];
    out[cOLOG[sc] + ((size_t)n * A + 0) * HW + ploc] = a0 + ol_b[0];
    out[cOLOG[sc] + ((size_t)n * A + 1) * HW + ploc] = a1 + ol_b[1];
    out[cOLOG[sc] + ((size_t)n * A + 2) * HW + ploc] = a2 + ol_b[2];
}

// ---------------------------- host orchestration ----------------------------
extern "C" void kernel_launch(void* const* d_in, const int* in_sizes, int n_in,
                              void* d_out, int out_size)
{
    const float* f0 = (const float*)d_in[0];
    const float* f1 = (const float*)d_in[1];
    const float* f2 = (const float*)d_in[2];
    const float* f3 = (const float*)d_in[3];
    const float* pc1_w = (const float*)d_in[4];
    const float* pc1_b = (const float*)d_in[5];
    const float* pc2_w = (const float*)d_in[6];
    const float* pc2_b = (const float*)d_in[7];
    const float* oc1_w = (const float*)d_in[8];
    const float* oc1_b = (const float*)d_in[9];
    const float* oc2_w = (const float*)d_in[10];
    const float* oc2_b = (const float*)d_in[11];
    const float* rn1_w = (const float*)d_in[12];
    const float* rn1_b = (const float*)d_in[13];
    const float* rn2_w = (const float*)d_in[14];
    const float* rn2_b = (const float*)d_in[15];
    const float* pl_w  = (const float*)d_in[16];
    const float* pl_b  = (const float*)d_in[17];
    const float* pd_w  = (const float*)d_in[18];
    const float* pd_b  = (const float*)d_in[19];
    const float* ol_w  = (const float*)d_in[20];
    const float* ol_b  = (const float*)d_in[21];
    const float* od_w  = (const float*)d_in[22];
    const float* od_b  = (const float*)d_in[23];
    float* out = (float*)d_out;

    float *t2p, *t2o, *h2, *cell, *cand_hid, *cand_sc, *pproj;
    uint32_t *sAh, *sAl, *sAfh, *sAfl, *sBh, *sBl, *sDh, *sDl, *sCh, *sCl,
             *hsh, *hsl, *wsh, *wsl, *wdh, *wdl;
    cudaGetSymbolAddress((void**)&t2p, g_t2p);
    cudaGetSymbolAddress((void**)&t2o, g_t2o);
    cudaGetSymbolAddress((void**)&h2, g_h2);
    cudaGetSymbolAddress((void**)&cell, g_cell);
    cudaGetSymbolAddress((void**)&cand_hid, g_cand_hid);
    cudaGetSymbolAddress((void**)&cand_sc, g_cand_sc);
    cudaGetSymbolAddress((void**)&pproj, g_pproj);
    cudaGetSymbolAddress((void**)&sAh, g_sA_hi);
    cudaGetSymbolAddress((void**)&sAl, g_sA_lo);
    cudaGetSymbolAddress((void**)&sAfh, g_sAf_hi);
    cudaGetSymbolAddress((void**)&sAfl, g_sAf_lo);
    cudaGetSymbolAddress((void**)&sBh, g_sB_hi);
    cudaGetSymbolAddress((void**)&sBl, g_sB_lo);
    cudaGetSymbolAddress((void**)&sDh, g_sD_hi);
    cudaGetSymbolAddress((void**)&sDl, g_sD_lo);
    cudaGetSymbolAddress((void**)&sCh, g_sC_hi);
    cudaGetSymbolAddress((void**)&sCl, g_sC_lo);
    cudaGetSymbolAddress((void**)&hsh, g_hs_hi);
    cudaGetSymbolAddress((void**)&hsl, g_hs_lo);
    cudaGetSymbolAddress((void**)&wsh, g_wsp_hi);
    cudaGetSymbolAddress((void**)&wsl, g_wsp_lo);
    cudaGetSymbolAddress((void**)&wdh, g_wd_hi);
    cudaGetSymbolAddress((void**)&wdl, g_wd_lo);

    cudaFuncSetAttribute(conv3x3_dual,
                         cudaFuncAttributeMaxDynamicSharedMemorySize, CONV_SMEM);

    const dim3 convGrid(108, 4, NB * 2);
    const dim3 headGrid((SUMHW + 255) / 256, NB * 2);
    const dim3 gemmGrid(STILE, 4, NB);

    // ---- prep: split weights + feats ----
    split_w_conv<<<dim3((WSPL + 255) / 256, 4), 256>>>(pc1_w, pc2_w, oc1_w, oc2_w, wsh, wsl);
    split_w_dense<<<dim3((WDNS + 255) / 256, 2), 256>>>(rn1_w, rn2_w, 2 * C, D, wdh, wdl);
    split_feats_kernel<<<dim3((SUMHW + 255) / 256, 128, NB), 256>>>(
        f0, f1, f2, f3, sAh, sAl, sAfh, sAfl);

    // ---- layer 1: person bf16 3-term -> sB(bf16); object fp16 2-term -> sD(fp16)
    conv3x3_dual<<<convGrid, 256, CONV_SMEM>>>(
        sAh, sAl, sAfh, sAfl,
        wsh, wsl, wsh + 2 * WSPL, wsl + 2 * WSPL,
        pc1_b, oc1_b,
        nullptr, sBh, sBl,
        nullptr, sDh, sDl,
        /*flags0=*/0, /*flags1=*/3);
    // ---- layer 2: person bf16 -> t2p; object fp16 -> t2o + sC(fp16)
    conv3x3_dual<<<convGrid, 256, CONV_SMEM>>>(
        sBh, sBl, sDh, sDl,
        wsh + WSPL, wsl + WSPL, wsh + 3 * WSPL, wsl + 3 * WSPL,
        pc2_b, oc2_b,
        t2p, nullptr, nullptr,
        t2o, sCh, sCl,
        /*flags0=*/0, /*flags1=*/3);

    // ---- heads (both branches) ----
    heads_all<<<headGrid, 256>>>(t2p, t2o, pl_w, pl_b, pd_w, pd_b, od_w, od_b, out, cell);

    // ---- person relational path ----
    topk_flat<<<dim3(4, NB), 1024>>>(cell, t2p, cand_hid, cand_sc);
    pproj_kernel<<<dim3(KTOP, NB), 256>>>(cand_hid, cand_sc, rn1_w, rn1_b, pproj);

    // ---- object relational path (fp16 2-term GEMMs) ----
    gemm_oproj_hsum<<<gemmGrid, 256>>>(wdh, sCh, sCl, pproj, hsh, hsl);
    gemm_mma<<<gemmGrid, 256>>>(wdh + WDNS, hsh, hsl, rn2_b, h2);
    ol_t<<<dim3(STILE, NB), 256>>>(h2, ol_w, ol_b, out);

    (void)in_sizes; (void)n_in; (void)out_size;
}